// round 4
// baseline (speedup 1.0000x reference)
#include <cuda_runtime.h>
#include <math.h>

#define BB 4
#define CIN 64
#define CHID 96
#define LL 4096
#define NN 16
#define RR 6
#define KK 4
#define DN 192
#define SEG 8
#define SEGLEN 512

// ---------------- static scratch (no allocation anywhere) ----------------
__device__ float g_diff [BB*CIN*LL];
__device__ float g_gate [BB*CIN*LL];
__device__ float g_d1   [BB*LL*CHID];
__device__ float g_xln  [BB*LL*CHID];
__device__ float g_xc   [BB*DN*LL];
__device__ float g_xcv  [BB*DN*LL];
__device__ float g_z    [BB*LL*DN];
__device__ float g_xs   [BB*KK*LL*DN];
__device__ float g_delta[BB*KK*LL*DN];
__device__ float g_bs   [BB*KK*LL*NN];
__device__ float g_cs   [BB*KK*LL*NN];
__device__ float g_ys   [BB*KK*LL*DN];
__device__ float g_yln  [BB*LL*DN];
__device__ float g_dd   [BB*LL*CHID];
__device__ float g_P [BB*KK*DN*(SEG-1)*NN];
__device__ float g_q [BB*KK*DN*(SEG-1)*NN];
__device__ float g_h0[BB*KK*DN*SEG*NN];

__device__ __forceinline__ float sigm(float x){ return 1.f/(1.f+__expf(-x)); }
__device__ __forceinline__ float siluf(float x){ return x*sigm(x); }

// ---------------- kDiff ----------------
__global__ void kDiff(const float* __restrict__ pre, const float* __restrict__ post){
    int i = blockIdx.x*blockDim.x + threadIdx.x;
    const float4 a = ((const float4*)pre)[i];
    const float4 b = ((const float4*)post)[i];
    float4 r;
    r.x = fabsf(b.x-a.x); r.y = fabsf(b.y-a.y);
    r.z = fabsf(b.z-a.z); r.w = fabsf(b.w-a.w);
    ((float4*)g_diff)[i] = r;
}

// ---------------- kGate2 ----------------
__global__ void kGate2(const float* __restrict__ pre, const float* __restrict__ post,
                       const float* __restrict__ w, const float* __restrict__ bias,
                       const float* __restrict__ bng, const float* __restrict__ bnb){
    __shared__ float sW[CIN*CIN];
    __shared__ float sP[CIN*32];
    __shared__ float sQ[CIN*32];
    __shared__ float sO[CIN*32];
    int b = blockIdx.x >> 7;
    int pix0 = (blockIdx.x & 127) * 32;
    int tid = threadIdx.x;
    for (int j = tid; j < CIN*CIN; j += 256) sW[j] = w[j];
    for (int j = tid; j < CIN*32; j += 256){
        int c = j >> 5, p = j & 31;
        int idx = (b*CIN + c)*LL + pix0 + p;
        sP[j] = pre[idx];
        sQ[j] = post[idx];
    }
    __syncthreads();
    int p = tid & 31, og = tid >> 5;
    float a1[8], a2[8];
    #pragma unroll
    for (int j = 0; j < 8; j++){ a1[j] = 0.f; a2[j] = 0.f; }
    for (int kk = 0; kk < CIN; kk++){
        float x1 = sP[kk*32 + p];
        float x2 = sQ[kk*32 + p];
        #pragma unroll
        for (int j = 0; j < 8; j++){
            float wv = sW[(og*8+j)*CIN + kk];
            a1[j] = fmaf(x1, wv, a1[j]);
            a2[j] = fmaf(x2, wv, a2[j]);
        }
    }
    #pragma unroll
    for (int j = 0; j < 8; j++){
        int o = og*8 + j;
        float inv = bng[o] * rsqrtf(1.00001f);
        float bz  = bias[o];
        float bb  = bnb[o];
        float t1 = (a1[j] + bz) * inv + bb;
        float t2 = (a2[j] + bz) * inv + bb;
        sO[o*32 + p] = sigm(siluf(t1)) * sigm(siluf(t2));
    }
    __syncthreads();
    for (int j = tid; j < CIN*32; j += 256){
        int o = j >> 5, pp = j & 31;
        g_gate[(b*CIN + o)*LL + pix0 + pp] = sO[j];
    }
}

// ---------------- kB: d1 = silu(bn(down(diff)))  -> (b,pix,96) ----------------
__global__ void kB(const float* __restrict__ w, const float* __restrict__ bias,
                   const float* __restrict__ bng, const float* __restrict__ bnb){
    __shared__ float sW[CHID*CIN];
    __shared__ float sA[CIN*32];
    int b = blockIdx.x >> 7;
    int pix0 = (blockIdx.x & 127) * 32;
    int tid = threadIdx.x;
    for (int j = tid; j < CHID*CIN; j += 256) sW[j] = w[j];
    for (int j = tid; j < CIN*32; j += 256){
        int c = j >> 5, p = j & 31;
        sA[j] = g_diff[(b*CIN + c)*LL + pix0 + p];
    }
    __syncthreads();
    int p = tid & 31, og = tid >> 5;
    float acc[12];
    #pragma unroll
    for (int j = 0; j < 12; j++) acc[j] = 0.f;
    for (int kk = 0; kk < CIN; kk++){
        float a = sA[kk*32 + p];
        #pragma unroll
        for (int j = 0; j < 12; j++)
            acc[j] = fmaf(a, sW[(og*12+j)*CIN + kk], acc[j]);
    }
    float res[12];
    #pragma unroll
    for (int j = 0; j < 12; j++){
        int o = og*12 + j;
        float inv = bng[o] * rsqrtf(1.00001f);
        float t = (acc[j] + bias[o]) * inv + bnb[o];
        res[j] = siluf(t);
    }
    float4* dst = (float4*)&g_d1[(b*LL + pix0 + p)*CHID + og*12];
    #pragma unroll
    for (int v = 0; v < 3; v++)
        dst[v] = make_float4(res[v*4], res[v*4+1], res[v*4+2], res[v*4+3]);
}

// ---------------- kC v2: xln = LN(pe(d1)), 128 thr, 32 pixels, 4p x 6o tiles ----------------
__global__ void kC(const float* __restrict__ w, const float* __restrict__ bias,
                   const float* __restrict__ lng, const float* __restrict__ lnb){
    __shared__ float sA[96*32];    // [k][p]
    __shared__ float sW[48*96];    // [k][o] chunk; reused as output stage [o][33]
    __shared__ float sS[32*16], sS2[32*16];
    __shared__ float sMean[32], sRstd[32];
    int b = blockIdx.x >> 7;
    int pix0 = (blockIdx.x & 127) * 32;
    int tid = threadIdx.x;     // 128
    // act transpose: g_d1 pixel-major -> sA[k][p]
    for (int j = tid; j < 32*24; j += 128){
        int p = j / 24, cq = j % 24;
        float4 v = *(const float4*)&g_d1[(b*LL + pix0 + p)*CHID + cq*4];
        sA[(cq*4+0)*32 + p] = v.x;
        sA[(cq*4+1)*32 + p] = v.y;
        sA[(cq*4+2)*32 + p] = v.z;
        sA[(cq*4+3)*32 + p] = v.w;
    }
    int pg = tid & 7, og = tid >> 3;   // og 0..15, 6 outputs each
    float acc[4][6];
    #pragma unroll
    for (int pi = 0; pi < 4; pi++)
        #pragma unroll
        for (int j = 0; j < 6; j++) acc[pi][j] = bias[og*6 + j];
    for (int kc = 0; kc < 2; kc++){
        __syncthreads();
        for (int j = tid; j < 96*12; j += 128){
            int o = j / 12, kq = j % 12;
            float4 v = *(const float4*)&w[o*CHID + kc*48 + kq*4];
            sW[(kq*4+0)*96 + o] = v.x;
            sW[(kq*4+1)*96 + o] = v.y;
            sW[(kq*4+2)*96 + o] = v.z;
            sW[(kq*4+3)*96 + o] = v.w;
        }
        __syncthreads();
        for (int k = 0; k < 48; k++){
            int kk = kc*48 + k;
            float4 a = *(float4*)&sA[kk*32 + pg*4];
            float2 w0 = *(float2*)&sW[k*96 + og*6];
            float2 w1 = *(float2*)&sW[k*96 + og*6 + 2];
            float2 w2 = *(float2*)&sW[k*96 + og*6 + 4];
            float av[4] = {a.x, a.y, a.z, a.w};
            float wv[6] = {w0.x, w0.y, w1.x, w1.y, w2.x, w2.y};
            #pragma unroll
            for (int pi = 0; pi < 4; pi++)
                #pragma unroll
                for (int j = 0; j < 6; j++)
                    acc[pi][j] = fmaf(av[pi], wv[j], acc[pi][j]);
        }
    }
    // LN reduction over o
    #pragma unroll
    for (int pi = 0; pi < 4; pi++){
        float s = 0.f, s2 = 0.f;
        #pragma unroll
        for (int j = 0; j < 6; j++){ s += acc[pi][j]; s2 += acc[pi][j]*acc[pi][j]; }
        sS [(pg*4+pi)*16 + og] = s;
        sS2[(pg*4+pi)*16 + og] = s2;
    }
    __syncthreads();
    if (tid < 32){
        float ss = 0.f, ss2 = 0.f;
        #pragma unroll
        for (int i = 0; i < 16; i++){ ss += sS[tid*16+i]; ss2 += sS2[tid*16+i]; }
        float m = ss * (1.f/96.f);
        float var = ss2 * (1.f/96.f) - m*m;
        sMean[tid] = m;  sRstd[tid] = rsqrtf(var + 1e-5f);
    }
    __syncthreads();
    // apply + stage [o][33] in sW region
    float* st = sW;
    #pragma unroll
    for (int pi = 0; pi < 4; pi++){
        int p = pg*4 + pi;
        float m = sMean[p], rs = sRstd[p];
        #pragma unroll
        for (int j = 0; j < 6; j++){
            int o = og*6 + j;
            st[o*33 + p] = (acc[pi][j] - m) * rs * lng[o] + lnb[o];
        }
    }
    __syncthreads();
    for (int j = tid; j < 32*96; j += 128){
        int p = j / 96, o = j % 96;
        g_xln[(b*LL + pix0 + p)*CHID + o] = st[o*33 + p];
    }
}

// ---------------- kD v2: in_proj 96->384, 128 thr, 32p, 4p x 4o tiles, 6 o-chunks ----------
__global__ void kD(const float* __restrict__ w, const float* __restrict__ bias){
    __shared__ float sA[96*32];    // [k][p]
    __shared__ float sW[96*64];    // [k][o] chunk
    __shared__ float sO[64*33];    // stage
    int b = blockIdx.x >> 7;
    int pix0 = (blockIdx.x & 127) * 32;
    int tid = threadIdx.x;   // 128
    for (int j = tid; j < 32*24; j += 128){
        int p = j / 24, cq = j % 24;
        float4 v = *(const float4*)&g_xln[(b*LL + pix0 + p)*CHID + cq*4];
        sA[(cq*4+0)*32 + p] = v.x;
        sA[(cq*4+1)*32 + p] = v.y;
        sA[(cq*4+2)*32 + p] = v.z;
        sA[(cq*4+3)*32 + p] = v.w;
    }
    int pg = tid & 7, og = tid >> 3;  // og 0..15, 4 outputs each (64 o per chunk)
    for (int ch = 0; ch < 6; ch++){
        __syncthreads();
        for (int j = tid; j < 64*24; j += 128){
            int o = j / 24, kq = j % 24;
            float4 v = *(const float4*)&w[(ch*64 + o)*CHID + kq*4];
            sW[(kq*4+0)*64 + o] = v.x;
            sW[(kq*4+1)*64 + o] = v.y;
            sW[(kq*4+2)*64 + o] = v.z;
            sW[(kq*4+3)*64 + o] = v.w;
        }
        __syncthreads();
        float acc[4][4];
        #pragma unroll
        for (int pi = 0; pi < 4; pi++)
            #pragma unroll
            for (int j = 0; j < 4; j++) acc[pi][j] = bias[ch*64 + og*4 + j];
        for (int k = 0; k < 96; k++){
            float4 a = *(float4*)&sA[k*32 + pg*4];
            float4 wv = *(float4*)&sW[k*64 + og*4];
            float av[4] = {a.x, a.y, a.z, a.w};
            float wf[4] = {wv.x, wv.y, wv.z, wv.w};
            #pragma unroll
            for (int pi = 0; pi < 4; pi++)
                #pragma unroll
                for (int j = 0; j < 4; j++)
                    acc[pi][j] = fmaf(av[pi], wf[j], acc[pi][j]);
        }
        #pragma unroll
        for (int pi = 0; pi < 4; pi++)
            #pragma unroll
            for (int j = 0; j < 4; j++)
                sO[(og*4+j)*33 + pg*4 + pi] = acc[pi][j];
        __syncthreads();
        if (ch < 3){
            for (int j = tid; j < 64*32; j += 128){
                int o = j >> 5, p = j & 31;
                g_xc[(b*DN + ch*64 + o)*LL + pix0 + p] = sO[o*33 + p];
            }
        } else {
            for (int j = tid; j < 32*64; j += 128){
                int p = j >> 6, o = j & 63;
                g_z[(b*LL + pix0 + p)*DN + (ch-3)*64 + o] = sO[o*33 + p];
            }
        }
    }
}

// ---------------- kE: depthwise 3x3 conv + bias + silu ----------------
__global__ void kE(const float* __restrict__ cw, const float* __restrict__ cb){
    __shared__ float sT[18*66];
    int bid = blockIdx.x;
    int rt = bid & 3;
    int bd = bid >> 2;
    int d  = bd % DN;
    int r0 = rt * 16;
    int tid = threadIdx.x;
    const float* src = g_xc + bd*LL;
    for (int j = tid; j < 18*66; j += 256){
        int r = j / 66 - 1 + r0;
        int c = j % 66 - 1;
        float v = 0.f;
        if (r >= 0 && r < 64 && c >= 0 && c < 64) v = src[r*64 + c];
        sT[j] = v;
    }
    float w9[9];
    #pragma unroll
    for (int i = 0; i < 9; i++) w9[i] = cw[d*9 + i];
    float bz = cb[d];
    __syncthreads();
    for (int j = tid; j < 16*64; j += 256){
        int r = j >> 6, c = j & 63;
        float s = bz;
        #pragma unroll
        for (int ky = 0; ky < 3; ky++)
            #pragma unroll
            for (int kx = 0; kx < 3; kx++)
                s = fmaf(w9[ky*3+kx], sT[(r+ky)*66 + c + kx], s);
        g_xcv[bd*LL + (r0+r)*64 + c] = siluf(s);
    }
}

// ---------------- kX v2: gather xs, x_proj GEMM (vectorized), dt GEMM + softplus --------
__global__ void kX(const float* __restrict__ xpw, const float* __restrict__ dtw,
                   const float* __restrict__ dtb){
    __shared__ float sxs[DN*17];     // [d][tt]
    __shared__ float sWx[DN*40];     // [d][c] padded to 40 ; reused as delta stage [16][192]
    __shared__ float sdtw[6*DN];     // [r][d]
    __shared__ float sdt[6*17];      // [r][tt]
    int tile = blockIdx.x & 255;
    int k    = (blockIdx.x >> 8) & 3;
    int b    = blockIdx.x >> 10;
    int t0   = tile * 16;
    int tid  = threadIdx.x;  // 256
    int base = (b*KK + k)*LL;

    // weights: xpw[k][c][d] -> sWx[d][c] (transposed, pad cols 38,39 with 0)
    for (int j = tid; j < 38*48; j += 256){
        int c = j / 48, dq = j % 48;
        float4 v = *(const float4*)&xpw[(k*38 + c)*DN + dq*4];
        sWx[(dq*4+0)*40 + c] = v.x;
        sWx[(dq*4+1)*40 + c] = v.y;
        sWx[(dq*4+2)*40 + c] = v.z;
        sWx[(dq*4+3)*40 + c] = v.w;
    }
    for (int j = tid; j < DN*2; j += 256){
        int d = j >> 1;
        sWx[d*40 + 38 + (j & 1)] = 0.f;
    }
    // dtw[k][d][r] -> sdtw[r][d]
    for (int j = tid; j < DN*6; j += 256){
        int d = j / 6, r = j % 6;
        sdtw[r*DN + d] = dtw[(k*DN + d)*6 + r];
    }
    // gather xs
    for (int j = tid; j < DN*16; j += 256){
        int d = j >> 4, tt = j & 15;
        int t = t0 + tt;
        int pix;
        if (k == 0)      pix = t;
        else if (k == 1) pix = (t & 63)*64 + (t >> 6);
        else if (k == 2) pix = LL - 1 - t;
        else { int tr = LL - 1 - t; pix = (tr & 63)*64 + (tr >> 6); }
        sxs[d*17 + tt] = g_xcv[(b*DN + d)*LL + pix];
    }
    __syncthreads();
    // write xs in scan order
    for (int j = tid; j < DN*16; j += 256){
        int tt = j / 192, d = j % 192;
        g_xs[(base + t0 + tt)*DN + d] = sxs[d*17 + tt];
    }
    // GEMM1: 38(pad40) outputs, threads (tt, cq) with cq<10, 4 outputs each
    if (tid < 160){
        int tt = tid & 15, cq = tid >> 4;
        float acc[4] = {0.f, 0.f, 0.f, 0.f};
        for (int d = 0; d < DN; d++){
            float a = sxs[d*17 + tt];
            float4 wv = *(float4*)&sWx[d*40 + cq*4];
            acc[0] = fmaf(a, wv.x, acc[0]);
            acc[1] = fmaf(a, wv.y, acc[1]);
            acc[2] = fmaf(a, wv.z, acc[2]);
            acc[3] = fmaf(a, wv.w, acc[3]);
        }
        #pragma unroll
        for (int j = 0; j < 4; j++){
            int c = cq*4 + j;
            if (c < RR)             sdt[c*17 + tt] = acc[j];
            else if (c < RR + NN)   g_bs[(base + t0 + tt)*NN + (c - RR)] = acc[j];
            else if (c < RR + 2*NN) g_cs[(base + t0 + tt)*NN + (c - RR - NN)] = acc[j];
        }
    }
    __syncthreads();
    // GEMM2: delta = softplus(dt_w @ dts + dt_b); stage into sWx region
    float* sdl = sWx;
    {
        int tt = tid & 15, dq = tid >> 4;   // dq 0..15, 12 d each
        float acc[12];
        #pragma unroll
        for (int j = 0; j < 12; j++) acc[j] = dtb[k*DN + dq*12 + j];
        #pragma unroll
        for (int r = 0; r < RR; r++){
            float a = sdt[r*17 + tt];
            #pragma unroll
            for (int jq = 0; jq < 3; jq++){
                float4 wv = *(float4*)&sdtw[r*DN + dq*12 + jq*4];
                acc[jq*4+0] = fmaf(a, wv.x, acc[jq*4+0]);
                acc[jq*4+1] = fmaf(a, wv.y, acc[jq*4+1]);
                acc[jq*4+2] = fmaf(a, wv.z, acc[jq*4+2]);
                acc[jq*4+3] = fmaf(a, wv.w, acc[jq*4+3]);
            }
        }
        #pragma unroll
        for (int j = 0; j < 12; j++){
            float x = acc[j];
            float dl = (x > 20.f) ? x : log1pf(__expf(x));
            sdl[tt*DN + dq*12 + j] = dl;
        }
    }
    __syncthreads();
    for (int j = tid; j < 16*DN; j += 256){
        int tt = j / 192, d = j % 192;
        g_delta[(base + t0 + tt)*DN + d] = sdl[j];
    }
}

// ---------------- kF1: per-segment propagator P and offset q ----------------
__global__ void kF1(const float* __restrict__ A_log){
    __shared__ float sD[16*8], sX[16*8], sB[16*16];
    int bid = blockIdx.x;
    int dg = (bid % 24) * 8;
    int s  = (bid / 24) % (SEG-1);
    int k  = (bid / (24*(SEG-1))) % 4;
    int b  = bid / (24*(SEG-1)*4);
    int tid = threadIdx.x;
    int ch = tid >> 4, n = tid & 15;
    int d  = dg + ch;
    int base = (b*KK + k)*LL + s*SEGLEN;

    float a = -__expf(A_log[(k*DN + d)*NN + n]);
    float h = 0.f, P = 1.f;

    int lt = tid >> 3, lc = tid & 7;
    float rD, rX, rB[2];
    rD = g_delta[(base + lt)*DN + dg + lc];
    rX = g_xs   [(base + lt)*DN + dg + lc];
    #pragma unroll
    for (int i = 0; i < 2; i++){
        int jj = tid + i*128;
        rB[i] = g_bs[base*NN + jj];
    }
    for (int chunk = 0; chunk < SEGLEN/16; chunk++){
        sD[tid] = rD;  sX[tid] = rX;
        sB[tid] = rB[0];  sB[tid+128] = rB[1];
        __syncthreads();
        if (chunk < SEGLEN/16 - 1){
            int t0n = (chunk + 1) * 16;
            rD = g_delta[(base + t0n + lt)*DN + dg + lc];
            rX = g_xs   [(base + t0n + lt)*DN + dg + lc];
            #pragma unroll
            for (int i = 0; i < 2; i++){
                int jj = tid + i*128;
                rB[i] = g_bs[(base + t0n)*NN + jj];
            }
        }
        #pragma unroll
        for (int t = 0; t < 16; t++){
            float dl = sD[t*8 + ch];
            float xv = sX[t*8 + ch];
            float Bn = sB[t*16 + n];
            float e  = __expf(dl * a);
            h = fmaf(e, h, dl * xv * Bn);
            P *= e;
        }
        __syncthreads();
    }
    int chain = (b*KK + k)*DN + d;
    g_P[(chain*(SEG-1) + s)*NN + n] = P;
    g_q[(chain*(SEG-1) + s)*NN + n] = h;
}

// ---------------- kF2: prefix over segments -> g_h0 ----------------
__global__ void kF2(){
    int gid = blockIdx.x*blockDim.x + threadIdx.x;
    int chain = gid >> 4, n = gid & 15;
    float h = 0.f;
    g_h0[(chain*SEG + 0)*NN + n] = 0.f;
    #pragma unroll
    for (int s = 0; s < SEG-1; s++){
        float P = g_P[(chain*(SEG-1) + s)*NN + n];
        float q = g_q[(chain*(SEG-1) + s)*NN + n];
        h = fmaf(P, h, q);
        g_h0[(chain*SEG + s + 1)*NN + n] = h;
    }
}

// ---------------- kF3: full scan per segment with h0, produce y ----------------
__global__ void kF3(const float* __restrict__ A_log, const float* __restrict__ Ds){
    __shared__ float sD[16*8], sX[16*8], sB[16*16], sC[16*16], sY[16*8];
    int bid = blockIdx.x;
    int dg = (bid % 24) * 8;
    int s  = (bid / 24) % SEG;
    int k  = (bid / (24*SEG)) % 4;
    int b  = bid / (24*SEG*4);
    int tid = threadIdx.x;
    int ch = tid >> 4, n = tid & 15;
    int d  = dg + ch;
    int base = (b*KK + k)*LL + s*SEGLEN;
    int chain = (b*KK + k)*DN + d;

    float a  = -__expf(A_log[(k*DN + d)*NN + n]);
    float Dv = Ds[k*DN + d];
    float h  = g_h0[(chain*SEG + s)*NN + n];

    int lt = tid >> 3, lc = tid & 7;
    float rD, rX, rB[2], rC[2];
    rD = g_delta[(base + lt)*DN + dg + lc];
    rX = g_xs   [(base + lt)*DN + dg + lc];
    #pragma unroll
    for (int i = 0; i < 2; i++){
        int jj = tid + i*128;
        rB[i] = g_bs[base*NN + jj];
        rC[i] = g_cs[base*NN + jj];
    }
    for (int chunk = 0; chunk < SEGLEN/16; chunk++){
        sD[tid] = rD;  sX[tid] = rX;
        sB[tid] = rB[0];  sB[tid+128] = rB[1];
        sC[tid] = rC[0];  sC[tid+128] = rC[1];
        __syncthreads();
        if (chunk < SEGLEN/16 - 1){
            int t0n = (chunk + 1) * 16;
            rD = g_delta[(base + t0n + lt)*DN + dg + lc];
            rX = g_xs   [(base + t0n + lt)*DN + dg + lc];
            #pragma unroll
            for (int i = 0; i < 2; i++){
                int jj = tid + i*128;
                rB[i] = g_bs[(base + t0n)*NN + jj];
                rC[i] = g_cs[(base + t0n)*NN + jj];
            }
        }
        #pragma unroll
        for (int t = 0; t < 16; t++){
            float dl = sD[t*8 + ch];
            float xv = sX[t*8 + ch];
            float Bn = sB[t*16 + n];
            float Cn = sC[t*16 + n];
            float e  = __expf(dl * a);
            h = fmaf(e, h, dl * xv * Bn);
            float p = h * Cn;
            p += __shfl_xor_sync(0xffffffffu, p, 8);
            p += __shfl_xor_sync(0xffffffffu, p, 4);
            p += __shfl_xor_sync(0xffffffffu, p, 2);
            p += __shfl_xor_sync(0xffffffffu, p, 1);
            if (n == 0) sY[t*8 + ch] = p + Dv * xv;
        }
        __syncthreads();
        g_ys[(base + chunk*16 + lt)*DN + dg + lc] = sY[lt*8 + lc];
    }
}

// ---------------- kG: combine 4 directions + out LN + silu(z) gate -> yln ----------------
__global__ void kG(const float* __restrict__ lng, const float* __restrict__ lnb){
    int gw   = (blockIdx.x*blockDim.x + threadIdx.x) >> 5;
    int lane = threadIdx.x & 31;
    for (int q = 0; q < 8; q++){
        int pg = gw*8 + q;
        int b  = pg >> 12;
        int l  = pg & 4095;
        int hh = l >> 6, ww = l & 63;
        int t1 = ww*64 + hh;
        int b4 = b*KK*LL;
        float y[6], zf[6];
        float s = 0.f, s2 = 0.f;
        #pragma unroll
        for (int i = 0; i < 6; i++){
            int dd = lane + i*32;
            float v = g_ys[(b4 + 0*LL + l)*DN + dd]
                    + g_ys[(b4 + 2*LL + (LL-1-l))*DN + dd]
                    + g_ys[(b4 + 1*LL + t1)*DN + dd]
                    + g_ys[(b4 + 3*LL + (LL-1-t1))*DN + dd];
            y[i]  = v;  s += v;  s2 += v*v;
            zf[i] = g_z[(b*LL + l)*DN + dd];
        }
        #pragma unroll
        for (int off = 16; off > 0; off >>= 1){
            s  += __shfl_xor_sync(0xffffffffu, s,  off);
            s2 += __shfl_xor_sync(0xffffffffu, s2, off);
        }
        float m   = s * (1.f/192.f);
        float var = s2 * (1.f/192.f) - m*m;
        float rstd = rsqrtf(var + 1e-5f);
        #pragma unroll
        for (int i = 0; i < 6; i++){
            int dd = lane + i*32;
            float yn = (y[i] - m) * rstd * lng[dd] + lnb[dd];
            g_yln[(b*LL + l)*DN + dd] = yn * siluf(zf[i]);
        }
    }
}

// ---------------- kH v2: out_proj 192->96, 128 thr, 32p, 4p x 6o tiles, K-chunks of 64 ----
__global__ void kH(const float* __restrict__ w, const float* __restrict__ bias){
    __shared__ float sA[192*32];   // [k][p] 24KB
    __shared__ float sW[64*96];    // [k][o] chunk 24KB; reused as stage [o][33]
    int b = blockIdx.x >> 7;
    int pix0 = (blockIdx.x & 127) * 32;
    int tid = threadIdx.x;   // 128
    for (int j = tid; j < 32*48; j += 128){
        int p = j / 48, dq = j % 48;
        float4 v = *(const float4*)&g_yln[(b*LL + pix0 + p)*DN + dq*4];
        sA[(dq*4+0)*32 + p] = v.x;
        sA[(dq*4+1)*32 + p] = v.y;
        sA[(dq*4+2)*32 + p] = v.z;
        sA[(dq*4+3)*32 + p] = v.w;
    }
    int pg = tid & 7, og = tid >> 3;   // og 0..15, 6 outputs each
    float acc[4][6];
    #pragma unroll
    for (int pi = 0; pi < 4; pi++)
        #pragma unroll
        for (int j = 0; j < 6; j++) acc[pi][j] = bias[og*6 + j];
    for (int kc = 0; kc < 3; kc++){
        __syncthreads();
        for (int j = tid; j < 96*16; j += 128){
            int o = j / 16, kq = j % 16;
            float4 v = *(const float4*)&w[o*DN + kc*64 + kq*4];
            sW[(kq*4+0)*96 + o] = v.x;
            sW[(kq*4+1)*96 + o] = v.y;
            sW[(kq*4+2)*96 + o] = v.z;
            sW[(kq*4+3)*96 + o] = v.w;
        }
        __syncthreads();
        for (int k = 0; k < 64; k++){
            int kk = kc*64 + k;
            float4 a = *(float4*)&sA[kk*32 + pg*4];
            float2 w0 = *(float2*)&sW[k*96 + og*6];
            float2 w1 = *(float2*)&sW[k*96 + og*6 + 2];
            float2 w2 = *(float2*)&sW[k*96 + og*6 + 4];
            float av[4] = {a.x, a.y, a.z, a.w};
            float wv[6] = {w0.x, w0.y, w1.x, w1.y, w2.x, w2.y};
            #pragma unroll
            for (int pi = 0; pi < 4; pi++)
                #pragma unroll
                for (int j = 0; j < 6; j++)
                    acc[pi][j] = fmaf(av[pi], wv[j], acc[pi][j]);
        }
    }
    __syncthreads();
    float* st = sW;
    #pragma unroll
    for (int pi = 0; pi < 4; pi++)
        #pragma unroll
        for (int j = 0; j < 6; j++)
            st[(og*6+j)*33 + pg*4 + pi] = acc[pi][j];
    __syncthreads();
    for (int j = tid; j < 32*96; j += 128){
        int p = j / 96, o = j % 96;
        g_dd[(b*LL + pix0 + p)*CHID + o] = st[o*33 + p];
    }
}

// ---------------- kI v2: up + bn + silu + residual + gate, 128 thr, 4p x 4o -------------
__global__ void kI(const float* __restrict__ w, const float* __restrict__ bias,
                   const float* __restrict__ bng, const float* __restrict__ bnb,
                   float* __restrict__ out){
    __shared__ float sA[96*32];   // [k][p]
    __shared__ float sW[96*64];   // [k][o]
    __shared__ float sO[64*33];
    int b = blockIdx.x >> 7;
    int pix0 = (blockIdx.x & 127) * 32;
    int tid = threadIdx.x;  // 128
    for (int j = tid; j < 32*24; j += 128){
        int p = j / 24, cq = j % 24;
        float4 v = *(const float4*)&g_dd[(b*LL + pix0 + p)*CHID + cq*4];
        sA[(cq*4+0)*32 + p] = v.x;
        sA[(cq*4+1)*32 + p] = v.y;
        sA[(cq*4+2)*32 + p] = v.z;
        sA[(cq*4+3)*32 + p] = v.w;
    }
    for (int j = tid; j < 64*24; j += 128){
        int o = j / 24, kq = j % 24;
        float4 v = *(const float4*)&w[o*CHID + kq*4];
        sW[(kq*4+0)*64 + o] = v.x;
        sW[(kq*4+1)*64 + o] = v.y;
        sW[(kq*4+2)*64 + o] = v.z;
        sW[(kq*4+3)*64 + o] = v.w;
    }
    __syncthreads();
    int pg = tid & 7, og = tid >> 3;   // og 0..15, 4 outputs each
    float acc[4][4];
    #pragma unroll
    for (int pi = 0; pi < 4; pi++)
        #pragma unroll
        for (int j = 0; j < 4; j++) acc[pi][j] = bias[og*4 + j];
    for (int k = 0; k < 96; k++){
        float4 a = *(float4*)&sA[k*32 + pg*4];
        float4 wv = *(float4*)&sW[k*64 + og*4];
        float av[4] = {a.x, a.y, a.z, a.w};
        float wf[4] = {wv.x, wv.y, wv.z, wv.w};
        #pragma unroll
        for (int pi = 0; pi < 4; pi++)
            #pragma unroll
            for (int j = 0; j < 4; j++)
                acc[pi][j] = fmaf(av[pi], wf[j], acc[pi][j]);
    }
    #pragma unroll
    for (int j = 0; j < 4; j++){
        int o = og*4 + j;
        float inv = bng[o] * rsqrtf(1.00001f);
        float bb = bnb[o];
        #pragma unroll
        for (int pi = 0; pi < 4; pi++){
            float t = acc[pi][j] * inv + bb;
            sO[o*33 + pg*4 + pi] = siluf(t);
        }
    }
    __syncthreads();
    for (int j = tid; j < 64*32; j += 128){
        int o = j >> 5, p = j & 31;
        int idx = (b*CIN + o)*LL + pix0 + p;
        out[idx] = (sO[o*33 + p] + g_diff[idx]) * g_gate[idx];
    }
}

// ---------------- launcher ----------------
extern "C" void kernel_launch(void* const* d_in, const int* in_sizes, int n_in,
                              void* d_out, int out_size){
    const float* pre        = (const float*)d_in[0];
    const float* post       = (const float*)d_in[1];
    const float* prepost_w  = (const float*)d_in[2];
    const float* prepost_b  = (const float*)d_in[3];
    const float* prepost_g  = (const float*)d_in[4];
    const float* prepost_bb = (const float*)d_in[5];
    const float* down_w     = (const float*)d_in[6];
    const float* down_b     = (const float*)d_in[7];
    const float* down_g     = (const float*)d_in[8];
    const float* down_bb    = (const float*)d_in[9];
    const float* up_w       = (const float*)d_in[10];
    const float* up_b       = (const float*)d_in[11];
    const float* up_g       = (const float*)d_in[12];
    const float* up_bb      = (const float*)d_in[13];
    const float* pe_w       = (const float*)d_in[14];
    const float* pe_b       = (const float*)d_in[15];
    const float* pe_ln_g    = (const float*)d_in[16];
    const float* pe_ln_b    = (const float*)d_in[17];
    const float* in_proj_w  = (const float*)d_in[18];
    const float* in_proj_b  = (const float*)d_in[19];
    const float* conv_w     = (const float*)d_in[20];
    const float* conv_b     = (const float*)d_in[21];
    const float* x_proj_w   = (const float*)d_in[22];
    const float* dt_w       = (const float*)d_in[23];
    const float* dt_b       = (const float*)d_in[24];
    const float* A_log      = (const float*)d_in[25];
    const float* Ds         = (const float*)d_in[26];
    const float* out_ln_g   = (const float*)d_in[27];
    const float* out_ln_b   = (const float*)d_in[28];
    const float* out_proj_w = (const float*)d_in[29];
    const float* out_proj_b = (const float*)d_in[30];
    float* out = (float*)d_out;

    kDiff<<<BB*CIN*LL/4/256, 256>>>(pre, post);
    kGate2<<<BB*(LL/32), 256>>>(pre, post, prepost_w, prepost_b, prepost_g, prepost_bb);
    kB<<<BB*(LL/32), 256>>>(down_w, down_b, down_g, down_bb);
    kC<<<BB*(LL/32), 128>>>(pe_w, pe_b, pe_ln_g, pe_ln_b);
    kD<<<BB*(LL/32), 128>>>(in_proj_w, in_proj_b);
    kE<<<BB*DN*4, 256>>>(conv_w, conv_b);
    kX<<<BB*KK*(LL/16), 256>>>(x_proj_w, dt_w, dt_b);
    kF1<<<BB*KK*(SEG-1)*(DN/8), 128>>>(A_log);
    kF2<<<(BB*KK*DN*NN)/256, 256>>>();
    kF3<<<BB*KK*SEG*(DN/8), 128>>>(A_log, Ds);
    kG<<<256, 256>>>(out_ln_g, out_ln_b);
    kH<<<BB*(LL/32), 128>>>(out_proj_w, out_proj_b);
    kI<<<BB*(LL/32), 128>>>(up_w, up_b, up_g, up_bb, out);
}

// round 5
// speedup vs baseline: 1.1401x; 1.1401x over previous
#include <cuda_runtime.h>
#include <math.h>

#define BB 4
#define CIN 64
#define CHID 96
#define LL 4096
#define NN 16
#define RR 6
#define KK 4
#define DN 192
#define SEG 8
#define SEGLEN 512

// ---------------- static scratch (no allocation anywhere) ----------------
__device__ float g_diff [BB*CIN*LL];
__device__ float g_gate [BB*CIN*LL];
__device__ float g_d1   [BB*LL*CHID];
__device__ float g_xln  [BB*LL*CHID];
__device__ float g_xc   [BB*DN*LL];
__device__ float g_xcv  [BB*DN*LL];
__device__ float g_z    [BB*LL*DN];
__device__ float g_xs   [BB*KK*LL*DN];
__device__ float g_delta[BB*KK*LL*DN];
__device__ float g_bs   [BB*KK*LL*NN];
__device__ float g_cs   [BB*KK*LL*NN];
__device__ float g_ys   [BB*KK*LL*DN];
__device__ float g_yln  [BB*LL*DN];
__device__ float g_dd   [BB*LL*CHID];
__device__ float g_P [BB*KK*DN*(SEG-1)*NN];
__device__ float g_q [BB*KK*DN*(SEG-1)*NN];
__device__ float g_h0[BB*KK*DN*SEG*NN];

__device__ __forceinline__ float sigm(float x){ return 1.f/(1.f+__expf(-x)); }
__device__ __forceinline__ float siluf(float x){ return x*sigm(x); }
__device__ __forceinline__ float dot4(float4 a, float4 w, float acc){
    acc = fmaf(a.x, w.x, acc);
    acc = fmaf(a.y, w.y, acc);
    acc = fmaf(a.z, w.z, acc);
    acc = fmaf(a.w, w.w, acc);
    return acc;
}

// ---------------- kDiff ----------------
__global__ void kDiff(const float* __restrict__ pre, const float* __restrict__ post){
    int i = blockIdx.x*blockDim.x + threadIdx.x;
    const float4 a = ((const float4*)pre)[i];
    const float4 b = ((const float4*)post)[i];
    float4 r;
    r.x = fabsf(b.x-a.x); r.y = fabsf(b.y-a.y);
    r.z = fabsf(b.z-a.z); r.w = fabsf(b.w-a.w);
    ((float4*)g_diff)[i] = r;
}

// ---------------- kGate2: g_gate = sig(silu(bn(W@pre))) * sig(silu(bn(W@post))) --------
__global__ void kGate2(const float* __restrict__ pre, const float* __restrict__ post,
                       const float* __restrict__ w, const float* __restrict__ bias,
                       const float* __restrict__ bng, const float* __restrict__ bnb){
    __shared__ float sW[CIN*CIN];   // raw (o,c)
    __shared__ float sP[CIN*32];    // [c][p]
    __shared__ float sQ[CIN*32];
    __shared__ float sO[CIN*32];
    int b = blockIdx.x >> 7;
    int pix0 = (blockIdx.x & 127) * 32;
    int tid = threadIdx.x;
    for (int j = tid; j < CIN*CIN/4; j += 256)
        ((float4*)sW)[j] = ((const float4*)w)[j];
    for (int j = tid; j < CIN*32; j += 256){
        int c = j >> 5, p = j & 31;
        int idx = (b*CIN + c)*LL + pix0 + p;
        sP[j] = pre[idx];
        sQ[j] = post[idx];
    }
    __syncthreads();
    int p = tid & 31, og = tid >> 5;     // 8 groups x 8 outputs
    float a1[8], a2[8];
    #pragma unroll
    for (int j = 0; j < 8; j++){ a1[j] = 0.f; a2[j] = 0.f; }
    for (int kq = 0; kq < 16; kq++){
        float x1[4], x2[4];
        #pragma unroll
        for (int i = 0; i < 4; i++){
            x1[i] = sP[(kq*4+i)*32 + p];
            x2[i] = sQ[(kq*4+i)*32 + p];
        }
        #pragma unroll
        for (int j = 0; j < 8; j++){
            float4 wv = *(float4*)&sW[(og*8+j)*CIN + kq*4];
            a1[j] = fmaf(x1[0],wv.x, fmaf(x1[1],wv.y, fmaf(x1[2],wv.z, fmaf(x1[3],wv.w, a1[j]))));
            a2[j] = fmaf(x2[0],wv.x, fmaf(x2[1],wv.y, fmaf(x2[2],wv.z, fmaf(x2[3],wv.w, a2[j]))));
        }
    }
    #pragma unroll
    for (int j = 0; j < 8; j++){
        int o = og*8 + j;
        float inv = bng[o] * rsqrtf(1.00001f);
        float bz  = bias[o];
        float bb  = bnb[o];
        float t1 = (a1[j] + bz) * inv + bb;
        float t2 = (a2[j] + bz) * inv + bb;
        sO[o*32 + p] = sigm(siluf(t1)) * sigm(siluf(t2));
    }
    __syncthreads();
    for (int j = tid; j < CIN*32; j += 256){
        int o = j >> 5, pp = j & 31;
        g_gate[(b*CIN + o)*LL + pix0 + pp] = sO[j];
    }
}

// ---------------- kB: d1 = silu(bn(down(diff)))  -> (b,pix,96) ----------------
__global__ void kB(const float* __restrict__ w, const float* __restrict__ bias,
                   const float* __restrict__ bng, const float* __restrict__ bnb){
    __shared__ float sW[CHID*CIN];  // raw (o,c)
    __shared__ float sA[CIN*32];    // [c][p]
    int b = blockIdx.x >> 7;
    int pix0 = (blockIdx.x & 127) * 32;
    int tid = threadIdx.x;
    for (int j = tid; j < CHID*CIN/4; j += 256)
        ((float4*)sW)[j] = ((const float4*)w)[j];
    for (int j = tid; j < CIN*32; j += 256){
        int c = j >> 5, p = j & 31;
        sA[j] = g_diff[(b*CIN + c)*LL + pix0 + p];
    }
    __syncthreads();
    int p = tid & 31, og = tid >> 5;   // 8 groups x 12 outputs
    float acc[12];
    #pragma unroll
    for (int j = 0; j < 12; j++) acc[j] = 0.f;
    for (int kq = 0; kq < 16; kq++){
        float x[4];
        #pragma unroll
        for (int i = 0; i < 4; i++) x[i] = sA[(kq*4+i)*32 + p];
        #pragma unroll
        for (int j = 0; j < 12; j++){
            float4 wv = *(float4*)&sW[(og*12+j)*CIN + kq*4];
            acc[j] = fmaf(x[0],wv.x, fmaf(x[1],wv.y, fmaf(x[2],wv.z, fmaf(x[3],wv.w, acc[j]))));
        }
    }
    float res[12];
    #pragma unroll
    for (int j = 0; j < 12; j++){
        int o = og*12 + j;
        float inv = bng[o] * rsqrtf(1.00001f);
        float t = (acc[j] + bias[o]) * inv + bnb[o];
        res[j] = siluf(t);
    }
    float4* dst = (float4*)&g_d1[(b*LL + pix0 + p)*CHID + og*12];
    #pragma unroll
    for (int v = 0; v < 3; v++)
        dst[v] = make_float4(res[v*4], res[v*4+1], res[v*4+2], res[v*4+3]);
}

// ---------------- kC: xln = LN(pe(d1)), 256 thr, 16 pixels ----------------
__global__ void kC(const float* __restrict__ w, const float* __restrict__ bias,
                   const float* __restrict__ lng, const float* __restrict__ lnb){
    __shared__ float sW[CHID*CHID];   // raw (o,c) 36.9KB
    __shared__ float sA[16*100];      // [p][c] padded
    __shared__ float sS[16*16], sS2[16*16];
    __shared__ float sM[16], sR[16];
    int b = blockIdx.x >> 8;
    int pix0 = (blockIdx.x & 255) * 16;
    int tid = threadIdx.x;
    for (int j = tid; j < CHID*CHID/4; j += 256)
        ((float4*)sW)[j] = ((const float4*)w)[j];
    for (int j = tid; j < 16*24; j += 256){
        int p = j / 24, cq = j % 24;
        float4 v = *(const float4*)&g_d1[(b*LL + pix0 + p)*CHID + cq*4];
        *(float4*)&sA[p*100 + cq*4] = v;
    }
    __syncthreads();
    int p = tid & 15, og = tid >> 4;   // 16 groups x 6 outputs
    float acc[6];
    #pragma unroll
    for (int j = 0; j < 6; j++) acc[j] = bias[og*6 + j];
    for (int kq = 0; kq < 24; kq++){
        float4 a4 = *(float4*)&sA[p*100 + kq*4];
        #pragma unroll
        for (int j = 0; j < 6; j++){
            float4 wv = *(float4*)&sW[(og*6+j)*CHID + kq*4];
            acc[j] = dot4(a4, wv, acc[j]);
        }
    }
    float s = 0.f, s2 = 0.f;
    #pragma unroll
    for (int j = 0; j < 6; j++){ s += acc[j]; s2 += acc[j]*acc[j]; }
    sS[p*16 + og] = s;  sS2[p*16 + og] = s2;
    __syncthreads();
    if (tid < 16){
        float ss = 0.f, ss2 = 0.f;
        #pragma unroll
        for (int i = 0; i < 16; i++){ ss += sS[tid*16+i]; ss2 += sS2[tid*16+i]; }
        float m = ss * (1.f/96.f);
        float var = ss2 * (1.f/96.f) - m*m;
        sM[tid] = m;  sR[tid] = rsqrtf(var + 1e-5f);
    }
    __syncthreads();
    float m = sM[p], rstd = sR[p];
    float* dst = &g_xln[(b*LL + pix0 + p)*CHID];
    #pragma unroll
    for (int j = 0; j < 6; j++){
        int o = og*6 + j;
        dst[o] = (acc[j] - m) * rstd * lng[o] + lnb[o];
    }
}

// ---------------- kD: in_proj 96->384, 256 thr, 32 pixels, 6 o-chunks ----------------
__global__ void kD(const float* __restrict__ w, const float* __restrict__ bias){
    __shared__ float sA[32*100];   // [p][c] padded
    __shared__ float sW[64*96];    // raw chunk (o,c)
    __shared__ float sO[64*33];
    int b = blockIdx.x >> 7;
    int pix0 = (blockIdx.x & 127) * 32;
    int tid = threadIdx.x;
    for (int j = tid; j < 32*24; j += 256){
        int p = j / 24, cq = j % 24;
        float4 v = *(const float4*)&g_xln[(b*LL + pix0 + p)*CHID + cq*4];
        *(float4*)&sA[p*100 + cq*4] = v;
    }
    int p = tid & 31, og = tid >> 5;   // 8 groups x 8 outputs
    for (int ch = 0; ch < 6; ch++){
        __syncthreads();
        for (int j = tid; j < 64*96/4; j += 256)
            ((float4*)sW)[j] = ((const float4*)(w + ch*64*CHID))[j];
        __syncthreads();
        float acc[8];
        #pragma unroll
        for (int j = 0; j < 8; j++) acc[j] = bias[ch*64 + og*8 + j];
        for (int kq = 0; kq < 24; kq++){
            float4 a4 = *(float4*)&sA[p*100 + kq*4];
            #pragma unroll
            for (int j = 0; j < 8; j++){
                float4 wv = *(float4*)&sW[(og*8+j)*CHID + kq*4];
                acc[j] = dot4(a4, wv, acc[j]);
            }
        }
        #pragma unroll
        for (int j = 0; j < 8; j++) sO[(og*8+j)*33 + p] = acc[j];
        __syncthreads();
        if (ch < 3){
            for (int j = tid; j < 64*32; j += 256){
                int o = j >> 5, pp = j & 31;
                g_xc[(b*DN + ch*64 + o)*LL + pix0 + pp] = sO[o*33 + pp];
            }
        } else {
            for (int j = tid; j < 32*64; j += 256){
                int pp = j >> 6, oz = j & 63;
                g_z[(b*LL + pix0 + pp)*DN + (ch-3)*64 + oz] = sO[oz*33 + pp];
            }
        }
    }
}

// ---------------- kE: depthwise 3x3 conv + bias + silu ----------------
__global__ void kE(const float* __restrict__ cw, const float* __restrict__ cb){
    __shared__ float sT[18*66];
    int bid = blockIdx.x;
    int rt = bid & 3;
    int bd = bid >> 2;
    int d  = bd % DN;
    int r0 = rt * 16;
    int tid = threadIdx.x;
    const float* src = g_xc + bd*LL;
    for (int j = tid; j < 18*66; j += 256){
        int r = j / 66 - 1 + r0;
        int c = j % 66 - 1;
        float v = 0.f;
        if (r >= 0 && r < 64 && c >= 0 && c < 64) v = src[r*64 + c];
        sT[j] = v;
    }
    float w9[9];
    #pragma unroll
    for (int i = 0; i < 9; i++) w9[i] = cw[d*9 + i];
    float bz = cb[d];
    __syncthreads();
    for (int j = tid; j < 16*64; j += 256){
        int r = j >> 6, c = j & 63;
        float s = bz;
        #pragma unroll
        for (int ky = 0; ky < 3; ky++)
            #pragma unroll
            for (int kx = 0; kx < 3; kx++)
                s = fmaf(w9[ky*3+kx], sT[(r+ky)*66 + c + kx], s);
        g_xcv[bd*LL + (r0+r)*64 + c] = siluf(s);
    }
}

// ---------------- kX: gather xs, x_proj GEMM, dt GEMM + softplus ----------------
__global__ void kX(const float* __restrict__ xpw, const float* __restrict__ dtw,
                   const float* __restrict__ dtb){
    __shared__ float sxs[16*196];    // [tt][d] padded; 12.5KB
    __shared__ float sWx[38*DN];     // raw (c,d) 29.2KB ; reused as delta stage
    __shared__ float sdtw[DN*6];     // raw (d,r)
    __shared__ float sdt[6*17];      // [r][tt]
    int tile = blockIdx.x & 255;
    int k    = (blockIdx.x >> 8) & 3;
    int b    = blockIdx.x >> 10;
    int t0   = tile * 16;
    int tid  = threadIdx.x;  // 256
    int base = (b*KK + k)*LL;

    for (int j = tid; j < 38*DN/4; j += 256)
        ((float4*)sWx)[j] = ((const float4*)(xpw + k*38*DN))[j];
    for (int j = tid; j < DN*6/2; j += 256)
        ((float2*)sdtw)[j] = ((const float2*)(dtw + k*DN*6))[j];
    for (int j = tid; j < DN*16; j += 256){
        int d = j >> 4, tt = j & 15;
        int t = t0 + tt;
        int pix;
        if (k == 0)      pix = t;
        else if (k == 1) pix = (t & 63)*64 + (t >> 6);
        else if (k == 2) pix = LL - 1 - t;
        else { int tr = LL - 1 - t; pix = (tr & 63)*64 + (tr >> 6); }
        sxs[tt*196 + d] = g_xcv[(b*DN + d)*LL + pix];
    }
    __syncthreads();
    // write xs in scan order (float4)
    for (int j = tid; j < 16*48; j += 256){
        int tt = j / 48, dq = j % 48;
        *(float4*)&g_xs[(base + t0 + tt)*DN + dq*4] = *(float4*)&sxs[tt*196 + dq*4];
    }
    // GEMM1: 38 outputs x 16 steps
    for (int j = tid; j < 38*16; j += 256){
        int c = j >> 4, tt = j & 15;
        float acc = 0.f;
        for (int dq = 0; dq < 48; dq++){
            float4 a4 = *(float4*)&sxs[tt*196 + dq*4];
            float4 wv = *(float4*)&sWx[c*DN + dq*4];
            acc = dot4(a4, wv, acc);
        }
        if (c < RR)            sdt[c*17 + tt] = acc;
        else if (c < RR + NN)  g_bs[(base + t0 + tt)*NN + (c - RR)] = acc;
        else                   g_cs[(base + t0 + tt)*NN + (c - RR - NN)] = acc;
    }
    __syncthreads();
    // GEMM2: delta = softplus(dt_w @ dts + dt_b); stage into sWx
    float* sdl = sWx;
    {
        int tt = tid & 15, dq = tid >> 4;   // 16 d each
        float acc[12];
        #pragma unroll
        for (int j = 0; j < 12; j++) acc[j] = dtb[k*DN + dq*12 + j];
        float dts[6];
        #pragma unroll
        for (int r = 0; r < RR; r++) dts[r] = sdt[r*17 + tt];
        #pragma unroll
        for (int j = 0; j < 12; j++){
            int d = dq*12 + j;
            float a = acc[j];
            #pragma unroll
            for (int r = 0; r < RR; r++)
                a = fmaf(dts[r], sdtw[d*6 + r], a);
            float dl = (a > 20.f) ? a : log1pf(__expf(a));
            acc[j] = dl;
        }
        __syncthreads();
        #pragma unroll
        for (int j = 0; j < 12; j++) sdl[tt*DN + dq*12 + j] = acc[j];
    }
    __syncthreads();
    for (int j = tid; j < 16*48; j += 256){
        int tt = j / 48, dq = j % 48;
        *(float4*)&g_delta[(base + t0 + tt)*DN + dq*4] = *(float4*)&sdl[tt*DN + dq*4];
    }
}

// ---------------- kF1: per-segment propagator P and offset q ----------------
__global__ void kF1(const float* __restrict__ A_log){
    __shared__ float sD[16*8], sX[16*8], sB[16*16];
    int bid = blockIdx.x;
    int dg = (bid % 24) * 8;
    int s  = (bid / 24) % (SEG-1);
    int k  = (bid / (24*(SEG-1))) % 4;
    int b  = bid / (24*(SEG-1)*4);
    int tid = threadIdx.x;
    int ch = tid >> 4, n = tid & 15;
    int d  = dg + ch;
    int base = (b*KK + k)*LL + s*SEGLEN;

    float a = -__expf(A_log[(k*DN + d)*NN + n]);
    float h = 0.f, P = 1.f;

    int lt = tid >> 3, lc = tid & 7;
    float rD, rX, rB[2];
    rD = g_delta[(base + lt)*DN + dg + lc];
    rX = g_xs   [(base + lt)*DN + dg + lc];
    #pragma unroll
    for (int i = 0; i < 2; i++){
        int jj = tid + i*128;
        rB[i] = g_bs[base*NN + jj];
    }
    for (int chunk = 0; chunk < SEGLEN/16; chunk++){
        sD[tid] = rD;  sX[tid] = rX;
        sB[tid] = rB[0];  sB[tid+128] = rB[1];
        __syncthreads();
        if (chunk < SEGLEN/16 - 1){
            int t0n = (chunk + 1) * 16;
            rD = g_delta[(base + t0n + lt)*DN + dg + lc];
            rX = g_xs   [(base + t0n + lt)*DN + dg + lc];
            #pragma unroll
            for (int i = 0; i < 2; i++){
                int jj = tid + i*128;
                rB[i] = g_bs[(base + t0n)*NN + jj];
            }
        }
        #pragma unroll
        for (int t = 0; t < 16; t++){
            float dl = sD[t*8 + ch];
            float xv = sX[t*8 + ch];
            float Bn = sB[t*16 + n];
            float e  = __expf(dl * a);
            h = fmaf(e, h, dl * xv * Bn);
            P *= e;
        }
        __syncthreads();
    }
    int chain = (b*KK + k)*DN + d;
    g_P[(chain*(SEG-1) + s)*NN + n] = P;
    g_q[(chain*(SEG-1) + s)*NN + n] = h;
}

// ---------------- kF2: prefix over segments -> g_h0 ----------------
__global__ void kF2(){
    int gid = blockIdx.x*blockDim.x + threadIdx.x;
    int chain = gid >> 4, n = gid & 15;
    float h = 0.f;
    g_h0[(chain*SEG + 0)*NN + n] = 0.f;
    #pragma unroll
    for (int s = 0; s < SEG-1; s++){
        float P = g_P[(chain*(SEG-1) + s)*NN + n];
        float q = g_q[(chain*(SEG-1) + s)*NN + n];
        h = fmaf(P, h, q);
        g_h0[(chain*SEG + s + 1)*NN + n] = h;
    }
}

// ---------------- kF3: full scan per segment with h0, produce y ----------------
__global__ void kF3(const float* __restrict__ A_log, const float* __restrict__ Ds){
    __shared__ float sD[16*8], sX[16*8], sB[16*16], sC[16*16], sY[16*8];
    int bid = blockIdx.x;
    int dg = (bid % 24) * 8;
    int s  = (bid / 24) % SEG;
    int k  = (bid / (24*SEG)) % 4;
    int b  = bid / (24*SEG*4);
    int tid = threadIdx.x;
    int ch = tid >> 4, n = tid & 15;
    int d  = dg + ch;
    int base = (b*KK + k)*LL + s*SEGLEN;
    int chain = (b*KK + k)*DN + d;

    float a  = -__expf(A_log[(k*DN + d)*NN + n]);
    float Dv = Ds[k*DN + d];
    float h  = g_h0[(chain*SEG + s)*NN + n];

    int lt = tid >> 3, lc = tid & 7;
    float rD, rX, rB[2], rC[2];
    rD = g_delta[(base + lt)*DN + dg + lc];
    rX = g_xs   [(base + lt)*DN + dg + lc];
    #pragma unroll
    for (int i = 0; i < 2; i++){
        int jj = tid + i*128;
        rB[i] = g_bs[base*NN + jj];
        rC[i] = g_cs[base*NN + jj];
    }
    for (int chunk = 0; chunk < SEGLEN/16; chunk++){
        sD[tid] = rD;  sX[tid] = rX;
        sB[tid] = rB[0];  sB[tid+128] = rB[1];
        sC[tid] = rC[0];  sC[tid+128] = rC[1];
        __syncthreads();
        if (chunk < SEGLEN/16 - 1){
            int t0n = (chunk + 1) * 16;
            rD = g_delta[(base + t0n + lt)*DN + dg + lc];
            rX = g_xs   [(base + t0n + lt)*DN + dg + lc];
            #pragma unroll
            for (int i = 0; i < 2; i++){
                int jj = tid + i*128;
                rB[i] = g_bs[(base + t0n)*NN + jj];
                rC[i] = g_cs[(base + t0n)*NN + jj];
            }
        }
        #pragma unroll
        for (int t = 0; t < 16; t++){
            float dl = sD[t*8 + ch];
            float xv = sX[t*8 + ch];
            float Bn = sB[t*16 + n];
            float Cn = sC[t*16 + n];
            float e  = __expf(dl * a);
            h = fmaf(e, h, dl * xv * Bn);
            float p = h * Cn;
            p += __shfl_xor_sync(0xffffffffu, p, 8);
            p += __shfl_xor_sync(0xffffffffu, p, 4);
            p += __shfl_xor_sync(0xffffffffu, p, 2);
            p += __shfl_xor_sync(0xffffffffu, p, 1);
            if (n == 0) sY[t*8 + ch] = p + Dv * xv;
        }
        __syncthreads();
        g_ys[(base + chunk*16 + lt)*DN + dg + lc] = sY[lt*8 + lc];
    }
}

// ---------------- kG: combine 4 directions + out LN + silu(z) gate -> yln ----------------
__global__ void kG(const float* __restrict__ lng, const float* __restrict__ lnb){
    int gw   = (blockIdx.x*blockDim.x + threadIdx.x) >> 5;
    int lane = threadIdx.x & 31;
    for (int q = 0; q < 8; q++){
        int pg = gw*8 + q;
        int b  = pg >> 12;
        int l  = pg & 4095;
        int hh = l >> 6, ww = l & 63;
        int t1 = ww*64 + hh;
        int b4 = b*KK*LL;
        float y[6], zf[6];
        float s = 0.f, s2 = 0.f;
        #pragma unroll
        for (int i = 0; i < 6; i++){
            int dd = lane + i*32;
            float v = g_ys[(b4 + 0*LL + l)*DN + dd]
                    + g_ys[(b4 + 2*LL + (LL-1-l))*DN + dd]
                    + g_ys[(b4 + 1*LL + t1)*DN + dd]
                    + g_ys[(b4 + 3*LL + (LL-1-t1))*DN + dd];
            y[i]  = v;  s += v;  s2 += v*v;
            zf[i] = g_z[(b*LL + l)*DN + dd];
        }
        #pragma unroll
        for (int off = 16; off > 0; off >>= 1){
            s  += __shfl_xor_sync(0xffffffffu, s,  off);
            s2 += __shfl_xor_sync(0xffffffffu, s2, off);
        }
        float m   = s * (1.f/192.f);
        float var = s2 * (1.f/192.f) - m*m;
        float rstd = rsqrtf(var + 1e-5f);
        #pragma unroll
        for (int i = 0; i < 6; i++){
            int dd = lane + i*32;
            float yn = (y[i] - m) * rstd * lng[dd] + lnb[dd];
            g_yln[(b*LL + l)*DN + dd] = yn * siluf(zf[i]);
        }
    }
}

// ---------------- kH: out_proj 192->96, 256 thr, 16 pixels, K-chunks of 64 ----------------
__global__ void kH(const float* __restrict__ w, const float* __restrict__ bias){
    __shared__ float sA[16*196];   // [p][c] padded 12.5KB
    __shared__ float sW[96*64];    // raw chunk (o, k_local) 24.6KB
    __shared__ float sO[96*17];
    int b = blockIdx.x >> 8;
    int pix0 = (blockIdx.x & 255) * 16;
    int tid = threadIdx.x;
    for (int j = tid; j < 16*48; j += 256){
        int p = j / 48, dq = j % 48;
        float4 v = *(const float4*)&g_yln[(b*LL + pix0 + p)*DN + dq*4];
        *(float4*)&sA[p*196 + dq*4] = v;
    }
    int p = tid & 15, og = tid >> 4;   // 16 groups x 6 outputs
    float acc[6];
    #pragma unroll
    for (int j = 0; j < 6; j++) acc[j] = bias[og*6 + j];
    for (int kc = 0; kc < 3; kc++){
        __syncthreads();
        for (int j = tid; j < 96*16; j += 256){
            int o = j / 16, kq = j % 16;
            *(float4*)&sW[o*64 + kq*4] = *(const float4*)&w[o*DN + kc*64 + kq*4];
        }
        __syncthreads();
        for (int kq = 0; kq < 16; kq++){
            float4 a4 = *(float4*)&sA[p*196 + kc*64 + kq*4];
            #pragma unroll
            for (int j = 0; j < 6; j++){
                float4 wv = *(float4*)&sW[(og*6+j)*64 + kq*4];
                acc[j] = dot4(a4, wv, acc[j]);
            }
        }
    }
    __syncthreads();
    #pragma unroll
    for (int j = 0; j < 6; j++) sO[(og*6+j)*17 + p] = acc[j];
    __syncthreads();
    for (int j = tid; j < 16*96; j += 256){
        int pp = j / 96, o = j % 96;
        g_dd[(b*LL + pix0 + pp)*CHID + o] = sO[o*17 + pp];
    }
}

// ---------------- kI: up + bn + silu + residual + gate, 256 thr, 32 pixels ----------------
__global__ void kI(const float* __restrict__ w, const float* __restrict__ bias,
                   const float* __restrict__ bng, const float* __restrict__ bnb,
                   float* __restrict__ out){
    __shared__ float sA[32*100];  // [p][c] padded
    __shared__ float sW[64*96];   // raw (o,c)
    __shared__ float sO[64*33];
    int b = blockIdx.x >> 7;
    int pix0 = (blockIdx.x & 127) * 32;
    int tid = threadIdx.x;
    for (int j = tid; j < 64*96/4; j += 256)
        ((float4*)sW)[j] = ((const float4*)w)[j];
    for (int j = tid; j < 32*24; j += 256){
        int p = j / 24, cq = j % 24;
        float4 v = *(const float4*)&g_dd[(b*LL + pix0 + p)*CHID + cq*4];
        *(float4*)&sA[p*100 + cq*4] = v;
    }
    __syncthreads();
    int p = tid & 31, og = tid >> 5;   // 8 groups x 8 outputs
    float acc[8];
    #pragma unroll
    for (int j = 0; j < 8; j++) acc[j] = bias[og*8 + j];
    for (int kq = 0; kq < 24; kq++){
        float4 a4 = *(float4*)&sA[p*100 + kq*4];
        #pragma unroll
        for (int j = 0; j < 8; j++){
            float4 wv = *(float4*)&sW[(og*8+j)*CHID + kq*4];
            acc[j] = dot4(a4, wv, acc[j]);
        }
    }
    #pragma unroll
    for (int j = 0; j < 8; j++){
        int o = og*8 + j;
        float inv = bng[o] * rsqrtf(1.00001f);
        float t = acc[j] * inv + bnb[o];
        sO[o*33 + p] = siluf(t);
    }
    __syncthreads();
    for (int j = tid; j < 64*32; j += 256){
        int o = j >> 5, pp = j & 31;
        int idx = (b*CIN + o)*LL + pix0 + pp;
        out[idx] = (sO[o*33 + pp] + g_diff[idx]) * g_gate[idx];
    }
}

// ---------------- launcher ----------------
extern "C" void kernel_launch(void* const* d_in, const int* in_sizes, int n_in,
                              void* d_out, int out_size){
    const float* pre        = (const float*)d_in[0];
    const float* post       = (const float*)d_in[1];
    const float* prepost_w  = (const float*)d_in[2];
    const float* prepost_b  = (const float*)d_in[3];
    const float* prepost_g  = (const float*)d_in[4];
    const float* prepost_bb = (const float*)d_in[5];
    const float* down_w     = (const float*)d_in[6];
    const float* down_b     = (const float*)d_in[7];
    const float* down_g     = (const float*)d_in[8];
    const float* down_bb    = (const float*)d_in[9];
    const float* up_w       = (const float*)d_in[10];
    const float* up_b       = (const float*)d_in[11];
    const float* up_g       = (const float*)d_in[12];
    const float* up_bb      = (const float*)d_in[13];
    const float* pe_w       = (const float*)d_in[14];
    const float* pe_b       = (const float*)d_in[15];
    const float* pe_ln_g    = (const float*)d_in[16];
    const float* pe_ln_b    = (const float*)d_in[17];
    const float* in_proj_w  = (const float*)d_in[18];
    const float* in_proj_b  = (const float*)d_in[19];
    const float* conv_w     = (const float*)d_in[20];
    const float* conv_b     = (const float*)d_in[21];
    const float* x_proj_w   = (const float*)d_in[22];
    const float* dt_w       = (const float*)d_in[23];
    const float* dt_b       = (const float*)d_in[24];
    const float* A_log      = (const float*)d_in[25];
    const float* Ds         = (const float*)d_in[26];
    const float* out_ln_g   = (const float*)d_in[27];
    const float* out_ln_b   = (const float*)d_in[28];
    const float* out_proj_w = (const float*)d_in[29];
    const float* out_proj_b = (const float*)d_in[30];
    float* out = (float*)d_out;

    kDiff<<<BB*CIN*LL/4/256, 256>>>(pre, post);
    kGate2<<<BB*(LL/32), 256>>>(pre, post, prepost_w, prepost_b, prepost_g, prepost_bb);
    kB<<<BB*(LL/32), 256>>>(down_w, down_b, down_g, down_bb);
    kC<<<BB*(LL/16), 256>>>(pe_w, pe_b, pe_ln_g, pe_ln_b);
    kD<<<BB*(LL/32), 256>>>(in_proj_w, in_proj_b);
    kE<<<BB*DN*4, 256>>>(conv_w, conv_b);
    kX<<<BB*KK*(LL/16), 256>>>(x_proj_w, dt_w, dt_b);
    kF1<<<BB*KK*(SEG-1)*(DN/8), 128>>>(A_log);
    kF2<<<(BB*KK*DN*NN)/256, 256>>>();
    kF3<<<BB*KK*SEG*(DN/8), 128>>>(A_log, Ds);
    kG<<<256, 256>>>(out_ln_g, out_ln_b);
    kH<<<BB*(LL/16), 256>>>(out_proj_w, out_proj_b);
    kI<<<BB*(LL/32), 256>>>(up_w, up_b, up_g, up_bb, out);
}

// round 6
// speedup vs baseline: 1.1958x; 1.0489x over previous
#include <cuda_runtime.h>
#include <math.h>

#define BB 4
#define CIN 64
#define CHID 96
#define LL 4096
#define NN 16
#define RR 6
#define KK 4
#define DN 192
#define SEG 8
#define SEGLEN 512

// ---------------- static scratch (no allocation anywhere) ----------------
__device__ float g_diff [BB*CIN*LL];
__device__ float g_gate [BB*CIN*LL];
__device__ float g_d1   [BB*LL*CHID];
__device__ float g_xln  [BB*LL*CHID];
__device__ float g_xc   [BB*DN*LL];
__device__ float g_xcv  [BB*DN*LL];
__device__ float g_z    [BB*LL*DN];
__device__ float g_xs   [BB*KK*LL*DN];
__device__ float g_delta[BB*KK*LL*DN];
__device__ float g_bs   [BB*KK*LL*NN];
__device__ float g_cs   [BB*KK*LL*NN];
__device__ float g_ys   [BB*KK*LL*DN];
__device__ float g_yln  [BB*LL*DN];
__device__ float g_dd   [BB*LL*CHID];
__device__ float g_P [BB*KK*DN*(SEG-1)*NN];
__device__ float g_q [BB*KK*DN*(SEG-1)*NN];
__device__ float g_h0[BB*KK*DN*SEG*NN];

__device__ __forceinline__ float sigm(float x){ return 1.f/(1.f+__expf(-x)); }
__device__ __forceinline__ float siluf(float x){ return x*sigm(x); }
__device__ __forceinline__ float dot4(float4 a, float4 w, float acc){
    acc = fmaf(a.x, w.x, acc);
    acc = fmaf(a.y, w.y, acc);
    acc = fmaf(a.z, w.z, acc);
    acc = fmaf(a.w, w.w, acc);
    return acc;
}

// ---------------- kDiff ----------------
__global__ void kDiff(const float* __restrict__ pre, const float* __restrict__ post){
    int i = blockIdx.x*blockDim.x + threadIdx.x;
    const float4 a = ((const float4*)pre)[i];
    const float4 b = ((const float4*)post)[i];
    float4 r;
    r.x = fabsf(b.x-a.x); r.y = fabsf(b.y-a.y);
    r.z = fabsf(b.z-a.z); r.w = fabsf(b.w-a.w);
    ((float4*)g_diff)[i] = r;
}

// ---------------- kGate2 ----------------
__global__ void kGate2(const float* __restrict__ pre, const float* __restrict__ post,
                       const float* __restrict__ w, const float* __restrict__ bias,
                       const float* __restrict__ bng, const float* __restrict__ bnb){
    __shared__ float sW[CIN*CIN];
    __shared__ float sP[CIN*32];
    __shared__ float sQ[CIN*32];
    __shared__ float sO[CIN*32];
    int b = blockIdx.x >> 7;
    int pix0 = (blockIdx.x & 127) * 32;
    int tid = threadIdx.x;
    for (int j = tid; j < CIN*CIN/4; j += 256)
        ((float4*)sW)[j] = ((const float4*)w)[j];
    for (int j = tid; j < CIN*32; j += 256){
        int c = j >> 5, p = j & 31;
        int idx = (b*CIN + c)*LL + pix0 + p;
        sP[j] = pre[idx];
        sQ[j] = post[idx];
    }
    __syncthreads();
    int p = tid & 31, og = tid >> 5;
    float a1[8], a2[8];
    #pragma unroll
    for (int j = 0; j < 8; j++){ a1[j] = 0.f; a2[j] = 0.f; }
    for (int kq = 0; kq < 16; kq++){
        float x1[4], x2[4];
        #pragma unroll
        for (int i = 0; i < 4; i++){
            x1[i] = sP[(kq*4+i)*32 + p];
            x2[i] = sQ[(kq*4+i)*32 + p];
        }
        #pragma unroll
        for (int j = 0; j < 8; j++){
            float4 wv = *(float4*)&sW[(og*8+j)*CIN + kq*4];
            a1[j] = fmaf(x1[0],wv.x, fmaf(x1[1],wv.y, fmaf(x1[2],wv.z, fmaf(x1[3],wv.w, a1[j]))));
            a2[j] = fmaf(x2[0],wv.x, fmaf(x2[1],wv.y, fmaf(x2[2],wv.z, fmaf(x2[3],wv.w, a2[j]))));
        }
    }
    #pragma unroll
    for (int j = 0; j < 8; j++){
        int o = og*8 + j;
        float inv = bng[o] * rsqrtf(1.00001f);
        float bz  = bias[o];
        float bb  = bnb[o];
        float t1 = (a1[j] + bz) * inv + bb;
        float t2 = (a2[j] + bz) * inv + bb;
        sO[o*32 + p] = sigm(siluf(t1)) * sigm(siluf(t2));
    }
    __syncthreads();
    for (int j = tid; j < CIN*32; j += 256){
        int o = j >> 5, pp = j & 31;
        g_gate[(b*CIN + o)*LL + pix0 + pp] = sO[j];
    }
}

// ---------------- kB: d1 = silu(bn(down(diff)))  -> (b,pix,96) ----------------
__global__ void kB(const float* __restrict__ w, const float* __restrict__ bias,
                   const float* __restrict__ bng, const float* __restrict__ bnb){
    __shared__ float sW[CHID*CIN];
    __shared__ float sA[CIN*32];
    int b = blockIdx.x >> 7;
    int pix0 = (blockIdx.x & 127) * 32;
    int tid = threadIdx.x;
    for (int j = tid; j < CHID*CIN/4; j += 256)
        ((float4*)sW)[j] = ((const float4*)w)[j];
    for (int j = tid; j < CIN*32; j += 256){
        int c = j >> 5, p = j & 31;
        sA[j] = g_diff[(b*CIN + c)*LL + pix0 + p];
    }
    __syncthreads();
    int p = tid & 31, og = tid >> 5;
    float acc[12];
    #pragma unroll
    for (int j = 0; j < 12; j++) acc[j] = 0.f;
    for (int kq = 0; kq < 16; kq++){
        float x[4];
        #pragma unroll
        for (int i = 0; i < 4; i++) x[i] = sA[(kq*4+i)*32 + p];
        #pragma unroll
        for (int j = 0; j < 12; j++){
            float4 wv = *(float4*)&sW[(og*12+j)*CIN + kq*4];
            acc[j] = fmaf(x[0],wv.x, fmaf(x[1],wv.y, fmaf(x[2],wv.z, fmaf(x[3],wv.w, acc[j]))));
        }
    }
    float res[12];
    #pragma unroll
    for (int j = 0; j < 12; j++){
        int o = og*12 + j;
        float inv = bng[o] * rsqrtf(1.00001f);
        float t = (acc[j] + bias[o]) * inv + bnb[o];
        res[j] = siluf(t);
    }
    float4* dst = (float4*)&g_d1[(b*LL + pix0 + p)*CHID + og*12];
    #pragma unroll
    for (int v = 0; v < 3; v++)
        dst[v] = make_float4(res[v*4], res[v*4+1], res[v*4+2], res[v*4+3]);
}

// ---------------- kC v3: xln = LN(pe(d1)), 256 thr, 32 pixels, P=2 x T=6 ----------------
__global__ void kC(const float* __restrict__ w, const float* __restrict__ bias,
                   const float* __restrict__ lng, const float* __restrict__ lnb){
    __shared__ float sA[32*100];      // [p][k] padded (12.8KB)
    __shared__ float sW[96*48];       // [o][k_local] chunk (18.4KB); reused as stage [o][33]
    __shared__ float sS[32*16], sS2[32*16];
    __shared__ float sM[32], sR[32];
    int b = blockIdx.x >> 7;
    int pix0 = (blockIdx.x & 127) * 32;
    int tid = threadIdx.x;
    for (int j = tid; j < 32*24; j += 256){
        int p = j / 24, cq = j % 24;
        *(float4*)&sA[p*100 + cq*4] = *(const float4*)&g_d1[(b*LL + pix0 + p)*CHID + cq*4];
    }
    int p = tid & 15, og = tid >> 4;   // 16 og x 6 outputs, 2 pixels (p, p+16)
    float acc[2][6];
    #pragma unroll
    for (int j = 0; j < 6; j++){ acc[0][j] = bias[og*6+j]; acc[1][j] = acc[0][j]; }
    for (int kc = 0; kc < 2; kc++){
        __syncthreads();
        for (int j = tid; j < 96*12; j += 256){
            int o = j / 12, kq = j % 12;
            *(float4*)&sW[o*48 + kq*4] = *(const float4*)&w[o*CHID + kc*48 + kq*4];
        }
        __syncthreads();
        #pragma unroll 4
        for (int kq = 0; kq < 12; kq++){
            float4 a0 = *(float4*)&sA[p*100 + kc*48 + kq*4];
            float4 a1 = *(float4*)&sA[(p+16)*100 + kc*48 + kq*4];
            #pragma unroll
            for (int j = 0; j < 6; j++){
                float4 wv = *(float4*)&sW[(og*6+j)*48 + kq*4];
                acc[0][j] = dot4(a0, wv, acc[0][j]);
                acc[1][j] = dot4(a1, wv, acc[1][j]);
            }
        }
    }
    #pragma unroll
    for (int pi = 0; pi < 2; pi++){
        float s = 0.f, s2 = 0.f;
        #pragma unroll
        for (int j = 0; j < 6; j++){ s += acc[pi][j]; s2 += acc[pi][j]*acc[pi][j]; }
        sS [(p + pi*16)*16 + og] = s;
        sS2[(p + pi*16)*16 + og] = s2;
    }
    __syncthreads();
    if (tid < 32){
        float ss = 0.f, ss2 = 0.f;
        #pragma unroll
        for (int i = 0; i < 16; i++){ ss += sS[tid*16+i]; ss2 += sS2[tid*16+i]; }
        float m = ss * (1.f/96.f);
        float var = ss2 * (1.f/96.f) - m*m;
        sM[tid] = m;  sR[tid] = rsqrtf(var + 1e-5f);
    }
    __syncthreads();
    float* st = sW;   // stage [o][33]
    #pragma unroll
    for (int pi = 0; pi < 2; pi++){
        int pp = p + pi*16;
        float m = sM[pp], rs = sR[pp];
        #pragma unroll
        for (int j = 0; j < 6; j++){
            int o = og*6 + j;
            st[o*33 + pp] = (acc[pi][j] - m) * rs * lng[o] + lnb[o];
        }
    }
    __syncthreads();
    for (int j = tid; j < 32*96; j += 256){
        int pp = j / 96, o = j % 96;
        g_xln[(b*LL + pix0 + pp)*CHID + o] = st[o*33 + pp];
    }
}

// ---------------- kD v3: in_proj 96->384, 256 thr, 32p, P=2 x T=4, 6 o-chunks ------------
__global__ void kD(const float* __restrict__ w, const float* __restrict__ bias){
    __shared__ float sA[32*100];   // [p][k] padded
    __shared__ float sW[64*96];    // raw chunk (o,k)
    __shared__ float sO[64*33];
    int b = blockIdx.x >> 7;
    int pix0 = (blockIdx.x & 127) * 32;
    int tid = threadIdx.x;
    for (int j = tid; j < 32*24; j += 256){
        int p = j / 24, cq = j % 24;
        *(float4*)&sA[p*100 + cq*4] = *(const float4*)&g_xln[(b*LL + pix0 + p)*CHID + cq*4];
    }
    int p = tid & 15, og = tid >> 4;   // 16 og x 4 outputs, 2 pixels
    for (int ch = 0; ch < 6; ch++){
        __syncthreads();
        for (int j = tid; j < 64*96/4; j += 256)
            ((float4*)sW)[j] = ((const float4*)(w + ch*64*CHID))[j];
        __syncthreads();
        float acc[2][4];
        #pragma unroll
        for (int j = 0; j < 4; j++){ acc[0][j] = bias[ch*64 + og*4 + j]; acc[1][j] = acc[0][j]; }
        #pragma unroll 4
        for (int kq = 0; kq < 24; kq++){
            float4 a0 = *(float4*)&sA[p*100 + kq*4];
            float4 a1 = *(float4*)&sA[(p+16)*100 + kq*4];
            #pragma unroll
            for (int j = 0; j < 4; j++){
                float4 wv = *(float4*)&sW[(og*4+j)*CHID + kq*4];
                acc[0][j] = dot4(a0, wv, acc[0][j]);
                acc[1][j] = dot4(a1, wv, acc[1][j]);
            }
        }
        #pragma unroll
        for (int j = 0; j < 4; j++){
            sO[(og*4+j)*33 + p]      = acc[0][j];
            sO[(og*4+j)*33 + p + 16] = acc[1][j];
        }
        __syncthreads();
        if (ch < 3){
            for (int j = tid; j < 64*32; j += 256){
                int o = j >> 5, pp = j & 31;
                g_xc[(b*DN + ch*64 + o)*LL + pix0 + pp] = sO[o*33 + pp];
            }
        } else {
            for (int j = tid; j < 32*64; j += 256){
                int pp = j >> 6, oz = j & 63;
                g_z[(b*LL + pix0 + pp)*DN + (ch-3)*64 + oz] = sO[oz*33 + pp];
            }
        }
    }
}

// ---------------- kE: depthwise 3x3 conv + bias + silu ----------------
__global__ void kE(const float* __restrict__ cw, const float* __restrict__ cb){
    __shared__ float sT[18*66];
    int bid = blockIdx.x;
    int rt = bid & 3;
    int bd = bid >> 2;
    int d  = bd % DN;
    int r0 = rt * 16;
    int tid = threadIdx.x;
    const float* src = g_xc + bd*LL;
    for (int j = tid; j < 18*66; j += 256){
        int r = j / 66 - 1 + r0;
        int c = j % 66 - 1;
        float v = 0.f;
        if (r >= 0 && r < 64 && c >= 0 && c < 64) v = src[r*64 + c];
        sT[j] = v;
    }
    float w9[9];
    #pragma unroll
    for (int i = 0; i < 9; i++) w9[i] = cw[d*9 + i];
    float bz = cb[d];
    __syncthreads();
    for (int j = tid; j < 16*64; j += 256){
        int r = j >> 6, c = j & 63;
        float s = bz;
        #pragma unroll
        for (int ky = 0; ky < 3; ky++)
            #pragma unroll
            for (int kx = 0; kx < 3; kx++)
                s = fmaf(w9[ky*3+kx], sT[(r+ky)*66 + c + kx], s);
        g_xcv[bd*LL + (r0+r)*64 + c] = siluf(s);
    }
}

// ---------------- kX: gather xs, x_proj GEMM, dt GEMM + softplus ----------------
__global__ void kX(const float* __restrict__ xpw, const float* __restrict__ dtw,
                   const float* __restrict__ dtb){
    __shared__ float sxs[16*196];
    __shared__ float sWx[38*DN];
    __shared__ float sdtw[DN*6];
    __shared__ float sdt[6*17];
    int tile = blockIdx.x & 255;
    int k    = (blockIdx.x >> 8) & 3;
    int b    = blockIdx.x >> 10;
    int t0   = tile * 16;
    int tid  = threadIdx.x;
    int base = (b*KK + k)*LL;

    for (int j = tid; j < 38*DN/4; j += 256)
        ((float4*)sWx)[j] = ((const float4*)(xpw + k*38*DN))[j];
    for (int j = tid; j < DN*6/2; j += 256)
        ((float2*)sdtw)[j] = ((const float2*)(dtw + k*DN*6))[j];
    for (int j = tid; j < DN*16; j += 256){
        int d = j >> 4, tt = j & 15;
        int t = t0 + tt;
        int pix;
        if (k == 0)      pix = t;
        else if (k == 1) pix = (t & 63)*64 + (t >> 6);
        else if (k == 2) pix = LL - 1 - t;
        else { int tr = LL - 1 - t; pix = (tr & 63)*64 + (tr >> 6); }
        sxs[tt*196 + d] = g_xcv[(b*DN + d)*LL + pix];
    }
    __syncthreads();
    for (int j = tid; j < 16*48; j += 256){
        int tt = j / 48, dq = j % 48;
        *(float4*)&g_xs[(base + t0 + tt)*DN + dq*4] = *(float4*)&sxs[tt*196 + dq*4];
    }
    for (int j = tid; j < 38*16; j += 256){
        int c = j >> 4, tt = j & 15;
        float acc = 0.f;
        for (int dq = 0; dq < 48; dq++){
            float4 a4 = *(float4*)&sxs[tt*196 + dq*4];
            float4 wv = *(float4*)&sWx[c*DN + dq*4];
            acc = dot4(a4, wv, acc);
        }
        if (c < RR)            sdt[c*17 + tt] = acc;
        else if (c < RR + NN)  g_bs[(base + t0 + tt)*NN + (c - RR)] = acc;
        else                   g_cs[(base + t0 + tt)*NN + (c - RR - NN)] = acc;
    }
    __syncthreads();
    float* sdl = sWx;
    {
        int tt = tid & 15, dq = tid >> 4;
        float acc[12];
        #pragma unroll
        for (int j = 0; j < 12; j++) acc[j] = dtb[k*DN + dq*12 + j];
        float dts[6];
        #pragma unroll
        for (int r = 0; r < RR; r++) dts[r] = sdt[r*17 + tt];
        #pragma unroll
        for (int j = 0; j < 12; j++){
            int d = dq*12 + j;
            float a = acc[j];
            #pragma unroll
            for (int r = 0; r < RR; r++)
                a = fmaf(dts[r], sdtw[d*6 + r], a);
            float dl = (a > 20.f) ? a : log1pf(__expf(a));
            acc[j] = dl;
        }
        __syncthreads();
        #pragma unroll
        for (int j = 0; j < 12; j++) sdl[tt*DN + dq*12 + j] = acc[j];
    }
    __syncthreads();
    for (int j = tid; j < 16*48; j += 256){
        int tt = j / 48, dq = j % 48;
        *(float4*)&g_delta[(base + t0 + tt)*DN + dq*4] = *(float4*)&sdl[tt*DN + dq*4];
    }
}

// ---------------- kF1: per-segment propagator P and offset q ----------------
__global__ void kF1(const float* __restrict__ A_log){
    __shared__ float sD[16*8], sX[16*8], sB[16*16];
    int bid = blockIdx.x;
    int dg = (bid % 24) * 8;
    int s  = (bid / 24) % (SEG-1);
    int k  = (bid / (24*(SEG-1))) % 4;
    int b  = bid / (24*(SEG-1)*4);
    int tid = threadIdx.x;
    int ch = tid >> 4, n = tid & 15;
    int d  = dg + ch;
    int base = (b*KK + k)*LL + s*SEGLEN;

    float a = -__expf(A_log[(k*DN + d)*NN + n]);
    float h = 0.f, P = 1.f;

    int lt = tid >> 3, lc = tid & 7;
    float rD, rX, rB[2];
    rD = g_delta[(base + lt)*DN + dg + lc];
    rX = g_xs   [(base + lt)*DN + dg + lc];
    #pragma unroll
    for (int i = 0; i < 2; i++){
        int jj = tid + i*128;
        rB[i] = g_bs[base*NN + jj];
    }
    for (int chunk = 0; chunk < SEGLEN/16; chunk++){
        sD[tid] = rD;  sX[tid] = rX;
        sB[tid] = rB[0];  sB[tid+128] = rB[1];
        __syncthreads();
        if (chunk < SEGLEN/16 - 1){
            int t0n = (chunk + 1) * 16;
            rD = g_delta[(base + t0n + lt)*DN + dg + lc];
            rX = g_xs   [(base + t0n + lt)*DN + dg + lc];
            #pragma unroll
            for (int i = 0; i < 2; i++){
                int jj = tid + i*128;
                rB[i] = g_bs[(base + t0n)*NN + jj];
            }
        }
        #pragma unroll
        for (int t = 0; t < 16; t++){
            float dl = sD[t*8 + ch];
            float xv = sX[t*8 + ch];
            float Bn = sB[t*16 + n];
            float e  = __expf(dl * a);
            h = fmaf(e, h, dl * xv * Bn);
            P *= e;
        }
        __syncthreads();
    }
    int chain = (b*KK + k)*DN + d;
    g_P[(chain*(SEG-1) + s)*NN + n] = P;
    g_q[(chain*(SEG-1) + s)*NN + n] = h;
}

// ---------------- kF2: prefix over segments -> g_h0 ----------------
__global__ void kF2(){
    int gid = blockIdx.x*blockDim.x + threadIdx.x;
    int chain = gid >> 4, n = gid & 15;
    float h = 0.f;
    g_h0[(chain*SEG + 0)*NN + n] = 0.f;
    #pragma unroll
    for (int s = 0; s < SEG-1; s++){
        float P = g_P[(chain*(SEG-1) + s)*NN + n];
        float q = g_q[(chain*(SEG-1) + s)*NN + n];
        h = fmaf(P, h, q);
        g_h0[(chain*SEG + s + 1)*NN + n] = h;
    }
}

// ---------------- kF3: full scan per segment with h0, produce y ----------------
__global__ void kF3(const float* __restrict__ A_log, const float* __restrict__ Ds){
    __shared__ float sD[16*8], sX[16*8], sB[16*16], sC[16*16], sY[16*8];
    int bid = blockIdx.x;
    int dg = (bid % 24) * 8;
    int s  = (bid / 24) % SEG;
    int k  = (bid / (24*SEG)) % 4;
    int b  = bid / (24*SEG*4);
    int tid = threadIdx.x;
    int ch = tid >> 4, n = tid & 15;
    int d  = dg + ch;
    int base = (b*KK + k)*LL + s*SEGLEN;
    int chain = (b*KK + k)*DN + d;

    float a  = -__expf(A_log[(k*DN + d)*NN + n]);
    float Dv = Ds[k*DN + d];
    float h  = g_h0[(chain*SEG + s)*NN + n];

    int lt = tid >> 3, lc = tid & 7;
    float rD, rX, rB[2], rC[2];
    rD = g_delta[(base + lt)*DN + dg + lc];
    rX = g_xs   [(base + lt)*DN + dg + lc];
    #pragma unroll
    for (int i = 0; i < 2; i++){
        int jj = tid + i*128;
        rB[i] = g_bs[base*NN + jj];
        rC[i] = g_cs[base*NN + jj];
    }
    for (int chunk = 0; chunk < SEGLEN/16; chunk++){
        sD[tid] = rD;  sX[tid] = rX;
        sB[tid] = rB[0];  sB[tid+128] = rB[1];
        sC[tid] = rC[0];  sC[tid+128] = rC[1];
        __syncthreads();
        if (chunk < SEGLEN/16 - 1){
            int t0n = (chunk + 1) * 16;
            rD = g_delta[(base + t0n + lt)*DN + dg + lc];
            rX = g_xs   [(base + t0n + lt)*DN + dg + lc];
            #pragma unroll
            for (int i = 0; i < 2; i++){
                int jj = tid + i*128;
                rB[i] = g_bs[(base + t0n)*NN + jj];
                rC[i] = g_cs[(base + t0n)*NN + jj];
            }
        }
        #pragma unroll
        for (int t = 0; t < 16; t++){
            float dl = sD[t*8 + ch];
            float xv = sX[t*8 + ch];
            float Bn = sB[t*16 + n];
            float Cn = sC[t*16 + n];
            float e  = __expf(dl * a);
            h = fmaf(e, h, dl * xv * Bn);
            float p = h * Cn;
            p += __shfl_xor_sync(0xffffffffu, p, 8);
            p += __shfl_xor_sync(0xffffffffu, p, 4);
            p += __shfl_xor_sync(0xffffffffu, p, 2);
            p += __shfl_xor_sync(0xffffffffu, p, 1);
            if (n == 0) sY[t*8 + ch] = p + Dv * xv;
        }
        __syncthreads();
        g_ys[(base + chunk*16 + lt)*DN + dg + lc] = sY[lt*8 + lc];
    }
}

// ---------------- kG: combine 4 directions + out LN + silu(z) gate -> yln ----------------
__global__ void kG(const float* __restrict__ lng, const float* __restrict__ lnb){
    int gw   = (blockIdx.x*blockDim.x + threadIdx.x) >> 5;
    int lane = threadIdx.x & 31;
    for (int q = 0; q < 8; q++){
        int pg = gw*8 + q;
        int b  = pg >> 12;
        int l  = pg & 4095;
        int hh = l >> 6, ww = l & 63;
        int t1 = ww*64 + hh;
        int b4 = b*KK*LL;
        float y[6], zf[6];
        float s = 0.f, s2 = 0.f;
        #pragma unroll
        for (int i = 0; i < 6; i++){
            int dd = lane + i*32;
            float v = g_ys[(b4 + 0*LL + l)*DN + dd]
                    + g_ys[(b4 + 2*LL + (LL-1-l))*DN + dd]
                    + g_ys[(b4 + 1*LL + t1)*DN + dd]
                    + g_ys[(b4 + 3*LL + (LL-1-t1))*DN + dd];
            y[i]  = v;  s += v;  s2 += v*v;
            zf[i] = g_z[(b*LL + l)*DN + dd];
        }
        #pragma unroll
        for (int off = 16; off > 0; off >>= 1){
            s  += __shfl_xor_sync(0xffffffffu, s,  off);
            s2 += __shfl_xor_sync(0xffffffffu, s2, off);
        }
        float m   = s * (1.f/192.f);
        float var = s2 * (1.f/192.f) - m*m;
        float rstd = rsqrtf(var + 1e-5f);
        #pragma unroll
        for (int i = 0; i < 6; i++){
            int dd = lane + i*32;
            float yn = (y[i] - m) * rstd * lng[dd] + lnb[dd];
            g_yln[(b*LL + l)*DN + dd] = yn * siluf(zf[i]);
        }
    }
}

// ---------------- kH v3: out_proj 192->96, 256 thr, 32p, P=2 x T=6, 4 k-chunks ----------
__global__ void kH(const float* __restrict__ w, const float* __restrict__ bias){
    __shared__ float sA[32*196];   // [p][k] padded (25.1KB)
    __shared__ float sW[96*48];    // [o][k_local] chunk (18.4KB); reused as stage
    int b = blockIdx.x >> 7;
    int pix0 = (blockIdx.x & 127) * 32;
    int tid = threadIdx.x;
    for (int j = tid; j < 32*48; j += 256){
        int p = j / 48, dq = j % 48;
        *(float4*)&sA[p*196 + dq*4] = *(const float4*)&g_yln[(b*LL + pix0 + p)*DN + dq*4];
    }
    int p = tid & 15, og = tid >> 4;   // 16 og x 6 outputs, 2 pixels
    float acc[2][6];
    #pragma unroll
    for (int j = 0; j < 6; j++){ acc[0][j] = bias[og*6+j]; acc[1][j] = acc[0][j]; }
    for (int kc = 0; kc < 4; kc++){
        __syncthreads();
        for (int j = tid; j < 96*12; j += 256){
            int o = j / 12, kq = j % 12;
            *(float4*)&sW[o*48 + kq*4] = *(const float4*)&w[o*DN + kc*48 + kq*4];
        }
        __syncthreads();
        #pragma unroll 4
        for (int kq = 0; kq < 12; kq++){
            float4 a0 = *(float4*)&sA[p*196 + kc*48 + kq*4];
            float4 a1 = *(float4*)&sA[(p+16)*196 + kc*48 + kq*4];
            #pragma unroll
            for (int j = 0; j < 6; j++){
                float4 wv = *(float4*)&sW[(og*6+j)*48 + kq*4];
                acc[0][j] = dot4(a0, wv, acc[0][j]);
                acc[1][j] = dot4(a1, wv, acc[1][j]);
            }
        }
    }
    __syncthreads();
    float* st = sW;   // stage [o][33]
    #pragma unroll
    for (int pi = 0; pi < 2; pi++)
        #pragma unroll
        for (int j = 0; j < 6; j++)
            st[(og*6+j)*33 + p + pi*16] = acc[pi][j];
    __syncthreads();
    for (int j = tid; j < 32*96; j += 256){
        int pp = j / 96, o = j % 96;
        g_dd[(b*LL + pix0 + pp)*CHID + o] = st[o*33 + pp];
    }
}

// ---------------- kI v3: up + bn + silu + residual + gate, 256 thr, 32p, P=2 x T=4 ------
__global__ void kI(const float* __restrict__ w, const float* __restrict__ bias,
                   const float* __restrict__ bng, const float* __restrict__ bnb,
                   float* __restrict__ out){
    __shared__ float sA[32*100];  // [p][k] padded
    __shared__ float sW[64*96];   // raw (o,k)
    __shared__ float sO[64*33];
    int b = blockIdx.x >> 7;
    int pix0 = (blockIdx.x & 127) * 32;
    int tid = threadIdx.x;
    for (int j = tid; j < 64*96/4; j += 256)
        ((float4*)sW)[j] = ((const float4*)w)[j];
    for (int j = tid; j < 32*24; j += 256){
        int p = j / 24, cq = j % 24;
        *(float4*)&sA[p*100 + cq*4] = *(const float4*)&g_dd[(b*LL + pix0 + p)*CHID + cq*4];
    }
    __syncthreads();
    int p = tid & 15, og = tid >> 4;   // 16 og x 4 outputs, 2 pixels
    float acc[2][4];
    #pragma unroll
    for (int j = 0; j < 4; j++){ acc[0][j] = bias[og*4+j]; acc[1][j] = acc[0][j]; }
    #pragma unroll 4
    for (int kq = 0; kq < 24; kq++){
        float4 a0 = *(float4*)&sA[p*100 + kq*4];
        float4 a1 = *(float4*)&sA[(p+16)*100 + kq*4];
        #pragma unroll
        for (int j = 0; j < 4; j++){
            float4 wv = *(float4*)&sW[(og*4+j)*CHID + kq*4];
            acc[0][j] = dot4(a0, wv, acc[0][j]);
            acc[1][j] = dot4(a1, wv, acc[1][j]);
        }
    }
    #pragma unroll
    for (int j = 0; j < 4; j++){
        int o = og*4 + j;
        float inv = bng[o] * rsqrtf(1.00001f);
        float bb = bnb[o];
        sO[o*33 + p]      = siluf(acc[0][j] * inv + bb);
        sO[o*33 + p + 16] = siluf(acc[1][j] * inv + bb);
    }
    __syncthreads();
    for (int j = tid; j < 64*32; j += 256){
        int o = j >> 5, pp = j & 31;
        int idx = (b*CIN + o)*LL + pix0 + pp;
        out[idx] = (sO[o*33 + pp] + g_diff[idx]) * g_gate[idx];
    }
}

// ---------------- launcher ----------------
extern "C" void kernel_launch(void* const* d_in, const int* in_sizes, int n_in,
                              void* d_out, int out_size){
    const float* pre        = (const float*)d_in[0];
    const float* post       = (const float*)d_in[1];
    const float* prepost_w  = (const float*)d_in[2];
    const float* prepost_b  = (const float*)d_in[3];
    const float* prepost_g  = (const float*)d_in[4];
    const float* prepost_bb = (const float*)d_in[5];
    const float* down_w     = (const float*)d_in[6];
    const float* down_b     = (const float*)d_in[7];
    const float* down_g     = (const float*)d_in[8];
    const float* down_bb    = (const float*)d_in[9];
    const float* up_w       = (const float*)d_in[10];
    const float* up_b       = (const float*)d_in[11];
    const float* up_g       = (const float*)d_in[12];
    const float* up_bb      = (const float*)d_in[13];
    const float* pe_w       = (const float*)d_in[14];
    const float* pe_b       = (const float*)d_in[15];
    const float* pe_ln_g    = (const float*)d_in[16];
    const float* pe_ln_b    = (const float*)d_in[17];
    const float* in_proj_w  = (const float*)d_in[18];
    const float* in_proj_b  = (const float*)d_in[19];
    const float* conv_w     = (const float*)d_in[20];
    const float* conv_b     = (const float*)d_in[21];
    const float* x_proj_w   = (const float*)d_in[22];
    const float* dt_w       = (const float*)d_in[23];
    const float* dt_b       = (const float*)d_in[24];
    const float* A_log      = (const float*)d_in[25];
    const float* Ds         = (const float*)d_in[26];
    const float* out_ln_g   = (const float*)d_in[27];
    const float* out_ln_b   = (const float*)d_in[28];
    const float* out_proj_w = (const float*)d_in[29];
    const float* out_proj_b = (const float*)d_in[30];
    float* out = (float*)d_out;

    kDiff<<<BB*CIN*LL/4/256, 256>>>(pre, post);
    kGate2<<<BB*(LL/32), 256>>>(pre, post, prepost_w, prepost_b, prepost_g, prepost_bb);
    kB<<<BB*(LL/32), 256>>>(down_w, down_b, down_g, down_bb);
    kC<<<BB*(LL/32), 256>>>(pe_w, pe_b, pe_ln_g, pe_ln_b);
    kD<<<BB*(LL/32), 256>>>(in_proj_w, in_proj_b);
    kE<<<BB*DN*4, 256>>>(conv_w, conv_b);
    kX<<<BB*KK*(LL/16), 256>>>(x_proj_w, dt_w, dt_b);
    kF1<<<BB*KK*(SEG-1)*(DN/8), 128>>>(A_log);
    kF2<<<(BB*KK*DN*NN)/256, 256>>>();
    kF3<<<BB*KK*SEG*(DN/8), 128>>>(A_log, Ds);
    kG<<<256, 256>>>(out_ln_g, out_ln_b);
    kH<<<BB*(LL/32), 256>>>(out_proj_w, out_proj_b);
    kI<<<BB*(LL/32), 256>>>(up_w, up_b, up_g, up_bb, out);
}

// round 7
// speedup vs baseline: 1.2529x; 1.0478x over previous
#include <cuda_runtime.h>
#include <math.h>

#define BB 4
#define CIN 64
#define CHID 96
#define LL 4096
#define NN 16
#define RR 6
#define KK 4
#define DN 192
#define SEG 8
#define SEGLEN 512

// ---------------- static scratch (no allocation anywhere) ----------------
__device__ float g_diff [BB*CIN*LL];
__device__ float g_gate [BB*CIN*LL];
__device__ float g_d1   [BB*LL*CHID];
__device__ float g_xln  [BB*LL*CHID];
__device__ float g_xc   [BB*DN*LL];
__device__ float g_xcv  [BB*DN*LL];
__device__ float g_z    [BB*LL*DN];
__device__ float g_xs   [BB*KK*LL*DN];
__device__ float g_delta[BB*KK*LL*DN];
__device__ float g_bs   [BB*KK*LL*NN];
__device__ float g_cs   [BB*KK*LL*NN];
__device__ float g_ys   [BB*KK*LL*DN];
__device__ float g_yln  [BB*LL*DN];
__device__ float g_dd   [BB*LL*CHID];
__device__ float g_P [BB*KK*DN*(SEG-1)*NN];
__device__ float g_q [BB*KK*DN*(SEG-1)*NN];
__device__ float g_h0[BB*KK*DN*SEG*NN];

__device__ __forceinline__ float sigm(float x){ return 1.f/(1.f+__expf(-x)); }
__device__ __forceinline__ float siluf(float x){ return x*sigm(x); }
__device__ __forceinline__ float dot4(float4 a, float4 w, float acc){
    acc = fmaf(a.x, w.x, acc);
    acc = fmaf(a.y, w.y, acc);
    acc = fmaf(a.z, w.z, acc);
    acc = fmaf(a.w, w.w, acc);
    return acc;
}

// ---------------- kDiff ----------------
__global__ void kDiff(const float* __restrict__ pre, const float* __restrict__ post){
    int i = blockIdx.x*blockDim.x + threadIdx.x;
    const float4 a = ((const float4*)pre)[i];
    const float4 b = ((const float4*)post)[i];
    float4 r;
    r.x = fabsf(b.x-a.x); r.y = fabsf(b.y-a.y);
    r.z = fabsf(b.z-a.z); r.w = fabsf(b.w-a.w);
    ((float4*)g_diff)[i] = r;
}

// ---------------- kGate2 ----------------
__global__ void kGate2(const float* __restrict__ pre, const float* __restrict__ post,
                       const float* __restrict__ w, const float* __restrict__ bias,
                       const float* __restrict__ bng, const float* __restrict__ bnb){
    __shared__ float sW[CIN*CIN];
    __shared__ float sP[CIN*32];
    __shared__ float sQ[CIN*32];
    __shared__ float sO[CIN*32];
    int b = blockIdx.x >> 7;
    int pix0 = (blockIdx.x & 127) * 32;
    int tid = threadIdx.x;
    for (int j = tid; j < CIN*CIN/4; j += 256)
        ((float4*)sW)[j] = ((const float4*)w)[j];
    for (int j = tid; j < CIN*32; j += 256){
        int c = j >> 5, p = j & 31;
        int idx = (b*CIN + c)*LL + pix0 + p;
        sP[j] = pre[idx];
        sQ[j] = post[idx];
    }
    __syncthreads();
    int p = tid & 31, og = tid >> 5;
    float a1[8], a2[8];
    #pragma unroll
    for (int j = 0; j < 8; j++){ a1[j] = 0.f; a2[j] = 0.f; }
    for (int kq = 0; kq < 16; kq++){
        float x1[4], x2[4];
        #pragma unroll
        for (int i = 0; i < 4; i++){
            x1[i] = sP[(kq*4+i)*32 + p];
            x2[i] = sQ[(kq*4+i)*32 + p];
        }
        #pragma unroll
        for (int j = 0; j < 8; j++){
            float4 wv = *(float4*)&sW[(og*8+j)*CIN + kq*4];
            a1[j] = fmaf(x1[0],wv.x, fmaf(x1[1],wv.y, fmaf(x1[2],wv.z, fmaf(x1[3],wv.w, a1[j]))));
            a2[j] = fmaf(x2[0],wv.x, fmaf(x2[1],wv.y, fmaf(x2[2],wv.z, fmaf(x2[3],wv.w, a2[j]))));
        }
    }
    #pragma unroll
    for (int j = 0; j < 8; j++){
        int o = og*8 + j;
        float inv = bng[o] * rsqrtf(1.00001f);
        float bz  = bias[o];
        float bb  = bnb[o];
        float t1 = (a1[j] + bz) * inv + bb;
        float t2 = (a2[j] + bz) * inv + bb;
        sO[o*32 + p] = sigm(siluf(t1)) * sigm(siluf(t2));
    }
    __syncthreads();
    for (int j = tid; j < CIN*32; j += 256){
        int o = j >> 5, pp = j & 31;
        g_gate[(b*CIN + o)*LL + pix0 + pp] = sO[j];
    }
}

// ---------------- kB ----------------
__global__ void kB(const float* __restrict__ w, const float* __restrict__ bias,
                   const float* __restrict__ bng, const float* __restrict__ bnb){
    __shared__ float sW[CHID*CIN];
    __shared__ float sA[CIN*32];
    int b = blockIdx.x >> 7;
    int pix0 = (blockIdx.x & 127) * 32;
    int tid = threadIdx.x;
    for (int j = tid; j < CHID*CIN/4; j += 256)
        ((float4*)sW)[j] = ((const float4*)w)[j];
    for (int j = tid; j < CIN*32; j += 256){
        int c = j >> 5, p = j & 31;
        sA[j] = g_diff[(b*CIN + c)*LL + pix0 + p];
    }
    __syncthreads();
    int p = tid & 31, og = tid >> 5;
    float acc[12];
    #pragma unroll
    for (int j = 0; j < 12; j++) acc[j] = 0.f;
    for (int kq = 0; kq < 16; kq++){
        float x[4];
        #pragma unroll
        for (int i = 0; i < 4; i++) x[i] = sA[(kq*4+i)*32 + p];
        #pragma unroll
        for (int j = 0; j < 12; j++){
            float4 wv = *(float4*)&sW[(og*12+j)*CIN + kq*4];
            acc[j] = fmaf(x[0],wv.x, fmaf(x[1],wv.y, fmaf(x[2],wv.z, fmaf(x[3],wv.w, acc[j]))));
        }
    }
    float res[12];
    #pragma unroll
    for (int j = 0; j < 12; j++){
        int o = og*12 + j;
        float inv = bng[o] * rsqrtf(1.00001f);
        float t = (acc[j] + bias[o]) * inv + bnb[o];
        res[j] = siluf(t);
    }
    float4* dst = (float4*)&g_d1[(b*LL + pix0 + p)*CHID + og*12];
    #pragma unroll
    for (int v = 0; v < 3; v++)
        dst[v] = make_float4(res[v*4], res[v*4+1], res[v*4+2], res[v*4+3]);
}

// ---------------- kC: xln = LN(pe(d1)), 256 thr, 32 pixels, P=2 x T=6 ----------------
__global__ void kC(const float* __restrict__ w, const float* __restrict__ bias,
                   const float* __restrict__ lng, const float* __restrict__ lnb){
    __shared__ float sA[32*100];
    __shared__ float sW[96*48];
    __shared__ float sS[32*16], sS2[32*16];
    __shared__ float sM[32], sR[32];
    int b = blockIdx.x >> 7;
    int pix0 = (blockIdx.x & 127) * 32;
    int tid = threadIdx.x;
    for (int j = tid; j < 32*24; j += 256){
        int p = j / 24, cq = j % 24;
        *(float4*)&sA[p*100 + cq*4] = *(const float4*)&g_d1[(b*LL + pix0 + p)*CHID + cq*4];
    }
    int p = tid & 15, og = tid >> 4;
    float acc[2][6];
    #pragma unroll
    for (int j = 0; j < 6; j++){ acc[0][j] = bias[og*6+j]; acc[1][j] = acc[0][j]; }
    for (int kc = 0; kc < 2; kc++){
        __syncthreads();
        for (int j = tid; j < 96*12; j += 256){
            int o = j / 12, kq = j % 12;
            *(float4*)&sW[o*48 + kq*4] = *(const float4*)&w[o*CHID + kc*48 + kq*4];
        }
        __syncthreads();
        #pragma unroll 4
        for (int kq = 0; kq < 12; kq++){
            float4 a0 = *(float4*)&sA[p*100 + kc*48 + kq*4];
            float4 a1 = *(float4*)&sA[(p+16)*100 + kc*48 + kq*4];
            #pragma unroll
            for (int j = 0; j < 6; j++){
                float4 wv = *(float4*)&sW[(og*6+j)*48 + kq*4];
                acc[0][j] = dot4(a0, wv, acc[0][j]);
                acc[1][j] = dot4(a1, wv, acc[1][j]);
            }
        }
    }
    #pragma unroll
    for (int pi = 0; pi < 2; pi++){
        float s = 0.f, s2 = 0.f;
        #pragma unroll
        for (int j = 0; j < 6; j++){ s += acc[pi][j]; s2 += acc[pi][j]*acc[pi][j]; }
        sS [(p + pi*16)*16 + og] = s;
        sS2[(p + pi*16)*16 + og] = s2;
    }
    __syncthreads();
    if (tid < 32){
        float ss = 0.f, ss2 = 0.f;
        #pragma unroll
        for (int i = 0; i < 16; i++){ ss += sS[tid*16+i]; ss2 += sS2[tid*16+i]; }
        float m = ss * (1.f/96.f);
        float var = ss2 * (1.f/96.f) - m*m;
        sM[tid] = m;  sR[tid] = rsqrtf(var + 1e-5f);
    }
    __syncthreads();
    float* st = sW;
    #pragma unroll
    for (int pi = 0; pi < 2; pi++){
        int pp = p + pi*16;
        float m = sM[pp], rs = sR[pp];
        #pragma unroll
        for (int j = 0; j < 6; j++){
            int o = og*6 + j;
            st[o*33 + pp] = (acc[pi][j] - m) * rs * lng[o] + lnb[o];
        }
    }
    __syncthreads();
    for (int j = tid; j < 32*96; j += 256){
        int pp = j / 96, o = j % 96;
        g_xln[(b*LL + pix0 + pp)*CHID + o] = st[o*33 + pp];
    }
}

// ---------------- kD: in_proj 96->384, 256 thr, 32p, P=2 x T=4, 6 o-chunks ------------
__global__ void kD(const float* __restrict__ w, const float* __restrict__ bias){
    __shared__ float sA[32*100];
    __shared__ float sW[64*96];
    __shared__ float sO[64*33];
    int b = blockIdx.x >> 7;
    int pix0 = (blockIdx.x & 127) * 32;
    int tid = threadIdx.x;
    for (int j = tid; j < 32*24; j += 256){
        int p = j / 24, cq = j % 24;
        *(float4*)&sA[p*100 + cq*4] = *(const float4*)&g_xln[(b*LL + pix0 + p)*CHID + cq*4];
    }
    int p = tid & 15, og = tid >> 4;
    for (int ch = 0; ch < 6; ch++){
        __syncthreads();
        for (int j = tid; j < 64*96/4; j += 256)
            ((float4*)sW)[j] = ((const float4*)(w + ch*64*CHID))[j];
        __syncthreads();
        float acc[2][4];
        #pragma unroll
        for (int j = 0; j < 4; j++){ acc[0][j] = bias[ch*64 + og*4 + j]; acc[1][j] = acc[0][j]; }
        #pragma unroll 4
        for (int kq = 0; kq < 24; kq++){
            float4 a0 = *(float4*)&sA[p*100 + kq*4];
            float4 a1 = *(float4*)&sA[(p+16)*100 + kq*4];
            #pragma unroll
            for (int j = 0; j < 4; j++){
                float4 wv = *(float4*)&sW[(og*4+j)*CHID + kq*4];
                acc[0][j] = dot4(a0, wv, acc[0][j]);
                acc[1][j] = dot4(a1, wv, acc[1][j]);
            }
        }
        #pragma unroll
        for (int j = 0; j < 4; j++){
            sO[(og*4+j)*33 + p]      = acc[0][j];
            sO[(og*4+j)*33 + p + 16] = acc[1][j];
        }
        __syncthreads();
        if (ch < 3){
            for (int j = tid; j < 64*32; j += 256){
                int o = j >> 5, pp = j & 31;
                g_xc[(b*DN + ch*64 + o)*LL + pix0 + pp] = sO[o*33 + pp];
            }
        } else {
            for (int j = tid; j < 32*64; j += 256){
                int pp = j >> 6, oz = j & 63;
                g_z[(b*LL + pix0 + pp)*DN + (ch-3)*64 + oz] = sO[oz*33 + pp];
            }
        }
    }
}

// ---------------- kE: depthwise 3x3 conv + bias + silu ----------------
__global__ void kE(const float* __restrict__ cw, const float* __restrict__ cb){
    __shared__ float sT[18*66];
    int bid = blockIdx.x;
    int rt = bid & 3;
    int bd = bid >> 2;
    int d  = bd % DN;
    int r0 = rt * 16;
    int tid = threadIdx.x;
    const float* src = g_xc + bd*LL;
    for (int j = tid; j < 18*66; j += 256){
        int r = j / 66 - 1 + r0;
        int c = j % 66 - 1;
        float v = 0.f;
        if (r >= 0 && r < 64 && c >= 0 && c < 64) v = src[r*64 + c];
        sT[j] = v;
    }
    float w9[9];
    #pragma unroll
    for (int i = 0; i < 9; i++) w9[i] = cw[d*9 + i];
    float bz = cb[d];
    __syncthreads();
    for (int j = tid; j < 16*64; j += 256){
        int r = j >> 6, c = j & 63;
        float s = bz;
        #pragma unroll
        for (int ky = 0; ky < 3; ky++)
            #pragma unroll
            for (int kx = 0; kx < 3; kx++)
                s = fmaf(w9[ky*3+kx], sT[(r+ky)*66 + c + kx], s);
        g_xcv[bd*LL + (r0+r)*64 + c] = siluf(s);
    }
}

// ---------------- kX: gather xs, x_proj GEMM, dt GEMM + softplus ----------------
__global__ void kX(const float* __restrict__ xpw, const float* __restrict__ dtw,
                   const float* __restrict__ dtb){
    __shared__ float sxs[16*196];
    __shared__ float sWx[38*DN];
    __shared__ float sdtw[DN*6];
    __shared__ float sdt[6*17];
    int tile = blockIdx.x & 255;
    int k    = (blockIdx.x >> 8) & 3;
    int b    = blockIdx.x >> 10;
    int t0   = tile * 16;
    int tid  = threadIdx.x;
    int base = (b*KK + k)*LL;

    for (int j = tid; j < 38*DN/4; j += 256)
        ((float4*)sWx)[j] = ((const float4*)(xpw + k*38*DN))[j];
    for (int j = tid; j < DN*6/2; j += 256)
        ((float2*)sdtw)[j] = ((const float2*)(dtw + k*DN*6))[j];
    for (int j = tid; j < DN*16; j += 256){
        int d = j >> 4, tt = j & 15;
        int t = t0 + tt;
        int pix;
        if (k == 0)      pix = t;
        else if (k == 1) pix = (t & 63)*64 + (t >> 6);
        else if (k == 2) pix = LL - 1 - t;
        else { int tr = LL - 1 - t; pix = (tr & 63)*64 + (tr >> 6); }
        sxs[tt*196 + d] = g_xcv[(b*DN + d)*LL + pix];
    }
    __syncthreads();
    for (int j = tid; j < 16*48; j += 256){
        int tt = j / 48, dq = j % 48;
        *(float4*)&g_xs[(base + t0 + tt)*DN + dq*4] = *(float4*)&sxs[tt*196 + dq*4];
    }
    for (int j = tid; j < 38*16; j += 256){
        int c = j >> 4, tt = j & 15;
        float acc = 0.f;
        for (int dq = 0; dq < 48; dq++){
            float4 a4 = *(float4*)&sxs[tt*196 + dq*4];
            float4 wv = *(float4*)&sWx[c*DN + dq*4];
            acc = dot4(a4, wv, acc);
        }
        if (c < RR)            sdt[c*17 + tt] = acc;
        else if (c < RR + NN)  g_bs[(base + t0 + tt)*NN + (c - RR)] = acc;
        else                   g_cs[(base + t0 + tt)*NN + (c - RR - NN)] = acc;
    }
    __syncthreads();
    float* sdl = sWx;
    {
        int tt = tid & 15, dq = tid >> 4;
        float acc[12];
        #pragma unroll
        for (int j = 0; j < 12; j++) acc[j] = dtb[k*DN + dq*12 + j];
        float dts[6];
        #pragma unroll
        for (int r = 0; r < RR; r++) dts[r] = sdt[r*17 + tt];
        #pragma unroll
        for (int j = 0; j < 12; j++){
            int d = dq*12 + j;
            float a = acc[j];
            #pragma unroll
            for (int r = 0; r < RR; r++)
                a = fmaf(dts[r], sdtw[d*6 + r], a);
            float dl = (a > 20.f) ? a : log1pf(__expf(a));
            acc[j] = dl;
        }
        __syncthreads();
        #pragma unroll
        for (int j = 0; j < 12; j++) sdl[tt*DN + dq*12 + j] = acc[j];
    }
    __syncthreads();
    for (int j = tid; j < 16*48; j += 256){
        int tt = j / 48, dq = j % 48;
        *(float4*)&g_delta[(base + t0 + tt)*DN + dq*4] = *(float4*)&sdl[tt*DN + dq*4];
    }
}

// ---------------- kF1 v2: per-segment propagator P and offset q ----------------
// 128 thr = 8 chains x 16 states; stages u = delta*x
__global__ void kF1(const float* __restrict__ A_log){
    __shared__ float sD[16*8], sU[16*8], sB[16*16];
    int bid = blockIdx.x;
    int dg = (bid % 24) * 8;
    int s  = (bid / 24) % (SEG-1);
    int k  = (bid / (24*(SEG-1))) % 4;
    int b  = bid / (24*(SEG-1)*4);
    int tid = threadIdx.x;
    int ch = tid >> 4, n = tid & 15;
    int d  = dg + ch;
    int base = (b*KK + k)*LL + s*SEGLEN;

    float a = -__expf(A_log[(k*DN + d)*NN + n]);
    float h = 0.f, P = 1.f;

    int lt = tid >> 3, lc = tid & 7;
    float rD, rX, rB[2];
    rD = g_delta[(base + lt)*DN + dg + lc];
    rX = g_xs   [(base + lt)*DN + dg + lc];
    #pragma unroll
    for (int i = 0; i < 2; i++){
        int jj = tid + i*128;
        rB[i] = g_bs[base*NN + jj];
    }
    for (int chunk = 0; chunk < SEGLEN/16; chunk++){
        sD[tid] = rD;  sU[tid] = rD * rX;
        sB[tid] = rB[0];  sB[tid+128] = rB[1];
        __syncthreads();
        if (chunk < SEGLEN/16 - 1){
            int t0n = (chunk + 1) * 16;
            rD = g_delta[(base + t0n + lt)*DN + dg + lc];
            rX = g_xs   [(base + t0n + lt)*DN + dg + lc];
            #pragma unroll
            for (int i = 0; i < 2; i++){
                int jj = tid + i*128;
                rB[i] = g_bs[(base + t0n)*NN + jj];
            }
        }
        #pragma unroll
        for (int t = 0; t < 16; t++){
            float dl = sD[t*8 + ch];
            float u  = sU[t*8 + ch];
            float Bn = sB[t*16 + n];
            float e  = __expf(dl * a);
            h = fmaf(e, h, u * Bn);
            P *= e;
        }
        __syncthreads();
    }
    int chain = (b*KK + k)*DN + d;
    g_P[(chain*(SEG-1) + s)*NN + n] = P;
    g_q[(chain*(SEG-1) + s)*NN + n] = h;
}

// ---------------- kF2: prefix over segments -> g_h0 ----------------
__global__ void kF2(){
    int gid = blockIdx.x*blockDim.x + threadIdx.x;
    int chain = gid >> 4, n = gid & 15;
    float h = 0.f;
    g_h0[(chain*SEG + 0)*NN + n] = 0.f;
    #pragma unroll
    for (int s = 0; s < SEG-1; s++){
        float P = g_P[(chain*(SEG-1) + s)*NN + n];
        float q = g_q[(chain*(SEG-1) + s)*NN + n];
        h = fmaf(P, h, q);
        g_h0[(chain*SEG + s + 1)*NN + n] = h;
    }
}

// ---------------- kF3 v2: full scan; smem transpose-reduce instead of shfl ------------
// 128 thr = 8 chains x 16 states. PhaseA: recurrence, store p=h*C (+D*x on n==0) to sP.
// PhaseB: threads re-map to (t,chain), sum 16 states, write y to gmem.
__global__ void kF3(const float* __restrict__ A_log, const float* __restrict__ Ds){
    __shared__ float sD[16*8], sU[16*8], sX[16*8], sB[16*16], sC[16*16];
    __shared__ float sP[NN*129];   // [n][t*8+ch], row pad 129 -> conflict-free phaseB
    int bid = blockIdx.x;
    int dg = (bid % 24) * 8;
    int s  = (bid / 24) % SEG;
    int k  = (bid / (24*SEG)) % 4;
    int b  = bid / (24*SEG*4);
    int tid = threadIdx.x;
    int ch = tid >> 4, n = tid & 15;
    int d  = dg + ch;
    int base = (b*KK + k)*LL + s*SEGLEN;
    int chain = (b*KK + k)*DN + d;

    float a  = -__expf(A_log[(k*DN + d)*NN + n]);
    float Dv = Ds[k*DN + d];
    float h  = g_h0[(chain*SEG + s)*NN + n];

    int lt = tid >> 3, lc = tid & 7;   // (t, chain) mapping for staging & phaseB
    float rD, rX, rB[2], rC[2];
    rD = g_delta[(base + lt)*DN + dg + lc];
    rX = g_xs   [(base + lt)*DN + dg + lc];
    #pragma unroll
    for (int i = 0; i < 2; i++){
        int jj = tid + i*128;
        rB[i] = g_bs[base*NN + jj];
        rC[i] = g_cs[base*NN + jj];
    }
    for (int chunk = 0; chunk < SEGLEN/16; chunk++){
        sD[tid] = rD;  sU[tid] = rD * rX;  sX[tid] = rX;
        sB[tid] = rB[0];  sB[tid+128] = rB[1];
        sC[tid] = rC[0];  sC[tid+128] = rC[1];
        __syncthreads();
        if (chunk < SEGLEN/16 - 1){
            int t0n = (chunk + 1) * 16;
            rD = g_delta[(base + t0n + lt)*DN + dg + lc];
            rX = g_xs   [(base + t0n + lt)*DN + dg + lc];
            #pragma unroll
            for (int i = 0; i < 2; i++){
                int jj = tid + i*128;
                rB[i] = g_bs[(base + t0n)*NN + jj];
                rC[i] = g_cs[(base + t0n)*NN + jj];
            }
        }
        // Phase A: recurrence, store h*C per state
        #pragma unroll
        for (int t = 0; t < 16; t++){
            float dl = sD[t*8 + ch];
            float u  = sU[t*8 + ch];
            float Bn = sB[t*16 + n];
            float Cn = sC[t*16 + n];
            float e  = __expf(dl * a);
            h = fmaf(e, h, u * Bn);
            float p = h * Cn;
            if (n == 0) p = fmaf(Dv, sX[t*8 + ch], p);
            sP[n*129 + t*8 + ch] = p;
        }
        __syncthreads();
        // Phase B: thread (t=lt, chain=lc) sums 16 states, writes y
        {
            float y = 0.f;
            #pragma unroll
            for (int nn = 0; nn < NN; nn++)
                y += sP[nn*129 + tid];
            g_ys[(base + chunk*16 + lt)*DN + dg + lc] = y;
        }
        // next chunk's staging writes sD/sU/sX/sB/sC (not sP) then syncs before
        // phaseA touches sP again -> no extra barrier needed
    }
}

// ---------------- kG: combine 4 directions + out LN + silu(z) gate -> yln ----------------
__global__ void kG(const float* __restrict__ lng, const float* __restrict__ lnb){
    int gw   = (blockIdx.x*blockDim.x + threadIdx.x) >> 5;
    int lane = threadIdx.x & 31;
    for (int q = 0; q < 8; q++){
        int pg = gw*8 + q;
        int b  = pg >> 12;
        int l  = pg & 4095;
        int hh = l >> 6, ww = l & 63;
        int t1 = ww*64 + hh;
        int b4 = b*KK*LL;
        float y[6], zf[6];
        float s = 0.f, s2 = 0.f;
        #pragma unroll
        for (int i = 0; i < 6; i++){
            int dd = lane + i*32;
            float v = g_ys[(b4 + 0*LL + l)*DN + dd]
                    + g_ys[(b4 + 2*LL + (LL-1-l))*DN + dd]
                    + g_ys[(b4 + 1*LL + t1)*DN + dd]
                    + g_ys[(b4 + 3*LL + (LL-1-t1))*DN + dd];
            y[i]  = v;  s += v;  s2 += v*v;
            zf[i] = g_z[(b*LL + l)*DN + dd];
        }
        #pragma unroll
        for (int off = 16; off > 0; off >>= 1){
            s  += __shfl_xor_sync(0xffffffffu, s,  off);
            s2 += __shfl_xor_sync(0xffffffffu, s2, off);
        }
        float m   = s * (1.f/192.f);
        float var = s2 * (1.f/192.f) - m*m;
        float rstd = rsqrtf(var + 1e-5f);
        #pragma unroll
        for (int i = 0; i < 6; i++){
            int dd = lane + i*32;
            float yn = (y[i] - m) * rstd * lng[dd] + lnb[dd];
            g_yln[(b*LL + l)*DN + dd] = yn * siluf(zf[i]);
        }
    }
}

// ---------------- kH: out_proj 192->96, 256 thr, 32p, P=2 x T=6, 4 k-chunks ----------
__global__ void kH(const float* __restrict__ w, const float* __restrict__ bias){
    __shared__ float sA[32*196];
    __shared__ float sW[96*48];
    int b = blockIdx.x >> 7;
    int pix0 = (blockIdx.x & 127) * 32;
    int tid = threadIdx.x;
    for (int j = tid; j < 32*48; j += 256){
        int p = j / 48, dq = j % 48;
        *(float4*)&sA[p*196 + dq*4] = *(const float4*)&g_yln[(b*LL + pix0 + p)*DN + dq*4];
    }
    int p = tid & 15, og = tid >> 4;
    float acc[2][6];
    #pragma unroll
    for (int j = 0; j < 6; j++){ acc[0][j] = bias[og*6+j]; acc[1][j] = acc[0][j]; }
    for (int kc = 0; kc < 4; kc++){
        __syncthreads();
        for (int j = tid; j < 96*12; j += 256){
            int o = j / 12, kq = j % 12;
            *(float4*)&sW[o*48 + kq*4] = *(const float4*)&w[o*DN + kc*48 + kq*4];
        }
        __syncthreads();
        #pragma unroll 4
        for (int kq = 0; kq < 12; kq++){
            float4 a0 = *(float4*)&sA[p*196 + kc*48 + kq*4];
            float4 a1 = *(float4*)&sA[(p+16)*196 + kc*48 + kq*4];
            #pragma unroll
            for (int j = 0; j < 6; j++){
                float4 wv = *(float4*)&sW[(og*6+j)*48 + kq*4];
                acc[0][j] = dot4(a0, wv, acc[0][j]);
                acc[1][j] = dot4(a1, wv, acc[1][j]);
            }
        }
    }
    __syncthreads();
    float* st = sW;
    #pragma unroll
    for (int pi = 0; pi < 2; pi++)
        #pragma unroll
        for (int j = 0; j < 6; j++)
            st[(og*6+j)*33 + p + pi*16] = acc[pi][j];
    __syncthreads();
    for (int j = tid; j < 32*96; j += 256){
        int pp = j / 96, o = j % 96;
        g_dd[(b*LL + pix0 + pp)*CHID + o] = st[o*33 + pp];
    }
}

// ---------------- kI: up + bn + silu + residual + gate, 256 thr, 32p, P=2 x T=4 ------
__global__ void kI(const float* __restrict__ w, const float* __restrict__ bias,
                   const float* __restrict__ bng, const float* __restrict__ bnb,
                   float* __restrict__ out){
    __shared__ float sA[32*100];
    __shared__ float sW[64*96];
    __shared__ float sO[64*33];
    int b = blockIdx.x >> 7;
    int pix0 = (blockIdx.x & 127) * 32;
    int tid = threadIdx.x;
    for (int j = tid; j < 64*96/4; j += 256)
        ((float4*)sW)[j] = ((const float4*)w)[j];
    for (int j = tid; j < 32*24; j += 256){
        int p = j / 24, cq = j % 24;
        *(float4*)&sA[p*100 + cq*4] = *(const float4*)&g_dd[(b*LL + pix0 + p)*CHID + cq*4];
    }
    __syncthreads();
    int p = tid & 15, og = tid >> 4;
    float acc[2][4];
    #pragma unroll
    for (int j = 0; j < 4; j++){ acc[0][j] = bias[og*4+j]; acc[1][j] = acc[0][j]; }
    #pragma unroll 4
    for (int kq = 0; kq < 24; kq++){
        float4 a0 = *(float4*)&sA[p*100 + kq*4];
        float4 a1 = *(float4*)&sA[(p+16)*100 + kq*4];
        #pragma unroll
        for (int j = 0; j < 4; j++){
            float4 wv = *(float4*)&sW[(og*4+j)*CHID + kq*4];
            acc[0][j] = dot4(a0, wv, acc[0][j]);
            acc[1][j] = dot4(a1, wv, acc[1][j]);
        }
    }
    #pragma unroll
    for (int j = 0; j < 4; j++){
        int o = og*4 + j;
        float inv = bng[o] * rsqrtf(1.00001f);
        float bb = bnb[o];
        sO[o*33 + p]      = siluf(acc[0][j] * inv + bb);
        sO[o*33 + p + 16] = siluf(acc[1][j] * inv + bb);
    }
    __syncthreads();
    for (int j = tid; j < 64*32; j += 256){
        int o = j >> 5, pp = j & 31;
        int idx = (b*CIN + o)*LL + pix0 + pp;
        out[idx] = (sO[o*33 + pp] + g_diff[idx]) * g_gate[idx];
    }
}

// ---------------- launcher ----------------
extern "C" void kernel_launch(void* const* d_in, const int* in_sizes, int n_in,
                              void* d_out, int out_size){
    const float* pre        = (const float*)d_in[0];
    const float* post       = (const float*)d_in[1];
    const float* prepost_w  = (const float*)d_in[2];
    const float* prepost_b  = (const float*)d_in[3];
    const float* prepost_g  = (const float*)d_in[4];
    const float* prepost_bb = (const float*)d_in[5];
    const float* down_w     = (const float*)d_in[6];
    const float* down_b     = (const float*)d_in[7];
    const float* down_g     = (const float*)d_in[8];
    const float* down_bb    = (const float*)d_in[9];
    const float* up_w       = (const float*)d_in[10];
    const float* up_b       = (const float*)d_in[11];
    const float* up_g       = (const float*)d_in[12];
    const float* up_bb      = (const float*)d_in[13];
    const float* pe_w       = (const float*)d_in[14];
    const float* pe_b       = (const float*)d_in[15];
    const float* pe_ln_g    = (const float*)d_in[16];
    const float* pe_ln_b    = (const float*)d_in[17];
    const float* in_proj_w  = (const float*)d_in[18];
    const float* in_proj_b  = (const float*)d_in[19];
    const float* conv_w     = (const float*)d_in[20];
    const float* conv_b     = (const float*)d_in[21];
    const float* x_proj_w   = (const float*)d_in[22];
    const float* dt_w       = (const float*)d_in[23];
    const float* dt_b       = (const float*)d_in[24];
    const float* A_log      = (const float*)d_in[25];
    const float* Ds         = (const float*)d_in[26];
    const float* out_ln_g   = (const float*)d_in[27];
    const float* out_ln_b   = (const float*)d_in[28];
    const float* out_proj_w = (const float*)d_in[29];
    const float* out_proj_b = (const float*)d_in[30];
    float* out = (float*)d_out;

    kDiff<<<BB*CIN*LL/4/256, 256>>>(pre, post);
    kGate2<<<BB*(LL/32), 256>>>(pre, post, prepost_w, prepost_b, prepost_g, prepost_bb);
    kB<<<BB*(LL/32), 256>>>(down_w, down_b, down_g, down_bb);
    kC<<<BB*(LL/32), 256>>>(pe_w, pe_b, pe_ln_g, pe_ln_b);
    kD<<<BB*(LL/32), 256>>>(in_proj_w, in_proj_b);
    kE<<<BB*DN*4, 256>>>(conv_w, conv_b);
    kX<<<BB*KK*(LL/16), 256>>>(x_proj_w, dt_w, dt_b);
    kF1<<<BB*KK*(SEG-1)*(DN/8), 128>>>(A_log);
    kF2<<<(BB*KK*DN*NN)/256, 256>>>();
    kF3<<<BB*KK*SEG*(DN/8), 128>>>(A_log, Ds);
    kG<<<256, 256>>>(out_ln_g, out_ln_b);
    kH<<<BB*(LL/32), 256>>>(out_proj_w, out_proj_b);
    kI<<<BB*(LL/32), 256>>>(up_w, up_b, up_g, up_bb, out);
}

// round 8
// speedup vs baseline: 1.3143x; 1.0490x over previous
#include <cuda_runtime.h>
#include <math.h>

#define BB 4
#define CIN 64
#define CHID 96
#define LL 4096
#define NN 16
#define RR 6
#define KK 4
#define DN 192
#define SEG 8
#define SEGLEN 512

// ---------------- static scratch (no allocation anywhere) ----------------
__device__ float g_diff [BB*CIN*LL];
__device__ float g_gate [BB*CIN*LL];
__device__ float g_d1   [BB*LL*CHID];
__device__ float g_xln  [BB*LL*CHID];
__device__ float g_xc   [BB*DN*LL];
__device__ float g_xcv  [BB*DN*LL];
__device__ float g_z    [BB*LL*DN];
__device__ float g_xs   [BB*KK*LL*DN];
__device__ float g_delta[BB*KK*LL*DN];
__device__ float g_bs   [BB*KK*LL*NN];
__device__ float g_cs   [BB*KK*LL*NN];
__device__ float g_ys   [BB*KK*LL*DN];
__device__ float g_dd   [BB*LL*CHID];
__device__ float g_P [BB*KK*DN*(SEG-1)*NN];
__device__ float g_q [BB*KK*DN*(SEG-1)*NN];
__device__ float g_h0[BB*KK*DN*SEG*NN];

__device__ __forceinline__ float sigm(float x){ return 1.f/(1.f+__expf(-x)); }
__device__ __forceinline__ float siluf(float x){ return x*sigm(x); }
__device__ __forceinline__ float dot4(float4 a, float4 w, float acc){
    acc = fmaf(a.x, w.x, acc);
    acc = fmaf(a.y, w.y, acc);
    acc = fmaf(a.z, w.z, acc);
    acc = fmaf(a.w, w.w, acc);
    return acc;
}

// ---------------- kDiff ----------------
__global__ void kDiff(const float* __restrict__ pre, const float* __restrict__ post){
    int i = blockIdx.x*blockDim.x + threadIdx.x;
    const float4 a = ((const float4*)pre)[i];
    const float4 b = ((const float4*)post)[i];
    float4 r;
    r.x = fabsf(b.x-a.x); r.y = fabsf(b.y-a.y);
    r.z = fabsf(b.z-a.z); r.w = fabsf(b.w-a.w);
    ((float4*)g_diff)[i] = r;
}

// ---------------- kGate2 ----------------
__global__ void kGate2(const float* __restrict__ pre, const float* __restrict__ post,
                       const float* __restrict__ w, const float* __restrict__ bias,
                       const float* __restrict__ bng, const float* __restrict__ bnb){
    __shared__ float sW[CIN*CIN];
    __shared__ float sP[CIN*32];
    __shared__ float sQ[CIN*32];
    __shared__ float sO[CIN*32];
    int b = blockIdx.x >> 7;
    int pix0 = (blockIdx.x & 127) * 32;
    int tid = threadIdx.x;
    for (int j = tid; j < CIN*CIN/4; j += 256)
        ((float4*)sW)[j] = ((const float4*)w)[j];
    for (int j = tid; j < CIN*32; j += 256){
        int c = j >> 5, p = j & 31;
        int idx = (b*CIN + c)*LL + pix0 + p;
        sP[j] = pre[idx];
        sQ[j] = post[idx];
    }
    __syncthreads();
    int p = tid & 31, og = tid >> 5;
    float a1[8], a2[8];
    #pragma unroll
    for (int j = 0; j < 8; j++){ a1[j] = 0.f; a2[j] = 0.f; }
    for (int kq = 0; kq < 16; kq++){
        float x1[4], x2[4];
        #pragma unroll
        for (int i = 0; i < 4; i++){
            x1[i] = sP[(kq*4+i)*32 + p];
            x2[i] = sQ[(kq*4+i)*32 + p];
        }
        #pragma unroll
        for (int j = 0; j < 8; j++){
            float4 wv = *(float4*)&sW[(og*8+j)*CIN + kq*4];
            a1[j] = fmaf(x1[0],wv.x, fmaf(x1[1],wv.y, fmaf(x1[2],wv.z, fmaf(x1[3],wv.w, a1[j]))));
            a2[j] = fmaf(x2[0],wv.x, fmaf(x2[1],wv.y, fmaf(x2[2],wv.z, fmaf(x2[3],wv.w, a2[j]))));
        }
    }
    #pragma unroll
    for (int j = 0; j < 8; j++){
        int o = og*8 + j;
        float inv = bng[o] * rsqrtf(1.00001f);
        float bz  = bias[o];
        float bb  = bnb[o];
        float t1 = (a1[j] + bz) * inv + bb;
        float t2 = (a2[j] + bz) * inv + bb;
        sO[o*32 + p] = sigm(siluf(t1)) * sigm(siluf(t2));
    }
    __syncthreads();
    for (int j = tid; j < CIN*32; j += 256){
        int o = j >> 5, pp = j & 31;
        g_gate[(b*CIN + o)*LL + pix0 + pp] = sO[j];
    }
}

// ---------------- kB ----------------
__global__ void kB(const float* __restrict__ w, const float* __restrict__ bias,
                   const float* __restrict__ bng, const float* __restrict__ bnb){
    __shared__ float sW[CHID*CIN];
    __shared__ float sA[CIN*32];
    int b = blockIdx.x >> 7;
    int pix0 = (blockIdx.x & 127) * 32;
    int tid = threadIdx.x;
    for (int j = tid; j < CHID*CIN/4; j += 256)
        ((float4*)sW)[j] = ((const float4*)w)[j];
    for (int j = tid; j < CIN*32; j += 256){
        int c = j >> 5, p = j & 31;
        sA[j] = g_diff[(b*CIN + c)*LL + pix0 + p];
    }
    __syncthreads();
    int p = tid & 31, og = tid >> 5;
    float acc[12];
    #pragma unroll
    for (int j = 0; j < 12; j++) acc[j] = 0.f;
    for (int kq = 0; kq < 16; kq++){
        float x[4];
        #pragma unroll
        for (int i = 0; i < 4; i++) x[i] = sA[(kq*4+i)*32 + p];
        #pragma unroll
        for (int j = 0; j < 12; j++){
            float4 wv = *(float4*)&sW[(og*12+j)*CIN + kq*4];
            acc[j] = fmaf(x[0],wv.x, fmaf(x[1],wv.y, fmaf(x[2],wv.z, fmaf(x[3],wv.w, acc[j]))));
        }
    }
    float res[12];
    #pragma unroll
    for (int j = 0; j < 12; j++){
        int o = og*12 + j;
        float inv = bng[o] * rsqrtf(1.00001f);
        float t = (acc[j] + bias[o]) * inv + bnb[o];
        res[j] = siluf(t);
    }
    float4* dst = (float4*)&g_d1[(b*LL + pix0 + p)*CHID + og*12];
    #pragma unroll
    for (int v = 0; v < 3; v++)
        dst[v] = make_float4(res[v*4], res[v*4+1], res[v*4+2], res[v*4+3]);
}

// ---------------- kC: xln = LN(pe(d1)), 256 thr, 32 pixels, P=2 x T=6 ----------------
__global__ void kC(const float* __restrict__ w, const float* __restrict__ bias,
                   const float* __restrict__ lng, const float* __restrict__ lnb){
    __shared__ float sA[32*100];
    __shared__ float sW[96*48];
    __shared__ float sS[32*16], sS2[32*16];
    __shared__ float sM[32], sR[32];
    int b = blockIdx.x >> 7;
    int pix0 = (blockIdx.x & 127) * 32;
    int tid = threadIdx.x;
    for (int j = tid; j < 32*24; j += 256){
        int p = j / 24, cq = j % 24;
        *(float4*)&sA[p*100 + cq*4] = *(const float4*)&g_d1[(b*LL + pix0 + p)*CHID + cq*4];
    }
    int p = tid & 15, og = tid >> 4;
    float acc[2][6];
    #pragma unroll
    for (int j = 0; j < 6; j++){ acc[0][j] = bias[og*6+j]; acc[1][j] = acc[0][j]; }
    for (int kc = 0; kc < 2; kc++){
        __syncthreads();
        for (int j = tid; j < 96*12; j += 256){
            int o = j / 12, kq = j % 12;
            *(float4*)&sW[o*48 + kq*4] = *(const float4*)&w[o*CHID + kc*48 + kq*4];
        }
        __syncthreads();
        #pragma unroll 4
        for (int kq = 0; kq < 12; kq++){
            float4 a0 = *(float4*)&sA[p*100 + kc*48 + kq*4];
            float4 a1 = *(float4*)&sA[(p+16)*100 + kc*48 + kq*4];
            #pragma unroll
            for (int j = 0; j < 6; j++){
                float4 wv = *(float4*)&sW[(og*6+j)*48 + kq*4];
                acc[0][j] = dot4(a0, wv, acc[0][j]);
                acc[1][j] = dot4(a1, wv, acc[1][j]);
            }
        }
    }
    #pragma unroll
    for (int pi = 0; pi < 2; pi++){
        float s = 0.f, s2 = 0.f;
        #pragma unroll
        for (int j = 0; j < 6; j++){ s += acc[pi][j]; s2 += acc[pi][j]*acc[pi][j]; }
        sS [(p + pi*16)*16 + og] = s;
        sS2[(p + pi*16)*16 + og] = s2;
    }
    __syncthreads();
    if (tid < 32){
        float ss = 0.f, ss2 = 0.f;
        #pragma unroll
        for (int i = 0; i < 16; i++){ ss += sS[tid*16+i]; ss2 += sS2[tid*16+i]; }
        float m = ss * (1.f/96.f);
        float var = ss2 * (1.f/96.f) - m*m;
        sM[tid] = m;  sR[tid] = rsqrtf(var + 1e-5f);
    }
    __syncthreads();
    float* st = sW;
    #pragma unroll
    for (int pi = 0; pi < 2; pi++){
        int pp = p + pi*16;
        float m = sM[pp], rs = sR[pp];
        #pragma unroll
        for (int j = 0; j < 6; j++){
            int o = og*6 + j;
            st[o*33 + pp] = (acc[pi][j] - m) * rs * lng[o] + lnb[o];
        }
    }
    __syncthreads();
    for (int j = tid; j < 32*96; j += 256){
        int pp = j / 96, o = j % 96;
        g_xln[(b*LL + pix0 + pp)*CHID + o] = st[o*33 + pp];
    }
}

// ---------------- kD v4: in_proj 96->384, chunk split across grid ----------------
// grid = BB*(LL/32)*6 ; bid -> (ch, b, tile)
__global__ void kD(const float* __restrict__ w, const float* __restrict__ bias){
    __shared__ float sA[32*100];
    __shared__ float sW[64*96];
    __shared__ float sO[64*33];
    int bid = blockIdx.x;
    int ch  = bid % 6;
    int rest = bid / 6;
    int b = rest >> 7;
    int pix0 = (rest & 127) * 32;
    int tid = threadIdx.x;
    for (int j = tid; j < 32*24; j += 256){
        int p = j / 24, cq = j % 24;
        *(float4*)&sA[p*100 + cq*4] = *(const float4*)&g_xln[(b*LL + pix0 + p)*CHID + cq*4];
    }
    for (int j = tid; j < 64*96/4; j += 256)
        ((float4*)sW)[j] = ((const float4*)(w + ch*64*CHID))[j];
    __syncthreads();
    int p = tid & 15, og = tid >> 4;
    float acc[2][4];
    #pragma unroll
    for (int j = 0; j < 4; j++){ acc[0][j] = bias[ch*64 + og*4 + j]; acc[1][j] = acc[0][j]; }
    #pragma unroll 4
    for (int kq = 0; kq < 24; kq++){
        float4 a0 = *(float4*)&sA[p*100 + kq*4];
        float4 a1 = *(float4*)&sA[(p+16)*100 + kq*4];
        #pragma unroll
        for (int j = 0; j < 4; j++){
            float4 wv = *(float4*)&sW[(og*4+j)*CHID + kq*4];
            acc[0][j] = dot4(a0, wv, acc[0][j]);
            acc[1][j] = dot4(a1, wv, acc[1][j]);
        }
    }
    #pragma unroll
    for (int j = 0; j < 4; j++){
        sO[(og*4+j)*33 + p]      = acc[0][j];
        sO[(og*4+j)*33 + p + 16] = acc[1][j];
    }
    __syncthreads();
    if (ch < 3){
        for (int j = tid; j < 64*32; j += 256){
            int o = j >> 5, pp = j & 31;
            g_xc[(b*DN + ch*64 + o)*LL + pix0 + pp] = sO[o*33 + pp];
        }
    } else {
        for (int j = tid; j < 32*64; j += 256){
            int pp = j >> 6, oz = j & 63;
            g_z[(b*LL + pix0 + pp)*DN + (ch-3)*64 + oz] = sO[oz*33 + pp];
        }
    }
}

// ---------------- kE: depthwise 3x3 conv + bias + silu ----------------
__global__ void kE(const float* __restrict__ cw, const float* __restrict__ cb){
    __shared__ float sT[18*66];
    int bid = blockIdx.x;
    int rt = bid & 3;
    int bd = bid >> 2;
    int d  = bd % DN;
    int r0 = rt * 16;
    int tid = threadIdx.x;
    const float* src = g_xc + bd*LL;
    for (int j = tid; j < 18*66; j += 256){
        int r = j / 66 - 1 + r0;
        int c = j % 66 - 1;
        float v = 0.f;
        if (r >= 0 && r < 64 && c >= 0 && c < 64) v = src[r*64 + c];
        sT[j] = v;
    }
    float w9[9];
    #pragma unroll
    for (int i = 0; i < 9; i++) w9[i] = cw[d*9 + i];
    float bz = cb[d];
    __syncthreads();
    for (int j = tid; j < 16*64; j += 256){
        int r = j >> 6, c = j & 63;
        float s = bz;
        #pragma unroll
        for (int ky = 0; ky < 3; ky++)
            #pragma unroll
            for (int kx = 0; kx < 3; kx++)
                s = fmaf(w9[ky*3+kx], sT[(r+ky)*66 + c + kx], s);
        g_xcv[bd*LL + (r0+r)*64 + c] = siluf(s);
    }
}

// ---------------- kX: gather xs, x_proj GEMM, dt GEMM + softplus ----------------
__global__ void kX(const float* __restrict__ xpw, const float* __restrict__ dtw,
                   const float* __restrict__ dtb){
    __shared__ float sxs[16*196];
    __shared__ float sWx[38*DN];
    __shared__ float sdtw[DN*6];
    __shared__ float sdt[6*17];
    int tile = blockIdx.x & 255;
    int k    = (blockIdx.x >> 8) & 3;
    int b    = blockIdx.x >> 10;
    int t0   = tile * 16;
    int tid  = threadIdx.x;
    int base = (b*KK + k)*LL;

    for (int j = tid; j < 38*DN/4; j += 256)
        ((float4*)sWx)[j] = ((const float4*)(xpw + k*38*DN))[j];
    for (int j = tid; j < DN*6/2; j += 256)
        ((float2*)sdtw)[j] = ((const float2*)(dtw + k*DN*6))[j];
    for (int j = tid; j < DN*16; j += 256){
        int d = j >> 4, tt = j & 15;
        int t = t0 + tt;
        int pix;
        if (k == 0)      pix = t;
        else if (k == 1) pix = (t & 63)*64 + (t >> 6);
        else if (k == 2) pix = LL - 1 - t;
        else { int tr = LL - 1 - t; pix = (tr & 63)*64 + (tr >> 6); }
        sxs[tt*196 + d] = g_xcv[(b*DN + d)*LL + pix];
    }
    __syncthreads();
    for (int j = tid; j < 16*48; j += 256){
        int tt = j / 48, dq = j % 48;
        *(float4*)&g_xs[(base + t0 + tt)*DN + dq*4] = *(float4*)&sxs[tt*196 + dq*4];
    }
    for (int j = tid; j < 38*16; j += 256){
        int c = j >> 4, tt = j & 15;
        float acc = 0.f;
        for (int dq = 0; dq < 48; dq++){
            float4 a4 = *(float4*)&sxs[tt*196 + dq*4];
            float4 wv = *(float4*)&sWx[c*DN + dq*4];
            acc = dot4(a4, wv, acc);
        }
        if (c < RR)            sdt[c*17 + tt] = acc;
        else if (c < RR + NN)  g_bs[(base + t0 + tt)*NN + (c - RR)] = acc;
        else                   g_cs[(base + t0 + tt)*NN + (c - RR - NN)] = acc;
    }
    __syncthreads();
    float* sdl = sWx;
    {
        int tt = tid & 15, dq = tid >> 4;
        float acc[12];
        #pragma unroll
        for (int j = 0; j < 12; j++) acc[j] = dtb[k*DN + dq*12 + j];
        float dts[6];
        #pragma unroll
        for (int r = 0; r < RR; r++) dts[r] = sdt[r*17 + tt];
        #pragma unroll
        for (int j = 0; j < 12; j++){
            int d = dq*12 + j;
            float a = acc[j];
            #pragma unroll
            for (int r = 0; r < RR; r++)
                a = fmaf(dts[r], sdtw[d*6 + r], a);
            float dl = (a > 20.f) ? a : log1pf(__expf(a));
            acc[j] = dl;
        }
        __syncthreads();
        #pragma unroll
        for (int j = 0; j < 12; j++) sdl[tt*DN + dq*12 + j] = acc[j];
    }
    __syncthreads();
    for (int j = tid; j < 16*48; j += 256){
        int tt = j / 48, dq = j % 48;
        *(float4*)&g_delta[(base + t0 + tt)*DN + dq*4] = *(float4*)&sdl[tt*DN + dq*4];
    }
}

// ---------------- kF1: per-segment propagator P and offset q ----------------
__global__ void kF1(const float* __restrict__ A_log){
    __shared__ float sD[16*8], sU[16*8], sB[16*16];
    int bid = blockIdx.x;
    int dg = (bid % 24) * 8;
    int s  = (bid / 24) % (SEG-1);
    int k  = (bid / (24*(SEG-1))) % 4;
    int b  = bid / (24*(SEG-1)*4);
    int tid = threadIdx.x;
    int ch = tid >> 4, n = tid & 15;
    int d  = dg + ch;
    int base = (b*KK + k)*LL + s*SEGLEN;

    float a = -__expf(A_log[(k*DN + d)*NN + n]);
    float h = 0.f, P = 1.f;

    int lt = tid >> 3, lc = tid & 7;
    float rD, rX, rB[2];
    rD = g_delta[(base + lt)*DN + dg + lc];
    rX = g_xs   [(base + lt)*DN + dg + lc];
    #pragma unroll
    for (int i = 0; i < 2; i++){
        int jj = tid + i*128;
        rB[i] = g_bs[base*NN + jj];
    }
    for (int chunk = 0; chunk < SEGLEN/16; chunk++){
        sD[tid] = rD;  sU[tid] = rD * rX;
        sB[tid] = rB[0];  sB[tid+128] = rB[1];
        __syncthreads();
        if (chunk < SEGLEN/16 - 1){
            int t0n = (chunk + 1) * 16;
            rD = g_delta[(base + t0n + lt)*DN + dg + lc];
            rX = g_xs   [(base + t0n + lt)*DN + dg + lc];
            #pragma unroll
            for (int i = 0; i < 2; i++){
                int jj = tid + i*128;
                rB[i] = g_bs[(base + t0n)*NN + jj];
            }
        }
        #pragma unroll
        for (int t = 0; t < 16; t++){
            float dl = sD[t*8 + ch];
            float u  = sU[t*8 + ch];
            float Bn = sB[t*16 + n];
            float e  = __expf(dl * a);
            h = fmaf(e, h, u * Bn);
            P *= e;
        }
        __syncthreads();
    }
    int chain = (b*KK + k)*DN + d;
    g_P[(chain*(SEG-1) + s)*NN + n] = P;
    g_q[(chain*(SEG-1) + s)*NN + n] = h;
}

// ---------------- kF2: prefix over segments -> g_h0 ----------------
__global__ void kF2(){
    int gid = blockIdx.x*blockDim.x + threadIdx.x;
    int chain = gid >> 4, n = gid & 15;
    float h = 0.f;
    g_h0[(chain*SEG + 0)*NN + n] = 0.f;
    #pragma unroll
    for (int s = 0; s < SEG-1; s++){
        float P = g_P[(chain*(SEG-1) + s)*NN + n];
        float q = g_q[(chain*(SEG-1) + s)*NN + n];
        h = fmaf(P, h, q);
        g_h0[(chain*SEG + s + 1)*NN + n] = h;
    }
}

// ---------------- kF3 v3: full scan; smem transpose-reduce; D*x in phase B ------------
__global__ void kF3(const float* __restrict__ A_log, const float* __restrict__ Ds){
    __shared__ float sD[16*8], sU[16*8], sX[16*8], sB[16*16], sC[16*16];
    __shared__ float sP[NN*129];
    int bid = blockIdx.x;
    int dg = (bid % 24) * 8;
    int s  = (bid / 24) % SEG;
    int k  = (bid / (24*SEG)) % 4;
    int b  = bid / (24*SEG*4);
    int tid = threadIdx.x;
    int ch = tid >> 4, n = tid & 15;
    int d  = dg + ch;
    int base = (b*KK + k)*LL + s*SEGLEN;
    int chain = (b*KK + k)*DN + d;

    float a  = -__expf(A_log[(k*DN + d)*NN + n]);
    float h  = g_h0[(chain*SEG + s)*NN + n];

    int lt = tid >> 3, lc = tid & 7;   // (t, chain) mapping for staging & phaseB
    float Dv2 = Ds[k*DN + dg + lc];    // D for phase-B chain lc
    float rD, rX, rB[2], rC[2];
    rD = g_delta[(base + lt)*DN + dg + lc];
    rX = g_xs   [(base + lt)*DN + dg + lc];
    #pragma unroll
    for (int i = 0; i < 2; i++){
        int jj = tid + i*128;
        rB[i] = g_bs[base*NN + jj];
        rC[i] = g_cs[base*NN + jj];
    }
    for (int chunk = 0; chunk < SEGLEN/16; chunk++){
        sD[tid] = rD;  sU[tid] = rD * rX;  sX[tid] = rX;
        sB[tid] = rB[0];  sB[tid+128] = rB[1];
        sC[tid] = rC[0];  sC[tid+128] = rC[1];
        __syncthreads();
        if (chunk < SEGLEN/16 - 1){
            int t0n = (chunk + 1) * 16;
            rD = g_delta[(base + t0n + lt)*DN + dg + lc];
            rX = g_xs   [(base + t0n + lt)*DN + dg + lc];
            #pragma unroll
            for (int i = 0; i < 2; i++){
                int jj = tid + i*128;
                rB[i] = g_bs[(base + t0n)*NN + jj];
                rC[i] = g_cs[(base + t0n)*NN + jj];
            }
        }
        // Phase A: recurrence, store h*C per state
        #pragma unroll
        for (int t = 0; t < 16; t++){
            float dl = sD[t*8 + ch];
            float u  = sU[t*8 + ch];
            float Bn = sB[t*16 + n];
            float Cn = sC[t*16 + n];
            float e  = __expf(dl * a);
            h = fmaf(e, h, u * Bn);
            sP[n*129 + t*8 + ch] = h * Cn;
        }
        __syncthreads();
        // Phase B: thread (t=lt, chain=lc) sums 16 states + D*x, writes y
        {
            float y = Dv2 * sX[tid];
            #pragma unroll
            for (int nn = 0; nn < NN; nn++)
                y += sP[nn*129 + tid];
            g_ys[(base + chunk*16 + lt)*DN + dg + lc] = y;
        }
    }
}

// ---------------- kGH: combine 4 dirs + LN + silu(z) gate + out_proj -> g_dd -----------
// 256 thr, 32 pixels. Load phase: tp = tid>>3 (pixel), tc = tid&7 (24 channels each).
__global__ void kGH(const float* __restrict__ lng, const float* __restrict__ lnb,
                    const float* __restrict__ w, const float* __restrict__ bias){
    __shared__ float sA[32*196];   // [p][c] padded (25.1KB)
    __shared__ float sW[96*48];    // weight chunk / output stage (18.4KB)
    __shared__ float sS[256], sS2[256];
    __shared__ float sM[32], sR[32];
    int b = blockIdx.x >> 7;
    int pix0 = (blockIdx.x & 127) * 32;
    int tid = threadIdx.x;
    int tp = tid >> 3, tc = tid & 7;
    int l  = pix0 + tp;
    int hh = l >> 6, ww = l & 63;
    int t1 = ww*64 + hh;
    int b4 = b*KK*LL;
    const float* r0 = &g_ys[(b4 + l)*DN];
    const float* r1 = &g_ys[(b4 + 1*LL + t1)*DN];
    const float* r2 = &g_ys[(b4 + 2*LL + (LL-1-l))*DN];
    const float* r3 = &g_ys[(b4 + 3*LL + (LL-1-t1))*DN];
    float vloc[24];
    float s = 0.f, s2 = 0.f;
    #pragma unroll
    for (int jq = 0; jq < 6; jq++){
        int c = tc*24 + jq*4;
        float4 a0 = *(const float4*)&r0[c];
        float4 a1 = *(const float4*)&r1[c];
        float4 a2 = *(const float4*)&r2[c];
        float4 a3 = *(const float4*)&r3[c];
        float v0 = a0.x + a1.x + a2.x + a3.x;
        float v1 = a0.y + a1.y + a2.y + a3.y;
        float v2 = a0.z + a1.z + a2.z + a3.z;
        float v3 = a0.w + a1.w + a2.w + a3.w;
        vloc[jq*4+0] = v0; vloc[jq*4+1] = v1; vloc[jq*4+2] = v2; vloc[jq*4+3] = v3;
        s  += v0 + v1 + v2 + v3;
        s2 += v0*v0 + v1*v1 + v2*v2 + v3*v3;
    }
    sS[tid] = s;  sS2[tid] = s2;
    __syncthreads();
    if (tid < 32){
        float ss = 0.f, ss2 = 0.f;
        #pragma unroll
        for (int i = 0; i < 8; i++){ ss += sS[tid*8+i]; ss2 += sS2[tid*8+i]; }
        float m = ss * (1.f/192.f);
        float var = ss2 * (1.f/192.f) - m*m;
        sM[tid] = m;  sR[tid] = rsqrtf(var + 1e-5f);
    }
    __syncthreads();
    {
        float m = sM[tp], rs = sR[tp];
        const float* zrow = &g_z[(b*LL + l)*DN];
        #pragma unroll
        for (int jq = 0; jq < 6; jq++){
            int c = tc*24 + jq*4;
            float4 zv = *(const float4*)&zrow[c];
            float4 gv = *(const float4*)&lng[c];
            float4 bv = *(const float4*)&lnb[c];
            float y0 = ((vloc[jq*4+0]-m)*rs*gv.x + bv.x) * siluf(zv.x);
            float y1 = ((vloc[jq*4+1]-m)*rs*gv.y + bv.y) * siluf(zv.y);
            float y2 = ((vloc[jq*4+2]-m)*rs*gv.z + bv.z) * siluf(zv.z);
            float y3 = ((vloc[jq*4+3]-m)*rs*gv.w + bv.w) * siluf(zv.w);
            sA[tp*196 + c + 0] = y0;
            sA[tp*196 + c + 1] = y1;
            sA[tp*196 + c + 2] = y2;
            sA[tp*196 + c + 3] = y3;
        }
    }
    // GEMM (out_proj): p = tid&15, og = tid>>4, P=2 x T=6, 4 k-chunks of 48
    int p = tid & 15, og = tid >> 4;
    float acc[2][6];
    #pragma unroll
    for (int j = 0; j < 6; j++){ acc[0][j] = bias[og*6+j]; acc[1][j] = acc[0][j]; }
    for (int kc = 0; kc < 4; kc++){
        __syncthreads();
        for (int j = tid; j < 96*12; j += 256){
            int o = j / 12, kq = j % 12;
            *(float4*)&sW[o*48 + kq*4] = *(const float4*)&w[o*DN + kc*48 + kq*4];
        }
        __syncthreads();
        #pragma unroll 4
        for (int kq = 0; kq < 12; kq++){
            float4 a0 = *(float4*)&sA[p*196 + kc*48 + kq*4];
            float4 a1 = *(float4*)&sA[(p+16)*196 + kc*48 + kq*4];
            #pragma unroll
            for (int j = 0; j < 6; j++){
                float4 wv = *(float4*)&sW[(og*6+j)*48 + kq*4];
                acc[0][j] = dot4(a0, wv, acc[0][j]);
                acc[1][j] = dot4(a1, wv, acc[1][j]);
            }
        }
    }
    __syncthreads();
    float* st = sW;
    #pragma unroll
    for (int pi = 0; pi < 2; pi++)
        #pragma unroll
        for (int j = 0; j < 6; j++)
            st[(og*6+j)*33 + p + pi*16] = acc[pi][j];
    __syncthreads();
    for (int j = tid; j < 32*96; j += 256){
        int pp = j / 96, o = j % 96;
        g_dd[(b*LL + pix0 + pp)*CHID + o] = st[o*33 + pp];
    }
}

// ---------------- kI: up + bn + silu + residual + gate, 256 thr, 32p, P=2 x T=4 ------
__global__ void kI(const float* __restrict__ w, const float* __restrict__ bias,
                   const float* __restrict__ bng, const float* __restrict__ bnb,
                   float* __restrict__ out){
    __shared__ float sA[32*100];
    __shared__ float sW[64*96];
    __shared__ float sO[64*33];
    int b = blockIdx.x >> 7;
    int pix0 = (blockIdx.x & 127) * 32;
    int tid = threadIdx.x;
    for (int j = tid; j < 64*96/4; j += 256)
        ((float4*)sW)[j] = ((const float4*)w)[j];
    for (int j = tid; j < 32*24; j += 256){
        int p = j / 24, cq = j % 24;
        *(float4*)&sA[p*100 + cq*4] = *(const float4*)&g_dd[(b*LL + pix0 + p)*CHID + cq*4];
    }
    __syncthreads();
    int p = tid & 15, og = tid >> 4;
    float acc[2][4];
    #pragma unroll
    for (int j = 0; j < 4; j++){ acc[0][j] = bias[og*4+j]; acc[1][j] = acc[0][j]; }
    #pragma unroll 4
    for (int kq = 0; kq < 24; kq++){
        float4 a0 = *(float4*)&sA[p*100 + kq*4];
        float4 a1 = *(float4*)&sA[(p+16)*100 + kq*4];
        #pragma unroll
        for (int j = 0; j < 4; j++){
            float4 wv = *(float4*)&sW[(og*4+j)*CHID + kq*4];
            acc[0][j] = dot4(a0, wv, acc[0][j]);
            acc[1][j] = dot4(a1, wv, acc[1][j]);
        }
    }
    #pragma unroll
    for (int j = 0; j < 4; j++){
        int o = og*4 + j;
        float inv = bng[o] * rsqrtf(1.00001f);
        float bb = bnb[o];
        sO[o*33 + p]      = siluf(acc[0][j] * inv + bb);
        sO[o*33 + p + 16] = siluf(acc[1][j] * inv + bb);
    }
    __syncthreads();
    for (int j = tid; j < 64*32; j += 256){
        int o = j >> 5, pp = j & 31;
        int idx = (b*CIN + o)*LL + pix0 + pp;
        out[idx] = (sO[o*33 + pp] + g_diff[idx]) * g_gate[idx];
    }
}

// ---------------- launcher ----------------
extern "C" void kernel_launch(void* const* d_in, const int* in_sizes, int n_in,
                              void* d_out, int out_size){
    const float* pre        = (const float*)d_in[0];
    const float* post       = (const float*)d_in[1];
    const float* prepost_w  = (const float*)d_in[2];
    const float* prepost_b  = (const float*)d_in[3];
    const float* prepost_g  = (const float*)d_in[4];
    const float* prepost_bb = (const float*)d_in[5];
    const float* down_w     = (const float*)d_in[6];
    const float* down_b     = (const float*)d_in[7];
    const float* down_g     = (const float*)d_in[8];
    const float* down_bb    = (const float*)d_in[9];
    const float* up_w       = (const float*)d_in[10];
    const float* up_b       = (const float*)d_in[11];
    const float* up_g       = (const float*)d_in[12];
    const float* up_bb      = (const float*)d_in[13];
    const float* pe_w       = (const float*)d_in[14];
    const float* pe_b       = (const float*)d_in[15];
    const float* pe_ln_g    = (const float*)d_in[16];
    const float* pe_ln_b    = (const float*)d_in[17];
    const float* in_proj_w  = (const float*)d_in[18];
    const float* in_proj_b  = (const float*)d_in[19];
    const float* conv_w     = (const float*)d_in[20];
    const float* conv_b     = (const float*)d_in[21];
    const float* x_proj_w   = (const float*)d_in[22];
    const float* dt_w       = (const float*)d_in[23];
    const float* dt_b       = (const float*)d_in[24];
    const float* A_log      = (const float*)d_in[25];
    const float* Ds         = (const float*)d_in[26];
    const float* out_ln_g   = (const float*)d_in[27];
    const float* out_ln_b   = (const float*)d_in[28];
    const float* out_proj_w = (const float*)d_in[29];
    const float* out_proj_b = (const float*)d_in[30];
    float* out = (float*)d_out;

    kDiff<<<BB*CIN*LL/4/256, 256>>>(pre, post);
    kGate2<<<BB*(LL/32), 256>>>(pre, post, prepost_w, prepost_b, prepost_g, prepost_bb);
    kB<<<BB*(LL/32), 256>>>(down_w, down_b, down_g, down_bb);
    kC<<<BB*(LL/32), 256>>>(pe_w, pe_b, pe_ln_g, pe_ln_b);
    kD<<<BB*(LL/32)*6, 256>>>(in_proj_w, in_proj_b);
    kE<<<BB*DN*4, 256>>>(conv_w, conv_b);
    kX<<<BB*KK*(LL/16), 256>>>(x_proj_w, dt_w, dt_b);
    kF1<<<BB*KK*(SEG-1)*(DN/8), 128>>>(A_log);
    kF2<<<(BB*KK*DN*NN)/256, 256>>>();
    kF3<<<BB*KK*SEG*(DN/8), 128>>>(A_log, Ds);
    kGH<<<BB*(LL/32), 256>>>(out_ln_g, out_ln_b, out_proj_w, out_proj_b);
    kI<<<BB*(LL/32), 256>>>(up_w, up_b, up_g, up_bb, out);
}

// round 9
// speedup vs baseline: 1.3508x; 1.0278x over previous
#include <cuda_runtime.h>
#include <math.h>

#define BB 4
#define CIN 64
#define CHID 96
#define LL 4096
#define NN 16
#define RR 6
#define KK 4
#define DN 192
#define SEG 8
#define SEGLEN 512

// ---------------- static scratch (no allocation anywhere) ----------------
__device__ float g_diff [BB*CIN*LL];
__device__ float g_gate [BB*CIN*LL];
__device__ float g_d1   [BB*LL*CHID];
__device__ float g_xln  [BB*LL*CHID];
__device__ float g_xc   [BB*DN*LL];
__device__ float g_xcv  [BB*DN*LL];
__device__ float g_z    [BB*LL*DN];
__device__ float g_xs   [BB*2*LL*DN];     // only k=0,1 stored; k=2,3 are flips
__device__ float g_delta[BB*KK*LL*DN];
__device__ float g_bs   [BB*KK*LL*NN];
__device__ float g_cs   [BB*KK*LL*NN];
__device__ float g_ys   [BB*KK*LL*DN];
__device__ float g_dd   [BB*LL*CHID];
__device__ float g_P [BB*KK*DN*(SEG-1)*NN];
__device__ float g_q [BB*KK*DN*(SEG-1)*NN];
__device__ float g_h0[BB*KK*DN*SEG*NN];

__device__ __forceinline__ float sigm(float x){ return 1.f/(1.f+__expf(-x)); }
__device__ __forceinline__ float siluf(float x){ return x*sigm(x); }
__device__ __forceinline__ float dot4(float4 a, float4 w, float acc){
    acc = fmaf(a.x, w.x, acc);
    acc = fmaf(a.y, w.y, acc);
    acc = fmaf(a.z, w.z, acc);
    acc = fmaf(a.w, w.w, acc);
    return acc;
}

// ---------------- kGate2 (+ fused diff): g_gate, g_diff ----------------
__global__ void kGate2(const float* __restrict__ pre, const float* __restrict__ post,
                       const float* __restrict__ w, const float* __restrict__ bias,
                       const float* __restrict__ bng, const float* __restrict__ bnb){
    __shared__ float sW[CIN*CIN];
    __shared__ float sP[CIN*32];
    __shared__ float sQ[CIN*32];
    __shared__ float sO[CIN*32];
    int b = blockIdx.x >> 7;
    int pix0 = (blockIdx.x & 127) * 32;
    int tid = threadIdx.x;
    for (int j = tid; j < CIN*CIN/4; j += 256)
        ((float4*)sW)[j] = ((const float4*)w)[j];
    for (int j = tid; j < CIN*32; j += 256){
        int c = j >> 5, p = j & 31;
        int idx = (b*CIN + c)*LL + pix0 + p;
        float pv = pre[idx], qv = post[idx];
        sP[j] = pv;
        sQ[j] = qv;
        g_diff[idx] = fabsf(qv - pv);
    }
    __syncthreads();
    int p = tid & 31, og = tid >> 5;
    float a1[8], a2[8];
    #pragma unroll
    for (int j = 0; j < 8; j++){ a1[j] = 0.f; a2[j] = 0.f; }
    for (int kq = 0; kq < 16; kq++){
        float x1[4], x2[4];
        #pragma unroll
        for (int i = 0; i < 4; i++){
            x1[i] = sP[(kq*4+i)*32 + p];
            x2[i] = sQ[(kq*4+i)*32 + p];
        }
        #pragma unroll
        for (int j = 0; j < 8; j++){
            float4 wv = *(float4*)&sW[(og*8+j)*CIN + kq*4];
            a1[j] = fmaf(x1[0],wv.x, fmaf(x1[1],wv.y, fmaf(x1[2],wv.z, fmaf(x1[3],wv.w, a1[j]))));
            a2[j] = fmaf(x2[0],wv.x, fmaf(x2[1],wv.y, fmaf(x2[2],wv.z, fmaf(x2[3],wv.w, a2[j]))));
        }
    }
    #pragma unroll
    for (int j = 0; j < 8; j++){
        int o = og*8 + j;
        float inv = bng[o] * rsqrtf(1.00001f);
        float bz  = bias[o];
        float bb  = bnb[o];
        float t1 = (a1[j] + bz) * inv + bb;
        float t2 = (a2[j] + bz) * inv + bb;
        sO[o*32 + p] = sigm(siluf(t1)) * sigm(siluf(t2));
    }
    __syncthreads();
    for (int j = tid; j < CIN*32; j += 256){
        int o = j >> 5, pp = j & 31;
        g_gate[(b*CIN + o)*LL + pix0 + pp] = sO[j];
    }
}

// ---------------- kB ----------------
__global__ void kB(const float* __restrict__ w, const float* __restrict__ bias,
                   const float* __restrict__ bng, const float* __restrict__ bnb){
    __shared__ float sW[CHID*CIN];
    __shared__ float sA[CIN*32];
    int b = blockIdx.x >> 7;
    int pix0 = (blockIdx.x & 127) * 32;
    int tid = threadIdx.x;
    for (int j = tid; j < CHID*CIN/4; j += 256)
        ((float4*)sW)[j] = ((const float4*)w)[j];
    for (int j = tid; j < CIN*32; j += 256){
        int c = j >> 5, p = j & 31;
        sA[j] = g_diff[(b*CIN + c)*LL + pix0 + p];
    }
    __syncthreads();
    int p = tid & 31, og = tid >> 5;
    float acc[12];
    #pragma unroll
    for (int j = 0; j < 12; j++) acc[j] = 0.f;
    for (int kq = 0; kq < 16; kq++){
        float x[4];
        #pragma unroll
        for (int i = 0; i < 4; i++) x[i] = sA[(kq*4+i)*32 + p];
        #pragma unroll
        for (int j = 0; j < 12; j++){
            float4 wv = *(float4*)&sW[(og*12+j)*CIN + kq*4];
            acc[j] = fmaf(x[0],wv.x, fmaf(x[1],wv.y, fmaf(x[2],wv.z, fmaf(x[3],wv.w, acc[j]))));
        }
    }
    float res[12];
    #pragma unroll
    for (int j = 0; j < 12; j++){
        int o = og*12 + j;
        float inv = bng[o] * rsqrtf(1.00001f);
        float t = (acc[j] + bias[o]) * inv + bnb[o];
        res[j] = siluf(t);
    }
    float4* dst = (float4*)&g_d1[(b*LL + pix0 + p)*CHID + og*12];
    #pragma unroll
    for (int v = 0; v < 3; v++)
        dst[v] = make_float4(res[v*4], res[v*4+1], res[v*4+2], res[v*4+3]);
}

// ---------------- kC: xln = LN(pe(d1)), 256 thr, 32 pixels, P=2 x T=6 ----------------
__global__ void kC(const float* __restrict__ w, const float* __restrict__ bias,
                   const float* __restrict__ lng, const float* __restrict__ lnb){
    __shared__ float sA[32*100];
    __shared__ float sW[96*48];
    __shared__ float sS[32*16], sS2[32*16];
    __shared__ float sM[32], sR[32];
    int b = blockIdx.x >> 7;
    int pix0 = (blockIdx.x & 127) * 32;
    int tid = threadIdx.x;
    for (int j = tid; j < 32*24; j += 256){
        int p = j / 24, cq = j % 24;
        *(float4*)&sA[p*100 + cq*4] = *(const float4*)&g_d1[(b*LL + pix0 + p)*CHID + cq*4];
    }
    int p = tid & 15, og = tid >> 4;
    float acc[2][6];
    #pragma unroll
    for (int j = 0; j < 6; j++){ acc[0][j] = bias[og*6+j]; acc[1][j] = acc[0][j]; }
    for (int kc = 0; kc < 2; kc++){
        __syncthreads();
        for (int j = tid; j < 96*12; j += 256){
            int o = j / 12, kq = j % 12;
            *(float4*)&sW[o*48 + kq*4] = *(const float4*)&w[o*CHID + kc*48 + kq*4];
        }
        __syncthreads();
        #pragma unroll 4
        for (int kq = 0; kq < 12; kq++){
            float4 a0 = *(float4*)&sA[p*100 + kc*48 + kq*4];
            float4 a1 = *(float4*)&sA[(p+16)*100 + kc*48 + kq*4];
            #pragma unroll
            for (int j = 0; j < 6; j++){
                float4 wv = *(float4*)&sW[(og*6+j)*48 + kq*4];
                acc[0][j] = dot4(a0, wv, acc[0][j]);
                acc[1][j] = dot4(a1, wv, acc[1][j]);
            }
        }
    }
    #pragma unroll
    for (int pi = 0; pi < 2; pi++){
        float s = 0.f, s2 = 0.f;
        #pragma unroll
        for (int j = 0; j < 6; j++){ s += acc[pi][j]; s2 += acc[pi][j]*acc[pi][j]; }
        sS [(p + pi*16)*16 + og] = s;
        sS2[(p + pi*16)*16 + og] = s2;
    }
    __syncthreads();
    if (tid < 32){
        float ss = 0.f, ss2 = 0.f;
        #pragma unroll
        for (int i = 0; i < 16; i++){ ss += sS[tid*16+i]; ss2 += sS2[tid*16+i]; }
        float m = ss * (1.f/96.f);
        float var = ss2 * (1.f/96.f) - m*m;
        sM[tid] = m;  sR[tid] = rsqrtf(var + 1e-5f);
    }
    __syncthreads();
    float* st = sW;
    #pragma unroll
    for (int pi = 0; pi < 2; pi++){
        int pp = p + pi*16;
        float m = sM[pp], rs = sR[pp];
        #pragma unroll
        for (int j = 0; j < 6; j++){
            int o = og*6 + j;
            st[o*33 + pp] = (acc[pi][j] - m) * rs * lng[o] + lnb[o];
        }
    }
    __syncthreads();
    for (int j = tid; j < 32*96; j += 256){
        int pp = j / 96, o = j % 96;
        g_xln[(b*LL + pix0 + pp)*CHID + o] = st[o*33 + pp];
    }
}

// ---------------- kD: in_proj 96->384, chunk split across grid ----------------
__global__ void kD(const float* __restrict__ w, const float* __restrict__ bias){
    __shared__ float sA[32*100];
    __shared__ float sW[64*96];
    __shared__ float sO[64*33];
    int bid = blockIdx.x;
    int ch  = bid % 6;
    int rest = bid / 6;
    int b = rest >> 7;
    int pix0 = (rest & 127) * 32;
    int tid = threadIdx.x;
    for (int j = tid; j < 32*24; j += 256){
        int p = j / 24, cq = j % 24;
        *(float4*)&sA[p*100 + cq*4] = *(const float4*)&g_xln[(b*LL + pix0 + p)*CHID + cq*4];
    }
    for (int j = tid; j < 64*96/4; j += 256)
        ((float4*)sW)[j] = ((const float4*)(w + ch*64*CHID))[j];
    __syncthreads();
    int p = tid & 15, og = tid >> 4;
    float acc[2][4];
    #pragma unroll
    for (int j = 0; j < 4; j++){ acc[0][j] = bias[ch*64 + og*4 + j]; acc[1][j] = acc[0][j]; }
    #pragma unroll 4
    for (int kq = 0; kq < 24; kq++){
        float4 a0 = *(float4*)&sA[p*100 + kq*4];
        float4 a1 = *(float4*)&sA[(p+16)*100 + kq*4];
        #pragma unroll
        for (int j = 0; j < 4; j++){
            float4 wv = *(float4*)&sW[(og*4+j)*CHID + kq*4];
            acc[0][j] = dot4(a0, wv, acc[0][j]);
            acc[1][j] = dot4(a1, wv, acc[1][j]);
        }
    }
    #pragma unroll
    for (int j = 0; j < 4; j++){
        sO[(og*4+j)*33 + p]      = acc[0][j];
        sO[(og*4+j)*33 + p + 16] = acc[1][j];
    }
    __syncthreads();
    if (ch < 3){
        for (int j = tid; j < 64*32; j += 256){
            int o = j >> 5, pp = j & 31;
            g_xc[(b*DN + ch*64 + o)*LL + pix0 + pp] = sO[o*33 + pp];
        }
    } else {
        for (int j = tid; j < 32*64; j += 256){
            int pp = j >> 6, oz = j & 63;
            g_z[(b*LL + pix0 + pp)*DN + (ch-3)*64 + oz] = sO[oz*33 + pp];
        }
    }
}

// ---------------- kE: depthwise 3x3 conv + bias + silu ----------------
__global__ void kE(const float* __restrict__ cw, const float* __restrict__ cb){
    __shared__ float sT[18*66];
    int bid = blockIdx.x;
    int rt = bid & 3;
    int bd = bid >> 2;
    int d  = bd % DN;
    int r0 = rt * 16;
    int tid = threadIdx.x;
    const float* src = g_xc + bd*LL;
    for (int j = tid; j < 18*66; j += 256){
        int r = j / 66 - 1 + r0;
        int c = j % 66 - 1;
        float v = 0.f;
        if (r >= 0 && r < 64 && c >= 0 && c < 64) v = src[r*64 + c];
        sT[j] = v;
    }
    float w9[9];
    #pragma unroll
    for (int i = 0; i < 9; i++) w9[i] = cw[d*9 + i];
    float bz = cb[d];
    __syncthreads();
    for (int j = tid; j < 16*64; j += 256){
        int r = j >> 6, c = j & 63;
        float s = bz;
        #pragma unroll
        for (int ky = 0; ky < 3; ky++)
            #pragma unroll
            for (int kx = 0; kx < 3; kx++)
                s = fmaf(w9[ky*3+kx], sT[(r+ky)*66 + c + kx], s);
        g_xcv[bd*LL + (r0+r)*64 + c] = siluf(s);
    }
}

// ---------------- kX: gather xs, x_proj GEMM, dt GEMM + softplus ----------------
__global__ void kX(const float* __restrict__ xpw, const float* __restrict__ dtw,
                   const float* __restrict__ dtb){
    __shared__ float sxs[16*196];
    __shared__ float sWx[38*DN];
    __shared__ float sdtw[DN*6];
    __shared__ float sdt[6*17];
    int tile = blockIdx.x & 255;
    int k    = (blockIdx.x >> 8) & 3;
    int b    = blockIdx.x >> 10;
    int t0   = tile * 16;
    int tid  = threadIdx.x;
    int base = (b*KK + k)*LL;

    for (int j = tid; j < 38*DN/4; j += 256)
        ((float4*)sWx)[j] = ((const float4*)(xpw + k*38*DN))[j];
    for (int j = tid; j < DN*6/2; j += 256)
        ((float2*)sdtw)[j] = ((const float2*)(dtw + k*DN*6))[j];
    for (int j = tid; j < DN*16; j += 256){
        int d = j >> 4, tt = j & 15;
        int t = t0 + tt;
        int pix;
        if (k == 0)      pix = t;
        else if (k == 1) pix = (t & 63)*64 + (t >> 6);
        else if (k == 2) pix = LL - 1 - t;
        else { int tr = LL - 1 - t; pix = (tr & 63)*64 + (tr >> 6); }
        sxs[tt*196 + d] = g_xcv[(b*DN + d)*LL + pix];
    }
    __syncthreads();
    if (k < 2){
        int xbase = (b*2 + k)*LL;
        for (int j = tid; j < 16*48; j += 256){
            int tt = j / 48, dq = j % 48;
            *(float4*)&g_xs[(xbase + t0 + tt)*DN + dq*4] = *(float4*)&sxs[tt*196 + dq*4];
        }
    }
    for (int j = tid; j < 38*16; j += 256){
        int c = j >> 4, tt = j & 15;
        float acc = 0.f;
        for (int dq = 0; dq < 48; dq++){
            float4 a4 = *(float4*)&sxs[tt*196 + dq*4];
            float4 wv = *(float4*)&sWx[c*DN + dq*4];
            acc = dot4(a4, wv, acc);
        }
        if (c < RR)            sdt[c*17 + tt] = acc;
        else if (c < RR + NN)  g_bs[(base + t0 + tt)*NN + (c - RR)] = acc;
        else                   g_cs[(base + t0 + tt)*NN + (c - RR - NN)] = acc;
    }
    __syncthreads();
    float* sdl = sWx;
    {
        int tt = tid & 15, dq = tid >> 4;
        float acc[12];
        #pragma unroll
        for (int j = 0; j < 12; j++) acc[j] = dtb[k*DN + dq*12 + j];
        float dts[6];
        #pragma unroll
        for (int r = 0; r < RR; r++) dts[r] = sdt[r*17 + tt];
        #pragma unroll
        for (int j = 0; j < 12; j++){
            int d = dq*12 + j;
            float a = acc[j];
            #pragma unroll
            for (int r = 0; r < RR; r++)
                a = fmaf(dts[r], sdtw[d*6 + r], a);
            float dl = (a > 20.f) ? a : log1pf(__expf(a));
            acc[j] = dl;
        }
        __syncthreads();
        #pragma unroll
        for (int j = 0; j < 12; j++) sdl[tt*DN + dq*12 + j] = acc[j];
    }
    __syncthreads();
    for (int j = tid; j < 16*48; j += 256){
        int tt = j / 48, dq = j % 48;
        *(float4*)&g_delta[(base + t0 + tt)*DN + dq*4] = *(float4*)&sdl[tt*DN + dq*4];
    }
}

// ---------------- kF1 v3: per-segment P (one exp) and offset q; packed DU ----------------
__global__ void kF1(const float* __restrict__ A_log){
    __shared__ float sDU[16*8*2];   // [t*8+ch]{d,u}
    __shared__ float sB[16*16];
    __shared__ float sSum[8];
    int bid = blockIdx.x;
    int dg = (bid % 24) * 8;
    int s  = (bid / 24) % (SEG-1);
    int k  = (bid / (24*(SEG-1))) % 4;
    int b  = bid / (24*(SEG-1)*4);
    int tid = threadIdx.x;
    int ch = tid >> 4, n = tid & 15;
    int d  = dg + ch;
    int base = (b*KK + k)*LL + s*SEGLEN;
    int xrow = (b*2 + (k & 1))*LL;
    bool rev = (k >= 2);

    float a = -__expf(A_log[(k*DN + d)*NN + n]);
    float h = 0.f;

    int lt = tid >> 3, lc = tid & 7;
    float dsum = 0.f;
    float rD, rX, rB[2];
    {
        int t_abs = s*SEGLEN + lt;
        int xr = rev ? (LL-1 - t_abs) : t_abs;
        rD = g_delta[(base + lt)*DN + dg + lc];
        rX = g_xs   [(xrow + xr)*DN + dg + lc];
    }
    #pragma unroll
    for (int i = 0; i < 2; i++){
        int jj = tid + i*128;
        rB[i] = g_bs[base*NN + jj];
    }
    for (int chunk = 0; chunk < SEGLEN/16; chunk++){
        *(float2*)&sDU[tid*2] = make_float2(rD, rD * rX);
        sB[tid] = rB[0];  sB[tid+128] = rB[1];
        dsum += rD;
        __syncthreads();
        if (chunk < SEGLEN/16 - 1){
            int t0n = (chunk + 1) * 16;
            int t_abs = s*SEGLEN + t0n + lt;
            int xr = rev ? (LL-1 - t_abs) : t_abs;
            rD = g_delta[(base + t0n + lt)*DN + dg + lc];
            rX = g_xs   [(xrow + xr)*DN + dg + lc];
            #pragma unroll
            for (int i = 0; i < 2; i++){
                int jj = tid + i*128;
                rB[i] = g_bs[(base + t0n)*NN + jj];
            }
        }
        #pragma unroll
        for (int t = 0; t < 16; t++){
            float2 du = *(float2*)&sDU[(t*8 + ch)*2];
            float Bn = sB[t*16 + n];
            float e  = __expf(du.x * a);
            h = fmaf(e, h, du.y * Bn);
        }
        __syncthreads();
    }
    // reduce dsum over lt per chain (reuse sDU region)
    sDU[lt*8 + lc] = dsum;
    __syncthreads();
    if (tid < 8){
        float S = 0.f;
        #pragma unroll
        for (int i = 0; i < 16; i++) S += sDU[i*8 + tid];
        sSum[tid] = S;
    }
    __syncthreads();
    float P = __expf(a * sSum[ch]);
    int chain = (b*KK + k)*DN + d;
    g_P[(chain*(SEG-1) + s)*NN + n] = P;
    g_q[(chain*(SEG-1) + s)*NN + n] = h;
}

// ---------------- kF2: prefix over segments -> g_h0 ----------------
__global__ void kF2(){
    int gid = blockIdx.x*blockDim.x + threadIdx.x;
    int chain = gid >> 4, n = gid & 15;
    float h = 0.f;
    g_h0[(chain*SEG + 0)*NN + n] = 0.f;
    #pragma unroll
    for (int s = 0; s < SEG-1; s++){
        float P = g_P[(chain*(SEG-1) + s)*NN + n];
        float q = g_q[(chain*(SEG-1) + s)*NN + n];
        h = fmaf(P, h, q);
        g_h0[(chain*SEG + s + 1)*NN + n] = h;
    }
}

// ---------------- kF3 v4: packed DU/BC, x kept in register for phase B ----------------
__global__ void kF3(const float* __restrict__ A_log, const float* __restrict__ Ds){
    __shared__ float sDU[16*8*2];    // [t*8+ch]{d,u}
    __shared__ float sBC[16*16*2];   // [t*16+n]{B,C}
    __shared__ float sP[NN*129];
    int bid = blockIdx.x;
    int dg = (bid % 24) * 8;
    int s  = (bid / 24) % SEG;
    int k  = (bid / (24*SEG)) % 4;
    int b  = bid / (24*SEG*4);
    int tid = threadIdx.x;
    int ch = tid >> 4, n = tid & 15;
    int d  = dg + ch;
    int base = (b*KK + k)*LL + s*SEGLEN;
    int chain = (b*KK + k)*DN + d;
    int xrow = (b*2 + (k & 1))*LL;
    bool rev = (k >= 2);

    float a  = -__expf(A_log[(k*DN + d)*NN + n]);
    float h  = g_h0[(chain*SEG + s)*NN + n];

    int lt = tid >> 3, lc = tid & 7;
    float Dv2 = Ds[k*DN + dg + lc];
    float rD, rX, rB[2], rC[2];
    {
        int t_abs = s*SEGLEN + lt;
        int xr = rev ? (LL-1 - t_abs) : t_abs;
        rD = g_delta[(base + lt)*DN + dg + lc];
        rX = g_xs   [(xrow + xr)*DN + dg + lc];
    }
    #pragma unroll
    for (int i = 0; i < 2; i++){
        int jj = tid + i*128;
        rB[i] = g_bs[base*NN + jj];
        rC[i] = g_cs[base*NN + jj];
    }
    for (int chunk = 0; chunk < SEGLEN/16; chunk++){
        *(float2*)&sDU[tid*2] = make_float2(rD, rD * rX);
        *(float2*)&sBC[tid*2]       = make_float2(rB[0], rC[0]);
        *(float2*)&sBC[(tid+128)*2] = make_float2(rB[1], rC[1]);
        float xCur = rX;
        __syncthreads();
        if (chunk < SEGLEN/16 - 1){
            int t0n = (chunk + 1) * 16;
            int t_abs = s*SEGLEN + t0n + lt;
            int xr = rev ? (LL-1 - t_abs) : t_abs;
            rD = g_delta[(base + t0n + lt)*DN + dg + lc];
            rX = g_xs   [(xrow + xr)*DN + dg + lc];
            #pragma unroll
            for (int i = 0; i < 2; i++){
                int jj = tid + i*128;
                rB[i] = g_bs[(base + t0n)*NN + jj];
                rC[i] = g_cs[(base + t0n)*NN + jj];
            }
        }
        // Phase A: recurrence, store h*C per state
        #pragma unroll
        for (int t = 0; t < 16; t++){
            float2 du = *(float2*)&sDU[(t*8 + ch)*2];
            float2 bc = *(float2*)&sBC[(t*16 + n)*2];
            float e  = __expf(du.x * a);
            h = fmaf(e, h, du.y * bc.x);
            sP[n*129 + t*8 + ch] = h * bc.y;
        }
        __syncthreads();
        // Phase B: thread (t=lt, chain=lc) sums 16 states + D*x, writes y
        {
            float y = Dv2 * xCur;
            #pragma unroll
            for (int nn = 0; nn < NN; nn++)
                y += sP[nn*129 + tid];
            g_ys[(base + chunk*16 + lt)*DN + dg + lc] = y;
        }
    }
}

// ---------------- kGH: combine 4 dirs + LN + silu(z) gate + out_proj -> g_dd -----------
__global__ void kGH(const float* __restrict__ lng, const float* __restrict__ lnb,
                    const float* __restrict__ w, const float* __restrict__ bias){
    __shared__ float sA[32*196];
    __shared__ float sW[96*48];
    __shared__ float sS[256], sS2[256];
    __shared__ float sM[32], sR[32];
    int b = blockIdx.x >> 7;
    int pix0 = (blockIdx.x & 127) * 32;
    int tid = threadIdx.x;
    int tp = tid >> 3, tc = tid & 7;
    int l  = pix0 + tp;
    int hh = l >> 6, ww = l & 63;
    int t1 = ww*64 + hh;
    int b4 = b*KK*LL;
    const float* r0 = &g_ys[(b4 + l)*DN];
    const float* r1 = &g_ys[(b4 + 1*LL + t1)*DN];
    const float* r2 = &g_ys[(b4 + 2*LL + (LL-1-l))*DN];
    const float* r3 = &g_ys[(b4 + 3*LL + (LL-1-t1))*DN];
    float vloc[24];
    float s = 0.f, s2 = 0.f;
    #pragma unroll
    for (int jq = 0; jq < 6; jq++){
        int c = tc*24 + jq*4;
        float4 a0 = *(const float4*)&r0[c];
        float4 a1 = *(const float4*)&r1[c];
        float4 a2 = *(const float4*)&r2[c];
        float4 a3 = *(const float4*)&r3[c];
        float v0 = a0.x + a1.x + a2.x + a3.x;
        float v1 = a0.y + a1.y + a2.y + a3.y;
        float v2 = a0.z + a1.z + a2.z + a3.z;
        float v3 = a0.w + a1.w + a2.w + a3.w;
        vloc[jq*4+0] = v0; vloc[jq*4+1] = v1; vloc[jq*4+2] = v2; vloc[jq*4+3] = v3;
        s  += v0 + v1 + v2 + v3;
        s2 += v0*v0 + v1*v1 + v2*v2 + v3*v3;
    }
    sS[tid] = s;  sS2[tid] = s2;
    __syncthreads();
    if (tid < 32){
        float ss = 0.f, ss2 = 0.f;
        #pragma unroll
        for (int i = 0; i < 8; i++){ ss += sS[tid*8+i]; ss2 += sS2[tid*8+i]; }
        float m = ss * (1.f/192.f);
        float var = ss2 * (1.f/192.f) - m*m;
        sM[tid] = m;  sR[tid] = rsqrtf(var + 1e-5f);
    }
    __syncthreads();
    {
        float m = sM[tp], rs = sR[tp];
        const float* zrow = &g_z[(b*LL + l)*DN];
        #pragma unroll
        for (int jq = 0; jq < 6; jq++){
            int c = tc*24 + jq*4;
            float4 zv = *(const float4*)&zrow[c];
            float4 gv = *(const float4*)&lng[c];
            float4 bv = *(const float4*)&lnb[c];
            sA[tp*196 + c + 0] = ((vloc[jq*4+0]-m)*rs*gv.x + bv.x) * siluf(zv.x);
            sA[tp*196 + c + 1] = ((vloc[jq*4+1]-m)*rs*gv.y + bv.y) * siluf(zv.y);
            sA[tp*196 + c + 2] = ((vloc[jq*4+2]-m)*rs*gv.z + bv.z) * siluf(zv.z);
            sA[tp*196 + c + 3] = ((vloc[jq*4+3]-m)*rs*gv.w + bv.w) * siluf(zv.w);
        }
    }
    int p = tid & 15, og = tid >> 4;
    float acc[2][6];
    #pragma unroll
    for (int j = 0; j < 6; j++){ acc[0][j] = bias[og*6+j]; acc[1][j] = acc[0][j]; }
    for (int kc = 0; kc < 4; kc++){
        __syncthreads();
        for (int j = tid; j < 96*12; j += 256){
            int o = j / 12, kq = j % 12;
            *(float4*)&sW[o*48 + kq*4] = *(const float4*)&w[o*DN + kc*48 + kq*4];
        }
        __syncthreads();
        #pragma unroll 4
        for (int kq = 0; kq < 12; kq++){
            float4 a0 = *(float4*)&sA[p*196 + kc*48 + kq*4];
            float4 a1 = *(float4*)&sA[(p+16)*196 + kc*48 + kq*4];
            #pragma unroll
            for (int j = 0; j < 6; j++){
                float4 wv = *(float4*)&sW[(og*6+j)*48 + kq*4];
                acc[0][j] = dot4(a0, wv, acc[0][j]);
                acc[1][j] = dot4(a1, wv, acc[1][j]);
            }
        }
    }
    __syncthreads();
    float* st = sW;
    #pragma unroll
    for (int pi = 0; pi < 2; pi++)
        #pragma unroll
        for (int j = 0; j < 6; j++)
            st[(og*6+j)*33 + p + pi*16] = acc[pi][j];
    __syncthreads();
    for (int j = tid; j < 32*96; j += 256){
        int pp = j / 96, o = j % 96;
        g_dd[(b*LL + pix0 + pp)*CHID + o] = st[o*33 + pp];
    }
}

// ---------------- kI: up + bn + silu + residual + gate ----------------
__global__ void kI(const float* __restrict__ w, const float* __restrict__ bias,
                   const float* __restrict__ bng, const float* __restrict__ bnb,
                   float* __restrict__ out){
    __shared__ float sA[32*100];
    __shared__ float sW[64*96];
    __shared__ float sO[64*33];
    int b = blockIdx.x >> 7;
    int pix0 = (blockIdx.x & 127) * 32;
    int tid = threadIdx.x;
    for (int j = tid; j < 64*96/4; j += 256)
        ((float4*)sW)[j] = ((const float4*)w)[j];
    for (int j = tid; j < 32*24; j += 256){
        int p = j / 24, cq = j % 24;
        *(float4*)&sA[p*100 + cq*4] = *(const float4*)&g_dd[(b*LL + pix0 + p)*CHID + cq*4];
    }
    __syncthreads();
    int p = tid & 15, og = tid >> 4;
    float acc[2][4];
    #pragma unroll
    for (int j = 0; j < 4; j++){ acc[0][j] = bias[og*4+j]; acc[1][j] = acc[0][j]; }
    #pragma unroll 4
    for (int kq = 0; kq < 24; kq++){
        float4 a0 = *(float4*)&sA[p*100 + kq*4];
        float4 a1 = *(float4*)&sA[(p+16)*100 + kq*4];
        #pragma unroll
        for (int j = 0; j < 4; j++){
            float4 wv = *(float4*)&sW[(og*4+j)*CHID + kq*4];
            acc[0][j] = dot4(a0, wv, acc[0][j]);
            acc[1][j] = dot4(a1, wv, acc[1][j]);
        }
    }
    #pragma unroll
    for (int j = 0; j < 4; j++){
        int o = og*4 + j;
        float inv = bng[o] * rsqrtf(1.00001f);
        float bb = bnb[o];
        sO[o*33 + p]      = siluf(acc[0][j] * inv + bb);
        sO[o*33 + p + 16] = siluf(acc[1][j] * inv + bb);
    }
    __syncthreads();
    for (int j = tid; j < 64*32; j += 256){
        int o = j >> 5, pp = j & 31;
        int idx = (b*CIN + o)*LL + pix0 + pp;
        out[idx] = (sO[o*33 + pp] + g_diff[idx]) * g_gate[idx];
    }
}

// ---------------- launcher ----------------
extern "C" void kernel_launch(void* const* d_in, const int* in_sizes, int n_in,
                              void* d_out, int out_size){
    const float* pre        = (const float*)d_in[0];
    const float* post       = (const float*)d_in[1];
    const float* prepost_w  = (const float*)d_in[2];
    const float* prepost_b  = (const float*)d_in[3];
    const float* prepost_g  = (const float*)d_in[4];
    const float* prepost_bb = (const float*)d_in[5];
    const float* down_w     = (const float*)d_in[6];
    const float* down_b     = (const float*)d_in[7];
    const float* down_g     = (const float*)d_in[8];
    const float* down_bb    = (const float*)d_in[9];
    const float* up_w       = (const float*)d_in[10];
    const float* up_b       = (const float*)d_in[11];
    const float* up_g       = (const float*)d_in[12];
    const float* up_bb      = (const float*)d_in[13];
    const float* pe_w       = (const float*)d_in[14];
    const float* pe_b       = (const float*)d_in[15];
    const float* pe_ln_g    = (const float*)d_in[16];
    const float* pe_ln_b    = (const float*)d_in[17];
    const float* in_proj_w  = (const float*)d_in[18];
    const float* in_proj_b  = (const float*)d_in[19];
    const float* conv_w     = (const float*)d_in[20];
    const float* conv_b     = (const float*)d_in[21];
    const float* x_proj_w   = (const float*)d_in[22];
    const float* dt_w       = (const float*)d_in[23];
    const float* dt_b       = (const float*)d_in[24];
    const float* A_log      = (const float*)d_in[25];
    const float* Ds         = (const float*)d_in[26];
    const float* out_ln_g   = (const float*)d_in[27];
    const float* out_ln_b   = (const float*)d_in[28];
    const float* out_proj_w = (const float*)d_in[29];
    const float* out_proj_b = (const float*)d_in[30];
    float* out = (float*)d_out;

    kGate2<<<BB*(LL/32), 256>>>(pre, post, prepost_w, prepost_b, prepost_g, prepost_bb);
    kB<<<BB*(LL/32), 256>>>(down_w, down_b, down_g, down_bb);
    kC<<<BB*(LL/32), 256>>>(pe_w, pe_b, pe_ln_g, pe_ln_b);
    kD<<<BB*(LL/32)*6, 256>>>(in_proj_w, in_proj_b);
    kE<<<BB*DN*4, 256>>>(conv_w, conv_b);
    kX<<<BB*KK*(LL/16), 256>>>(x_proj_w, dt_w, dt_b);
    kF1<<<BB*KK*(SEG-1)*(DN/8), 128>>>(A_log);
    kF2<<<(BB*KK*DN*NN)/256, 256>>>();
    kF3<<<BB*KK*SEG*(DN/8), 128>>>(A_log, Ds);
    kGH<<<BB*(LL/32), 256>>>(out_ln_g, out_ln_b, out_proj_w, out_proj_b);
    kI<<<BB*(LL/32), 256>>>(up_w, up_b, up_g, up_bb, out);
}

// round 10
// speedup vs baseline: 1.3594x; 1.0063x over previous
#include <cuda_runtime.h>
#include <math.h>

#define BB 4
#define CIN 64
#define CHID 96
#define LL 4096
#define NN 16
#define RR 6
#define KK 4
#define DN 192
#define SEG 4
#define SEGLEN 1024

// ---------------- static scratch (no allocation anywhere) ----------------
__device__ float g_diff [BB*CIN*LL];
__device__ float g_gate [BB*CIN*LL];
__device__ float g_d1   [BB*LL*CHID];
__device__ float g_xln  [BB*LL*CHID];
__device__ float g_xc   [BB*DN*LL];
__device__ float g_xcv  [BB*DN*LL];
__device__ float g_z    [BB*LL*DN];
__device__ float g_xs   [BB*2*LL*DN];     // only k=0,1 stored; k=2,3 are flips
__device__ float g_delta[BB*KK*LL*DN];
__device__ float g_bs   [BB*KK*LL*NN];
__device__ float g_cs   [BB*KK*LL*NN];
__device__ float g_ys   [BB*KK*LL*DN];
__device__ float g_dd   [BB*LL*CHID];
__device__ float g_P [BB*KK*DN*(SEG-1)*NN];
__device__ float g_q [BB*KK*DN*(SEG-1)*NN];
__device__ float g_h0[BB*KK*DN*SEG*NN];

__device__ __forceinline__ float sigm(float x){ return 1.f/(1.f+__expf(-x)); }
__device__ __forceinline__ float siluf(float x){ return x*sigm(x); }
__device__ __forceinline__ float dot4(float4 a, float4 w, float acc){
    acc = fmaf(a.x, w.x, acc);
    acc = fmaf(a.y, w.y, acc);
    acc = fmaf(a.z, w.z, acc);
    acc = fmaf(a.w, w.w, acc);
    return acc;
}

// ---------------- kGate2 (+ fused diff): g_gate, g_diff ----------------
__global__ void kGate2(const float* __restrict__ pre, const float* __restrict__ post,
                       const float* __restrict__ w, const float* __restrict__ bias,
                       const float* __restrict__ bng, const float* __restrict__ bnb){
    __shared__ float sW[CIN*CIN];
    __shared__ float sP[CIN*32];
    __shared__ float sQ[CIN*32];
    __shared__ float sO[CIN*32];
    int b = blockIdx.x >> 7;
    int pix0 = (blockIdx.x & 127) * 32;
    int tid = threadIdx.x;
    for (int j = tid; j < CIN*CIN/4; j += 256)
        ((float4*)sW)[j] = ((const float4*)w)[j];
    for (int j = tid; j < CIN*32; j += 256){
        int c = j >> 5, p = j & 31;
        int idx = (b*CIN + c)*LL + pix0 + p;
        float pv = pre[idx], qv = post[idx];
        sP[j] = pv;
        sQ[j] = qv;
        g_diff[idx] = fabsf(qv - pv);
    }
    __syncthreads();
    int p = tid & 31, og = tid >> 5;
    float a1[8], a2[8];
    #pragma unroll
    for (int j = 0; j < 8; j++){ a1[j] = 0.f; a2[j] = 0.f; }
    for (int kq = 0; kq < 16; kq++){
        float x1[4], x2[4];
        #pragma unroll
        for (int i = 0; i < 4; i++){
            x1[i] = sP[(kq*4+i)*32 + p];
            x2[i] = sQ[(kq*4+i)*32 + p];
        }
        #pragma unroll
        for (int j = 0; j < 8; j++){
            float4 wv = *(float4*)&sW[(og*8+j)*CIN + kq*4];
            a1[j] = fmaf(x1[0],wv.x, fmaf(x1[1],wv.y, fmaf(x1[2],wv.z, fmaf(x1[3],wv.w, a1[j]))));
            a2[j] = fmaf(x2[0],wv.x, fmaf(x2[1],wv.y, fmaf(x2[2],wv.z, fmaf(x2[3],wv.w, a2[j]))));
        }
    }
    #pragma unroll
    for (int j = 0; j < 8; j++){
        int o = og*8 + j;
        float inv = bng[o] * rsqrtf(1.00001f);
        float bz  = bias[o];
        float bb  = bnb[o];
        float t1 = (a1[j] + bz) * inv + bb;
        float t2 = (a2[j] + bz) * inv + bb;
        sO[o*32 + p] = sigm(siluf(t1)) * sigm(siluf(t2));
    }
    __syncthreads();
    for (int j = tid; j < CIN*32; j += 256){
        int o = j >> 5, pp = j & 31;
        g_gate[(b*CIN + o)*LL + pix0 + pp] = sO[j];
    }
}

// ---------------- kB ----------------
__global__ void kB(const float* __restrict__ w, const float* __restrict__ bias,
                   const float* __restrict__ bng, const float* __restrict__ bnb){
    __shared__ float sW[CHID*CIN];
    __shared__ float sA[CIN*32];
    int b = blockIdx.x >> 7;
    int pix0 = (blockIdx.x & 127) * 32;
    int tid = threadIdx.x;
    for (int j = tid; j < CHID*CIN/4; j += 256)
        ((float4*)sW)[j] = ((const float4*)w)[j];
    for (int j = tid; j < CIN*32; j += 256){
        int c = j >> 5, p = j & 31;
        sA[j] = g_diff[(b*CIN + c)*LL + pix0 + p];
    }
    __syncthreads();
    int p = tid & 31, og = tid >> 5;
    float acc[12];
    #pragma unroll
    for (int j = 0; j < 12; j++) acc[j] = 0.f;
    for (int kq = 0; kq < 16; kq++){
        float x[4];
        #pragma unroll
        for (int i = 0; i < 4; i++) x[i] = sA[(kq*4+i)*32 + p];
        #pragma unroll
        for (int j = 0; j < 12; j++){
            float4 wv = *(float4*)&sW[(og*12+j)*CIN + kq*4];
            acc[j] = fmaf(x[0],wv.x, fmaf(x[1],wv.y, fmaf(x[2],wv.z, fmaf(x[3],wv.w, acc[j]))));
        }
    }
    float res[12];
    #pragma unroll
    for (int j = 0; j < 12; j++){
        int o = og*12 + j;
        float inv = bng[o] * rsqrtf(1.00001f);
        float t = (acc[j] + bias[o]) * inv + bnb[o];
        res[j] = siluf(t);
    }
    float4* dst = (float4*)&g_d1[(b*LL + pix0 + p)*CHID + og*12];
    #pragma unroll
    for (int v = 0; v < 3; v++)
        dst[v] = make_float4(res[v*4], res[v*4+1], res[v*4+2], res[v*4+3]);
}

// ---------------- kC: xln = LN(pe(d1)), 256 thr, 32 pixels, P=2 x T=6 ----------------
__global__ void kC(const float* __restrict__ w, const float* __restrict__ bias,
                   const float* __restrict__ lng, const float* __restrict__ lnb){
    __shared__ float sA[32*100];
    __shared__ float sW[96*48];
    __shared__ float sS[32*16], sS2[32*16];
    __shared__ float sM[32], sR[32];
    int b = blockIdx.x >> 7;
    int pix0 = (blockIdx.x & 127) * 32;
    int tid = threadIdx.x;
    for (int j = tid; j < 32*24; j += 256){
        int p = j / 24, cq = j % 24;
        *(float4*)&sA[p*100 + cq*4] = *(const float4*)&g_d1[(b*LL + pix0 + p)*CHID + cq*4];
    }
    int p = tid & 15, og = tid >> 4;
    float acc[2][6];
    #pragma unroll
    for (int j = 0; j < 6; j++){ acc[0][j] = bias[og*6+j]; acc[1][j] = acc[0][j]; }
    for (int kc = 0; kc < 2; kc++){
        __syncthreads();
        for (int j = tid; j < 96*12; j += 256){
            int o = j / 12, kq = j % 12;
            *(float4*)&sW[o*48 + kq*4] = *(const float4*)&w[o*CHID + kc*48 + kq*4];
        }
        __syncthreads();
        #pragma unroll 4
        for (int kq = 0; kq < 12; kq++){
            float4 a0 = *(float4*)&sA[p*100 + kc*48 + kq*4];
            float4 a1 = *(float4*)&sA[(p+16)*100 + kc*48 + kq*4];
            #pragma unroll
            for (int j = 0; j < 6; j++){
                float4 wv = *(float4*)&sW[(og*6+j)*48 + kq*4];
                acc[0][j] = dot4(a0, wv, acc[0][j]);
                acc[1][j] = dot4(a1, wv, acc[1][j]);
            }
        }
    }
    #pragma unroll
    for (int pi = 0; pi < 2; pi++){
        float s = 0.f, s2 = 0.f;
        #pragma unroll
        for (int j = 0; j < 6; j++){ s += acc[pi][j]; s2 += acc[pi][j]*acc[pi][j]; }
        sS [(p + pi*16)*16 + og] = s;
        sS2[(p + pi*16)*16 + og] = s2;
    }
    __syncthreads();
    if (tid < 32){
        float ss = 0.f, ss2 = 0.f;
        #pragma unroll
        for (int i = 0; i < 16; i++){ ss += sS[tid*16+i]; ss2 += sS2[tid*16+i]; }
        float m = ss * (1.f/96.f);
        float var = ss2 * (1.f/96.f) - m*m;
        sM[tid] = m;  sR[tid] = rsqrtf(var + 1e-5f);
    }
    __syncthreads();
    float* st = sW;
    #pragma unroll
    for (int pi = 0; pi < 2; pi++){
        int pp = p + pi*16;
        float m = sM[pp], rs = sR[pp];
        #pragma unroll
        for (int j = 0; j < 6; j++){
            int o = og*6 + j;
            st[o*33 + pp] = (acc[pi][j] - m) * rs * lng[o] + lnb[o];
        }
    }
    __syncthreads();
    for (int j = tid; j < 32*96; j += 256){
        int pp = j / 96, o = j % 96;
        g_xln[(b*LL + pix0 + pp)*CHID + o] = st[o*33 + pp];
    }
}

// ---------------- kD: in_proj 96->384, 256 thr, 32p, P=2 x T=4, 6 serial o-chunks ------
__global__ void kD(const float* __restrict__ w, const float* __restrict__ bias){
    __shared__ float sA[32*100];
    __shared__ float sW[64*96];
    __shared__ float sO[64*33];
    int b = blockIdx.x >> 7;
    int pix0 = (blockIdx.x & 127) * 32;
    int tid = threadIdx.x;
    for (int j = tid; j < 32*24; j += 256){
        int p = j / 24, cq = j % 24;
        *(float4*)&sA[p*100 + cq*4] = *(const float4*)&g_xln[(b*LL + pix0 + p)*CHID + cq*4];
    }
    int p = tid & 15, og = tid >> 4;
    for (int ch = 0; ch < 6; ch++){
        __syncthreads();
        for (int j = tid; j < 64*96/4; j += 256)
            ((float4*)sW)[j] = ((const float4*)(w + ch*64*CHID))[j];
        __syncthreads();
        float acc[2][4];
        #pragma unroll
        for (int j = 0; j < 4; j++){ acc[0][j] = bias[ch*64 + og*4 + j]; acc[1][j] = acc[0][j]; }
        #pragma unroll 4
        for (int kq = 0; kq < 24; kq++){
            float4 a0 = *(float4*)&sA[p*100 + kq*4];
            float4 a1 = *(float4*)&sA[(p+16)*100 + kq*4];
            #pragma unroll
            for (int j = 0; j < 4; j++){
                float4 wv = *(float4*)&sW[(og*4+j)*CHID + kq*4];
                acc[0][j] = dot4(a0, wv, acc[0][j]);
                acc[1][j] = dot4(a1, wv, acc[1][j]);
            }
        }
        #pragma unroll
        for (int j = 0; j < 4; j++){
            sO[(og*4+j)*33 + p]      = acc[0][j];
            sO[(og*4+j)*33 + p + 16] = acc[1][j];
        }
        __syncthreads();
        if (ch < 3){
            for (int j = tid; j < 64*32; j += 256){
                int o = j >> 5, pp = j & 31;
                g_xc[(b*DN + ch*64 + o)*LL + pix0 + pp] = sO[o*33 + pp];
            }
        } else {
            for (int j = tid; j < 32*64; j += 256){
                int pp = j >> 6, oz = j & 63;
                g_z[(b*LL + pix0 + pp)*DN + (ch-3)*64 + oz] = sO[oz*33 + pp];
            }
        }
    }
}

// ---------------- kE v2: depthwise 3x3 conv + bias + silu, one block per (b,d) ---------
__global__ void kE(const float* __restrict__ cw, const float* __restrict__ cb){
    __shared__ float sT[66*66];
    int bd = blockIdx.x;              // b*DN + d
    int d  = bd % DN;
    int tid = threadIdx.x;
    const float* src = g_xc + bd*LL;
    for (int j = tid; j < 66*66; j += 256){
        int rr = j / 66, cc = j % 66;
        int r = rr - 1, c = cc - 1;
        float v = 0.f;
        if (r >= 0 && r < 64 && c >= 0 && c < 64) v = src[r*64 + c];
        sT[j] = v;
    }
    float w9[9];
    #pragma unroll
    for (int i = 0; i < 9; i++) w9[i] = cw[d*9 + i];
    float bz = cb[d];
    __syncthreads();
    float* dst = g_xcv + bd*LL;
    for (int j = tid; j < 64*64; j += 256){
        int r = j >> 6, c = j & 63;
        float s = bz;
        #pragma unroll
        for (int ky = 0; ky < 3; ky++)
            #pragma unroll
            for (int kx = 0; kx < 3; kx++)
                s = fmaf(w9[ky*3+kx], sT[(r+ky)*66 + c + kx], s);
        dst[j] = siluf(s);
    }
}

// ---------------- kX: gather xs, x_proj GEMM, dt GEMM + softplus ----------------
__global__ void kX(const float* __restrict__ xpw, const float* __restrict__ dtw,
                   const float* __restrict__ dtb){
    __shared__ float sxs[16*196];
    __shared__ float sWx[38*DN];
    __shared__ float sdtw[DN*6];
    __shared__ float sdt[6*17];
    int tile = blockIdx.x & 255;
    int k    = (blockIdx.x >> 8) & 3;
    int b    = blockIdx.x >> 10;
    int t0   = tile * 16;
    int tid  = threadIdx.x;
    int base = (b*KK + k)*LL;

    for (int j = tid; j < 38*DN/4; j += 256)
        ((float4*)sWx)[j] = ((const float4*)(xpw + k*38*DN))[j];
    for (int j = tid; j < DN*6/2; j += 256)
        ((float2*)sdtw)[j] = ((const float2*)(dtw + k*DN*6))[j];
    for (int j = tid; j < DN*16; j += 256){
        int d = j >> 4, tt = j & 15;
        int t = t0 + tt;
        int pix;
        if (k == 0)      pix = t;
        else if (k == 1) pix = (t & 63)*64 + (t >> 6);
        else if (k == 2) pix = LL - 1 - t;
        else { int tr = LL - 1 - t; pix = (tr & 63)*64 + (tr >> 6); }
        sxs[tt*196 + d] = g_xcv[(b*DN + d)*LL + pix];
    }
    __syncthreads();
    if (k < 2){
        int xbase = (b*2 + k)*LL;
        for (int j = tid; j < 16*48; j += 256){
            int tt = j / 48, dq = j % 48;
            *(float4*)&g_xs[(xbase + t0 + tt)*DN + dq*4] = *(float4*)&sxs[tt*196 + dq*4];
        }
    }
    for (int j = tid; j < 38*16; j += 256){
        int c = j >> 4, tt = j & 15;
        float acc = 0.f;
        for (int dq = 0; dq < 48; dq++){
            float4 a4 = *(float4*)&sxs[tt*196 + dq*4];
            float4 wv = *(float4*)&sWx[c*DN + dq*4];
            acc = dot4(a4, wv, acc);
        }
        if (c < RR)            sdt[c*17 + tt] = acc;
        else if (c < RR + NN)  g_bs[(base + t0 + tt)*NN + (c - RR)] = acc;
        else                   g_cs[(base + t0 + tt)*NN + (c - RR - NN)] = acc;
    }
    __syncthreads();
    float* sdl = sWx;
    {
        int tt = tid & 15, dq = tid >> 4;
        float acc[12];
        #pragma unroll
        for (int j = 0; j < 12; j++) acc[j] = dtb[k*DN + dq*12 + j];
        float dts[6];
        #pragma unroll
        for (int r = 0; r < RR; r++) dts[r] = sdt[r*17 + tt];
        #pragma unroll
        for (int j = 0; j < 12; j++){
            int d = dq*12 + j;
            float a = acc[j];
            #pragma unroll
            for (int r = 0; r < RR; r++)
                a = fmaf(dts[r], sdtw[d*6 + r], a);
            float dl = (a > 20.f) ? a : log1pf(__expf(a));
            acc[j] = dl;
        }
        __syncthreads();
        #pragma unroll
        for (int j = 0; j < 12; j++) sdl[tt*DN + dq*12 + j] = acc[j];
    }
    __syncthreads();
    for (int j = tid; j < 16*48; j += 256){
        int tt = j / 48, dq = j % 48;
        *(float4*)&g_delta[(base + t0 + tt)*DN + dq*4] = *(float4*)&sdl[tt*DN + dq*4];
    }
}

// ---------------- kF1: per-segment P (one exp) and offset q; packed DU ----------------
__global__ void kF1(const float* __restrict__ A_log){
    __shared__ float sDU[16*8*2];   // [t*8+ch]{d,u}
    __shared__ float sB[16*16];
    __shared__ float sSum[8];
    int bid = blockIdx.x;
    int dg = (bid % 24) * 8;
    int s  = (bid / 24) % (SEG-1);
    int k  = (bid / (24*(SEG-1))) % 4;
    int b  = bid / (24*(SEG-1)*4);
    int tid = threadIdx.x;
    int ch = tid >> 4, n = tid & 15;
    int d  = dg + ch;
    int base = (b*KK + k)*LL + s*SEGLEN;
    int xrow = (b*2 + (k & 1))*LL;
    bool rev = (k >= 2);

    float a = -__expf(A_log[(k*DN + d)*NN + n]);
    float h = 0.f;

    int lt = tid >> 3, lc = tid & 7;
    float dsum = 0.f;
    float rD, rX, rB[2];
    {
        int t_abs = s*SEGLEN + lt;
        int xr = rev ? (LL-1 - t_abs) : t_abs;
        rD = g_delta[(base + lt)*DN + dg + lc];
        rX = g_xs   [(xrow + xr)*DN + dg + lc];
    }
    #pragma unroll
    for (int i = 0; i < 2; i++){
        int jj = tid + i*128;
        rB[i] = g_bs[base*NN + jj];
    }
    for (int chunk = 0; chunk < SEGLEN/16; chunk++){
        *(float2*)&sDU[tid*2] = make_float2(rD, rD * rX);
        sB[tid] = rB[0];  sB[tid+128] = rB[1];
        dsum += rD;
        __syncthreads();
        if (chunk < SEGLEN/16 - 1){
            int t0n = (chunk + 1) * 16;
            int t_abs = s*SEGLEN + t0n + lt;
            int xr = rev ? (LL-1 - t_abs) : t_abs;
            rD = g_delta[(base + t0n + lt)*DN + dg + lc];
            rX = g_xs   [(xrow + xr)*DN + dg + lc];
            #pragma unroll
            for (int i = 0; i < 2; i++){
                int jj = tid + i*128;
                rB[i] = g_bs[(base + t0n)*NN + jj];
            }
        }
        #pragma unroll
        for (int t = 0; t < 16; t++){
            float2 du = *(float2*)&sDU[(t*8 + ch)*2];
            float Bn = sB[t*16 + n];
            float e  = __expf(du.x * a);
            h = fmaf(e, h, du.y * Bn);
        }
        __syncthreads();
    }
    sDU[lt*8 + lc] = dsum;
    __syncthreads();
    if (tid < 8){
        float S = 0.f;
        #pragma unroll
        for (int i = 0; i < 16; i++) S += sDU[i*8 + tid];
        sSum[tid] = S;
    }
    __syncthreads();
    float P = __expf(a * sSum[ch]);
    int chain = (b*KK + k)*DN + d;
    g_P[(chain*(SEG-1) + s)*NN + n] = P;
    g_q[(chain*(SEG-1) + s)*NN + n] = h;
}

// ---------------- kF2: prefix over segments -> g_h0 ----------------
__global__ void kF2(){
    int gid = blockIdx.x*blockDim.x + threadIdx.x;
    int chain = gid >> 4, n = gid & 15;
    float h = 0.f;
    g_h0[(chain*SEG + 0)*NN + n] = 0.f;
    #pragma unroll
    for (int s = 0; s < SEG-1; s++){
        float P = g_P[(chain*(SEG-1) + s)*NN + n];
        float q = g_q[(chain*(SEG-1) + s)*NN + n];
        h = fmaf(P, h, q);
        g_h0[(chain*SEG + s + 1)*NN + n] = h;
    }
}

// ---------------- kF3: packed DU/BC, smem transpose-reduce ----------------
__global__ void kF3(const float* __restrict__ A_log, const float* __restrict__ Ds){
    __shared__ float sDU[16*8*2];    // [t*8+ch]{d,u}
    __shared__ float sBC[16*16*2];   // [t*16+n]{B,C}
    __shared__ float sP[NN*129];
    int bid = blockIdx.x;
    int dg = (bid % 24) * 8;
    int s  = (bid / 24) % SEG;
    int k  = (bid / (24*SEG)) % 4;
    int b  = bid / (24*SEG*4);
    int tid = threadIdx.x;
    int ch = tid >> 4, n = tid & 15;
    int d  = dg + ch;
    int base = (b*KK + k)*LL + s*SEGLEN;
    int chain = (b*KK + k)*DN + d;
    int xrow = (b*2 + (k & 1))*LL;
    bool rev = (k >= 2);

    float a  = -__expf(A_log[(k*DN + d)*NN + n]);
    float h  = g_h0[(chain*SEG + s)*NN + n];

    int lt = tid >> 3, lc = tid & 7;
    float Dv2 = Ds[k*DN + dg + lc];
    float rD, rX, rB[2], rC[2];
    {
        int t_abs = s*SEGLEN + lt;
        int xr = rev ? (LL-1 - t_abs) : t_abs;
        rD = g_delta[(base + lt)*DN + dg + lc];
        rX = g_xs   [(xrow + xr)*DN + dg + lc];
    }
    #pragma unroll
    for (int i = 0; i < 2; i++){
        int jj = tid + i*128;
        rB[i] = g_bs[base*NN + jj];
        rC[i] = g_cs[base*NN + jj];
    }
    for (int chunk = 0; chunk < SEGLEN/16; chunk++){
        *(float2*)&sDU[tid*2] = make_float2(rD, rD * rX);
        *(float2*)&sBC[tid*2]       = make_float2(rB[0], rC[0]);
        *(float2*)&sBC[(tid+128)*2] = make_float2(rB[1], rC[1]);
        float xCur = rX;
        __syncthreads();
        if (chunk < SEGLEN/16 - 1){
            int t0n = (chunk + 1) * 16;
            int t_abs = s*SEGLEN + t0n + lt;
            int xr = rev ? (LL-1 - t_abs) : t_abs;
            rD = g_delta[(base + t0n + lt)*DN + dg + lc];
            rX = g_xs   [(xrow + xr)*DN + dg + lc];
            #pragma unroll
            for (int i = 0; i < 2; i++){
                int jj = tid + i*128;
                rB[i] = g_bs[(base + t0n)*NN + jj];
                rC[i] = g_cs[(base + t0n)*NN + jj];
            }
        }
        #pragma unroll
        for (int t = 0; t < 16; t++){
            float2 du = *(float2*)&sDU[(t*8 + ch)*2];
            float2 bc = *(float2*)&sBC[(t*16 + n)*2];
            float e  = __expf(du.x * a);
            h = fmaf(e, h, du.y * bc.x);
            sP[n*129 + t*8 + ch] = h * bc.y;
        }
        __syncthreads();
        {
            float y = Dv2 * xCur;
            #pragma unroll
            for (int nn = 0; nn < NN; nn++)
                y += sP[nn*129 + tid];
            g_ys[(base + chunk*16 + lt)*DN + dg + lc] = y;
        }
    }
}

// ---------------- kGH: combine 4 dirs + LN + silu(z) gate + out_proj -> g_dd -----------
__global__ void kGH(const float* __restrict__ lng, const float* __restrict__ lnb,
                    const float* __restrict__ w, const float* __restrict__ bias){
    __shared__ float sA[32*196];
    __shared__ float sW[96*48];
    __shared__ float sS[256], sS2[256];
    __shared__ float sM[32], sR[32];
    int b = blockIdx.x >> 7;
    int pix0 = (blockIdx.x & 127) * 32;
    int tid = threadIdx.x;
    int tp = tid >> 3, tc = tid & 7;
    int l  = pix0 + tp;
    int hh = l >> 6, ww = l & 63;
    int t1 = ww*64 + hh;
    int b4 = b*KK*LL;
    const float* r0 = &g_ys[(b4 + l)*DN];
    const float* r1 = &g_ys[(b4 + 1*LL + t1)*DN];
    const float* r2 = &g_ys[(b4 + 2*LL + (LL-1-l))*DN];
    const float* r3 = &g_ys[(b4 + 3*LL + (LL-1-t1))*DN];
    float vloc[24];
    float s = 0.f, s2 = 0.f;
    #pragma unroll
    for (int jq = 0; jq < 6; jq++){
        int c = tc*24 + jq*4;
        float4 a0 = *(const float4*)&r0[c];
        float4 a1 = *(const float4*)&r1[c];
        float4 a2 = *(const float4*)&r2[c];
        float4 a3 = *(const float4*)&r3[c];
        float v0 = a0.x + a1.x + a2.x + a3.x;
        float v1 = a0.y + a1.y + a2.y + a3.y;
        float v2 = a0.z + a1.z + a2.z + a3.z;
        float v3 = a0.w + a1.w + a2.w + a3.w;
        vloc[jq*4+0] = v0; vloc[jq*4+1] = v1; vloc[jq*4+2] = v2; vloc[jq*4+3] = v3;
        s  += v0 + v1 + v2 + v3;
        s2 += v0*v0 + v1*v1 + v2*v2 + v3*v3;
    }
    sS[tid] = s;  sS2[tid] = s2;
    __syncthreads();
    if (tid < 32){
        float ss = 0.f, ss2 = 0.f;
        #pragma unroll
        for (int i = 0; i < 8; i++){ ss += sS[tid*8+i]; ss2 += sS2[tid*8+i]; }
        float m = ss * (1.f/192.f);
        float var = ss2 * (1.f/192.f) - m*m;
        sM[tid] = m;  sR[tid] = rsqrtf(var + 1e-5f);
    }
    __syncthreads();
    {
        float m = sM[tp], rs = sR[tp];
        const float* zrow = &g_z[(b*LL + l)*DN];
        #pragma unroll
        for (int jq = 0; jq < 6; jq++){
            int c = tc*24 + jq*4;
            float4 zv = *(const float4*)&zrow[c];
            float4 gv = *(const float4*)&lng[c];
            float4 bv = *(const float4*)&lnb[c];
            sA[tp*196 + c + 0] = ((vloc[jq*4+0]-m)*rs*gv.x + bv.x) * siluf(zv.x);
            sA[tp*196 + c + 1] = ((vloc[jq*4+1]-m)*rs*gv.y + bv.y) * siluf(zv.y);
            sA[tp*196 + c + 2] = ((vloc[jq*4+2]-m)*rs*gv.z + bv.z) * siluf(zv.z);
            sA[tp*196 + c + 3] = ((vloc[jq*4+3]-m)*rs*gv.w + bv.w) * siluf(zv.w);
        }
    }
    int p = tid & 15, og = tid >> 4;
    float acc[2][6];
    #pragma unroll
    for (int j = 0; j < 6; j++){ acc[0][j] = bias[og*6+j]; acc[1][j] = acc[0][j]; }
    for (int kc = 0; kc < 4; kc++){
        __syncthreads();
        for (int j = tid; j < 96*12; j += 256){
            int o = j / 12, kq = j % 12;
            *(float4*)&sW[o*48 + kq*4] = *(const float4*)&w[o*DN + kc*48 + kq*4];
        }
        __syncthreads();
        #pragma unroll 4
        for (int kq = 0; kq < 12; kq++){
            float4 a0 = *(float4*)&sA[p*196 + kc*48 + kq*4];
            float4 a1 = *(float4*)&sA[(p+16)*196 + kc*48 + kq*4];
            #pragma unroll
            for (int j = 0; j < 6; j++){
                float4 wv = *(float4*)&sW[(og*6+j)*48 + kq*4];
                acc[0][j] = dot4(a0, wv, acc[0][j]);
                acc[1][j] = dot4(a1, wv, acc[1][j]);
            }
        }
    }
    __syncthreads();
    float* st = sW;
    #pragma unroll
    for (int pi = 0; pi < 2; pi++)
        #pragma unroll
        for (int j = 0; j < 6; j++)
            st[(og*6+j)*33 + p + pi*16] = acc[pi][j];
    __syncthreads();
    for (int j = tid; j < 32*96; j += 256){
        int pp = j / 96, o = j % 96;
        g_dd[(b*LL + pix0 + pp)*CHID + o] = st[o*33 + pp];
    }
}

// ---------------- kI: up + bn + silu + residual + gate ----------------
__global__ void kI(const float* __restrict__ w, const float* __restrict__ bias,
                   const float* __restrict__ bng, const float* __restrict__ bnb,
                   float* __restrict__ out){
    __shared__ float sA[32*100];
    __shared__ float sW[64*96];
    __shared__ float sO[64*33];
    int b = blockIdx.x >> 7;
    int pix0 = (blockIdx.x & 127) * 32;
    int tid = threadIdx.x;
    for (int j = tid; j < 64*96/4; j += 256)
        ((float4*)sW)[j] = ((const float4*)w)[j];
    for (int j = tid; j < 32*24; j += 256){
        int p = j / 24, cq = j % 24;
        *(float4*)&sA[p*100 + cq*4] = *(const float4*)&g_dd[(b*LL + pix0 + p)*CHID + cq*4];
    }
    __syncthreads();
    int p = tid & 15, og = tid >> 4;
    float acc[2][4];
    #pragma unroll
    for (int j = 0; j < 4; j++){ acc[0][j] = bias[og*4+j]; acc[1][j] = acc[0][j]; }
    #pragma unroll 4
    for (int kq = 0; kq < 24; kq++){
        float4 a0 = *(float4*)&sA[p*100 + kq*4];
        float4 a1 = *(float4*)&sA[(p+16)*100 + kq*4];
        #pragma unroll
        for (int j = 0; j < 4; j++){
            float4 wv = *(float4*)&sW[(og*4+j)*CHID + kq*4];
            acc[0][j] = dot4(a0, wv, acc[0][j]);
            acc[1][j] = dot4(a1, wv, acc[1][j]);
        }
    }
    #pragma unroll
    for (int j = 0; j < 4; j++){
        int o = og*4 + j;
        float inv = bng[o] * rsqrtf(1.00001f);
        float bb = bnb[o];
        sO[o*33 + p]      = siluf(acc[0][j] * inv + bb);
        sO[o*33 + p + 16] = siluf(acc[1][j] * inv + bb);
    }
    __syncthreads();
    for (int j = tid; j < 64*32; j += 256){
        int o = j >> 5, pp = j & 31;
        int idx = (b*CIN + o)*LL + pix0 + pp;
        out[idx] = (sO[o*33 + pp] + g_diff[idx]) * g_gate[idx];
    }
}

// ---------------- launcher ----------------
extern "C" void kernel_launch(void* const* d_in, const int* in_sizes, int n_in,
                              void* d_out, int out_size){
    const float* pre        = (const float*)d_in[0];
    const float* post       = (const float*)d_in[1];
    const float* prepost_w  = (const float*)d_in[2];
    const float* prepost_b  = (const float*)d_in[3];
    const float* prepost_g  = (const float*)d_in[4];
    const float* prepost_bb = (const float*)d_in[5];
    const float* down_w     = (const float*)d_in[6];
    const float* down_b     = (const float*)d_in[7];
    const float* down_g     = (const float*)d_in[8];
    const float* down_bb    = (const float*)d_in[9];
    const float* up_w       = (const float*)d_in[10];
    const float* up_b       = (const float*)d_in[11];
    const float* up_g       = (const float*)d_in[12];
    const float* up_bb      = (const float*)d_in[13];
    const float* pe_w       = (const float*)d_in[14];
    const float* pe_b       = (const float*)d_in[15];
    const float* pe_ln_g    = (const float*)d_in[16];
    const float* pe_ln_b    = (const float*)d_in[17];
    const float* in_proj_w  = (const float*)d_in[18];
    const float* in_proj_b  = (const float*)d_in[19];
    const float* conv_w     = (const float*)d_in[20];
    const float* conv_b     = (const float*)d_in[21];
    const float* x_proj_w   = (const float*)d_in[22];
    const float* dt_w       = (const float*)d_in[23];
    const float* dt_b       = (const float*)d_in[24];
    const float* A_log      = (const float*)d_in[25];
    const float* Ds         = (const float*)d_in[26];
    const float* out_ln_g   = (const float*)d_in[27];
    const float* out_ln_b   = (const float*)d_in[28];
    const float* out_proj_w = (const float*)d_in[29];
    const float* out_proj_b = (const float*)d_in[30];
    float* out = (float*)d_out;

    kGate2<<<BB*(LL/32), 256>>>(pre, post, prepost_w, prepost_b, prepost_g, prepost_bb);
    kB<<<BB*(LL/32), 256>>>(down_w, down_b, down_g, down_bb);
    kC<<<BB*(LL/32), 256>>>(pe_w, pe_b, pe_ln_g, pe_ln_b);
    kD<<<BB*(LL/32), 256>>>(in_proj_w, in_proj_b);
    kE<<<BB*DN, 256>>>(conv_w, conv_b);
    kX<<<BB*KK*(LL/16), 256>>>(x_proj_w, dt_w, dt_b);
    kF1<<<BB*KK*(SEG-1)*(DN/8), 128>>>(A_log);
    kF2<<<(BB*KK*DN*NN)/256, 256>>>();
    kF3<<<BB*KK*SEG*(DN/8), 128>>>(A_log, Ds);
    kGH<<<BB*(LL/32), 256>>>(out_ln_g, out_ln_b, out_proj_w, out_proj_b);
    kI<<<BB*(LL/32), 256>>>(up_w, up_b, up_g, up_bb, out);
}

// round 11
// speedup vs baseline: 1.3984x; 1.0287x over previous
#include <cuda_runtime.h>
#include <math.h>
#include <stdint.h>

#define BB 4
#define CIN 64
#define CHID 96
#define LL 4096
#define NN 16
#define RR 6
#define KK 4
#define DN 192
#define SEG 4
#define SEGLEN 1024

// ---------------- static scratch (no allocation anywhere) ----------------
__device__ float g_diff [BB*CIN*LL];
__device__ float g_gate [BB*CIN*LL];
__device__ float g_d1   [BB*LL*CHID];
__device__ float g_xln  [BB*LL*CHID];
__device__ float g_xc   [BB*DN*LL];
__device__ float g_xcv  [BB*DN*LL];
__device__ float g_z    [BB*LL*DN];
__device__ float g_xs   [BB*2*LL*DN];     // only k=0,1 stored; k=2,3 are flips
__device__ float g_delta[BB*KK*LL*DN];
__device__ float g_bs   [BB*KK*LL*NN];
__device__ float g_cs   [BB*KK*LL*NN];
__device__ float g_ys   [BB*KK*LL*DN];
__device__ float g_dd   [BB*LL*CHID];
__device__ float g_P [BB*KK*DN*(SEG-1)*NN];
__device__ float g_q [BB*KK*DN*(SEG-1)*NN];
__device__ float g_h0[BB*KK*DN*SEG*NN];

__device__ __forceinline__ float sigm(float x){ return 1.f/(1.f+__expf(-x)); }
__device__ __forceinline__ float siluf(float x){ return x*sigm(x); }
__device__ __forceinline__ float dot4(float4 a, float4 w, float acc){
    acc = fmaf(a.x, w.x, acc);
    acc = fmaf(a.y, w.y, acc);
    acc = fmaf(a.z, w.z, acc);
    acc = fmaf(a.w, w.w, acc);
    return acc;
}
__device__ __forceinline__ uint32_t tf32(float x){
    uint32_t r; asm("cvt.rna.tf32.f32 %0, %1;" : "=r"(r) : "f"(x)); return r;
}

// ---------------- kGate2 (+ fused diff): g_gate, g_diff ----------------
__global__ void kGate2(const float* __restrict__ pre, const float* __restrict__ post,
                       const float* __restrict__ w, const float* __restrict__ bias,
                       const float* __restrict__ bng, const float* __restrict__ bnb){
    __shared__ float sW[CIN*CIN];
    __shared__ float sP[CIN*32];
    __shared__ float sQ[CIN*32];
    __shared__ float sO[CIN*32];
    int b = blockIdx.x >> 7;
    int pix0 = (blockIdx.x & 127) * 32;
    int tid = threadIdx.x;
    for (int j = tid; j < CIN*CIN/4; j += 256)
        ((float4*)sW)[j] = ((const float4*)w)[j];
    for (int j = tid; j < CIN*32; j += 256){
        int c = j >> 5, p = j & 31;
        int idx = (b*CIN + c)*LL + pix0 + p;
        float pv = pre[idx], qv = post[idx];
        sP[j] = pv;
        sQ[j] = qv;
        g_diff[idx] = fabsf(qv - pv);
    }
    __syncthreads();
    int p = tid & 31, og = tid >> 5;
    float a1[8], a2[8];
    #pragma unroll
    for (int j = 0; j < 8; j++){ a1[j] = 0.f; a2[j] = 0.f; }
    for (int kq = 0; kq < 16; kq++){
        float x1[4], x2[4];
        #pragma unroll
        for (int i = 0; i < 4; i++){
            x1[i] = sP[(kq*4+i)*32 + p];
            x2[i] = sQ[(kq*4+i)*32 + p];
        }
        #pragma unroll
        for (int j = 0; j < 8; j++){
            float4 wv = *(float4*)&sW[(og*8+j)*CIN + kq*4];
            a1[j] = fmaf(x1[0],wv.x, fmaf(x1[1],wv.y, fmaf(x1[2],wv.z, fmaf(x1[3],wv.w, a1[j]))));
            a2[j] = fmaf(x2[0],wv.x, fmaf(x2[1],wv.y, fmaf(x2[2],wv.z, fmaf(x2[3],wv.w, a2[j]))));
        }
    }
    #pragma unroll
    for (int j = 0; j < 8; j++){
        int o = og*8 + j;
        float inv = bng[o] * rsqrtf(1.00001f);
        float bz  = bias[o];
        float bb  = bnb[o];
        float t1 = (a1[j] + bz) * inv + bb;
        float t2 = (a2[j] + bz) * inv + bb;
        sO[o*32 + p] = sigm(siluf(t1)) * sigm(siluf(t2));
    }
    __syncthreads();
    for (int j = tid; j < CIN*32; j += 256){
        int o = j >> 5, pp = j & 31;
        g_gate[(b*CIN + o)*LL + pix0 + pp] = sO[j];
    }
}

// ---------------- kB ----------------
__global__ void kB(const float* __restrict__ w, const float* __restrict__ bias,
                   const float* __restrict__ bng, const float* __restrict__ bnb){
    __shared__ float sW[CHID*CIN];
    __shared__ float sA[CIN*32];
    int b = blockIdx.x >> 7;
    int pix0 = (blockIdx.x & 127) * 32;
    int tid = threadIdx.x;
    for (int j = tid; j < CHID*CIN/4; j += 256)
        ((float4*)sW)[j] = ((const float4*)w)[j];
    for (int j = tid; j < CIN*32; j += 256){
        int c = j >> 5, p = j & 31;
        sA[j] = g_diff[(b*CIN + c)*LL + pix0 + p];
    }
    __syncthreads();
    int p = tid & 31, og = tid >> 5;
    float acc[12];
    #pragma unroll
    for (int j = 0; j < 12; j++) acc[j] = 0.f;
    for (int kq = 0; kq < 16; kq++){
        float x[4];
        #pragma unroll
        for (int i = 0; i < 4; i++) x[i] = sA[(kq*4+i)*32 + p];
        #pragma unroll
        for (int j = 0; j < 12; j++){
            float4 wv = *(float4*)&sW[(og*12+j)*CIN + kq*4];
            acc[j] = fmaf(x[0],wv.x, fmaf(x[1],wv.y, fmaf(x[2],wv.z, fmaf(x[3],wv.w, acc[j]))));
        }
    }
    float res[12];
    #pragma unroll
    for (int j = 0; j < 12; j++){
        int o = og*12 + j;
        float inv = bng[o] * rsqrtf(1.00001f);
        float t = (acc[j] + bias[o]) * inv + bnb[o];
        res[j] = siluf(t);
    }
    float4* dst = (float4*)&g_d1[(b*LL + pix0 + p)*CHID + og*12];
    #pragma unroll
    for (int v = 0; v < 3; v++)
        dst[v] = make_float4(res[v*4], res[v*4+1], res[v*4+2], res[v*4+3]);
}

// ---------------- kC: xln = LN(pe(d1)), 256 thr, 32 pixels, P=2 x T=6 ----------------
__global__ void kC(const float* __restrict__ w, const float* __restrict__ bias,
                   const float* __restrict__ lng, const float* __restrict__ lnb){
    __shared__ float sA[32*100];
    __shared__ float sW[96*48];
    __shared__ float sS[32*16], sS2[32*16];
    __shared__ float sM[32], sR[32];
    int b = blockIdx.x >> 7;
    int pix0 = (blockIdx.x & 127) * 32;
    int tid = threadIdx.x;
    for (int j = tid; j < 32*24; j += 256){
        int p = j / 24, cq = j % 24;
        *(float4*)&sA[p*100 + cq*4] = *(const float4*)&g_d1[(b*LL + pix0 + p)*CHID + cq*4];
    }
    int p = tid & 15, og = tid >> 4;
    float acc[2][6];
    #pragma unroll
    for (int j = 0; j < 6; j++){ acc[0][j] = bias[og*6+j]; acc[1][j] = acc[0][j]; }
    for (int kc = 0; kc < 2; kc++){
        __syncthreads();
        for (int j = tid; j < 96*12; j += 256){
            int o = j / 12, kq = j % 12;
            *(float4*)&sW[o*48 + kq*4] = *(const float4*)&w[o*CHID + kc*48 + kq*4];
        }
        __syncthreads();
        #pragma unroll 4
        for (int kq = 0; kq < 12; kq++){
            float4 a0 = *(float4*)&sA[p*100 + kc*48 + kq*4];
            float4 a1 = *(float4*)&sA[(p+16)*100 + kc*48 + kq*4];
            #pragma unroll
            for (int j = 0; j < 6; j++){
                float4 wv = *(float4*)&sW[(og*6+j)*48 + kq*4];
                acc[0][j] = dot4(a0, wv, acc[0][j]);
                acc[1][j] = dot4(a1, wv, acc[1][j]);
            }
        }
    }
    #pragma unroll
    for (int pi = 0; pi < 2; pi++){
        float s = 0.f, s2 = 0.f;
        #pragma unroll
        for (int j = 0; j < 6; j++){ s += acc[pi][j]; s2 += acc[pi][j]*acc[pi][j]; }
        sS [(p + pi*16)*16 + og] = s;
        sS2[(p + pi*16)*16 + og] = s2;
    }
    __syncthreads();
    if (tid < 32){
        float ss = 0.f, ss2 = 0.f;
        #pragma unroll
        for (int i = 0; i < 16; i++){ ss += sS[tid*16+i]; ss2 += sS2[tid*16+i]; }
        float m = ss * (1.f/96.f);
        float var = ss2 * (1.f/96.f) - m*m;
        sM[tid] = m;  sR[tid] = rsqrtf(var + 1e-5f);
    }
    __syncthreads();
    float* st = sW;
    #pragma unroll
    for (int pi = 0; pi < 2; pi++){
        int pp = p + pi*16;
        float m = sM[pp], rs = sR[pp];
        #pragma unroll
        for (int j = 0; j < 6; j++){
            int o = og*6 + j;
            st[o*33 + pp] = (acc[pi][j] - m) * rs * lng[o] + lnb[o];
        }
    }
    __syncthreads();
    for (int j = tid; j < 32*96; j += 256){
        int pp = j / 96, o = j % 96;
        g_xln[(b*LL + pix0 + pp)*CHID + o] = st[o*33 + pp];
    }
}

// ---------------- kD v5: in_proj 96->384 via tf32 mma.m16n8k8 ----------------
// 256 thr = 8 warps; 32 pixels/block; 6 serial o-chunks of 64.
// warp: pt = wid&1 (16 pixels), ob = (wid>>1)*16 (two n=8 tiles).
__global__ void kD(const float* __restrict__ w, const float* __restrict__ bias){
    __shared__ float sA[32*100];   // [p][k] tf32 bits (pad 100 -> conflict-free frags)
    __shared__ float sW[64*100];   // [o][k] tf32 bits
    __shared__ float sO[64*33];
    uint32_t* sAu = (uint32_t*)sA;
    uint32_t* sWu = (uint32_t*)sW;
    int b = blockIdx.x >> 7;
    int pix0 = (blockIdx.x & 127) * 32;
    int tid = threadIdx.x;
    int wid = tid >> 5, lane = tid & 31;
    int gid = lane >> 2, tig = lane & 3;
    int pt = wid & 1;
    int ob = (wid >> 1) * 16;

    for (int j = tid; j < 32*24; j += 256){
        int p = j / 24, cq = j % 24;
        float4 v = *(const float4*)&g_xln[(b*LL + pix0 + p)*CHID + cq*4];
        uint32_t* dst = &sAu[p*100 + cq*4];
        dst[0] = tf32(v.x); dst[1] = tf32(v.y); dst[2] = tf32(v.z); dst[3] = tf32(v.w);
    }
    int prow = pt*16 + gid;
    for (int ch = 0; ch < 6; ch++){
        __syncthreads();
        for (int j = tid; j < 64*24; j += 256){
            int o = j / 24, kq = j % 24;
            float4 v = *(const float4*)&w[(ch*64 + o)*CHID + kq*4];
            uint32_t* dst = &sWu[o*100 + kq*4];
            dst[0] = tf32(v.x); dst[1] = tf32(v.y); dst[2] = tf32(v.z); dst[3] = tf32(v.w);
        }
        __syncthreads();
        float acc[2][4];
        #pragma unroll
        for (int j = 0; j < 2; j++){
            float b0v = bias[ch*64 + ob + j*8 + 2*tig];
            float b1v = bias[ch*64 + ob + j*8 + 2*tig + 1];
            acc[j][0] = b0v; acc[j][1] = b1v; acc[j][2] = b0v; acc[j][3] = b1v;
        }
        #pragma unroll 4
        for (int s = 0; s < 12; s++){
            int k0 = s*8;
            uint32_t a0 = sAu[prow*100     + k0 + tig];
            uint32_t a1 = sAu[(prow+8)*100 + k0 + tig];
            uint32_t a2 = sAu[prow*100     + k0 + tig + 4];
            uint32_t a3 = sAu[(prow+8)*100 + k0 + tig + 4];
            #pragma unroll
            for (int j = 0; j < 2; j++){
                uint32_t b0 = sWu[(ob + j*8 + gid)*100 + k0 + tig];
                uint32_t b1 = sWu[(ob + j*8 + gid)*100 + k0 + tig + 4];
                asm volatile(
                    "mma.sync.aligned.m16n8k8.row.col.f32.tf32.tf32.f32 "
                    "{%0,%1,%2,%3},{%4,%5,%6,%7},{%8,%9},{%0,%1,%2,%3};"
                    : "+f"(acc[j][0]), "+f"(acc[j][1]), "+f"(acc[j][2]), "+f"(acc[j][3])
                    : "r"(a0), "r"(a1), "r"(a2), "r"(a3), "r"(b0), "r"(b1));
            }
        }
        #pragma unroll
        for (int j = 0; j < 2; j++){
            int o0 = ob + j*8 + 2*tig;
            sO[o0*33 + prow]         = acc[j][0];
            sO[(o0+1)*33 + prow]     = acc[j][1];
            sO[o0*33 + prow + 8]     = acc[j][2];
            sO[(o0+1)*33 + prow + 8] = acc[j][3];
        }
        __syncthreads();
        if (ch < 3){
            for (int j = tid; j < 64*32; j += 256){
                int o = j >> 5, pp = j & 31;
                g_xc[(b*DN + ch*64 + o)*LL + pix0 + pp] = sO[o*33 + pp];
            }
        } else {
            for (int j = tid; j < 32*64; j += 256){
                int pp = j >> 6, oz = j & 63;
                g_z[(b*LL + pix0 + pp)*DN + (ch-3)*64 + oz] = sO[oz*33 + pp];
            }
        }
    }
}

// ---------------- kE: depthwise 3x3 conv + bias + silu, one block per (b,d) ---------
__global__ void kE(const float* __restrict__ cw, const float* __restrict__ cb){
    __shared__ float sT[66*66];
    int bd = blockIdx.x;
    int d  = bd % DN;
    int tid = threadIdx.x;
    const float* src = g_xc + bd*LL;
    for (int j = tid; j < 66*66; j += 256){
        int rr = j / 66, cc = j % 66;
        int r = rr - 1, c = cc - 1;
        float v = 0.f;
        if (r >= 0 && r < 64 && c >= 0 && c < 64) v = src[r*64 + c];
        sT[j] = v;
    }
    float w9[9];
    #pragma unroll
    for (int i = 0; i < 9; i++) w9[i] = cw[d*9 + i];
    float bz = cb[d];
    __syncthreads();
    float* dst = g_xcv + bd*LL;
    for (int j = tid; j < 64*64; j += 256){
        int r = j >> 6, c = j & 63;
        float s = bz;
        #pragma unroll
        for (int ky = 0; ky < 3; ky++)
            #pragma unroll
            for (int kx = 0; kx < 3; kx++)
                s = fmaf(w9[ky*3+kx], sT[(r+ky)*66 + c + kx], s);
        dst[j] = siluf(s);
    }
}

// ---------------- kX: gather xs, x_proj GEMM, dt GEMM + softplus ----------------
__global__ void kX(const float* __restrict__ xpw, const float* __restrict__ dtw,
                   const float* __restrict__ dtb){
    __shared__ float sxs[16*196];
    __shared__ float sWx[38*DN];
    __shared__ float sdtw[DN*6];
    __shared__ float sdt[6*17];
    int tile = blockIdx.x & 255;
    int k    = (blockIdx.x >> 8) & 3;
    int b    = blockIdx.x >> 10;
    int t0   = tile * 16;
    int tid  = threadIdx.x;
    int base = (b*KK + k)*LL;

    for (int j = tid; j < 38*DN/4; j += 256)
        ((float4*)sWx)[j] = ((const float4*)(xpw + k*38*DN))[j];
    for (int j = tid; j < DN*6/2; j += 256)
        ((float2*)sdtw)[j] = ((const float2*)(dtw + k*DN*6))[j];
    for (int j = tid; j < DN*16; j += 256){
        int d = j >> 4, tt = j & 15;
        int t = t0 + tt;
        int pix;
        if (k == 0)      pix = t;
        else if (k == 1) pix = (t & 63)*64 + (t >> 6);
        else if (k == 2) pix = LL - 1 - t;
        else { int tr = LL - 1 - t; pix = (tr & 63)*64 + (tr >> 6); }
        sxs[tt*196 + d] = g_xcv[(b*DN + d)*LL + pix];
    }
    __syncthreads();
    if (k < 2){
        int xbase = (b*2 + k)*LL;
        for (int j = tid; j < 16*48; j += 256){
            int tt = j / 48, dq = j % 48;
            *(float4*)&g_xs[(xbase + t0 + tt)*DN + dq*4] = *(float4*)&sxs[tt*196 + dq*4];
        }
    }
    for (int j = tid; j < 38*16; j += 256){
        int c = j >> 4, tt = j & 15;
        float acc = 0.f;
        for (int dq = 0; dq < 48; dq++){
            float4 a4 = *(float4*)&sxs[tt*196 + dq*4];
            float4 wv = *(float4*)&sWx[c*DN + dq*4];
            acc = dot4(a4, wv, acc);
        }
        if (c < RR)            sdt[c*17 + tt] = acc;
        else if (c < RR + NN)  g_bs[(base + t0 + tt)*NN + (c - RR)] = acc;
        else                   g_cs[(base + t0 + tt)*NN + (c - RR - NN)] = acc;
    }
    __syncthreads();
    float* sdl = sWx;
    {
        int tt = tid & 15, dq = tid >> 4;
        float acc[12];
        #pragma unroll
        for (int j = 0; j < 12; j++) acc[j] = dtb[k*DN + dq*12 + j];
        float dts[6];
        #pragma unroll
        for (int r = 0; r < RR; r++) dts[r] = sdt[r*17 + tt];
        #pragma unroll
        for (int j = 0; j < 12; j++){
            int d = dq*12 + j;
            float a = acc[j];
            #pragma unroll
            for (int r = 0; r < RR; r++)
                a = fmaf(dts[r], sdtw[d*6 + r], a);
            float dl = (a > 20.f) ? a : log1pf(__expf(a));
            acc[j] = dl;
        }
        __syncthreads();
        #pragma unroll
        for (int j = 0; j < 12; j++) sdl[tt*DN + dq*12 + j] = acc[j];
    }
    __syncthreads();
    for (int j = tid; j < 16*48; j += 256){
        int tt = j / 48, dq = j % 48;
        *(float4*)&g_delta[(base + t0 + tt)*DN + dq*4] = *(float4*)&sdl[tt*DN + dq*4];
    }
}

// ---------------- kF1: per-segment P (one exp) and offset q; packed DU ----------------
__global__ void kF1(const float* __restrict__ A_log){
    __shared__ float sDU[16*8*2];
    __shared__ float sB[16*16];
    __shared__ float sSum[8];
    int bid = blockIdx.x;
    int dg = (bid % 24) * 8;
    int s  = (bid / 24) % (SEG-1);
    int k  = (bid / (24*(SEG-1))) % 4;
    int b  = bid / (24*(SEG-1)*4);
    int tid = threadIdx.x;
    int ch = tid >> 4, n = tid & 15;
    int d  = dg + ch;
    int base = (b*KK + k)*LL + s*SEGLEN;
    int xrow = (b*2 + (k & 1))*LL;
    bool rev = (k >= 2);

    float a = -__expf(A_log[(k*DN + d)*NN + n]);
    float h = 0.f;

    int lt = tid >> 3, lc = tid & 7;
    float dsum = 0.f;
    float rD, rX, rB[2];
    {
        int t_abs = s*SEGLEN + lt;
        int xr = rev ? (LL-1 - t_abs) : t_abs;
        rD = g_delta[(base + lt)*DN + dg + lc];
        rX = g_xs   [(xrow + xr)*DN + dg + lc];
    }
    #pragma unroll
    for (int i = 0; i < 2; i++){
        int jj = tid + i*128;
        rB[i] = g_bs[base*NN + jj];
    }
    for (int chunk = 0; chunk < SEGLEN/16; chunk++){
        *(float2*)&sDU[tid*2] = make_float2(rD, rD * rX);
        sB[tid] = rB[0];  sB[tid+128] = rB[1];
        dsum += rD;
        __syncthreads();
        if (chunk < SEGLEN/16 - 1){
            int t0n = (chunk + 1) * 16;
            int t_abs = s*SEGLEN + t0n + lt;
            int xr = rev ? (LL-1 - t_abs) : t_abs;
            rD = g_delta[(base + t0n + lt)*DN + dg + lc];
            rX = g_xs   [(xrow + xr)*DN + dg + lc];
            #pragma unroll
            for (int i = 0; i < 2; i++){
                int jj = tid + i*128;
                rB[i] = g_bs[(base + t0n)*NN + jj];
            }
        }
        #pragma unroll
        for (int t = 0; t < 16; t++){
            float2 du = *(float2*)&sDU[(t*8 + ch)*2];
            float Bn = sB[t*16 + n];
            float e  = __expf(du.x * a);
            h = fmaf(e, h, du.y * Bn);
        }
        __syncthreads();
    }
    sDU[lt*8 + lc] = dsum;
    __syncthreads();
    if (tid < 8){
        float S = 0.f;
        #pragma unroll
        for (int i = 0; i < 16; i++) S += sDU[i*8 + tid];
        sSum[tid] = S;
    }
    __syncthreads();
    float P = __expf(a * sSum[ch]);
    int chain = (b*KK + k)*DN + d;
    g_P[(chain*(SEG-1) + s)*NN + n] = P;
    g_q[(chain*(SEG-1) + s)*NN + n] = h;
}

// ---------------- kF2: prefix over segments -> g_h0 ----------------
__global__ void kF2(){
    int gid = blockIdx.x*blockDim.x + threadIdx.x;
    int chain = gid >> 4, n = gid & 15;
    float h = 0.f;
    g_h0[(chain*SEG + 0)*NN + n] = 0.f;
    #pragma unroll
    for (int s = 0; s < SEG-1; s++){
        float P = g_P[(chain*(SEG-1) + s)*NN + n];
        float q = g_q[(chain*(SEG-1) + s)*NN + n];
        h = fmaf(P, h, q);
        g_h0[(chain*SEG + s + 1)*NN + n] = h;
    }
}

// ---------------- kF3: packed DU/BC, smem transpose-reduce ----------------
__global__ void kF3(const float* __restrict__ A_log, const float* __restrict__ Ds){
    __shared__ float sDU[16*8*2];
    __shared__ float sBC[16*16*2];
    __shared__ float sP[NN*129];
    int bid = blockIdx.x;
    int dg = (bid % 24) * 8;
    int s  = (bid / 24) % SEG;
    int k  = (bid / (24*SEG)) % 4;
    int b  = bid / (24*SEG*4);
    int tid = threadIdx.x;
    int ch = tid >> 4, n = tid & 15;
    int d  = dg + ch;
    int base = (b*KK + k)*LL + s*SEGLEN;
    int chain = (b*KK + k)*DN + d;
    int xrow = (b*2 + (k & 1))*LL;
    bool rev = (k >= 2);

    float a  = -__expf(A_log[(k*DN + d)*NN + n]);
    float h  = g_h0[(chain*SEG + s)*NN + n];

    int lt = tid >> 3, lc = tid & 7;
    float Dv2 = Ds[k*DN + dg + lc];
    float rD, rX, rB[2], rC[2];
    {
        int t_abs = s*SEGLEN + lt;
        int xr = rev ? (LL-1 - t_abs) : t_abs;
        rD = g_delta[(base + lt)*DN + dg + lc];
        rX = g_xs   [(xrow + xr)*DN + dg + lc];
    }
    #pragma unroll
    for (int i = 0; i < 2; i++){
        int jj = tid + i*128;
        rB[i] = g_bs[base*NN + jj];
        rC[i] = g_cs[base*NN + jj];
    }
    for (int chunk = 0; chunk < SEGLEN/16; chunk++){
        *(float2*)&sDU[tid*2] = make_float2(rD, rD * rX);
        *(float2*)&sBC[tid*2]       = make_float2(rB[0], rC[0]);
        *(float2*)&sBC[(tid+128)*2] = make_float2(rB[1], rC[1]);
        float xCur = rX;
        __syncthreads();
        if (chunk < SEGLEN/16 - 1){
            int t0n = (chunk + 1) * 16;
            int t_abs = s*SEGLEN + t0n + lt;
            int xr = rev ? (LL-1 - t_abs) : t_abs;
            rD = g_delta[(base + t0n + lt)*DN + dg + lc];
            rX = g_xs   [(xrow + xr)*DN + dg + lc];
            #pragma unroll
            for (int i = 0; i < 2; i++){
                int jj = tid + i*128;
                rB[i] = g_bs[(base + t0n)*NN + jj];
                rC[i] = g_cs[(base + t0n)*NN + jj];
            }
        }
        #pragma unroll
        for (int t = 0; t < 16; t++){
            float2 du = *(float2*)&sDU[(t*8 + ch)*2];
            float2 bc = *(float2*)&sBC[(t*16 + n)*2];
            float e  = __expf(du.x * a);
            h = fmaf(e, h, du.y * bc.x);
            sP[n*129 + t*8 + ch] = h * bc.y;
        }
        __syncthreads();
        {
            float y = Dv2 * xCur;
            #pragma unroll
            for (int nn = 0; nn < NN; nn++)
                y += sP[nn*129 + tid];
            g_ys[(base + chunk*16 + lt)*DN + dg + lc] = y;
        }
    }
}

// ---------------- kGH: combine 4 dirs + LN + silu(z) gate + out_proj -> g_dd -----------
__global__ void kGH(const float* __restrict__ lng, const float* __restrict__ lnb,
                    const float* __restrict__ w, const float* __restrict__ bias){
    __shared__ float sA[32*196];
    __shared__ float sW[96*48];
    __shared__ float sS[256], sS2[256];
    __shared__ float sM[32], sR[32];
    int b = blockIdx.x >> 7;
    int pix0 = (blockIdx.x & 127) * 32;
    int tid = threadIdx.x;
    int tp = tid >> 3, tc = tid & 7;
    int l  = pix0 + tp;
    int hh = l >> 6, ww = l & 63;
    int t1 = ww*64 + hh;
    int b4 = b*KK*LL;
    const float* r0 = &g_ys[(b4 + l)*DN];
    const float* r1 = &g_ys[(b4 + 1*LL + t1)*DN];
    const float* r2 = &g_ys[(b4 + 2*LL + (LL-1-l))*DN];
    const float* r3 = &g_ys[(b4 + 3*LL + (LL-1-t1))*DN];
    float vloc[24];
    float s = 0.f, s2 = 0.f;
    #pragma unroll
    for (int jq = 0; jq < 6; jq++){
        int c = tc*24 + jq*4;
        float4 a0 = *(const float4*)&r0[c];
        float4 a1 = *(const float4*)&r1[c];
        float4 a2 = *(const float4*)&r2[c];
        float4 a3 = *(const float4*)&r3[c];
        float v0 = a0.x + a1.x + a2.x + a3.x;
        float v1 = a0.y + a1.y + a2.y + a3.y;
        float v2 = a0.z + a1.z + a2.z + a3.z;
        float v3 = a0.w + a1.w + a2.w + a3.w;
        vloc[jq*4+0] = v0; vloc[jq*4+1] = v1; vloc[jq*4+2] = v2; vloc[jq*4+3] = v3;
        s  += v0 + v1 + v2 + v3;
        s2 += v0*v0 + v1*v1 + v2*v2 + v3*v3;
    }
    sS[tid] = s;  sS2[tid] = s2;
    __syncthreads();
    if (tid < 32){
        float ss = 0.f, ss2 = 0.f;
        #pragma unroll
        for (int i = 0; i < 8; i++){ ss += sS[tid*8+i]; ss2 += sS2[tid*8+i]; }
        float m = ss * (1.f/192.f);
        float var = ss2 * (1.f/192.f) - m*m;
        sM[tid] = m;  sR[tid] = rsqrtf(var + 1e-5f);
    }
    __syncthreads();
    {
        float m = sM[tp], rs = sR[tp];
        const float* zrow = &g_z[(b*LL + l)*DN];
        #pragma unroll
        for (int jq = 0; jq < 6; jq++){
            int c = tc*24 + jq*4;
            float4 zv = *(const float4*)&zrow[c];
            float4 gv = *(const float4*)&lng[c];
            float4 bv = *(const float4*)&lnb[c];
            sA[tp*196 + c + 0] = ((vloc[jq*4+0]-m)*rs*gv.x + bv.x) * siluf(zv.x);
            sA[tp*196 + c + 1] = ((vloc[jq*4+1]-m)*rs*gv.y + bv.y) * siluf(zv.y);
            sA[tp*196 + c + 2] = ((vloc[jq*4+2]-m)*rs*gv.z + bv.z) * siluf(zv.z);
            sA[tp*196 + c + 3] = ((vloc[jq*4+3]-m)*rs*gv.w + bv.w) * siluf(zv.w);
        }
    }
    int p = tid & 15, og = tid >> 4;
    float acc[2][6];
    #pragma unroll
    for (int j = 0; j < 6; j++){ acc[0][j] = bias[og*6+j]; acc[1][j] = acc[0][j]; }
    for (int kc = 0; kc < 4; kc++){
        __syncthreads();
        for (int j = tid; j < 96*12; j += 256){
            int o = j / 12, kq = j % 12;
            *(float4*)&sW[o*48 + kq*4] = *(const float4*)&w[o*DN + kc*48 + kq*4];
        }
        __syncthreads();
        #pragma unroll 4
        for (int kq = 0; kq < 12; kq++){
            float4 a0 = *(float4*)&sA[p*196 + kc*48 + kq*4];
            float4 a1 = *(float4*)&sA[(p+16)*196 + kc*48 + kq*4];
            #pragma unroll
            for (int j = 0; j < 6; j++){
                float4 wv = *(float4*)&sW[(og*6+j)*48 + kq*4];
                acc[0][j] = dot4(a0, wv, acc[0][j]);
                acc[1][j] = dot4(a1, wv, acc[1][j]);
            }
        }
    }
    __syncthreads();
    float* st = sW;
    #pragma unroll
    for (int pi = 0; pi < 2; pi++)
        #pragma unroll
        for (int j = 0; j < 6; j++)
            st[(og*6+j)*33 + p + pi*16] = acc[pi][j];
    __syncthreads();
    for (int j = tid; j < 32*96; j += 256){
        int pp = j / 96, o = j % 96;
        g_dd[(b*LL + pix0 + pp)*CHID + o] = st[o*33 + pp];
    }
}

// ---------------- kI: up + bn + silu + residual + gate ----------------
__global__ void kI(const float* __restrict__ w, const float* __restrict__ bias,
                   const float* __restrict__ bng, const float* __restrict__ bnb,
                   float* __restrict__ out){
    __shared__ float sA[32*100];
    __shared__ float sW[64*96];
    __shared__ float sO[64*33];
    int b = blockIdx.x >> 7;
    int pix0 = (blockIdx.x & 127) * 32;
    int tid = threadIdx.x;
    for (int j = tid; j < 64*96/4; j += 256)
        ((float4*)sW)[j] = ((const float4*)w)[j];
    for (int j = tid; j < 32*24; j += 256){
        int p = j / 24, cq = j % 24;
        *(float4*)&sA[p*100 + cq*4] = *(const float4*)&g_dd[(b*LL + pix0 + p)*CHID + cq*4];
    }
    __syncthreads();
    int p = tid & 15, og = tid >> 4;
    float acc[2][4];
    #pragma unroll
    for (int j = 0; j < 4; j++){ acc[0][j] = bias[og*4+j]; acc[1][j] = acc[0][j]; }
    #pragma unroll 4
    for (int kq = 0; kq < 24; kq++){
        float4 a0 = *(float4*)&sA[p*100 + kq*4];
        float4 a1 = *(float4*)&sA[(p+16)*100 + kq*4];
        #pragma unroll
        for (int j = 0; j < 4; j++){
            float4 wv = *(float4*)&sW[(og*4+j)*CHID + kq*4];
            acc[0][j] = dot4(a0, wv, acc[0][j]);
            acc[1][j] = dot4(a1, wv, acc[1][j]);
        }
    }
    #pragma unroll
    for (int j = 0; j < 4; j++){
        int o = og*4 + j;
        float inv = bng[o] * rsqrtf(1.00001f);
        float bb = bnb[o];
        sO[o*33 + p]      = siluf(acc[0][j] * inv + bb);
        sO[o*33 + p + 16] = siluf(acc[1][j] * inv + bb);
    }
    __syncthreads();
    for (int j = tid; j < 64*32; j += 256){
        int o = j >> 5, pp = j & 31;
        int idx = (b*CIN + o)*LL + pix0 + pp;
        out[idx] = (sO[o*33 + pp] + g_diff[idx]) * g_gate[idx];
    }
}

// ---------------- launcher ----------------
extern "C" void kernel_launch(void* const* d_in, const int* in_sizes, int n_in,
                              void* d_out, int out_size){
    const float* pre        = (const float*)d_in[0];
    const float* post       = (const float*)d_in[1];
    const float* prepost_w  = (const float*)d_in[2];
    const float* prepost_b  = (const float*)d_in[3];
    const float* prepost_g  = (const float*)d_in[4];
    const float* prepost_bb = (const float*)d_in[5];
    const float* down_w     = (const float*)d_in[6];
    const float* down_b     = (const float*)d_in[7];
    const float* down_g     = (const float*)d_in[8];
    const float* down_bb    = (const float*)d_in[9];
    const float* up_w       = (const float*)d_in[10];
    const float* up_b       = (const float*)d_in[11];
    const float* up_g       = (const float*)d_in[12];
    const float* up_bb      = (const float*)d_in[13];
    const float* pe_w       = (const float*)d_in[14];
    const float* pe_b       = (const float*)d_in[15];
    const float* pe_ln_g    = (const float*)d_in[16];
    const float* pe_ln_b    = (const float*)d_in[17];
    const float* in_proj_w  = (const float*)d_in[18];
    const float* in_proj_b  = (const float*)d_in[19];
    const float* conv_w     = (const float*)d_in[20];
    const float* conv_b     = (const float*)d_in[21];
    const float* x_proj_w   = (const float*)d_in[22];
    const float* dt_w       = (const float*)d_in[23];
    const float* dt_b       = (const float*)d_in[24];
    const float* A_log      = (const float*)d_in[25];
    const float* Ds         = (const float*)d_in[26];
    const float* out_ln_g   = (const float*)d_in[27];
    const float* out_ln_b   = (const float*)d_in[28];
    const float* out_proj_w = (const float*)d_in[29];
    const float* out_proj_b = (const float*)d_in[30];
    float* out = (float*)d_out;

    kGate2<<<BB*(LL/32), 256>>>(pre, post, prepost_w, prepost_b, prepost_g, prepost_bb);
    kB<<<BB*(LL/32), 256>>>(down_w, down_b, down_g, down_bb);
    kC<<<BB*(LL/32), 256>>>(pe_w, pe_b, pe_ln_g, pe_ln_b);
    kD<<<BB*(LL/32), 256>>>(in_proj_w, in_proj_b);
    kE<<<BB*DN, 256>>>(conv_w, conv_b);
    kX<<<BB*KK*(LL/16), 256>>>(x_proj_w, dt_w, dt_b);
    kF1<<<BB*KK*(SEG-1)*(DN/8), 128>>>(A_log);
    kF2<<<(BB*KK*DN*NN)/256, 256>>>();
    kF3<<<BB*KK*SEG*(DN/8), 128>>>(A_log, Ds);
    kGH<<<BB*(LL/32), 256>>>(out_ln_g, out_ln_b, out_proj_w, out_proj_b);
    kI<<<BB*(LL/32), 256>>>(up_w, up_b, up_g, up_bb, out);
}

// round 12
// speedup vs baseline: 1.4344x; 1.0257x over previous
#include <cuda_runtime.h>
#include <math.h>
#include <stdint.h>

#define BB 4
#define CIN 64
#define CHID 96
#define LL 4096
#define NN 16
#define RR 6
#define KK 4
#define DN 192
#define SEG 4
#define SEGLEN 1024

// ---------------- static scratch (no allocation anywhere) ----------------
__device__ float g_diff [BB*CIN*LL];
__device__ float g_gate [BB*CIN*LL];
__device__ float g_d1   [BB*LL*CHID];
__device__ float g_xln  [BB*LL*CHID];
__device__ float g_xc   [BB*DN*LL];
__device__ float g_xcv  [BB*DN*LL];
__device__ float g_z    [BB*LL*DN];
__device__ float g_xs   [BB*2*LL*DN];     // only k=0,1 stored; k=2,3 are flips
__device__ float g_delta[BB*KK*LL*DN];
__device__ float g_bs   [BB*KK*LL*NN];
__device__ float g_cs   [BB*KK*LL*NN];
__device__ float g_ys   [BB*KK*LL*DN];
__device__ float g_dd   [BB*LL*CHID];
__device__ float g_P [BB*KK*DN*(SEG-1)*NN];
__device__ float g_q [BB*KK*DN*(SEG-1)*NN];
__device__ float g_h0[BB*KK*DN*SEG*NN];

__device__ __forceinline__ float sigm(float x){ return 1.f/(1.f+__expf(-x)); }
__device__ __forceinline__ float siluf(float x){ return x*sigm(x); }
__device__ __forceinline__ float dot4(float4 a, float4 w, float acc){
    acc = fmaf(a.x, w.x, acc);
    acc = fmaf(a.y, w.y, acc);
    acc = fmaf(a.z, w.z, acc);
    acc = fmaf(a.w, w.w, acc);
    return acc;
}
__device__ __forceinline__ uint32_t tf32(float x){
    uint32_t r; asm("cvt.rna.tf32.f32 %0, %1;" : "=r"(r) : "f"(x)); return r;
}
#define MMA_TF32(acc, a0,a1,a2,a3, b0,b1) \
    asm volatile( \
        "mma.sync.aligned.m16n8k8.row.col.f32.tf32.tf32.f32 " \
        "{%0,%1,%2,%3},{%4,%5,%6,%7},{%8,%9},{%0,%1,%2,%3};" \
        : "+f"(acc[0]), "+f"(acc[1]), "+f"(acc[2]), "+f"(acc[3]) \
        : "r"(a0), "r"(a1), "r"(a2), "r"(a3), "r"(b0), "r"(b1))

// ---------------- kGate2 (+ fused diff): g_gate, g_diff ----------------
__global__ void kGate2(const float* __restrict__ pre, const float* __restrict__ post,
                       const float* __restrict__ w, const float* __restrict__ bias,
                       const float* __restrict__ bng, const float* __restrict__ bnb){
    __shared__ float sW[CIN*CIN];
    __shared__ float sP[CIN*32];
    __shared__ float sQ[CIN*32];
    __shared__ float sO[CIN*32];
    int b = blockIdx.x >> 7;
    int pix0 = (blockIdx.x & 127) * 32;
    int tid = threadIdx.x;
    for (int j = tid; j < CIN*CIN/4; j += 256)
        ((float4*)sW)[j] = ((const float4*)w)[j];
    for (int j = tid; j < CIN*32; j += 256){
        int c = j >> 5, p = j & 31;
        int idx = (b*CIN + c)*LL + pix0 + p;
        float pv = pre[idx], qv = post[idx];
        sP[j] = pv;
        sQ[j] = qv;
        g_diff[idx] = fabsf(qv - pv);
    }
    __syncthreads();
    int p = tid & 31, og = tid >> 5;
    float a1[8], a2[8];
    #pragma unroll
    for (int j = 0; j < 8; j++){ a1[j] = 0.f; a2[j] = 0.f; }
    for (int kq = 0; kq < 16; kq++){
        float x1[4], x2[4];
        #pragma unroll
        for (int i = 0; i < 4; i++){
            x1[i] = sP[(kq*4+i)*32 + p];
            x2[i] = sQ[(kq*4+i)*32 + p];
        }
        #pragma unroll
        for (int j = 0; j < 8; j++){
            float4 wv = *(float4*)&sW[(og*8+j)*CIN + kq*4];
            a1[j] = fmaf(x1[0],wv.x, fmaf(x1[1],wv.y, fmaf(x1[2],wv.z, fmaf(x1[3],wv.w, a1[j]))));
            a2[j] = fmaf(x2[0],wv.x, fmaf(x2[1],wv.y, fmaf(x2[2],wv.z, fmaf(x2[3],wv.w, a2[j]))));
        }
    }
    #pragma unroll
    for (int j = 0; j < 8; j++){
        int o = og*8 + j;
        float inv = bng[o] * rsqrtf(1.00001f);
        float bz  = bias[o];
        float bb  = bnb[o];
        float t1 = (a1[j] + bz) * inv + bb;
        float t2 = (a2[j] + bz) * inv + bb;
        sO[o*32 + p] = sigm(siluf(t1)) * sigm(siluf(t2));
    }
    __syncthreads();
    for (int j = tid; j < CIN*32; j += 256){
        int o = j >> 5, pp = j & 31;
        g_gate[(b*CIN + o)*LL + pix0 + pp] = sO[j];
    }
}

// ---------------- kB ----------------
__global__ void kB(const float* __restrict__ w, const float* __restrict__ bias,
                   const float* __restrict__ bng, const float* __restrict__ bnb){
    __shared__ float sW[CHID*CIN];
    __shared__ float sA[CIN*32];
    int b = blockIdx.x >> 7;
    int pix0 = (blockIdx.x & 127) * 32;
    int tid = threadIdx.x;
    for (int j = tid; j < CHID*CIN/4; j += 256)
        ((float4*)sW)[j] = ((const float4*)w)[j];
    for (int j = tid; j < CIN*32; j += 256){
        int c = j >> 5, p = j & 31;
        sA[j] = g_diff[(b*CIN + c)*LL + pix0 + p];
    }
    __syncthreads();
    int p = tid & 31, og = tid >> 5;
    float acc[12];
    #pragma unroll
    for (int j = 0; j < 12; j++) acc[j] = 0.f;
    for (int kq = 0; kq < 16; kq++){
        float x[4];
        #pragma unroll
        for (int i = 0; i < 4; i++) x[i] = sA[(kq*4+i)*32 + p];
        #pragma unroll
        for (int j = 0; j < 12; j++){
            float4 wv = *(float4*)&sW[(og*12+j)*CIN + kq*4];
            acc[j] = fmaf(x[0],wv.x, fmaf(x[1],wv.y, fmaf(x[2],wv.z, fmaf(x[3],wv.w, acc[j]))));
        }
    }
    float res[12];
    #pragma unroll
    for (int j = 0; j < 12; j++){
        int o = og*12 + j;
        float inv = bng[o] * rsqrtf(1.00001f);
        float t = (acc[j] + bias[o]) * inv + bnb[o];
        res[j] = siluf(t);
    }
    float4* dst = (float4*)&g_d1[(b*LL + pix0 + p)*CHID + og*12];
    #pragma unroll
    for (int v = 0; v < 3; v++)
        dst[v] = make_float4(res[v*4], res[v*4+1], res[v*4+2], res[v*4+3]);
}

// ---------------- kC: xln = LN(pe(d1)), 256 thr, 32 pixels, P=2 x T=6 ----------------
__global__ void kC(const float* __restrict__ w, const float* __restrict__ bias,
                   const float* __restrict__ lng, const float* __restrict__ lnb){
    __shared__ float sA[32*100];
    __shared__ float sW[96*48];
    __shared__ float sS[32*16], sS2[32*16];
    __shared__ float sM[32], sR[32];
    int b = blockIdx.x >> 7;
    int pix0 = (blockIdx.x & 127) * 32;
    int tid = threadIdx.x;
    for (int j = tid; j < 32*24; j += 256){
        int p = j / 24, cq = j % 24;
        *(float4*)&sA[p*100 + cq*4] = *(const float4*)&g_d1[(b*LL + pix0 + p)*CHID + cq*4];
    }
    int p = tid & 15, og = tid >> 4;
    float acc[2][6];
    #pragma unroll
    for (int j = 0; j < 6; j++){ acc[0][j] = bias[og*6+j]; acc[1][j] = acc[0][j]; }
    for (int kc = 0; kc < 2; kc++){
        __syncthreads();
        for (int j = tid; j < 96*12; j += 256){
            int o = j / 12, kq = j % 12;
            *(float4*)&sW[o*48 + kq*4] = *(const float4*)&w[o*CHID + kc*48 + kq*4];
        }
        __syncthreads();
        #pragma unroll 4
        for (int kq = 0; kq < 12; kq++){
            float4 a0 = *(float4*)&sA[p*100 + kc*48 + kq*4];
            float4 a1 = *(float4*)&sA[(p+16)*100 + kc*48 + kq*4];
            #pragma unroll
            for (int j = 0; j < 6; j++){
                float4 wv = *(float4*)&sW[(og*6+j)*48 + kq*4];
                acc[0][j] = dot4(a0, wv, acc[0][j]);
                acc[1][j] = dot4(a1, wv, acc[1][j]);
            }
        }
    }
    #pragma unroll
    for (int pi = 0; pi < 2; pi++){
        float s = 0.f, s2 = 0.f;
        #pragma unroll
        for (int j = 0; j < 6; j++){ s += acc[pi][j]; s2 += acc[pi][j]*acc[pi][j]; }
        sS [(p + pi*16)*16 + og] = s;
        sS2[(p + pi*16)*16 + og] = s2;
    }
    __syncthreads();
    if (tid < 32){
        float ss = 0.f, ss2 = 0.f;
        #pragma unroll
        for (int i = 0; i < 16; i++){ ss += sS[tid*16+i]; ss2 += sS2[tid*16+i]; }
        float m = ss * (1.f/96.f);
        float var = ss2 * (1.f/96.f) - m*m;
        sM[tid] = m;  sR[tid] = rsqrtf(var + 1e-5f);
    }
    __syncthreads();
    float* st = sW;
    #pragma unroll
    for (int pi = 0; pi < 2; pi++){
        int pp = p + pi*16;
        float m = sM[pp], rs = sR[pp];
        #pragma unroll
        for (int j = 0; j < 6; j++){
            int o = og*6 + j;
            st[o*33 + pp] = (acc[pi][j] - m) * rs * lng[o] + lnb[o];
        }
    }
    __syncthreads();
    for (int j = tid; j < 32*96; j += 256){
        int pp = j / 96, o = j % 96;
        g_xln[(b*LL + pix0 + pp)*CHID + o] = st[o*33 + pp];
    }
}

// ---------------- kD: in_proj 96->384 via tf32 mma.m16n8k8 ----------------
__global__ void kD(const float* __restrict__ w, const float* __restrict__ bias){
    __shared__ float sA[32*100];   // [p][k] tf32 bits
    __shared__ float sW[64*100];   // [o][k] tf32 bits
    __shared__ float sO[64*33];
    uint32_t* sAu = (uint32_t*)sA;
    uint32_t* sWu = (uint32_t*)sW;
    int b = blockIdx.x >> 7;
    int pix0 = (blockIdx.x & 127) * 32;
    int tid = threadIdx.x;
    int wid = tid >> 5, lane = tid & 31;
    int gid = lane >> 2, tig = lane & 3;
    int pt = wid & 1;
    int ob = (wid >> 1) * 16;

    for (int j = tid; j < 32*24; j += 256){
        int p = j / 24, cq = j % 24;
        float4 v = *(const float4*)&g_xln[(b*LL + pix0 + p)*CHID + cq*4];
        uint32_t* dst = &sAu[p*100 + cq*4];
        dst[0] = tf32(v.x); dst[1] = tf32(v.y); dst[2] = tf32(v.z); dst[3] = tf32(v.w);
    }
    int prow = pt*16 + gid;
    for (int ch = 0; ch < 6; ch++){
        __syncthreads();
        for (int j = tid; j < 64*24; j += 256){
            int o = j / 24, kq = j % 24;
            float4 v = *(const float4*)&w[(ch*64 + o)*CHID + kq*4];
            uint32_t* dst = &sWu[o*100 + kq*4];
            dst[0] = tf32(v.x); dst[1] = tf32(v.y); dst[2] = tf32(v.z); dst[3] = tf32(v.w);
        }
        __syncthreads();
        float acc[2][4];
        #pragma unroll
        for (int j = 0; j < 2; j++){
            float b0v = bias[ch*64 + ob + j*8 + 2*tig];
            float b1v = bias[ch*64 + ob + j*8 + 2*tig + 1];
            acc[j][0] = b0v; acc[j][1] = b1v; acc[j][2] = b0v; acc[j][3] = b1v;
        }
        #pragma unroll 4
        for (int s = 0; s < 12; s++){
            int k0 = s*8;
            uint32_t a0 = sAu[prow*100     + k0 + tig];
            uint32_t a1 = sAu[(prow+8)*100 + k0 + tig];
            uint32_t a2 = sAu[prow*100     + k0 + tig + 4];
            uint32_t a3 = sAu[(prow+8)*100 + k0 + tig + 4];
            #pragma unroll
            for (int j = 0; j < 2; j++){
                uint32_t b0 = sWu[(ob + j*8 + gid)*100 + k0 + tig];
                uint32_t b1 = sWu[(ob + j*8 + gid)*100 + k0 + tig + 4];
                MMA_TF32(acc[j], a0,a1,a2,a3, b0,b1);
            }
        }
        #pragma unroll
        for (int j = 0; j < 2; j++){
            int o0 = ob + j*8 + 2*tig;
            sO[o0*33 + prow]         = acc[j][0];
            sO[(o0+1)*33 + prow]     = acc[j][1];
            sO[o0*33 + prow + 8]     = acc[j][2];
            sO[(o0+1)*33 + prow + 8] = acc[j][3];
        }
        __syncthreads();
        if (ch < 3){
            for (int j = tid; j < 64*32; j += 256){
                int o = j >> 5, pp = j & 31;
                g_xc[(b*DN + ch*64 + o)*LL + pix0 + pp] = sO[o*33 + pp];
            }
        } else {
            for (int j = tid; j < 32*64; j += 256){
                int pp = j >> 6, oz = j & 63;
                g_z[(b*LL + pix0 + pp)*DN + (ch-3)*64 + oz] = sO[oz*33 + pp];
            }
        }
    }
}

// ---------------- kE: depthwise 3x3 conv + bias + silu, one block per (b,d) ---------
__global__ void kE(const float* __restrict__ cw, const float* __restrict__ cb){
    __shared__ float sT[66*66];
    int bd = blockIdx.x;
    int d  = bd % DN;
    int tid = threadIdx.x;
    const float* src = g_xc + bd*LL;
    for (int j = tid; j < 66*66; j += 256){
        int rr = j / 66, cc = j % 66;
        int r = rr - 1, c = cc - 1;
        float v = 0.f;
        if (r >= 0 && r < 64 && c >= 0 && c < 64) v = src[r*64 + c];
        sT[j] = v;
    }
    float w9[9];
    #pragma unroll
    for (int i = 0; i < 9; i++) w9[i] = cw[d*9 + i];
    float bz = cb[d];
    __syncthreads();
    float* dst = g_xcv + bd*LL;
    for (int j = tid; j < 64*64; j += 256){
        int r = j >> 6, c = j & 63;
        float s = bz;
        #pragma unroll
        for (int ky = 0; ky < 3; ky++)
            #pragma unroll
            for (int kx = 0; kx < 3; kx++)
                s = fmaf(w9[ky*3+kx], sT[(r+ky)*66 + c + kx], s);
        dst[j] = siluf(s);
    }
}

// ---------------- kX: gather xs, x_proj GEMM, dt GEMM + softplus ----------------
__global__ void kX(const float* __restrict__ xpw, const float* __restrict__ dtw,
                   const float* __restrict__ dtb){
    __shared__ float sxs[16*196];
    __shared__ float sWx[38*DN];
    __shared__ float sdtw[DN*6];
    __shared__ float sdt[6*17];
    int tile = blockIdx.x & 255;
    int k    = (blockIdx.x >> 8) & 3;
    int b    = blockIdx.x >> 10;
    int t0   = tile * 16;
    int tid  = threadIdx.x;
    int base = (b*KK + k)*LL;

    for (int j = tid; j < 38*DN/4; j += 256)
        ((float4*)sWx)[j] = ((const float4*)(xpw + k*38*DN))[j];
    for (int j = tid; j < DN*6/2; j += 256)
        ((float2*)sdtw)[j] = ((const float2*)(dtw + k*DN*6))[j];
    for (int j = tid; j < DN*16; j += 256){
        int d = j >> 4, tt = j & 15;
        int t = t0 + tt;
        int pix;
        if (k == 0)      pix = t;
        else if (k == 1) pix = (t & 63)*64 + (t >> 6);
        else if (k == 2) pix = LL - 1 - t;
        else { int tr = LL - 1 - t; pix = (tr & 63)*64 + (tr >> 6); }
        sxs[tt*196 + d] = g_xcv[(b*DN + d)*LL + pix];
    }
    __syncthreads();
    if (k < 2){
        int xbase = (b*2 + k)*LL;
        for (int j = tid; j < 16*48; j += 256){
            int tt = j / 48, dq = j % 48;
            *(float4*)&g_xs[(xbase + t0 + tt)*DN + dq*4] = *(float4*)&sxs[tt*196 + dq*4];
        }
    }
    for (int j = tid; j < 38*16; j += 256){
        int c = j >> 4, tt = j & 15;
        float acc = 0.f;
        for (int dq = 0; dq < 48; dq++){
            float4 a4 = *(float4*)&sxs[tt*196 + dq*4];
            float4 wv = *(float4*)&sWx[c*DN + dq*4];
            acc = dot4(a4, wv, acc);
        }
        if (c < RR)            sdt[c*17 + tt] = acc;
        else if (c < RR + NN)  g_bs[(base + t0 + tt)*NN + (c - RR)] = acc;
        else                   g_cs[(base + t0 + tt)*NN + (c - RR - NN)] = acc;
    }
    __syncthreads();
    float* sdl = sWx;
    {
        int tt = tid & 15, dq = tid >> 4;
        float acc[12];
        #pragma unroll
        for (int j = 0; j < 12; j++) acc[j] = dtb[k*DN + dq*12 + j];
        float dts[6];
        #pragma unroll
        for (int r = 0; r < RR; r++) dts[r] = sdt[r*17 + tt];
        #pragma unroll
        for (int j = 0; j < 12; j++){
            int d = dq*12 + j;
            float a = acc[j];
            #pragma unroll
            for (int r = 0; r < RR; r++)
                a = fmaf(dts[r], sdtw[d*6 + r], a);
            float dl = (a > 20.f) ? a : log1pf(__expf(a));
            acc[j] = dl;
        }
        __syncthreads();
        #pragma unroll
        for (int j = 0; j < 12; j++) sdl[tt*DN + dq*12 + j] = acc[j];
    }
    __syncthreads();
    for (int j = tid; j < 16*48; j += 256){
        int tt = j / 48, dq = j % 48;
        *(float4*)&g_delta[(base + t0 + tt)*DN + dq*4] = *(float4*)&sdl[tt*DN + dq*4];
    }
}

// ---------------- kF1: per-segment P (one exp) and offset q; packed DU ----------------
__global__ void kF1(const float* __restrict__ A_log){
    __shared__ float sDU[16*8*2];
    __shared__ float sB[16*16];
    __shared__ float sSum[8];
    int bid = blockIdx.x;
    int dg = (bid % 24) * 8;
    int s  = (bid / 24) % (SEG-1);
    int k  = (bid / (24*(SEG-1))) % 4;
    int b  = bid / (24*(SEG-1)*4);
    int tid = threadIdx.x;
    int ch = tid >> 4, n = tid & 15;
    int d  = dg + ch;
    int base = (b*KK + k)*LL + s*SEGLEN;
    int xrow = (b*2 + (k & 1))*LL;
    bool rev = (k >= 2);

    float a = -__expf(A_log[(k*DN + d)*NN + n]);
    float h = 0.f;

    int lt = tid >> 3, lc = tid & 7;
    float dsum = 0.f;
    float rD, rX, rB[2];
    {
        int t_abs = s*SEGLEN + lt;
        int xr = rev ? (LL-1 - t_abs) : t_abs;
        rD = g_delta[(base + lt)*DN + dg + lc];
        rX = g_xs   [(xrow + xr)*DN + dg + lc];
    }
    #pragma unroll
    for (int i = 0; i < 2; i++){
        int jj = tid + i*128;
        rB[i] = g_bs[base*NN + jj];
    }
    for (int chunk = 0; chunk < SEGLEN/16; chunk++){
        *(float2*)&sDU[tid*2] = make_float2(rD, rD * rX);
        sB[tid] = rB[0];  sB[tid+128] = rB[1];
        dsum += rD;
        __syncthreads();
        if (chunk < SEGLEN/16 - 1){
            int t0n = (chunk + 1) * 16;
            int t_abs = s*SEGLEN + t0n + lt;
            int xr = rev ? (LL-1 - t_abs) : t_abs;
            rD = g_delta[(base + t0n + lt)*DN + dg + lc];
            rX = g_xs   [(xrow + xr)*DN + dg + lc];
            #pragma unroll
            for (int i = 0; i < 2; i++){
                int jj = tid + i*128;
                rB[i] = g_bs[(base + t0n)*NN + jj];
            }
        }
        #pragma unroll
        for (int t = 0; t < 16; t++){
            float2 du = *(float2*)&sDU[(t*8 + ch)*2];
            float Bn = sB[t*16 + n];
            float e  = __expf(du.x * a);
            h = fmaf(e, h, du.y * Bn);
        }
        __syncthreads();
    }
    sDU[lt*8 + lc] = dsum;
    __syncthreads();
    if (tid < 8){
        float S = 0.f;
        #pragma unroll
        for (int i = 0; i < 16; i++) S += sDU[i*8 + tid];
        sSum[tid] = S;
    }
    __syncthreads();
    float P = __expf(a * sSum[ch]);
    int chain = (b*KK + k)*DN + d;
    g_P[(chain*(SEG-1) + s)*NN + n] = P;
    g_q[(chain*(SEG-1) + s)*NN + n] = h;
}

// ---------------- kF2: prefix over segments -> g_h0 ----------------
__global__ void kF2(){
    int gid = blockIdx.x*blockDim.x + threadIdx.x;
    int chain = gid >> 4, n = gid & 15;
    float h = 0.f;
    g_h0[(chain*SEG + 0)*NN + n] = 0.f;
    #pragma unroll
    for (int s = 0; s < SEG-1; s++){
        float P = g_P[(chain*(SEG-1) + s)*NN + n];
        float q = g_q[(chain*(SEG-1) + s)*NN + n];
        h = fmaf(P, h, q);
        g_h0[(chain*SEG + s + 1)*NN + n] = h;
    }
}

// ---------------- kF3: packed DU/BC, smem transpose-reduce ----------------
__global__ void kF3(const float* __restrict__ A_log, const float* __restrict__ Ds){
    __shared__ float sDU[16*8*2];
    __shared__ float sBC[16*16*2];
    __shared__ float sP[NN*129];
    int bid = blockIdx.x;
    int dg = (bid % 24) * 8;
    int s  = (bid / 24) % SEG;
    int k  = (bid / (24*SEG)) % 4;
    int b  = bid / (24*SEG*4);
    int tid = threadIdx.x;
    int ch = tid >> 4, n = tid & 15;
    int d  = dg + ch;
    int base = (b*KK + k)*LL + s*SEGLEN;
    int chain = (b*KK + k)*DN + d;
    int xrow = (b*2 + (k & 1))*LL;
    bool rev = (k >= 2);

    float a  = -__expf(A_log[(k*DN + d)*NN + n]);
    float h  = g_h0[(chain*SEG + s)*NN + n];

    int lt = tid >> 3, lc = tid & 7;
    float Dv2 = Ds[k*DN + dg + lc];
    float rD, rX, rB[2], rC[2];
    {
        int t_abs = s*SEGLEN + lt;
        int xr = rev ? (LL-1 - t_abs) : t_abs;
        rD = g_delta[(base + lt)*DN + dg + lc];
        rX = g_xs   [(xrow + xr)*DN + dg + lc];
    }
    #pragma unroll
    for (int i = 0; i < 2; i++){
        int jj = tid + i*128;
        rB[i] = g_bs[base*NN + jj];
        rC[i] = g_cs[base*NN + jj];
    }
    for (int chunk = 0; chunk < SEGLEN/16; chunk++){
        *(float2*)&sDU[tid*2] = make_float2(rD, rD * rX);
        *(float2*)&sBC[tid*2]       = make_float2(rB[0], rC[0]);
        *(float2*)&sBC[(tid+128)*2] = make_float2(rB[1], rC[1]);
        float xCur = rX;
        __syncthreads();
        if (chunk < SEGLEN/16 - 1){
            int t0n = (chunk + 1) * 16;
            int t_abs = s*SEGLEN + t0n + lt;
            int xr = rev ? (LL-1 - t_abs) : t_abs;
            rD = g_delta[(base + t0n + lt)*DN + dg + lc];
            rX = g_xs   [(xrow + xr)*DN + dg + lc];
            #pragma unroll
            for (int i = 0; i < 2; i++){
                int jj = tid + i*128;
                rB[i] = g_bs[(base + t0n)*NN + jj];
                rC[i] = g_cs[(base + t0n)*NN + jj];
            }
        }
        #pragma unroll
        for (int t = 0; t < 16; t++){
            float2 du = *(float2*)&sDU[(t*8 + ch)*2];
            float2 bc = *(float2*)&sBC[(t*16 + n)*2];
            float e  = __expf(du.x * a);
            h = fmaf(e, h, du.y * bc.x);
            sP[n*129 + t*8 + ch] = h * bc.y;
        }
        __syncthreads();
        {
            float y = Dv2 * xCur;
            #pragma unroll
            for (int nn = 0; nn < NN; nn++)
                y += sP[nn*129 + tid];
            g_ys[(base + chunk*16 + lt)*DN + dg + lc] = y;
        }
    }
}

// ---------------- kGH v2: combine + LN + gate, then tf32 mma out_proj -> g_dd ----------
__global__ void kGH(const float* __restrict__ lng, const float* __restrict__ lnb,
                    const float* __restrict__ w, const float* __restrict__ bias){
    __shared__ float sA[32*196];   // [p][k] tf32 bits after gate stage
    __shared__ float sW[96*52];    // [o][k_local] tf32 bits chunk; reused as stage [o][33]
    __shared__ float sS[256], sS2[256];
    __shared__ float sM[32], sR[32];
    uint32_t* sAu = (uint32_t*)sA;
    uint32_t* sWu = (uint32_t*)sW;
    int b = blockIdx.x >> 7;
    int pix0 = (blockIdx.x & 127) * 32;
    int tid = threadIdx.x;
    int tp = tid >> 3, tc = tid & 7;
    int l  = pix0 + tp;
    int hh = l >> 6, ww = l & 63;
    int t1 = ww*64 + hh;
    int b4 = b*KK*LL;
    const float* r0 = &g_ys[(b4 + l)*DN];
    const float* r1 = &g_ys[(b4 + 1*LL + t1)*DN];
    const float* r2 = &g_ys[(b4 + 2*LL + (LL-1-l))*DN];
    const float* r3 = &g_ys[(b4 + 3*LL + (LL-1-t1))*DN];
    float vloc[24];
    float s = 0.f, s2 = 0.f;
    #pragma unroll
    for (int jq = 0; jq < 6; jq++){
        int c = tc*24 + jq*4;
        float4 a0 = *(const float4*)&r0[c];
        float4 a1 = *(const float4*)&r1[c];
        float4 a2 = *(const float4*)&r2[c];
        float4 a3 = *(const float4*)&r3[c];
        float v0 = a0.x + a1.x + a2.x + a3.x;
        float v1 = a0.y + a1.y + a2.y + a3.y;
        float v2 = a0.z + a1.z + a2.z + a3.z;
        float v3 = a0.w + a1.w + a2.w + a3.w;
        vloc[jq*4+0] = v0; vloc[jq*4+1] = v1; vloc[jq*4+2] = v2; vloc[jq*4+3] = v3;
        s  += v0 + v1 + v2 + v3;
        s2 += v0*v0 + v1*v1 + v2*v2 + v3*v3;
    }
    sS[tid] = s;  sS2[tid] = s2;
    __syncthreads();
    if (tid < 32){
        float ss = 0.f, ss2 = 0.f;
        #pragma unroll
        for (int i = 0; i < 8; i++){ ss += sS[tid*8+i]; ss2 += sS2[tid*8+i]; }
        float m = ss * (1.f/192.f);
        float var = ss2 * (1.f/192.f) - m*m;
        sM[tid] = m;  sR[tid] = rsqrtf(var + 1e-5f);
    }
    __syncthreads();
    {
        float m = sM[tp], rs = sR[tp];
        const float* zrow = &g_z[(b*LL + l)*DN];
        #pragma unroll
        for (int jq = 0; jq < 6; jq++){
            int c = tc*24 + jq*4;
            float4 zv = *(const float4*)&zrow[c];
            float4 gv = *(const float4*)&lng[c];
            float4 bv = *(const float4*)&lnb[c];
            sAu[tp*196 + c + 0] = tf32(((vloc[jq*4+0]-m)*rs*gv.x + bv.x) * siluf(zv.x));
            sAu[tp*196 + c + 1] = tf32(((vloc[jq*4+1]-m)*rs*gv.y + bv.y) * siluf(zv.y));
            sAu[tp*196 + c + 2] = tf32(((vloc[jq*4+2]-m)*rs*gv.z + bv.z) * siluf(zv.z));
            sAu[tp*196 + c + 3] = tf32(((vloc[jq*4+3]-m)*rs*gv.w + bv.w) * siluf(zv.w));
        }
    }
    // tf32 mma out_proj: 96 outputs, K=192 in 4 chunks of 48
    int wid = tid >> 5, lane = tid & 31;
    int gid = lane >> 2, tig = lane & 3;
    int pt = wid & 1;
    int ob = (wid >> 1) * 24;     // 3 n-tiles of 8 per warp-pair
    int prow = pt*16 + gid;
    float acc[3][4];
    #pragma unroll
    for (int j = 0; j < 3; j++){
        float b0v = bias[ob + j*8 + 2*tig];
        float b1v = bias[ob + j*8 + 2*tig + 1];
        acc[j][0] = b0v; acc[j][1] = b1v; acc[j][2] = b0v; acc[j][3] = b1v;
    }
    for (int kc = 0; kc < 4; kc++){
        __syncthreads();
        for (int j = tid; j < 96*12; j += 256){
            int o = j / 12, kq = j % 12;
            float4 v = *(const float4*)&w[o*DN + kc*48 + kq*4];
            uint32_t* dst = &sWu[o*52 + kq*4];
            dst[0] = tf32(v.x); dst[1] = tf32(v.y); dst[2] = tf32(v.z); dst[3] = tf32(v.w);
        }
        __syncthreads();
        #pragma unroll
        for (int sgl = 0; sgl < 6; sgl++){
            int kg = kc*48 + sgl*8;
            uint32_t a0 = sAu[prow*196     + kg + tig];
            uint32_t a1 = sAu[(prow+8)*196 + kg + tig];
            uint32_t a2 = sAu[prow*196     + kg + tig + 4];
            uint32_t a3 = sAu[(prow+8)*196 + kg + tig + 4];
            int kl = sgl*8;
            #pragma unroll
            for (int j = 0; j < 3; j++){
                uint32_t b0 = sWu[(ob + j*8 + gid)*52 + kl + tig];
                uint32_t b1 = sWu[(ob + j*8 + gid)*52 + kl + tig + 4];
                MMA_TF32(acc[j], a0,a1,a2,a3, b0,b1);
            }
        }
    }
    __syncthreads();
    float* st = sW;    // stage [o][33]
    #pragma unroll
    for (int j = 0; j < 3; j++){
        int o0 = ob + j*8 + 2*tig;
        st[o0*33 + prow]         = acc[j][0];
        st[(o0+1)*33 + prow]     = acc[j][1];
        st[o0*33 + prow + 8]     = acc[j][2];
        st[(o0+1)*33 + prow + 8] = acc[j][3];
    }
    __syncthreads();
    for (int j = tid; j < 32*96; j += 256){
        int pp = j / 96, o = j % 96;
        g_dd[(b*LL + pix0 + pp)*CHID + o] = st[o*33 + pp];
    }
}

// ---------------- kI v2: up-proj via tf32 mma + bn + silu + residual + gate ------------
__global__ void kI(const float* __restrict__ w, const float* __restrict__ bias,
                   const float* __restrict__ bng, const float* __restrict__ bnb,
                   float* __restrict__ out){
    __shared__ float sA[32*100];   // [p][k] tf32 bits
    __shared__ float sW[64*100];   // [o][k] tf32 bits
    __shared__ float sO[64*33];
    uint32_t* sAu = (uint32_t*)sA;
    uint32_t* sWu = (uint32_t*)sW;
    int b = blockIdx.x >> 7;
    int pix0 = (blockIdx.x & 127) * 32;
    int tid = threadIdx.x;
    int wid = tid >> 5, lane = tid & 31;
    int gid = lane >> 2, tig = lane & 3;
    int pt = wid & 1;
    int ob = (wid >> 1) * 16;
    int prow = pt*16 + gid;

    for (int j = tid; j < 32*24; j += 256){
        int p = j / 24, cq = j % 24;
        float4 v = *(const float4*)&g_dd[(b*LL + pix0 + p)*CHID + cq*4];
        uint32_t* dst = &sAu[p*100 + cq*4];
        dst[0] = tf32(v.x); dst[1] = tf32(v.y); dst[2] = tf32(v.z); dst[3] = tf32(v.w);
    }
    for (int j = tid; j < 64*24; j += 256){
        int o = j / 24, kq = j % 24;
        float4 v = *(const float4*)&w[o*CHID + kq*4];
        uint32_t* dst = &sWu[o*100 + kq*4];
        dst[0] = tf32(v.x); dst[1] = tf32(v.y); dst[2] = tf32(v.z); dst[3] = tf32(v.w);
    }
    __syncthreads();
    float acc[2][4];
    #pragma unroll
    for (int j = 0; j < 2; j++){
        float b0v = bias[ob + j*8 + 2*tig];
        float b1v = bias[ob + j*8 + 2*tig + 1];
        acc[j][0] = b0v; acc[j][1] = b1v; acc[j][2] = b0v; acc[j][3] = b1v;
    }
    #pragma unroll 4
    for (int s = 0; s < 12; s++){
        int k0 = s*8;
        uint32_t a0 = sAu[prow*100     + k0 + tig];
        uint32_t a1 = sAu[(prow+8)*100 + k0 + tig];
        uint32_t a2 = sAu[prow*100     + k0 + tig + 4];
        uint32_t a3 = sAu[(prow+8)*100 + k0 + tig + 4];
        #pragma unroll
        for (int j = 0; j < 2; j++){
            uint32_t b0 = sWu[(ob + j*8 + gid)*100 + k0 + tig];
            uint32_t b1 = sWu[(ob + j*8 + gid)*100 + k0 + tig + 4];
            MMA_TF32(acc[j], a0,a1,a2,a3, b0,b1);
        }
    }
    // epilogue at fragment store: bn + silu
    #pragma unroll
    for (int j = 0; j < 2; j++){
        int o0 = ob + j*8 + 2*tig;
        float inv0 = bng[o0]   * rsqrtf(1.00001f);
        float inv1 = bng[o0+1] * rsqrtf(1.00001f);
        float bb0 = bnb[o0], bb1 = bnb[o0+1];
        sO[o0*33 + prow]         = siluf(acc[j][0]*inv0 + bb0);
        sO[(o0+1)*33 + prow]     = siluf(acc[j][1]*inv1 + bb1);
        sO[o0*33 + prow + 8]     = siluf(acc[j][2]*inv0 + bb0);
        sO[(o0+1)*33 + prow + 8] = siluf(acc[j][3]*inv1 + bb1);
    }
    __syncthreads();
    for (int j = tid; j < 64*32; j += 256){
        int o = j >> 5, pp = j & 31;
        int idx = (b*CIN + o)*LL + pix0 + pp;
        out[idx] = (sO[o*33 + pp] + g_diff[idx]) * g_gate[idx];
    }
}

// ---------------- launcher ----------------
extern "C" void kernel_launch(void* const* d_in, const int* in_sizes, int n_in,
                              void* d_out, int out_size){
    const float* pre        = (const float*)d_in[0];
    const float* post       = (const float*)d_in[1];
    const float* prepost_w  = (const float*)d_in[2];
    const float* prepost_b  = (const float*)d_in[3];
    const float* prepost_g  = (const float*)d_in[4];
    const float* prepost_bb = (const float*)d_in[5];
    const float* down_w     = (const float*)d_in[6];
    const float* down_b     = (const float*)d_in[7];
    const float* down_g     = (const float*)d_in[8];
    const float* down_bb    = (const float*)d_in[9];
    const float* up_w       = (const float*)d_in[10];
    const float* up_b       = (const float*)d_in[11];
    const float* up_g       = (const float*)d_in[12];
    const float* up_bb      = (const float*)d_in[13];
    const float* pe_w       = (const float*)d_in[14];
    const float* pe_b       = (const float*)d_in[15];
    const float* pe_ln_g    = (const float*)d_in[16];
    const float* pe_ln_b    = (const float*)d_in[17];
    const float* in_proj_w  = (const float*)d_in[18];
    const float* in_proj_b  = (const float*)d_in[19];
    const float* conv_w     = (const float*)d_in[20];
    const float* conv_b     = (const float*)d_in[21];
    const float* x_proj_w   = (const float*)d_in[22];
    const float* dt_w       = (const float*)d_in[23];
    const float* dt_b       = (const float*)d_in[24];
    const float* A_log      = (const float*)d_in[25];
    const float* Ds         = (const float*)d_in[26];
    const float* out_ln_g   = (const float*)d_in[27];
    const float* out_ln_b   = (const float*)d_in[28];
    const float* out_proj_w = (const float*)d_in[29];
    const float* out_proj_b = (const float*)d_in[30];
    float* out = (float*)d_out;

    kGate2<<<BB*(LL/32), 256>>>(pre, post, prepost_w, prepost_b, prepost_g, prepost_bb);
    kB<<<BB*(LL/32), 256>>>(down_w, down_b, down_g, down_bb);
    kC<<<BB*(LL/32), 256>>>(pe_w, pe_b, pe_ln_g, pe_ln_b);
    kD<<<BB*(LL/32), 256>>>(in_proj_w, in_proj_b);
    kE<<<BB*DN, 256>>>(conv_w, conv_b);
    kX<<<BB*KK*(LL/16), 256>>>(x_proj_w, dt_w, dt_b);
    kF1<<<BB*KK*(SEG-1)*(DN/8), 128>>>(A_log);
    kF2<<<(BB*KK*DN*NN)/256, 256>>>();
    kF3<<<BB*KK*SEG*(DN/8), 128>>>(A_log, Ds);
    kGH<<<BB*(LL/32), 256>>>(out_ln_g, out_ln_b, out_proj_w, out_proj_b);
    kI<<<BB*(LL/32), 256>>>(up_w, up_b, up_g, up_bb, out);
}

// round 14
// speedup vs baseline: 1.4566x; 1.0155x over previous
#include <cuda_runtime.h>
#include <math.h>
#include <stdint.h>

#define BB 4
#define CIN 64
#define CHID 96
#define LL 4096
#define NN 16
#define RR 6
#define KK 4
#define DN 192
#define SEG 4
#define SEGLEN 1024

// ---------------- static scratch (no allocation anywhere) ----------------
__device__ float g_diff [BB*CIN*LL];
__device__ float g_gate [BB*CIN*LL];
__device__ float g_d1   [BB*LL*CHID];
__device__ float g_xln  [BB*LL*CHID];
__device__ float g_xc   [BB*DN*LL];
__device__ float g_xcv  [BB*DN*LL];
__device__ float g_z    [BB*LL*DN];
__device__ float g_xs   [BB*2*LL*DN];     // only k=0,1 stored; k=2,3 are flips
__device__ float g_delta[BB*KK*LL*DN];
__device__ float g_bs   [BB*KK*LL*NN];
__device__ float g_cs   [BB*KK*LL*NN];
__device__ float g_ys   [BB*KK*LL*DN];
__device__ float g_dd   [BB*LL*CHID];
__device__ float g_P [BB*KK*DN*(SEG-1)*NN];
__device__ float g_q [BB*KK*DN*(SEG-1)*NN];
__device__ float g_h0[BB*KK*DN*SEG*NN];

__device__ __forceinline__ float sigm(float x){ return 1.f/(1.f+__expf(-x)); }
__device__ __forceinline__ float siluf(float x){ return x*sigm(x); }
__device__ __forceinline__ float dot4(float4 a, float4 w, float acc){
    acc = fmaf(a.x, w.x, acc);
    acc = fmaf(a.y, w.y, acc);
    acc = fmaf(a.z, w.z, acc);
    acc = fmaf(a.w, w.w, acc);
    return acc;
}
__device__ __forceinline__ uint32_t tf32(float x){
    uint32_t r; asm("cvt.rna.tf32.f32 %0, %1;" : "=r"(r) : "f"(x)); return r;
}
#define MMA_TF32(acc, a0,a1,a2,a3, b0,b1) \
    asm volatile( \
        "mma.sync.aligned.m16n8k8.row.col.f32.tf32.tf32.f32 " \
        "{%0,%1,%2,%3},{%4,%5,%6,%7},{%8,%9},{%0,%1,%2,%3};" \
        : "+f"(acc[0]), "+f"(acc[1]), "+f"(acc[2]), "+f"(acc[3]) \
        : "r"(a0), "r"(a1), "r"(a2), "r"(a3), "r"(b0), "r"(b1))

// ---------------- kGate2 (+ fused diff): g_gate, g_diff ----------------
__global__ void kGate2(const float* __restrict__ pre, const float* __restrict__ post,
                       const float* __restrict__ w, const float* __restrict__ bias,
                       const float* __restrict__ bng, const float* __restrict__ bnb){
    __shared__ __align__(16) float sW[CIN*CIN];
    __shared__ __align__(16) float sP[CIN*32];
    __shared__ __align__(16) float sQ[CIN*32];
    __shared__ __align__(16) float sO[CIN*32];
    int b = blockIdx.x >> 7;
    int pix0 = (blockIdx.x & 127) * 32;
    int tid = threadIdx.x;
    for (int j = tid; j < CIN*CIN/4; j += 256)
        ((float4*)sW)[j] = ((const float4*)w)[j];
    for (int j = tid; j < CIN*32; j += 256){
        int c = j >> 5, p = j & 31;
        int idx = (b*CIN + c)*LL + pix0 + p;
        float pv = pre[idx], qv = post[idx];
        sP[j] = pv;
        sQ[j] = qv;
        g_diff[idx] = fabsf(qv - pv);
    }
    __syncthreads();
    int p = tid & 31, og = tid >> 5;
    float a1[8], a2[8];
    #pragma unroll
    for (int j = 0; j < 8; j++){ a1[j] = 0.f; a2[j] = 0.f; }
    for (int kq = 0; kq < 16; kq++){
        float x1[4], x2[4];
        #pragma unroll
        for (int i = 0; i < 4; i++){
            x1[i] = sP[(kq*4+i)*32 + p];
            x2[i] = sQ[(kq*4+i)*32 + p];
        }
        #pragma unroll
        for (int j = 0; j < 8; j++){
            float4 wv = *(float4*)&sW[(og*8+j)*CIN + kq*4];
            a1[j] = fmaf(x1[0],wv.x, fmaf(x1[1],wv.y, fmaf(x1[2],wv.z, fmaf(x1[3],wv.w, a1[j]))));
            a2[j] = fmaf(x2[0],wv.x, fmaf(x2[1],wv.y, fmaf(x2[2],wv.z, fmaf(x2[3],wv.w, a2[j]))));
        }
    }
    #pragma unroll
    for (int j = 0; j < 8; j++){
        int o = og*8 + j;
        float inv = bng[o] * rsqrtf(1.00001f);
        float bz  = bias[o];
        float bb  = bnb[o];
        float t1 = (a1[j] + bz) * inv + bb;
        float t2 = (a2[j] + bz) * inv + bb;
        sO[o*32 + p] = sigm(siluf(t1)) * sigm(siluf(t2));
    }
    __syncthreads();
    for (int j = tid; j < CIN*32; j += 256){
        int o = j >> 5, pp = j & 31;
        g_gate[(b*CIN + o)*LL + pix0 + pp] = sO[j];
    }
}

// ---------------- kB ----------------
__global__ void kB(const float* __restrict__ w, const float* __restrict__ bias,
                   const float* __restrict__ bng, const float* __restrict__ bnb){
    __shared__ __align__(16) float sW[CHID*CIN];
    __shared__ __align__(16) float sA[CIN*32];
    int b = blockIdx.x >> 7;
    int pix0 = (blockIdx.x & 127) * 32;
    int tid = threadIdx.x;
    for (int j = tid; j < CHID*CIN/4; j += 256)
        ((float4*)sW)[j] = ((const float4*)w)[j];
    for (int j = tid; j < CIN*32; j += 256){
        int c = j >> 5, p = j & 31;
        sA[j] = g_diff[(b*CIN + c)*LL + pix0 + p];
    }
    __syncthreads();
    int p = tid & 31, og = tid >> 5;
    float acc[12];
    #pragma unroll
    for (int j = 0; j < 12; j++) acc[j] = 0.f;
    for (int kq = 0; kq < 16; kq++){
        float x[4];
        #pragma unroll
        for (int i = 0; i < 4; i++) x[i] = sA[(kq*4+i)*32 + p];
        #pragma unroll
        for (int j = 0; j < 12; j++){
            float4 wv = *(float4*)&sW[(og*12+j)*CIN + kq*4];
            acc[j] = fmaf(x[0],wv.x, fmaf(x[1],wv.y, fmaf(x[2],wv.z, fmaf(x[3],wv.w, acc[j]))));
        }
    }
    float res[12];
    #pragma unroll
    for (int j = 0; j < 12; j++){
        int o = og*12 + j;
        float inv = bng[o] * rsqrtf(1.00001f);
        float t = (acc[j] + bias[o]) * inv + bnb[o];
        res[j] = siluf(t);
    }
    float4* dst = (float4*)&g_d1[(b*LL + pix0 + p)*CHID + og*12];
    #pragma unroll
    for (int v = 0; v < 3; v++)
        dst[v] = make_float4(res[v*4], res[v*4+1], res[v*4+2], res[v*4+3]);
}

// ---------------- kC: xln = LN(pe(d1)), 256 thr, 32 pixels, P=2 x T=6 ----------------
__global__ void kC(const float* __restrict__ w, const float* __restrict__ bias,
                   const float* __restrict__ lng, const float* __restrict__ lnb){
    __shared__ __align__(16) float sA[32*100];
    __shared__ __align__(16) float sW[96*48];
    __shared__ __align__(16) float sS[32*16];
    __shared__ __align__(16) float sS2[32*16];
    __shared__ float sM[32], sR[32];
    int b = blockIdx.x >> 7;
    int pix0 = (blockIdx.x & 127) * 32;
    int tid = threadIdx.x;
    for (int j = tid; j < 32*24; j += 256){
        int p = j / 24, cq = j % 24;
        *(float4*)&sA[p*100 + cq*4] = *(const float4*)&g_d1[(b*LL + pix0 + p)*CHID + cq*4];
    }
    int p = tid & 15, og = tid >> 4;
    float acc[2][6];
    #pragma unroll
    for (int j = 0; j < 6; j++){ acc[0][j] = bias[og*6+j]; acc[1][j] = acc[0][j]; }
    for (int kc = 0; kc < 2; kc++){
        __syncthreads();
        for (int j = tid; j < 96*12; j += 256){
            int o = j / 12, kq = j % 12;
            *(float4*)&sW[o*48 + kq*4] = *(const float4*)&w[o*CHID + kc*48 + kq*4];
        }
        __syncthreads();
        #pragma unroll 4
        for (int kq = 0; kq < 12; kq++){
            float4 a0 = *(float4*)&sA[p*100 + kc*48 + kq*4];
            float4 a1 = *(float4*)&sA[(p+16)*100 + kc*48 + kq*4];
            #pragma unroll
            for (int j = 0; j < 6; j++){
                float4 wv = *(float4*)&sW[(og*6+j)*48 + kq*4];
                acc[0][j] = dot4(a0, wv, acc[0][j]);
                acc[1][j] = dot4(a1, wv, acc[1][j]);
            }
        }
    }
    #pragma unroll
    for (int pi = 0; pi < 2; pi++){
        float s = 0.f, s2 = 0.f;
        #pragma unroll
        for (int j = 0; j < 6; j++){ s += acc[pi][j]; s2 += acc[pi][j]*acc[pi][j]; }
        sS [(p + pi*16)*16 + og] = s;
        sS2[(p + pi*16)*16 + og] = s2;
    }
    __syncthreads();
    if (tid < 32){
        float ss = 0.f, ss2 = 0.f;
        #pragma unroll
        for (int i = 0; i < 16; i++){ ss += sS[tid*16+i]; ss2 += sS2[tid*16+i]; }
        float m = ss * (1.f/96.f);
        float var = ss2 * (1.f/96.f) - m*m;
        sM[tid] = m;  sR[tid] = rsqrtf(var + 1e-5f);
    }
    __syncthreads();
    float* st = sW;
    #pragma unroll
    for (int pi = 0; pi < 2; pi++){
        int pp = p + pi*16;
        float m = sM[pp], rs = sR[pp];
        #pragma unroll
        for (int j = 0; j < 6; j++){
            int o = og*6 + j;
            st[o*33 + pp] = (acc[pi][j] - m) * rs * lng[o] + lnb[o];
        }
    }
    __syncthreads();
    for (int j = tid; j < 32*96; j += 256){
        int pp = j / 96, o = j % 96;
        g_xln[(b*LL + pix0 + pp)*CHID + o] = st[o*33 + pp];
    }
}

// ---------------- kD: in_proj 96->384 via tf32 mma.m16n8k8 ----------------
__global__ void kD(const float* __restrict__ w, const float* __restrict__ bias){
    __shared__ __align__(16) float sA[32*100];   // [p][k] tf32 bits
    __shared__ __align__(16) float sW[64*100];   // [o][k] tf32 bits
    __shared__ __align__(16) float sO[64*33];
    uint32_t* sAu = (uint32_t*)sA;
    uint32_t* sWu = (uint32_t*)sW;
    int b = blockIdx.x >> 7;
    int pix0 = (blockIdx.x & 127) * 32;
    int tid = threadIdx.x;
    int wid = tid >> 5, lane = tid & 31;
    int gid = lane >> 2, tig = lane & 3;
    int pt = wid & 1;
    int ob = (wid >> 1) * 16;

    for (int j = tid; j < 32*24; j += 256){
        int p = j / 24, cq = j % 24;
        float4 v = *(const float4*)&g_xln[(b*LL + pix0 + p)*CHID + cq*4];
        uint32_t* dst = &sAu[p*100 + cq*4];
        dst[0] = tf32(v.x); dst[1] = tf32(v.y); dst[2] = tf32(v.z); dst[3] = tf32(v.w);
    }
    int prow = pt*16 + gid;
    for (int ch = 0; ch < 6; ch++){
        __syncthreads();
        for (int j = tid; j < 64*24; j += 256){
            int o = j / 24, kq = j % 24;
            float4 v = *(const float4*)&w[(ch*64 + o)*CHID + kq*4];
            uint32_t* dst = &sWu[o*100 + kq*4];
            dst[0] = tf32(v.x); dst[1] = tf32(v.y); dst[2] = tf32(v.z); dst[3] = tf32(v.w);
        }
        __syncthreads();
        float acc[2][4];
        #pragma unroll
        for (int j = 0; j < 2; j++){
            float b0v = bias[ch*64 + ob + j*8 + 2*tig];
            float b1v = bias[ch*64 + ob + j*8 + 2*tig + 1];
            acc[j][0] = b0v; acc[j][1] = b1v; acc[j][2] = b0v; acc[j][3] = b1v;
        }
        #pragma unroll 4
        for (int s = 0; s < 12; s++){
            int k0 = s*8;
            uint32_t a0 = sAu[prow*100     + k0 + tig];
            uint32_t a1 = sAu[(prow+8)*100 + k0 + tig];
            uint32_t a2 = sAu[prow*100     + k0 + tig + 4];
            uint32_t a3 = sAu[(prow+8)*100 + k0 + tig + 4];
            #pragma unroll
            for (int j = 0; j < 2; j++){
                uint32_t b0 = sWu[(ob + j*8 + gid)*100 + k0 + tig];
                uint32_t b1 = sWu[(ob + j*8 + gid)*100 + k0 + tig + 4];
                MMA_TF32(acc[j], a0,a1,a2,a3, b0,b1);
            }
        }
        #pragma unroll
        for (int j = 0; j < 2; j++){
            int o0 = ob + j*8 + 2*tig;
            sO[o0*33 + prow]         = acc[j][0];
            sO[(o0+1)*33 + prow]     = acc[j][1];
            sO[o0*33 + prow + 8]     = acc[j][2];
            sO[(o0+1)*33 + prow + 8] = acc[j][3];
        }
        __syncthreads();
        if (ch < 3){
            for (int j = tid; j < 64*32; j += 256){
                int o = j >> 5, pp = j & 31;
                g_xc[(b*DN + ch*64 + o)*LL + pix0 + pp] = sO[o*33 + pp];
            }
        } else {
            for (int j = tid; j < 32*64; j += 256){
                int pp = j >> 6, oz = j & 63;
                g_z[(b*LL + pix0 + pp)*DN + (ch-3)*64 + oz] = sO[oz*33 + pp];
            }
        }
    }
}

// ---------------- kE: depthwise 3x3 conv + bias + silu, one block per (b,d) ---------
__global__ void kE(const float* __restrict__ cw, const float* __restrict__ cb){
    __shared__ float sT[66*66];
    int bd = blockIdx.x;
    int d  = bd % DN;
    int tid = threadIdx.x;
    const float* src = g_xc + bd*LL;
    for (int j = tid; j < 66*66; j += 256){
        int rr = j / 66, cc = j % 66;
        int r = rr - 1, c = cc - 1;
        float v = 0.f;
        if (r >= 0 && r < 64 && c >= 0 && c < 64) v = src[r*64 + c];
        sT[j] = v;
    }
    float w9[9];
    #pragma unroll
    for (int i = 0; i < 9; i++) w9[i] = cw[d*9 + i];
    float bz = cb[d];
    __syncthreads();
    float* dst = g_xcv + bd*LL;
    for (int j = tid; j < 64*64; j += 256){
        int r = j >> 6, c = j & 63;
        float s = bz;
        #pragma unroll
        for (int ky = 0; ky < 3; ky++)
            #pragma unroll
            for (int kx = 0; kx < 3; kx++)
                s = fmaf(w9[ky*3+kx], sT[(r+ky)*66 + c + kx], s);
        dst[j] = siluf(s);
    }
}

// ---------------- kX v3: gather xs, tf32 mma x_proj GEMM, dt GEMM + softplus ----------
__global__ void kX(const float* __restrict__ xpw, const float* __restrict__ dtw,
                   const float* __restrict__ dtb){
    __shared__ __align__(16) float sxs[16*196];   // floats, then tf32 bits in place
    __shared__ __align__(16) float sWk[40*100];   // [c][k_local] tf32 chunk
    __shared__ __align__(16) float sdtw[DN*6];
    __shared__ __align__(16) float sdl[16*DN];
    __shared__ __align__(16) float sdt[6*17];
    uint32_t* sxu = (uint32_t*)sxs;
    uint32_t* sWu = (uint32_t*)sWk;
    int tile = blockIdx.x & 255;
    int k    = (blockIdx.x >> 8) & 3;
    int b    = blockIdx.x >> 10;
    int t0   = tile * 16;
    int tid  = threadIdx.x;
    int wid = tid >> 5, lane = tid & 31;
    int gid = lane >> 2, tig = lane & 3;
    int base = (b*KK + k)*LL;

    for (int j = tid; j < DN*6/2; j += 256)
        ((float2*)sdtw)[j] = ((const float2*)(dtw + k*DN*6))[j];
    for (int j = tid; j < DN*16; j += 256){
        int d = j >> 4, tt = j & 15;
        int t = t0 + tt;
        int pix;
        if (k == 0)      pix = t;
        else if (k == 1) pix = (t & 63)*64 + (t >> 6);
        else if (k == 2) pix = LL - 1 - t;
        else { int tr = LL - 1 - t; pix = (tr & 63)*64 + (tr >> 6); }
        sxs[tt*196 + d] = g_xcv[(b*DN + d)*LL + pix];
    }
    __syncthreads();
    if (k < 2){
        int xbase = (b*2 + k)*LL;
        for (int j = tid; j < 16*48; j += 256){
            int tt = j / 48, dq = j % 48;
            *(float4*)&g_xs[(xbase + t0 + tt)*DN + dq*4] = *(float4*)&sxs[tt*196 + dq*4];
        }
    }
    __syncthreads();
    // convert activations to tf32 bits in place
    for (int j = tid; j < 16*DN; j += 256){
        int tt = j / 192, d = j - tt*192;
        sxu[tt*196 + d] = tf32(sxs[tt*196 + d]);
    }
    // GEMM1 via tf32 mma: N=40 (5 warps x 1 n-tile), K=192 in 2 chunks of 96
    float acc[4] = {0.f, 0.f, 0.f, 0.f};
    for (int kc = 0; kc < 2; kc++){
        __syncthreads();
        for (int j = tid; j < 40*24; j += 256){
            int c = j / 24, kq = j % 24;
            uint32_t* dst = &sWu[c*100 + kq*4];
            if (c < 38){
                float4 v = *(const float4*)&xpw[(k*38 + c)*DN + kc*96 + kq*4];
                dst[0] = tf32(v.x); dst[1] = tf32(v.y); dst[2] = tf32(v.z); dst[3] = tf32(v.w);
            } else {
                dst[0] = 0u; dst[1] = 0u; dst[2] = 0u; dst[3] = 0u;
            }
        }
        __syncthreads();
        if (wid < 5){
            #pragma unroll 4
            for (int s = 0; s < 12; s++){
                int kg = kc*96 + s*8;
                uint32_t a0 = sxu[gid*196     + kg + tig];
                uint32_t a1 = sxu[(gid+8)*196 + kg + tig];
                uint32_t a2 = sxu[gid*196     + kg + tig + 4];
                uint32_t a3 = sxu[(gid+8)*196 + kg + tig + 4];
                uint32_t b0 = sWu[(wid*8 + gid)*100 + s*8 + tig];
                uint32_t b1 = sWu[(wid*8 + gid)*100 + s*8 + tig + 4];
                MMA_TF32(acc, a0,a1,a2,a3, b0,b1);
            }
        }
    }
    __syncthreads();
    // scatter fragment outputs: rows (gid, gid+8), cols (wid*8+2*tig, +1)
    if (wid < 5){
        #pragma unroll
        for (int jj = 0; jj < 2; jj++){
            int c = wid*8 + 2*tig + jj;
            float v0 = acc[jj];       // row gid
            float v1 = acc[2 + jj];   // row gid+8
            if (c < RR){
                sdt[c*17 + gid]     = v0;
                sdt[c*17 + gid + 8] = v1;
            } else if (c < RR + NN){
                g_bs[(base + t0 + gid)*NN + (c - RR)]     = v0;
                g_bs[(base + t0 + gid + 8)*NN + (c - RR)] = v1;
            } else if (c < RR + 2*NN){
                g_cs[(base + t0 + gid)*NN + (c - RR - NN)]     = v0;
                g_cs[(base + t0 + gid + 8)*NN + (c - RR - NN)] = v1;
            }
        }
    }
    __syncthreads();
    // GEMM2: delta = softplus(dt_w @ dts + dt_b)
    {
        int tt = tid & 15, dq = tid >> 4;
        float a2[12];
        #pragma unroll
        for (int j = 0; j < 12; j++) a2[j] = dtb[k*DN + dq*12 + j];
        float dts[6];
        #pragma unroll
        for (int r = 0; r < RR; r++) dts[r] = sdt[r*17 + tt];
        #pragma unroll
        for (int j = 0; j < 12; j++){
            int d = dq*12 + j;
            float a = a2[j];
            #pragma unroll
            for (int r = 0; r < RR; r++)
                a = fmaf(dts[r], sdtw[d*6 + r], a);
            float dl = (a > 20.f) ? a : log1pf(__expf(a));
            sdl[tt*DN + dq*12 + j] = dl;
        }
    }
    __syncthreads();
    for (int j = tid; j < 16*48; j += 256){
        int tt = j / 48, dq = j % 48;
        *(float4*)&g_delta[(base + t0 + tt)*DN + dq*4] = *(float4*)&sdl[tt*DN + dq*4];
    }
}

// ---------------- kF1: per-segment P (one exp) and offset q; packed DU ----------------
__global__ void kF1(const float* __restrict__ A_log){
    __shared__ __align__(16) float sDU[16*8*2];
    __shared__ __align__(16) float sB[16*16];
    __shared__ float sSum[8];
    int bid = blockIdx.x;
    int dg = (bid % 24) * 8;
    int s  = (bid / 24) % (SEG-1);
    int k  = (bid / (24*(SEG-1))) % 4;
    int b  = bid / (24*(SEG-1)*4);
    int tid = threadIdx.x;
    int ch = tid >> 4, n = tid & 15;
    int d  = dg + ch;
    int base = (b*KK + k)*LL + s*SEGLEN;
    int xrow = (b*2 + (k & 1))*LL;
    bool rev = (k >= 2);

    float a = -__expf(A_log[(k*DN + d)*NN + n]);
    float h = 0.f;

    int lt = tid >> 3, lc = tid & 7;
    float dsum = 0.f;
    float rD, rX, rB[2];
    {
        int t_abs = s*SEGLEN + lt;
        int xr = rev ? (LL-1 - t_abs) : t_abs;
        rD = g_delta[(base + lt)*DN + dg + lc];
        rX = g_xs   [(xrow + xr)*DN + dg + lc];
    }
    #pragma unroll
    for (int i = 0; i < 2; i++){
        int jj = tid + i*128;
        rB[i] = g_bs[base*NN + jj];
    }
    for (int chunk = 0; chunk < SEGLEN/16; chunk++){
        *(float2*)&sDU[tid*2] = make_float2(rD, rD * rX);
        sB[tid] = rB[0];  sB[tid+128] = rB[1];
        dsum += rD;
        __syncthreads();
        if (chunk < SEGLEN/16 - 1){
            int t0n = (chunk + 1) * 16;
            int t_abs = s*SEGLEN + t0n + lt;
            int xr = rev ? (LL-1 - t_abs) : t_abs;
            rD = g_delta[(base + t0n + lt)*DN + dg + lc];
            rX = g_xs   [(xrow + xr)*DN + dg + lc];
            #pragma unroll
            for (int i = 0; i < 2; i++){
                int jj = tid + i*128;
                rB[i] = g_bs[(base + t0n)*NN + jj];
            }
        }
        #pragma unroll
        for (int t = 0; t < 16; t++){
            float2 du = *(float2*)&sDU[(t*8 + ch)*2];
            float Bn = sB[t*16 + n];
            float e  = __expf(du.x * a);
            h = fmaf(e, h, du.y * Bn);
        }
        __syncthreads();
    }
    sDU[lt*8 + lc] = dsum;
    __syncthreads();
    if (tid < 8){
        float S = 0.f;
        #pragma unroll
        for (int i = 0; i < 16; i++) S += sDU[i*8 + tid];
        sSum[tid] = S;
    }
    __syncthreads();
    float P = __expf(a * sSum[ch]);
    int chain = (b*KK + k)*DN + d;
    g_P[(chain*(SEG-1) + s)*NN + n] = P;
    g_q[(chain*(SEG-1) + s)*NN + n] = h;
}

// ---------------- kF2: prefix over segments -> g_h0 ----------------
__global__ void kF2(){
    int gid = blockIdx.x*blockDim.x + threadIdx.x;
    int chain = gid >> 4, n = gid & 15;
    float h = 0.f;
    g_h0[(chain*SEG + 0)*NN + n] = 0.f;
    #pragma unroll
    for (int s = 0; s < SEG-1; s++){
        float P = g_P[(chain*(SEG-1) + s)*NN + n];
        float q = g_q[(chain*(SEG-1) + s)*NN + n];
        h = fmaf(P, h, q);
        g_h0[(chain*SEG + s + 1)*NN + n] = h;
    }
}

// ---------------- kF3: packed DU/BC, smem transpose-reduce ----------------
__global__ void kF3(const float* __restrict__ A_log, const float* __restrict__ Ds){
    __shared__ __align__(16) float sDU[16*8*2];
    __shared__ __align__(16) float sBC[16*16*2];
    __shared__ __align__(16) float sP[NN*129];
    int bid = blockIdx.x;
    int dg = (bid % 24) * 8;
    int s  = (bid / 24) % SEG;
    int k  = (bid / (24*SEG)) % 4;
    int b  = bid / (24*SEG*4);
    int tid = threadIdx.x;
    int ch = tid >> 4, n = tid & 15;
    int d  = dg + ch;
    int base = (b*KK + k)*LL + s*SEGLEN;
    int chain = (b*KK + k)*DN + d;
    int xrow = (b*2 + (k & 1))*LL;
    bool rev = (k >= 2);

    float a  = -__expf(A_log[(k*DN + d)*NN + n]);
    float h  = g_h0[(chain*SEG + s)*NN + n];

    int lt = tid >> 3, lc = tid & 7;
    float Dv2 = Ds[k*DN + dg + lc];
    float rD, rX, rB[2], rC[2];
    {
        int t_abs = s*SEGLEN + lt;
        int xr = rev ? (LL-1 - t_abs) : t_abs;
        rD = g_delta[(base + lt)*DN + dg + lc];
        rX = g_xs   [(xrow + xr)*DN + dg + lc];
    }
    #pragma unroll
    for (int i = 0; i < 2; i++){
        int jj = tid + i*128;
        rB[i] = g_bs[base*NN + jj];
        rC[i] = g_cs[base*NN + jj];
    }
    for (int chunk = 0; chunk < SEGLEN/16; chunk++){
        *(float2*)&sDU[tid*2] = make_float2(rD, rD * rX);
        *(float2*)&sBC[tid*2]       = make_float2(rB[0], rC[0]);
        *(float2*)&sBC[(tid+128)*2] = make_float2(rB[1], rC[1]);
        float xCur = rX;
        __syncthreads();
        if (chunk < SEGLEN/16 - 1){
            int t0n = (chunk + 1) * 16;
            int t_abs = s*SEGLEN + t0n + lt;
            int xr = rev ? (LL-1 - t_abs) : t_abs;
            rD = g_delta[(base + t0n + lt)*DN + dg + lc];
            rX = g_xs   [(xrow + xr)*DN + dg + lc];
            #pragma unroll
            for (int i = 0; i < 2; i++){
                int jj = tid + i*128;
                rB[i] = g_bs[(base + t0n)*NN + jj];
                rC[i] = g_cs[(base + t0n)*NN + jj];
            }
        }
        #pragma unroll
        for (int t = 0; t < 16; t++){
            float2 du = *(float2*)&sDU[(t*8 + ch)*2];
            float2 bc = *(float2*)&sBC[(t*16 + n)*2];
            float e  = __expf(du.x * a);
            h = fmaf(e, h, du.y * bc.x);
            sP[n*129 + t*8 + ch] = h * bc.y;
        }
        __syncthreads();
        {
            float y = Dv2 * xCur;
            #pragma unroll
            for (int nn = 0; nn < NN; nn++)
                y += sP[nn*129 + tid];
            g_ys[(base + chunk*16 + lt)*DN + dg + lc] = y;
        }
    }
}

// ---------------- kGH: combine + LN + gate, then tf32 mma out_proj -> g_dd ----------
__global__ void kGH(const float* __restrict__ lng, const float* __restrict__ lnb,
                    const float* __restrict__ w, const float* __restrict__ bias){
    __shared__ __align__(16) float sA[32*196];
    __shared__ __align__(16) float sW[96*52];
    __shared__ __align__(16) float sS[256];
    __shared__ __align__(16) float sS2[256];
    __shared__ float sM[32], sR[32];
    uint32_t* sAu = (uint32_t*)sA;
    uint32_t* sWu = (uint32_t*)sW;
    int b = blockIdx.x >> 7;
    int pix0 = (blockIdx.x & 127) * 32;
    int tid = threadIdx.x;
    int tp = tid >> 3, tc = tid & 7;
    int l  = pix0 + tp;
    int hh = l >> 6, ww = l & 63;
    int t1 = ww*64 + hh;
    int b4 = b*KK*LL;
    const float* r0 = &g_ys[(b4 + l)*DN];
    const float* r1 = &g_ys[(b4 + 1*LL + t1)*DN];
    const float* r2 = &g_ys[(b4 + 2*LL + (LL-1-l))*DN];
    const float* r3 = &g_ys[(b4 + 3*LL + (LL-1-t1))*DN];
    float vloc[24];
    float s = 0.f, s2 = 0.f;
    #pragma unroll
    for (int jq = 0; jq < 6; jq++){
        int c = tc*24 + jq*4;
        float4 a0 = *(const float4*)&r0[c];
        float4 a1 = *(const float4*)&r1[c];
        float4 a2 = *(const float4*)&r2[c];
        float4 a3 = *(const float4*)&r3[c];
        float v0 = a0.x + a1.x + a2.x + a3.x;
        float v1 = a0.y + a1.y + a2.y + a3.y;
        float v2 = a0.z + a1.z + a2.z + a3.z;
        float v3 = a0.w + a1.w + a2.w + a3.w;
        vloc[jq*4+0] = v0; vloc[jq*4+1] = v1; vloc[jq*4+2] = v2; vloc[jq*4+3] = v3;
        s  += v0 + v1 + v2 + v3;
        s2 += v0*v0 + v1*v1 + v2*v2 + v3*v3;
    }
    sS[tid] = s;  sS2[tid] = s2;
    __syncthreads();
    if (tid < 32){
        float ss = 0.f, ss2 = 0.f;
        #pragma unroll
        for (int i = 0; i < 8; i++){ ss += sS[tid*8+i]; ss2 += sS2[tid*8+i]; }
        float m = ss * (1.f/192.f);
        float var = ss2 * (1.f/192.f) - m*m;
        sM[tid] = m;  sR[tid] = rsqrtf(var + 1e-5f);
    }
    __syncthreads();
    {
        float m = sM[tp], rs = sR[tp];
        const float* zrow = &g_z[(b*LL + l)*DN];
        #pragma unroll
        for (int jq = 0; jq < 6; jq++){
            int c = tc*24 + jq*4;
            float4 zv = *(const float4*)&zrow[c];
            float4 gv = *(const float4*)&lng[c];
            float4 bv = *(const float4*)&lnb[c];
            sAu[tp*196 + c + 0] = tf32(((vloc[jq*4+0]-m)*rs*gv.x + bv.x) * siluf(zv.x));
            sAu[tp*196 + c + 1] = tf32(((vloc[jq*4+1]-m)*rs*gv.y + bv.y) * siluf(zv.y));
            sAu[tp*196 + c + 2] = tf32(((vloc[jq*4+2]-m)*rs*gv.z + bv.z) * siluf(zv.z));
            sAu[tp*196 + c + 3] = tf32(((vloc[jq*4+3]-m)*rs*gv.w + bv.w) * siluf(zv.w));
        }
    }
    int wid = tid >> 5, lane = tid & 31;
    int gid = lane >> 2, tig = lane & 3;
    int pt = wid & 1;
    int ob = (wid >> 1) * 24;
    int prow = pt*16 + gid;
    float acc[3][4];
    #pragma unroll
    for (int j = 0; j < 3; j++){
        float b0v = bias[ob + j*8 + 2*tig];
        float b1v = bias[ob + j*8 + 2*tig + 1];
        acc[j][0] = b0v; acc[j][1] = b1v; acc[j][2] = b0v; acc[j][3] = b1v;
    }
    for (int kc = 0; kc < 4; kc++){
        __syncthreads();
        for (int j = tid; j < 96*12; j += 256){
            int o = j / 12, kq = j % 12;
            float4 v = *(const float4*)&w[o*DN + kc*48 + kq*4];
            uint32_t* dst = &sWu[o*52 + kq*4];
            dst[0] = tf32(v.x); dst[1] = tf32(v.y); dst[2] = tf32(v.z); dst[3] = tf32(v.w);
        }
        __syncthreads();
        #pragma unroll
        for (int sgl = 0; sgl < 6; sgl++){
            int kg = kc*48 + sgl*8;
            uint32_t a0 = sAu[prow*196     + kg + tig];
            uint32_t a1 = sAu[(prow+8)*196 + kg + tig];
            uint32_t a2 = sAu[prow*196     + kg + tig + 4];
            uint32_t a3 = sAu[(prow+8)*196 + kg + tig + 4];
            int kl = sgl*8;
            #pragma unroll
            for (int j = 0; j < 3; j++){
                uint32_t b0 = sWu[(ob + j*8 + gid)*52 + kl + tig];
                uint32_t b1 = sWu[(ob + j*8 + gid)*52 + kl + tig + 4];
                MMA_TF32(acc[j], a0,a1,a2,a3, b0,b1);
            }
        }
    }
    __syncthreads();
    float* st = sW;
    #pragma unroll
    for (int j = 0; j < 3; j++){
        int o0 = ob + j*8 + 2*tig;
        st[o0*33 + prow]         = acc[j][0];
        st[(o0+1)*33 + prow]     = acc[j][1];
        st[o0*33 + prow + 8]     = acc[j][2];
        st[(o0+1)*33 + prow + 8] = acc[j][3];
    }
    __syncthreads();
    for (int j = tid; j < 32*96; j += 256){
        int pp = j / 96, o = j % 96;
        g_dd[(b*LL + pix0 + pp)*CHID + o] = st[o*33 + pp];
    }
}

// ---------------- kI: up-proj via tf32 mma + bn + silu + residual + gate ------------
__global__ void kI(const float* __restrict__ w, const float* __restrict__ bias,
                   const float* __restrict__ bng, const float* __restrict__ bnb,
                   float* __restrict__ out){
    __shared__ __align__(16) float sA[32*100];
    __shared__ __align__(16) float sW[64*100];
    __shared__ __align__(16) float sO[64*33];
    uint32_t* sAu = (uint32_t*)sA;
    uint32_t* sWu = (uint32_t*)sW;
    int b = blockIdx.x >> 7;
    int pix0 = (blockIdx.x & 127) * 32;
    int tid = threadIdx.x;
    int wid = tid >> 5, lane = tid & 31;
    int gid = lane >> 2, tig = lane & 3;
    int pt = wid & 1;
    int ob = (wid >> 1) * 16;
    int prow = pt*16 + gid;

    for (int j = tid; j < 32*24; j += 256){
        int p = j / 24, cq = j % 24;
        float4 v = *(const float4*)&g_dd[(b*LL + pix0 + p)*CHID + cq*4];
        uint32_t* dst = &sAu[p*100 + cq*4];
        dst[0] = tf32(v.x); dst[1] = tf32(v.y); dst[2] = tf32(v.z); dst[3] = tf32(v.w);
    }
    for (int j = tid; j < 64*24; j += 256){
        int o = j / 24, kq = j % 24;
        float4 v = *(const float4*)&w[o*CHID + kq*4];
        uint32_t* dst = &sWu[o*100 + kq*4];
        dst[0] = tf32(v.x); dst[1] = tf32(v.y); dst[2] = tf32(v.z); dst[3] = tf32(v.w);
    }
    __syncthreads();
    float acc[2][4];
    #pragma unroll
    for (int j = 0; j < 2; j++){
        float b0v = bias[ob + j*8 + 2*tig];
        float b1v = bias[ob + j*8 + 2*tig + 1];
        acc[j][0] = b0v; acc[j][1] = b1v; acc[j][2] = b0v; acc[j][3] = b1v;
    }
    #pragma unroll 4
    for (int s = 0; s < 12; s++){
        int k0 = s*8;
        uint32_t a0 = sAu[prow*100     + k0 + tig];
        uint32_t a1 = sAu[(prow+8)*100 + k0 + tig];
        uint32_t a2 = sAu[prow*100     + k0 + tig + 4];
        uint32_t a3 = sAu[(prow+8)*100 + k0 + tig + 4];
        #pragma unroll
        for (int j = 0; j < 2; j++){
            uint32_t b0 = sWu[(ob + j*8 + gid)*100 + k0 + tig];
            uint32_t b1 = sWu[(ob + j*8 + gid)*100 + k0 + tig + 4];
            MMA_TF32(acc[j], a0,a1,a2,a3, b0,b1);
        }
    }
    #pragma unroll
    for (int j = 0; j < 2; j++){
        int o0 = ob + j*8 + 2*tig;
        float inv0 = bng[o0]   * rsqrtf(1.00001f);
        float inv1 = bng[o0+1] * rsqrtf(1.00001f);
        float bb0 = bnb[o0], bb1 = bnb[o0+1];
        sO[o0*33 + prow]         = siluf(acc[j][0]*inv0 + bb0);
        sO[(o0+1)*33 + prow]     = siluf(acc[j][1]*inv1 + bb1);
        sO[o0*33 + prow + 8]     = siluf(acc[j][2]*inv0 + bb0);
        sO[(o0+1)*33 + prow + 8] = siluf(acc[j][3]*inv1 + bb1);
    }
    __syncthreads();
    for (int j = tid; j < 64*32; j += 256){
        int o = j >> 5, pp = j & 31;
        int idx = (b*CIN + o)*LL + pix0 + pp;
        out[idx] = (sO[o*33 + pp] + g_diff[idx]) * g_gate[idx];
    }
}

// ---------------- launcher ----------------
extern "C" void kernel_launch(void* const* d_in, const int* in_sizes, int n_in,
                              void* d_out, int out_size){
    const float* pre        = (const float*)d_in[0];
    const float* post       = (const float*)d_in[1];
    const float* prepost_w  = (const float*)d_in[2];
    const float* prepost_b  = (const float*)d_in[3];
    const float* prepost_g  = (const float*)d_in[4];
    const float* prepost_bb = (const float*)d_in[5];
    const float* down_w     = (const float*)d_in[6];
    const float* down_b     = (const float*)d_in[7];
    const float* down_g     = (const float*)d_in[8];
    const float* down_bb    = (const float*)d_in[9];
    const float* up_w       = (const float*)d_in[10];
    const float* up_b       = (const float*)d_in[11];
    const float* up_g       = (const float*)d_in[12];
    const float* up_bb      = (const float*)d_in[13];
    const float* pe_w       = (const float*)d_in[14];
    const float* pe_b       = (const float*)d_in[15];
    const float* pe_ln_g    = (const float*)d_in[16];
    const float* pe_ln_b    = (const float*)d_in[17];
    const float* in_proj_w  = (const float*)d_in[18];
    const float* in_proj_b  = (const float*)d_in[19];
    const float* conv_w     = (const float*)d_in[20];
    const float* conv_b     = (const float*)d_in[21];
    const float* x_proj_w   = (const float*)d_in[22];
    const float* dt_w       = (const float*)d_in[23];
    const float* dt_b       = (const float*)d_in[24];
    const float* A_log      = (const float*)d_in[25];
    const float* Ds         = (const float*)d_in[26];
    const float* out_ln_g   = (const float*)d_in[27];
    const float* out_ln_b   = (const float*)d_in[28];
    const float* out_proj_w = (const float*)d_in[29];
    const float* out_proj_b = (const float*)d_in[30];
    float* out = (float*)d_out;

    kGate2<<<BB*(LL/32), 256>>>(pre, post, prepost_w, prepost_b, prepost_g, prepost_bb);
    kB<<<BB*(LL/32), 256>>>(down_w, down_b, down_g, down_bb);
    kC<<<BB*(LL/32), 256>>>(pe_w, pe_b, pe_ln_g, pe_ln_b);
    kD<<<BB*(LL/32), 256>>>(in_proj_w, in_proj_b);
    kE<<<BB*DN, 256>>>(conv_w, conv_b);
    kX<<<BB*KK*(LL/16), 256>>>(x_proj_w, dt_w, dt_b);
    kF1<<<BB*KK*(SEG-1)*(DN/8), 128>>>(A_log);
    kF2<<<(BB*KK*DN*NN)/256, 256>>>();
    kF3<<<BB*KK*SEG*(DN/8), 128>>>(A_log, Ds);
    kGH<<<BB*(LL/32), 256>>>(out_ln_g, out_ln_b, out_proj_w, out_proj_b);
    kI<<<BB*(LL/32), 256>>>(up_w, up_b, up_g, up_bb, out);
}

// round 15
// speedup vs baseline: 1.6545x; 1.1359x over previous
#include <cuda_runtime.h>
#include <math.h>
#include <stdint.h>

#define BB 4
#define CIN 64
#define CHID 96
#define LL 4096
#define NN 16
#define RR 6
#define KK 4
#define DN 192
#define SEG 4
#define SEGLEN 1024

// ---------------- static scratch (no allocation anywhere) ----------------
__device__ float g_diff [BB*CIN*LL];
__device__ float g_gate [BB*CIN*LL];
__device__ float g_d1   [BB*LL*CHID];
__device__ float g_xc   [BB*DN*LL];
__device__ float g_xcv  [BB*DN*LL];
__device__ float g_z    [BB*LL*DN];
__device__ float g_xs   [BB*2*LL*DN];     // only k=0,1 stored; k=2,3 are flips
__device__ float g_delta[BB*KK*LL*DN];
__device__ float g_bs   [BB*KK*LL*NN];
__device__ float g_cs   [BB*KK*LL*NN];
__device__ float g_ys   [BB*KK*LL*DN];
__device__ float g_dd   [BB*LL*CHID];
__device__ float g_P [BB*KK*DN*(SEG-1)*NN];
__device__ float g_q [BB*KK*DN*(SEG-1)*NN];
__device__ float g_h0[BB*KK*DN*SEG*NN];

#define LOG2E 1.44269504f

__device__ __forceinline__ float sigm(float x){ return 1.f/(1.f+__expf(-x)); }
__device__ __forceinline__ float siluf(float x){ return x*sigm(x); }
__device__ __forceinline__ float dot4(float4 a, float4 w, float acc){
    acc = fmaf(a.x, w.x, acc);
    acc = fmaf(a.y, w.y, acc);
    acc = fmaf(a.z, w.z, acc);
    acc = fmaf(a.w, w.w, acc);
    return acc;
}
__device__ __forceinline__ uint32_t tf32(float x){
    uint32_t r; asm("cvt.rna.tf32.f32 %0, %1;" : "=r"(r) : "f"(x)); return r;
}
#define MMA_TF32(acc, a0,a1,a2,a3, b0,b1) \
    asm volatile( \
        "mma.sync.aligned.m16n8k8.row.col.f32.tf32.tf32.f32 " \
        "{%0,%1,%2,%3},{%4,%5,%6,%7},{%8,%9},{%0,%1,%2,%3};" \
        : "+f"(acc[0]), "+f"(acc[1]), "+f"(acc[2]), "+f"(acc[3]) \
        : "r"(a0), "r"(a1), "r"(a2), "r"(a3), "r"(b0), "r"(b1))

// ---------------- kGB: fused gate (prepost x2) + diff + down-proj ----------------
// 256 thr, 32 pixels. Phase 1: gate GEMM; phase 2: sP := |Q-P|, down GEMM.
__global__ void kGB(const float* __restrict__ pre, const float* __restrict__ post,
                    const float* __restrict__ w, const float* __restrict__ bias,
                    const float* __restrict__ bng, const float* __restrict__ bnb,
                    const float* __restrict__ dw, const float* __restrict__ dbias,
                    const float* __restrict__ dbng, const float* __restrict__ dbnb){
    __shared__ __align__(16) float sP[CIN*32];      // 8KB
    __shared__ __align__(16) float sQ[CIN*32];      // 8KB
    __shared__ __align__(16) float sW[CHID*CIN];    // 24KB (gate uses first 16KB)
    __shared__ __align__(16) float sO[CIN*32];      // 8KB
    int b = blockIdx.x >> 7;
    int pix0 = (blockIdx.x & 127) * 32;
    int tid = threadIdx.x;
    for (int j = tid; j < CIN*CIN/4; j += 256)
        ((float4*)sW)[j] = ((const float4*)w)[j];
    for (int j = tid; j < CIN*32; j += 256){
        int c = j >> 5, p = j & 31;
        int idx = (b*CIN + c)*LL + pix0 + p;
        float pv = pre[idx], qv = post[idx];
        sP[j] = pv;
        sQ[j] = qv;
        g_diff[idx] = fabsf(qv - pv);
    }
    __syncthreads();
    int p = tid & 31, og = tid >> 5;
    // phase 1: gate GEMM (8 outputs per thread for both pre/post)
    {
        float a1[8], a2[8];
        #pragma unroll
        for (int j = 0; j < 8; j++){ a1[j] = 0.f; a2[j] = 0.f; }
        for (int kq = 0; kq < 16; kq++){
            float x1[4], x2[4];
            #pragma unroll
            for (int i = 0; i < 4; i++){
                x1[i] = sP[(kq*4+i)*32 + p];
                x2[i] = sQ[(kq*4+i)*32 + p];
            }
            #pragma unroll
            for (int j = 0; j < 8; j++){
                float4 wv = *(float4*)&sW[(og*8+j)*CIN + kq*4];
                a1[j] = fmaf(x1[0],wv.x, fmaf(x1[1],wv.y, fmaf(x1[2],wv.z, fmaf(x1[3],wv.w, a1[j]))));
                a2[j] = fmaf(x2[0],wv.x, fmaf(x2[1],wv.y, fmaf(x2[2],wv.z, fmaf(x2[3],wv.w, a2[j]))));
            }
        }
        #pragma unroll
        for (int j = 0; j < 8; j++){
            int o = og*8 + j;
            float inv = bng[o] * rsqrtf(1.00001f);
            float bz  = bias[o];
            float bb  = bnb[o];
            float t1 = (a1[j] + bz) * inv + bb;
            float t2 = (a2[j] + bz) * inv + bb;
            sO[o*32 + p] = sigm(siluf(t1)) * sigm(siluf(t2));
        }
    }
    __syncthreads();   // gate GEMM done: sP/sW safe to overwrite, sO complete
    // write gate, rewrite sP := |Q - P|, load down weights
    for (int j = tid; j < CIN*32; j += 256){
        int o = j >> 5, pp = j & 31;
        g_gate[(b*CIN + o)*LL + pix0 + pp] = sO[j];
        sP[j] = fabsf(sQ[j] - sP[j]);
    }
    for (int j = tid; j < CHID*CIN/4; j += 256)
        ((float4*)sW)[j] = ((const float4*)dw)[j];
    __syncthreads();
    // phase 2: down GEMM (12 outputs per thread)
    {
        float acc[12];
        #pragma unroll
        for (int j = 0; j < 12; j++) acc[j] = 0.f;
        for (int kq = 0; kq < 16; kq++){
            float x[4];
            #pragma unroll
            for (int i = 0; i < 4; i++) x[i] = sP[(kq*4+i)*32 + p];
            #pragma unroll
            for (int j = 0; j < 12; j++){
                float4 wv = *(float4*)&sW[(og*12+j)*CIN + kq*4];
                acc[j] = fmaf(x[0],wv.x, fmaf(x[1],wv.y, fmaf(x[2],wv.z, fmaf(x[3],wv.w, acc[j]))));
            }
        }
        float res[12];
        #pragma unroll
        for (int j = 0; j < 12; j++){
            int o = og*12 + j;
            float inv = dbng[o] * rsqrtf(1.00001f);
            float t = (acc[j] + dbias[o]) * inv + dbnb[o];
            res[j] = siluf(t);
        }
        float4* dst = (float4*)&g_d1[(b*LL + pix0 + p)*CHID + og*12];
        #pragma unroll
        for (int v = 0; v < 3; v++)
            dst[v] = make_float4(res[v*4], res[v*4+1], res[v*4+2], res[v*4+3]);
    }
}

// ---------------- kCD: fused LN(pe(d1)) + in_proj tf32 mma ----------------
// smem union buffer: sA[3200] | sW[6400] | sO[2112 (aliases sS/sS2/sM/sR)]
__global__ void kCD(const float* __restrict__ w, const float* __restrict__ bias,
                    const float* __restrict__ lng, const float* __restrict__ lnb,
                    const float* __restrict__ iw, const float* __restrict__ ibias){
    __shared__ __align__(16) float sMem[3200 + 6400 + 2112];
    float* sA = sMem;              // [p][k] pad 100: d1 floats, then xln tf32 bits
    float* sW = sMem + 3200;       // kC weights [o][48] chunks / kD weights tf32 [o][100]
    float* sO = sMem + 9600;       // kD output stage [o][33]; aliases LN reduce arrays
    float* sS  = sO;               // 512
    float* sS2 = sO + 512;         // 512
    float* sM  = sO + 1024;        // 32
    float* sR  = sO + 1056;        // 32
    uint32_t* sAu = (uint32_t*)sA;
    uint32_t* sWu = (uint32_t*)sW;
    int b = blockIdx.x >> 7;
    int pix0 = (blockIdx.x & 127) * 32;
    int tid = threadIdx.x;
    for (int j = tid; j < 32*24; j += 256){
        int p = j / 24, cq = j % 24;
        *(float4*)&sA[p*100 + cq*4] = *(const float4*)&g_d1[(b*LL + pix0 + p)*CHID + cq*4];
    }
    // ---- kC part: pe GEMM + LN ----
    int p = tid & 15, og = tid >> 4;
    float accC[2][6];
    #pragma unroll
    for (int j = 0; j < 6; j++){ accC[0][j] = bias[og*6+j]; accC[1][j] = accC[0][j]; }
    for (int kc = 0; kc < 2; kc++){
        __syncthreads();
        for (int j = tid; j < 96*12; j += 256){
            int o = j / 12, kq = j % 12;
            *(float4*)&sW[o*48 + kq*4] = *(const float4*)&w[o*CHID + kc*48 + kq*4];
        }
        __syncthreads();
        #pragma unroll 4
        for (int kq = 0; kq < 12; kq++){
            float4 a0 = *(float4*)&sA[p*100 + kc*48 + kq*4];
            float4 a1 = *(float4*)&sA[(p+16)*100 + kc*48 + kq*4];
            #pragma unroll
            for (int j = 0; j < 6; j++){
                float4 wv = *(float4*)&sW[(og*6+j)*48 + kq*4];
                accC[0][j] = dot4(a0, wv, accC[0][j]);
                accC[1][j] = dot4(a1, wv, accC[1][j]);
            }
        }
    }
    #pragma unroll
    for (int pi = 0; pi < 2; pi++){
        float s = 0.f, s2 = 0.f;
        #pragma unroll
        for (int j = 0; j < 6; j++){ s += accC[pi][j]; s2 += accC[pi][j]*accC[pi][j]; }
        sS [(p + pi*16)*16 + og] = s;
        sS2[(p + pi*16)*16 + og] = s2;
    }
    __syncthreads();
    if (tid < 32){
        float ss = 0.f, ss2 = 0.f;
        #pragma unroll
        for (int i = 0; i < 16; i++){ ss += sS[tid*16+i]; ss2 += sS2[tid*16+i]; }
        float m = ss * (1.f/96.f);
        float var = ss2 * (1.f/96.f) - m*m;
        sM[tid] = m;  sR[tid] = rsqrtf(var + 1e-5f);
    }
    __syncthreads();   // also guarantees all GEMM reads of sA(d1) complete
    // apply LN, write xln as tf32 bits into sA
    #pragma unroll
    for (int pi = 0; pi < 2; pi++){
        int pp = p + pi*16;
        float m = sM[pp], rs = sR[pp];
        #pragma unroll
        for (int j = 0; j < 6; j++){
            int o = og*6 + j;
            sAu[pp*100 + o] = tf32((accC[pi][j] - m) * rs * lng[o] + lnb[o]);
        }
    }
    // ---- kD part: in_proj via tf32 mma, 6 o-chunks ----
    int wid = tid >> 5, lane = tid & 31;
    int gid = lane >> 2, tig = lane & 3;
    int pt = wid & 1;
    int ob = (wid >> 1) * 16;
    int prow = pt*16 + gid;
    for (int ch = 0; ch < 6; ch++){
        __syncthreads();
        for (int j = tid; j < 64*24; j += 256){
            int o = j / 24, kq = j % 24;
            float4 v = *(const float4*)&iw[(ch*64 + o)*CHID + kq*4];
            uint32_t* dst = &sWu[o*100 + kq*4];
            dst[0] = tf32(v.x); dst[1] = tf32(v.y); dst[2] = tf32(v.z); dst[3] = tf32(v.w);
        }
        __syncthreads();
        float acc[2][4];
        #pragma unroll
        for (int j = 0; j < 2; j++){
            float b0v = ibias[ch*64 + ob + j*8 + 2*tig];
            float b1v = ibias[ch*64 + ob + j*8 + 2*tig + 1];
            acc[j][0] = b0v; acc[j][1] = b1v; acc[j][2] = b0v; acc[j][3] = b1v;
        }
        #pragma unroll 4
        for (int s = 0; s < 12; s++){
            int k0 = s*8;
            uint32_t a0 = sAu[prow*100     + k0 + tig];
            uint32_t a1 = sAu[(prow+8)*100 + k0 + tig];
            uint32_t a2 = sAu[prow*100     + k0 + tig + 4];
            uint32_t a3 = sAu[(prow+8)*100 + k0 + tig + 4];
            #pragma unroll
            for (int j = 0; j < 2; j++){
                uint32_t b0 = sWu[(ob + j*8 + gid)*100 + k0 + tig];
                uint32_t b1 = sWu[(ob + j*8 + gid)*100 + k0 + tig + 4];
                MMA_TF32(acc[j], a0,a1,a2,a3, b0,b1);
            }
        }
        #pragma unroll
        for (int j = 0; j < 2; j++){
            int o0 = ob + j*8 + 2*tig;
            sO[o0*33 + prow]         = acc[j][0];
            sO[(o0+1)*33 + prow]     = acc[j][1];
            sO[o0*33 + prow + 8]     = acc[j][2];
            sO[(o0+1)*33 + prow + 8] = acc[j][3];
        }
        __syncthreads();
        if (ch < 3){
            for (int j = tid; j < 64*32; j += 256){
                int o = j >> 5, pp = j & 31;
                g_xc[(b*DN + ch*64 + o)*LL + pix0 + pp] = sO[o*33 + pp];
            }
        } else {
            for (int j = tid; j < 32*64; j += 256){
                int pp = j >> 6, oz = j & 63;
                g_z[(b*LL + pix0 + pp)*DN + (ch-3)*64 + oz] = sO[oz*33 + pp];
            }
        }
    }
}

// ---------------- kE: depthwise 3x3 conv + bias + silu, one block per (b,d) ---------
__global__ void kE(const float* __restrict__ cw, const float* __restrict__ cb){
    __shared__ float sT[66*66];
    int bd = blockIdx.x;
    int d  = bd % DN;
    int tid = threadIdx.x;
    const float* src = g_xc + bd*LL;
    for (int j = tid; j < 66*66; j += 256){
        int rr = j / 66, cc = j % 66;
        int r = rr - 1, c = cc - 1;
        float v = 0.f;
        if (r >= 0 && r < 64 && c >= 0 && c < 64) v = src[r*64 + c];
        sT[j] = v;
    }
    float w9[9];
    #pragma unroll
    for (int i = 0; i < 9; i++) w9[i] = cw[d*9 + i];
    float bz = cb[d];
    __syncthreads();
    float* dst = g_xcv + bd*LL;
    for (int j = tid; j < 64*64; j += 256){
        int r = j >> 6, c = j & 63;
        float s = bz;
        #pragma unroll
        for (int ky = 0; ky < 3; ky++)
            #pragma unroll
            for (int kx = 0; kx < 3; kx++)
                s = fmaf(w9[ky*3+kx], sT[(r+ky)*66 + c + kx], s);
        dst[j] = siluf(s);
    }
}

// ---------------- kX: gather xs, tf32 mma x_proj GEMM, dt GEMM + softplus ----------
__global__ void kX(const float* __restrict__ xpw, const float* __restrict__ dtw,
                   const float* __restrict__ dtb){
    __shared__ __align__(16) float sxs[16*196];
    __shared__ __align__(16) float sWk[40*100];
    __shared__ __align__(16) float sdtw[DN*6];
    __shared__ __align__(16) float sdl[16*DN];
    __shared__ __align__(16) float sdt[6*17];
    uint32_t* sxu = (uint32_t*)sxs;
    uint32_t* sWu = (uint32_t*)sWk;
    int tile = blockIdx.x & 255;
    int k    = (blockIdx.x >> 8) & 3;
    int b    = blockIdx.x >> 10;
    int t0   = tile * 16;
    int tid  = threadIdx.x;
    int wid = tid >> 5, lane = tid & 31;
    int gid = lane >> 2, tig = lane & 3;
    int base = (b*KK + k)*LL;

    for (int j = tid; j < DN*6/2; j += 256)
        ((float2*)sdtw)[j] = ((const float2*)(dtw + k*DN*6))[j];
    for (int j = tid; j < DN*16; j += 256){
        int d = j >> 4, tt = j & 15;
        int t = t0 + tt;
        int pix;
        if (k == 0)      pix = t;
        else if (k == 1) pix = (t & 63)*64 + (t >> 6);
        else if (k == 2) pix = LL - 1 - t;
        else { int tr = LL - 1 - t; pix = (tr & 63)*64 + (tr >> 6); }
        sxs[tt*196 + d] = g_xcv[(b*DN + d)*LL + pix];
    }
    __syncthreads();
    if (k < 2){
        int xbase = (b*2 + k)*LL;
        for (int j = tid; j < 16*48; j += 256){
            int tt = j / 48, dq = j % 48;
            *(float4*)&g_xs[(xbase + t0 + tt)*DN + dq*4] = *(float4*)&sxs[tt*196 + dq*4];
        }
    }
    __syncthreads();
    for (int j = tid; j < 16*DN; j += 256){
        int tt = j / 192, d = j - tt*192;
        sxu[tt*196 + d] = tf32(sxs[tt*196 + d]);
    }
    float acc[4] = {0.f, 0.f, 0.f, 0.f};
    for (int kc = 0; kc < 2; kc++){
        __syncthreads();
        for (int j = tid; j < 40*24; j += 256){
            int c = j / 24, kq = j % 24;
            uint32_t* dst = &sWu[c*100 + kq*4];
            if (c < 38){
                float4 v = *(const float4*)&xpw[(k*38 + c)*DN + kc*96 + kq*4];
                dst[0] = tf32(v.x); dst[1] = tf32(v.y); dst[2] = tf32(v.z); dst[3] = tf32(v.w);
            } else {
                dst[0] = 0u; dst[1] = 0u; dst[2] = 0u; dst[3] = 0u;
            }
        }
        __syncthreads();
        if (wid < 5){
            #pragma unroll 4
            for (int s = 0; s < 12; s++){
                int kg = kc*96 + s*8;
                uint32_t a0 = sxu[gid*196     + kg + tig];
                uint32_t a1 = sxu[(gid+8)*196 + kg + tig];
                uint32_t a2 = sxu[gid*196     + kg + tig + 4];
                uint32_t a3 = sxu[(gid+8)*196 + kg + tig + 4];
                uint32_t b0 = sWu[(wid*8 + gid)*100 + s*8 + tig];
                uint32_t b1 = sWu[(wid*8 + gid)*100 + s*8 + tig + 4];
                MMA_TF32(acc, a0,a1,a2,a3, b0,b1);
            }
        }
    }
    __syncthreads();
    if (wid < 5){
        #pragma unroll
        for (int jj = 0; jj < 2; jj++){
            int c = wid*8 + 2*tig + jj;
            float v0 = acc[jj];
            float v1 = acc[2 + jj];
            if (c < RR){
                sdt[c*17 + gid]     = v0;
                sdt[c*17 + gid + 8] = v1;
            } else if (c < RR + NN){
                g_bs[(base + t0 + gid)*NN + (c - RR)]     = v0;
                g_bs[(base + t0 + gid + 8)*NN + (c - RR)] = v1;
            } else if (c < RR + 2*NN){
                g_cs[(base + t0 + gid)*NN + (c - RR - NN)]     = v0;
                g_cs[(base + t0 + gid + 8)*NN + (c - RR - NN)] = v1;
            }
        }
    }
    __syncthreads();
    {
        int tt = tid & 15, dq = tid >> 4;
        float a2[12];
        #pragma unroll
        for (int j = 0; j < 12; j++) a2[j] = dtb[k*DN + dq*12 + j];
        float dts[6];
        #pragma unroll
        for (int r = 0; r < RR; r++) dts[r] = sdt[r*17 + tt];
        #pragma unroll
        for (int j = 0; j < 12; j++){
            int d = dq*12 + j;
            float a = a2[j];
            #pragma unroll
            for (int r = 0; r < RR; r++)
                a = fmaf(dts[r], sdtw[d*6 + r], a);
            float dl = (a > 20.f) ? a : log1pf(__expf(a));
            sdl[tt*DN + dq*12 + j] = dl;
        }
    }
    __syncthreads();
    for (int j = tid; j < 16*48; j += 256){
        int tt = j / 48, dq = j % 48;
        *(float4*)&g_delta[(base + t0 + tt)*DN + dq*4] = *(float4*)&sdl[tt*DN + dq*4];
    }
}

// ---------------- kF1: per-segment P (one exp) and offset q; packed DU ----------------
__global__ void kF1(const float* __restrict__ A_log){
    __shared__ __align__(16) float sDU[16*8*2];
    __shared__ __align__(16) float sB[16*16];
    __shared__ float sSum[8];
    int bid = blockIdx.x;
    int dg = (bid % 24) * 8;
    int s  = (bid / 24) % (SEG-1);
    int k  = (bid / (24*(SEG-1))) % 4;
    int b  = bid / (24*(SEG-1)*4);
    int tid = threadIdx.x;
    int ch = tid >> 4, n = tid & 15;
    int d  = dg + ch;
    int base = (b*KK + k)*LL + s*SEGLEN;
    int xrow = (b*2 + (k & 1))*LL;
    bool rev = (k >= 2);

    float a = -__expf(A_log[(k*DN + d)*NN + n]) * LOG2E;
    float h = 0.f;

    int lt = tid >> 3, lc = tid & 7;
    float dsum = 0.f;
    float rD, rX, rB[2];
    {
        int t_abs = s*SEGLEN + lt;
        int xr = rev ? (LL-1 - t_abs) : t_abs;
        rD = g_delta[(base + lt)*DN + dg + lc];
        rX = g_xs   [(xrow + xr)*DN + dg + lc];
    }
    #pragma unroll
    for (int i = 0; i < 2; i++){
        int jj = tid + i*128;
        rB[i] = g_bs[base*NN + jj];
    }
    for (int chunk = 0; chunk < SEGLEN/16; chunk++){
        *(float2*)&sDU[tid*2] = make_float2(rD, rD * rX);
        sB[tid] = rB[0];  sB[tid+128] = rB[1];
        dsum += rD;
        __syncthreads();
        if (chunk < SEGLEN/16 - 1){
            int t0n = (chunk + 1) * 16;
            int t_abs = s*SEGLEN + t0n + lt;
            int xr = rev ? (LL-1 - t_abs) : t_abs;
            rD = g_delta[(base + t0n + lt)*DN + dg + lc];
            rX = g_xs   [(xrow + xr)*DN + dg + lc];
            #pragma unroll
            for (int i = 0; i < 2; i++){
                int jj = tid + i*128;
                rB[i] = g_bs[(base + t0n)*NN + jj];
            }
        }
        #pragma unroll
        for (int t = 0; t < 16; t++){
            float2 du = *(float2*)&sDU[(t*8 + ch)*2];
            float Bn = sB[t*16 + n];
            float e  = exp2f(du.x * a);
            h = fmaf(e, h, du.y * Bn);
        }
        __syncthreads();
    }
    sDU[lt*8 + lc] = dsum;
    __syncthreads();
    if (tid < 8){
        float S = 0.f;
        #pragma unroll
        for (int i = 0; i < 16; i++) S += sDU[i*8 + tid];
        sSum[tid] = S;
    }
    __syncthreads();
    float P = exp2f(a * sSum[ch]);
    int chain = (b*KK + k)*DN + d;
    g_P[(chain*(SEG-1) + s)*NN + n] = P;
    g_q[(chain*(SEG-1) + s)*NN + n] = h;
}

// ---------------- kF2: prefix over segments -> g_h0 ----------------
__global__ void kF2(){
    int gid = blockIdx.x*blockDim.x + threadIdx.x;
    int chain = gid >> 4, n = gid & 15;
    float h = 0.f;
    g_h0[(chain*SEG + 0)*NN + n] = 0.f;
    #pragma unroll
    for (int s = 0; s < SEG-1; s++){
        float P = g_P[(chain*(SEG-1) + s)*NN + n];
        float q = g_q[(chain*(SEG-1) + s)*NN + n];
        h = fmaf(P, h, q);
        g_h0[(chain*SEG + s + 1)*NN + n] = h;
    }
}

// ---------------- kF3: packed DU/BC, smem transpose-reduce ----------------
__global__ void kF3(const float* __restrict__ A_log, const float* __restrict__ Ds){
    __shared__ __align__(16) float sDU[16*8*2];
    __shared__ __align__(16) float sBC[16*16*2];
    __shared__ __align__(16) float sP[NN*129];
    int bid = blockIdx.x;
    int dg = (bid % 24) * 8;
    int s  = (bid / 24) % SEG;
    int k  = (bid / (24*SEG)) % 4;
    int b  = bid / (24*SEG*4);
    int tid = threadIdx.x;
    int ch = tid >> 4, n = tid & 15;
    int d  = dg + ch;
    int base = (b*KK + k)*LL + s*SEGLEN;
    int chain = (b*KK + k)*DN + d;
    int xrow = (b*2 + (k & 1))*LL;
    bool rev = (k >= 2);

    float a  = -__expf(A_log[(k*DN + d)*NN + n]) * LOG2E;
    float h  = g_h0[(chain*SEG + s)*NN + n];

    int lt = tid >> 3, lc = tid & 7;
    float Dv2 = Ds[k*DN + dg + lc];
    float rD, rX, rB[2], rC[2];
    {
        int t_abs = s*SEGLEN + lt;
        int xr = rev ? (LL-1 - t_abs) : t_abs;
        rD = g_delta[(base + lt)*DN + dg + lc];
        rX = g_xs   [(xrow + xr)*DN + dg + lc];
    }
    #pragma unroll
    for (int i = 0; i < 2; i++){
        int jj = tid + i*128;
        rB[i] = g_bs[base*NN + jj];
        rC[i] = g_cs[base*NN + jj];
    }
    for (int chunk = 0; chunk < SEGLEN/16; chunk++){
        *(float2*)&sDU[tid*2] = make_float2(rD, rD * rX);
        *(float2*)&sBC[tid*2]       = make_float2(rB[0], rC[0]);
        *(float2*)&sBC[(tid+128)*2] = make_float2(rB[1], rC[1]);
        float xCur = rX;
        __syncthreads();
        if (chunk < SEGLEN/16 - 1){
            int t0n = (chunk + 1) * 16;
            int t_abs = s*SEGLEN + t0n + lt;
            int xr = rev ? (LL-1 - t_abs) : t_abs;
            rD = g_delta[(base + t0n + lt)*DN + dg + lc];
            rX = g_xs   [(xrow + xr)*DN + dg + lc];
            #pragma unroll
            for (int i = 0; i < 2; i++){
                int jj = tid + i*128;
                rB[i] = g_bs[(base + t0n)*NN + jj];
                rC[i] = g_cs[(base + t0n)*NN + jj];
            }
        }
        #pragma unroll
        for (int t = 0; t < 16; t++){
            float2 du = *(float2*)&sDU[(t*8 + ch)*2];
            float2 bc = *(float2*)&sBC[(t*16 + n)*2];
            float e  = exp2f(du.x * a);
            h = fmaf(e, h, du.y * bc.x);
            sP[n*129 + t*8 + ch] = h * bc.y;
        }
        __syncthreads();
        {
            float y = Dv2 * xCur;
            #pragma unroll
            for (int nn = 0; nn < NN; nn++)
                y += sP[nn*129 + tid];
            g_ys[(base + chunk*16 + lt)*DN + dg + lc] = y;
        }
    }
}

// ---------------- kGH: combine + LN + gate, then tf32 mma out_proj -> g_dd ----------
__global__ void kGH(const float* __restrict__ lng, const float* __restrict__ lnb,
                    const float* __restrict__ w, const float* __restrict__ bias){
    __shared__ __align__(16) float sA[32*196];
    __shared__ __align__(16) float sW[96*52];
    __shared__ __align__(16) float sS[256];
    __shared__ __align__(16) float sS2[256];
    __shared__ float sM[32], sR[32];
    uint32_t* sAu = (uint32_t*)sA;
    uint32_t* sWu = (uint32_t*)sW;
    int b = blockIdx.x >> 7;
    int pix0 = (blockIdx.x & 127) * 32;
    int tid = threadIdx.x;
    int tp = tid >> 3, tc = tid & 7;
    int l  = pix0 + tp;
    int hh = l >> 6, ww = l & 63;
    int t1 = ww*64 + hh;
    int b4 = b*KK*LL;
    const float* r0 = &g_ys[(b4 + l)*DN];
    const float* r1 = &g_ys[(b4 + 1*LL + t1)*DN];
    const float* r2 = &g_ys[(b4 + 2*LL + (LL-1-l))*DN];
    const float* r3 = &g_ys[(b4 + 3*LL + (LL-1-t1))*DN];
    float vloc[24];
    float s = 0.f, s2 = 0.f;
    #pragma unroll
    for (int jq = 0; jq < 6; jq++){
        int c = tc*24 + jq*4;
        float4 a0 = *(const float4*)&r0[c];
        float4 a1 = *(const float4*)&r1[c];
        float4 a2 = *(const float4*)&r2[c];
        float4 a3 = *(const float4*)&r3[c];
        float v0 = a0.x + a1.x + a2.x + a3.x;
        float v1 = a0.y + a1.y + a2.y + a3.y;
        float v2 = a0.z + a1.z + a2.z + a3.z;
        float v3 = a0.w + a1.w + a2.w + a3.w;
        vloc[jq*4+0] = v0; vloc[jq*4+1] = v1; vloc[jq*4+2] = v2; vloc[jq*4+3] = v3;
        s  += v0 + v1 + v2 + v3;
        s2 += v0*v0 + v1*v1 + v2*v2 + v3*v3;
    }
    sS[tid] = s;  sS2[tid] = s2;
    __syncthreads();
    if (tid < 32){
        float ss = 0.f, ss2 = 0.f;
        #pragma unroll
        for (int i = 0; i < 8; i++){ ss += sS[tid*8+i]; ss2 += sS2[tid*8+i]; }
        float m = ss * (1.f/192.f);
        float var = ss2 * (1.f/192.f) - m*m;
        sM[tid] = m;  sR[tid] = rsqrtf(var + 1e-5f);
    }
    __syncthreads();
    {
        float m = sM[tp], rs = sR[tp];
        const float* zrow = &g_z[(b*LL + l)*DN];
        #pragma unroll
        for (int jq = 0; jq < 6; jq++){
            int c = tc*24 + jq*4;
            float4 zv = *(const float4*)&zrow[c];
            float4 gv = *(const float4*)&lng[c];
            float4 bv = *(const float4*)&lnb[c];
            sAu[tp*196 + c + 0] = tf32(((vloc[jq*4+0]-m)*rs*gv.x + bv.x) * siluf(zv.x));
            sAu[tp*196 + c + 1] = tf32(((vloc[jq*4+1]-m)*rs*gv.y + bv.y) * siluf(zv.y));
            sAu[tp*196 + c + 2] = tf32(((vloc[jq*4+2]-m)*rs*gv.z + bv.z) * siluf(zv.z));
            sAu[tp*196 + c + 3] = tf32(((vloc[jq*4+3]-m)*rs*gv.w + bv.w) * siluf(zv.w));
        }
    }
    int wid = tid >> 5, lane = tid & 31;
    int gid = lane >> 2, tig = lane & 3;
    int pt = wid & 1;
    int ob = (wid >> 1) * 24;
    int prow = pt*16 + gid;
    float acc[3][4];
    #pragma unroll
    for (int j = 0; j < 3; j++){
        float b0v = bias[ob + j*8 + 2*tig];
        float b1v = bias[ob + j*8 + 2*tig + 1];
        acc[j][0] = b0v; acc[j][1] = b1v; acc[j][2] = b0v; acc[j][3] = b1v;
    }
    for (int kc = 0; kc < 4; kc++){
        __syncthreads();
        for (int j = tid; j < 96*12; j += 256){
            int o = j / 12, kq = j % 12;
            float4 v = *(const float4*)&w[o*DN + kc*48 + kq*4];
            uint32_t* dst = &sWu[o*52 + kq*4];
            dst[0] = tf32(v.x); dst[1] = tf32(v.y); dst[2] = tf32(v.z); dst[3] = tf32(v.w);
        }
        __syncthreads();
        #pragma unroll
        for (int sgl = 0; sgl < 6; sgl++){
            int kg = kc*48 + sgl*8;
            uint32_t a0 = sAu[prow*196     + kg + tig];
            uint32_t a1 = sAu[(prow+8)*196 + kg + tig];
            uint32_t a2 = sAu[prow*196     + kg + tig + 4];
            uint32_t a3 = sAu[(prow+8)*196 + kg + tig + 4];
            int kl = sgl*8;
            #pragma unroll
            for (int j = 0; j < 3; j++){
                uint32_t b0 = sWu[(ob + j*8 + gid)*52 + kl + tig];
                uint32_t b1 = sWu[(ob + j*8 + gid)*52 + kl + tig + 4];
                MMA_TF32(acc[j], a0,a1,a2,a3, b0,b1);
            }
        }
    }
    __syncthreads();
    float* st = sW;
    #pragma unroll
    for (int j = 0; j < 3; j++){
        int o0 = ob + j*8 + 2*tig;
        st[o0*33 + prow]         = acc[j][0];
        st[(o0+1)*33 + prow]     = acc[j][1];
        st[o0*33 + prow + 8]     = acc[j][2];
        st[(o0+1)*33 + prow + 8] = acc[j][3];
    }
    __syncthreads();
    for (int j = tid; j < 32*96; j += 256){
        int pp = j / 96, o = j % 96;
        g_dd[(b*LL + pix0 + pp)*CHID + o] = st[o*33 + pp];
    }
}

// ---------------- kI: up-proj via tf32 mma + bn + silu + residual + gate ------------
__global__ void kI(const float* __restrict__ w, const float* __restrict__ bias,
                   const float* __restrict__ bng, const float* __restrict__ bnb,
                   float* __restrict__ out){
    __shared__ __align__(16) float sA[32*100];
    __shared__ __align__(16) float sW[64*100];
    __shared__ __align__(16) float sO[64*33];
    uint32_t* sAu = (uint32_t*)sA;
    uint32_t* sWu = (uint32_t*)sW;
    int b = blockIdx.x >> 7;
    int pix0 = (blockIdx.x & 127) * 32;
    int tid = threadIdx.x;
    int wid = tid >> 5, lane = tid & 31;
    int gid = lane >> 2, tig = lane & 3;
    int pt = wid & 1;
    int ob = (wid >> 1) * 16;
    int prow = pt*16 + gid;

    for (int j = tid; j < 32*24; j += 256){
        int p = j / 24, cq = j % 24;
        float4 v = *(const float4*)&g_dd[(b*LL + pix0 + p)*CHID + cq*4];
        uint32_t* dst = &sAu[p*100 + cq*4];
        dst[0] = tf32(v.x); dst[1] = tf32(v.y); dst[2] = tf32(v.z); dst[3] = tf32(v.w);
    }
    for (int j = tid; j < 64*24; j += 256){
        int o = j / 24, kq = j % 24;
        float4 v = *(const float4*)&w[o*CHID + kq*4];
        uint32_t* dst = &sWu[o*100 + kq*4];
        dst[0] = tf32(v.x); dst[1] = tf32(v.y); dst[2] = tf32(v.z); dst[3] = tf32(v.w);
    }
    __syncthreads();
    float acc[2][4];
    #pragma unroll
    for (int j = 0; j < 2; j++){
        float b0v = bias[ob + j*8 + 2*tig];
        float b1v = bias[ob + j*8 + 2*tig + 1];
        acc[j][0] = b0v; acc[j][1] = b1v; acc[j][2] = b0v; acc[j][3] = b1v;
    }
    #pragma unroll 4
    for (int s = 0; s < 12; s++){
        int k0 = s*8;
        uint32_t a0 = sAu[prow*100     + k0 + tig];
        uint32_t a1 = sAu[(prow+8)*100 + k0 + tig];
        uint32_t a2 = sAu[prow*100     + k0 + tig + 4];
        uint32_t a3 = sAu[(prow+8)*100 + k0 + tig + 4];
        #pragma unroll
        for (int j = 0; j < 2; j++){
            uint32_t b0 = sWu[(ob + j*8 + gid)*100 + k0 + tig];
            uint32_t b1 = sWu[(ob + j*8 + gid)*100 + k0 + tig + 4];
            MMA_TF32(acc[j], a0,a1,a2,a3, b0,b1);
        }
    }
    #pragma unroll
    for (int j = 0; j < 2; j++){
        int o0 = ob + j*8 + 2*tig;
        float inv0 = bng[o0]   * rsqrtf(1.00001f);
        float inv1 = bng[o0+1] * rsqrtf(1.00001f);
        float bb0 = bnb[o0], bb1 = bnb[o0+1];
        sO[o0*33 + prow]         = siluf(acc[j][0]*inv0 + bb0);
        sO[(o0+1)*33 + prow]     = siluf(acc[j][1]*inv1 + bb1);
        sO[o0*33 + prow + 8]     = siluf(acc[j][2]*inv0 + bb0);
        sO[(o0+1)*33 + prow + 8] = siluf(acc[j][3]*inv1 + bb1);
    }
    __syncthreads();
    for (int j = tid; j < 64*32; j += 256){
        int o = j >> 5, pp = j & 31;
        int idx = (b*CIN + o)*LL + pix0 + pp;
        out[idx] = (sO[o*33 + pp] + g_diff[idx]) * g_gate[idx];
    }
}

// ---------------- launcher ----------------
extern "C" void kernel_launch(void* const* d_in, const int* in_sizes, int n_in,
                              void* d_out, int out_size){
    const float* pre        = (const float*)d_in[0];
    const float* post       = (const float*)d_in[1];
    const float* prepost_w  = (const float*)d_in[2];
    const float* prepost_b  = (const float*)d_in[3];
    const float* prepost_g  = (const float*)d_in[4];
    const float* prepost_bb = (const float*)d_in[5];
    const float* down_w     = (const float*)d_in[6];
    const float* down_b     = (const float*)d_in[7];
    const float* down_g     = (const float*)d_in[8];
    const float* down_bb    = (const float*)d_in[9];
    const float* up_w       = (const float*)d_in[10];
    const float* up_b       = (const float*)d_in[11];
    const float* up_g       = (const float*)d_in[12];
    const float* up_bb      = (const float*)d_in[13];
    const float* pe_w       = (const float*)d_in[14];
    const float* pe_b       = (const float*)d_in[15];
    const float* pe_ln_g    = (const float*)d_in[16];
    const float* pe_ln_b    = (const float*)d_in[17];
    const float* in_proj_w  = (const float*)d_in[18];
    const float* in_proj_b  = (const float*)d_in[19];
    const float* conv_w     = (const float*)d_in[20];
    const float* conv_b     = (const float*)d_in[21];
    const float* x_proj_w   = (const float*)d_in[22];
    const float* dt_w       = (const float*)d_in[23];
    const float* dt_b       = (const float*)d_in[24];
    const float* A_log      = (const float*)d_in[25];
    const float* Ds         = (const float*)d_in[26];
    const float* out_ln_g   = (const float*)d_in[27];
    const float* out_ln_b   = (const float*)d_in[28];
    const float* out_proj_w = (const float*)d_in[29];
    const float* out_proj_b = (const float*)d_in[30];
    float* out = (float*)d_out;

    kGB<<<BB*(LL/32), 256>>>(pre, post, prepost_w, prepost_b, prepost_g, prepost_bb,
                             down_w, down_b, down_g, down_bb);
    kCD<<<BB*(LL/32), 256>>>(pe_w, pe_b, pe_ln_g, pe_ln_b, in_proj_w, in_proj_b);
    kE<<<BB*DN, 256>>>(conv_w, conv_b);
    kX<<<BB*KK*(LL/16), 256>>>(x_proj_w, dt_w, dt_b);
    kF1<<<BB*KK*(SEG-1)*(DN/8), 128>>>(A_log);
    kF2<<<(BB*KK*DN*NN)/256, 256>>>();
    kF3<<<BB*KK*SEG*(DN/8), 128>>>(A_log, Ds);
    kGH<<<BB*(LL/32), 256>>>(out_ln_g, out_ln_b, out_proj_w, out_proj_b);
    kI<<<BB*(LL/32), 256>>>(up_w, up_b, up_g, up_bb, out);
}

// round 16
// speedup vs baseline: 1.7367x; 1.0497x over previous
#include <cuda_runtime.h>
#include <math.h>
#include <stdint.h>

#define BB 4
#define CIN 64
#define CHID 96
#define LL 4096
#define NN 16
#define RR 6
#define KK 4
#define DN 192
#define SEG 4
#define SEGLEN 1024

// ---------------- static scratch (no allocation anywhere) ----------------
__device__ float g_diff [BB*CIN*LL];
__device__ float g_gate [BB*CIN*LL];
__device__ float g_d1   [BB*LL*CHID];
__device__ float g_xc   [BB*DN*LL];
__device__ float g_xcv  [BB*DN*LL];
__device__ float g_xcvT [BB*DN*LL];
__device__ float g_z    [BB*LL*DN];
__device__ float g_xs   [BB*2*LL*DN];     // only k=0,1 stored; k=2,3 are flips
__device__ float g_delta[BB*KK*LL*DN];
__device__ float g_bs   [BB*KK*LL*NN];
__device__ float g_cs   [BB*KK*LL*NN];
__device__ float g_ys   [BB*KK*LL*DN];
__device__ float g_dd   [BB*LL*CHID];
__device__ float g_P [BB*KK*DN*(SEG-1)*NN];
__device__ float g_q [BB*KK*DN*(SEG-1)*NN];
__device__ float g_h0[BB*KK*DN*SEG*NN];

#define LOG2E 1.44269504f

__device__ __forceinline__ float sigm(float x){ return 1.f/(1.f+__expf(-x)); }
__device__ __forceinline__ float siluf(float x){ return x*sigm(x); }
__device__ __forceinline__ float dot4(float4 a, float4 w, float acc){
    acc = fmaf(a.x, w.x, acc);
    acc = fmaf(a.y, w.y, acc);
    acc = fmaf(a.z, w.z, acc);
    acc = fmaf(a.w, w.w, acc);
    return acc;
}
__device__ __forceinline__ uint32_t tf32(float x){
    uint32_t r; asm("cvt.rna.tf32.f32 %0, %1;" : "=r"(r) : "f"(x)); return r;
}
#define MMA_TF32(acc, a0,a1,a2,a3, b0,b1) \
    asm volatile( \
        "mma.sync.aligned.m16n8k8.row.col.f32.tf32.tf32.f32 " \
        "{%0,%1,%2,%3},{%4,%5,%6,%7},{%8,%9},{%0,%1,%2,%3};" \
        : "+f"(acc[0]), "+f"(acc[1]), "+f"(acc[2]), "+f"(acc[3]) \
        : "r"(a0), "r"(a1), "r"(a2), "r"(a3), "r"(b0), "r"(b1))

// ---------------- kGB: fused gate (prepost x2) + diff + down-proj ----------------
__global__ void kGB(const float* __restrict__ pre, const float* __restrict__ post,
                    const float* __restrict__ w, const float* __restrict__ bias,
                    const float* __restrict__ bng, const float* __restrict__ bnb,
                    const float* __restrict__ dw, const float* __restrict__ dbias,
                    const float* __restrict__ dbng, const float* __restrict__ dbnb){
    __shared__ __align__(16) float sP[CIN*32];
    __shared__ __align__(16) float sQ[CIN*32];
    __shared__ __align__(16) float sW[CHID*CIN];
    __shared__ __align__(16) float sO[CIN*32];
    int b = blockIdx.x >> 7;
    int pix0 = (blockIdx.x & 127) * 32;
    int tid = threadIdx.x;
    for (int j = tid; j < CIN*CIN/4; j += 256)
        ((float4*)sW)[j] = ((const float4*)w)[j];
    for (int j = tid; j < CIN*32; j += 256){
        int c = j >> 5, p = j & 31;
        int idx = (b*CIN + c)*LL + pix0 + p;
        float pv = pre[idx], qv = post[idx];
        sP[j] = pv;
        sQ[j] = qv;
        g_diff[idx] = fabsf(qv - pv);
    }
    __syncthreads();
    int p = tid & 31, og = tid >> 5;
    {
        float a1[8], a2[8];
        #pragma unroll
        for (int j = 0; j < 8; j++){ a1[j] = 0.f; a2[j] = 0.f; }
        for (int kq = 0; kq < 16; kq++){
            float x1[4], x2[4];
            #pragma unroll
            for (int i = 0; i < 4; i++){
                x1[i] = sP[(kq*4+i)*32 + p];
                x2[i] = sQ[(kq*4+i)*32 + p];
            }
            #pragma unroll
            for (int j = 0; j < 8; j++){
                float4 wv = *(float4*)&sW[(og*8+j)*CIN + kq*4];
                a1[j] = fmaf(x1[0],wv.x, fmaf(x1[1],wv.y, fmaf(x1[2],wv.z, fmaf(x1[3],wv.w, a1[j]))));
                a2[j] = fmaf(x2[0],wv.x, fmaf(x2[1],wv.y, fmaf(x2[2],wv.z, fmaf(x2[3],wv.w, a2[j]))));
            }
        }
        #pragma unroll
        for (int j = 0; j < 8; j++){
            int o = og*8 + j;
            float inv = bng[o] * rsqrtf(1.00001f);
            float bz  = bias[o];
            float bb  = bnb[o];
            float t1 = (a1[j] + bz) * inv + bb;
            float t2 = (a2[j] + bz) * inv + bb;
            sO[o*32 + p] = sigm(siluf(t1)) * sigm(siluf(t2));
        }
    }
    __syncthreads();
    for (int j = tid; j < CIN*32; j += 256){
        int o = j >> 5, pp = j & 31;
        g_gate[(b*CIN + o)*LL + pix0 + pp] = sO[j];
        sP[j] = fabsf(sQ[j] - sP[j]);
    }
    for (int j = tid; j < CHID*CIN/4; j += 256)
        ((float4*)sW)[j] = ((const float4*)dw)[j];
    __syncthreads();
    {
        float acc[12];
        #pragma unroll
        for (int j = 0; j < 12; j++) acc[j] = 0.f;
        for (int kq = 0; kq < 16; kq++){
            float x[4];
            #pragma unroll
            for (int i = 0; i < 4; i++) x[i] = sP[(kq*4+i)*32 + p];
            #pragma unroll
            for (int j = 0; j < 12; j++){
                float4 wv = *(float4*)&sW[(og*12+j)*CIN + kq*4];
                acc[j] = fmaf(x[0],wv.x, fmaf(x[1],wv.y, fmaf(x[2],wv.z, fmaf(x[3],wv.w, acc[j]))));
            }
        }
        float res[12];
        #pragma unroll
        for (int j = 0; j < 12; j++){
            int o = og*12 + j;
            float inv = dbng[o] * rsqrtf(1.00001f);
            float t = (acc[j] + dbias[o]) * inv + dbnb[o];
            res[j] = siluf(t);
        }
        float4* dst = (float4*)&g_d1[(b*LL + pix0 + p)*CHID + og*12];
        #pragma unroll
        for (int v = 0; v < 3; v++)
            dst[v] = make_float4(res[v*4], res[v*4+1], res[v*4+2], res[v*4+3]);
    }
}

// ---------------- kCD: fused LN(pe(d1)) + in_proj tf32 mma ----------------
__global__ void kCD(const float* __restrict__ w, const float* __restrict__ bias,
                    const float* __restrict__ lng, const float* __restrict__ lnb,
                    const float* __restrict__ iw, const float* __restrict__ ibias){
    __shared__ __align__(16) float sMem[3200 + 6400 + 2112];
    float* sA = sMem;
    float* sW = sMem + 3200;
    float* sO = sMem + 9600;
    float* sS  = sO;
    float* sS2 = sO + 512;
    float* sM  = sO + 1024;
    float* sR  = sO + 1056;
    uint32_t* sAu = (uint32_t*)sA;
    uint32_t* sWu = (uint32_t*)sW;
    int b = blockIdx.x >> 7;
    int pix0 = (blockIdx.x & 127) * 32;
    int tid = threadIdx.x;
    for (int j = tid; j < 32*24; j += 256){
        int p = j / 24, cq = j % 24;
        *(float4*)&sA[p*100 + cq*4] = *(const float4*)&g_d1[(b*LL + pix0 + p)*CHID + cq*4];
    }
    int p = tid & 15, og = tid >> 4;
    float accC[2][6];
    #pragma unroll
    for (int j = 0; j < 6; j++){ accC[0][j] = bias[og*6+j]; accC[1][j] = accC[0][j]; }
    for (int kc = 0; kc < 2; kc++){
        __syncthreads();
        for (int j = tid; j < 96*12; j += 256){
            int o = j / 12, kq = j % 12;
            *(float4*)&sW[o*48 + kq*4] = *(const float4*)&w[o*CHID + kc*48 + kq*4];
        }
        __syncthreads();
        #pragma unroll 4
        for (int kq = 0; kq < 12; kq++){
            float4 a0 = *(float4*)&sA[p*100 + kc*48 + kq*4];
            float4 a1 = *(float4*)&sA[(p+16)*100 + kc*48 + kq*4];
            #pragma unroll
            for (int j = 0; j < 6; j++){
                float4 wv = *(float4*)&sW[(og*6+j)*48 + kq*4];
                accC[0][j] = dot4(a0, wv, accC[0][j]);
                accC[1][j] = dot4(a1, wv, accC[1][j]);
            }
        }
    }
    #pragma unroll
    for (int pi = 0; pi < 2; pi++){
        float s = 0.f, s2 = 0.f;
        #pragma unroll
        for (int j = 0; j < 6; j++){ s += accC[pi][j]; s2 += accC[pi][j]*accC[pi][j]; }
        sS [(p + pi*16)*16 + og] = s;
        sS2[(p + pi*16)*16 + og] = s2;
    }
    __syncthreads();
    if (tid < 32){
        float ss = 0.f, ss2 = 0.f;
        #pragma unroll
        for (int i = 0; i < 16; i++){ ss += sS[tid*16+i]; ss2 += sS2[tid*16+i]; }
        float m = ss * (1.f/96.f);
        float var = ss2 * (1.f/96.f) - m*m;
        sM[tid] = m;  sR[tid] = rsqrtf(var + 1e-5f);
    }
    __syncthreads();
    #pragma unroll
    for (int pi = 0; pi < 2; pi++){
        int pp = p + pi*16;
        float m = sM[pp], rs = sR[pp];
        #pragma unroll
        for (int j = 0; j < 6; j++){
            int o = og*6 + j;
            sAu[pp*100 + o] = tf32((accC[pi][j] - m) * rs * lng[o] + lnb[o]);
        }
    }
    int wid = tid >> 5, lane = tid & 31;
    int gid = lane >> 2, tig = lane & 3;
    int pt = wid & 1;
    int ob = (wid >> 1) * 16;
    int prow = pt*16 + gid;
    for (int ch = 0; ch < 6; ch++){
        __syncthreads();
        for (int j = tid; j < 64*24; j += 256){
            int o = j / 24, kq = j % 24;
            float4 v = *(const float4*)&iw[(ch*64 + o)*CHID + kq*4];
            uint32_t* dst = &sWu[o*100 + kq*4];
            dst[0] = tf32(v.x); dst[1] = tf32(v.y); dst[2] = tf32(v.z); dst[3] = tf32(v.w);
        }
        __syncthreads();
        float acc[2][4];
        #pragma unroll
        for (int j = 0; j < 2; j++){
            float b0v = ibias[ch*64 + ob + j*8 + 2*tig];
            float b1v = ibias[ch*64 + ob + j*8 + 2*tig + 1];
            acc[j][0] = b0v; acc[j][1] = b1v; acc[j][2] = b0v; acc[j][3] = b1v;
        }
        #pragma unroll 4
        for (int s = 0; s < 12; s++){
            int k0 = s*8;
            uint32_t a0 = sAu[prow*100     + k0 + tig];
            uint32_t a1 = sAu[(prow+8)*100 + k0 + tig];
            uint32_t a2 = sAu[prow*100     + k0 + tig + 4];
            uint32_t a3 = sAu[(prow+8)*100 + k0 + tig + 4];
            #pragma unroll
            for (int j = 0; j < 2; j++){
                uint32_t b0 = sWu[(ob + j*8 + gid)*100 + k0 + tig];
                uint32_t b1 = sWu[(ob + j*8 + gid)*100 + k0 + tig + 4];
                MMA_TF32(acc[j], a0,a1,a2,a3, b0,b1);
            }
        }
        #pragma unroll
        for (int j = 0; j < 2; j++){
            int o0 = ob + j*8 + 2*tig;
            sO[o0*33 + prow]         = acc[j][0];
            sO[(o0+1)*33 + prow]     = acc[j][1];
            sO[o0*33 + prow + 8]     = acc[j][2];
            sO[(o0+1)*33 + prow + 8] = acc[j][3];
        }
        __syncthreads();
        if (ch < 3){
            for (int j = tid; j < 64*32; j += 256){
                int o = j >> 5, pp = j & 31;
                g_xc[(b*DN + ch*64 + o)*LL + pix0 + pp] = sO[o*33 + pp];
            }
        } else {
            for (int j = tid; j < 32*64; j += 256){
                int pp = j >> 6, oz = j & 63;
                g_z[(b*LL + pix0 + pp)*DN + (ch-3)*64 + oz] = sO[oz*33 + pp];
            }
        }
    }
}

// ---------------- kE v3: depthwise 3x3 conv + silu; writes g_xcv and g_xcvT ---------
__global__ void kE(const float* __restrict__ cw, const float* __restrict__ cb){
    __shared__ float sT[66*66];
    __shared__ float sO[64*65];
    int bd = blockIdx.x;
    int d  = bd % DN;
    int tid = threadIdx.x;
    const float* src = g_xc + bd*LL;
    for (int j = tid; j < 66*66; j += 256){
        int rr = j / 66, cc = j % 66;
        int r = rr - 1, c = cc - 1;
        float v = 0.f;
        if (r >= 0 && r < 64 && c >= 0 && c < 64) v = src[r*64 + c];
        sT[j] = v;
    }
    float w9[9];
    #pragma unroll
    for (int i = 0; i < 9; i++) w9[i] = cw[d*9 + i];
    float bz = cb[d];
    __syncthreads();
    for (int j = tid; j < 64*64; j += 256){
        int r = j >> 6, c = j & 63;
        float s = bz;
        #pragma unroll
        for (int ky = 0; ky < 3; ky++)
            #pragma unroll
            for (int kx = 0; kx < 3; kx++)
                s = fmaf(w9[ky*3+kx], sT[(r+ky)*66 + c + kx], s);
        sO[r*65 + c] = siluf(s);
    }
    __syncthreads();
    float* dst  = g_xcv  + bd*LL;
    float* dstT = g_xcvT + bd*LL;
    for (int j = tid; j < 64*64; j += 256){
        int r = j >> 6, c = j & 63;
        dst[j]  = sO[r*65 + c];
        dstT[j] = sO[c*65 + r];
    }
}

// ---------------- kX v5: coalesced gather (xcv/xcvT), tf32 mma x_proj, dt GEMM -------
__global__ void kX(const float* __restrict__ xpw, const float* __restrict__ dtw,
                   const float* __restrict__ dtb){
    __shared__ __align__(16) float sxs[16*196];
    __shared__ __align__(16) float sWk[40*100];
    __shared__ __align__(16) float sdtw[DN*6];
    __shared__ __align__(16) float sdl[16*DN];
    __shared__ __align__(16) float sdt[6*17];
    uint32_t* sxu = (uint32_t*)sxs;
    uint32_t* sWu = (uint32_t*)sWk;
    int tile = blockIdx.x & 255;
    int k    = (blockIdx.x >> 8) & 3;
    int b    = blockIdx.x >> 10;
    int t0   = tile * 16;
    int tid  = threadIdx.x;
    int wid = tid >> 5, lane = tid & 31;
    int gid = lane >> 2, tig = lane & 3;
    int base = (b*KK + k)*LL;

    for (int j = tid; j < DN*6/2; j += 256)
        ((float2*)sdtw)[j] = ((const float2*)(dtw + k*DN*6))[j];
    // coalesced gather: k&1 selects transposed plane; k>=2 reads mirrored chunk
    {
        const float* src = (k & 1) ? g_xcvT : g_xcv;
        bool rev = (k >= 2);
        int coff = rev ? (LL - t0 - 16) : t0;
        for (int j = tid; j < DN*4; j += 256){
            int d = j >> 2, q = j & 3;
            float4 v = *(const float4*)&src[(b*DN + d)*LL + coff + q*4];
            int j0 = q*4;
            if (!rev){
                sxs[(j0+0)*196 + d] = v.x;
                sxs[(j0+1)*196 + d] = v.y;
                sxs[(j0+2)*196 + d] = v.z;
                sxs[(j0+3)*196 + d] = v.w;
            } else {
                sxs[(15-j0)*196 + d]   = v.x;
                sxs[(15-j0-1)*196 + d] = v.y;
                sxs[(15-j0-2)*196 + d] = v.z;
                sxs[(15-j0-3)*196 + d] = v.w;
            }
        }
    }
    __syncthreads();
    if (k < 2){
        int xbase = (b*2 + k)*LL;
        for (int j = tid; j < 16*48; j += 256){
            int tt = j / 48, dq = j % 48;
            *(float4*)&g_xs[(xbase + t0 + tt)*DN + dq*4] = *(float4*)&sxs[tt*196 + dq*4];
        }
    }
    __syncthreads();
    for (int j = tid; j < 16*DN; j += 256){
        int tt = j / 192, d = j - tt*192;
        sxu[tt*196 + d] = tf32(sxs[tt*196 + d]);
    }
    float acc[4] = {0.f, 0.f, 0.f, 0.f};
    for (int kc = 0; kc < 2; kc++){
        __syncthreads();
        for (int j = tid; j < 40*24; j += 256){
            int c = j / 24, kq = j % 24;
            uint32_t* dst = &sWu[c*100 + kq*4];
            if (c < 38){
                float4 v = *(const float4*)&xpw[(k*38 + c)*DN + kc*96 + kq*4];
                dst[0] = tf32(v.x); dst[1] = tf32(v.y); dst[2] = tf32(v.z); dst[3] = tf32(v.w);
            } else {
                dst[0] = 0u; dst[1] = 0u; dst[2] = 0u; dst[3] = 0u;
            }
        }
        __syncthreads();
        if (wid < 5){
            #pragma unroll 4
            for (int s = 0; s < 12; s++){
                int kg = kc*96 + s*8;
                uint32_t a0 = sxu[gid*196     + kg + tig];
                uint32_t a1 = sxu[(gid+8)*196 + kg + tig];
                uint32_t a2 = sxu[gid*196     + kg + tig + 4];
                uint32_t a3 = sxu[(gid+8)*196 + kg + tig + 4];
                uint32_t b0 = sWu[(wid*8 + gid)*100 + s*8 + tig];
                uint32_t b1 = sWu[(wid*8 + gid)*100 + s*8 + tig + 4];
                MMA_TF32(acc, a0,a1,a2,a3, b0,b1);
            }
        }
    }
    __syncthreads();
    if (wid < 5){
        #pragma unroll
        for (int jj = 0; jj < 2; jj++){
            int c = wid*8 + 2*tig + jj;
            float v0 = acc[jj];
            float v1 = acc[2 + jj];
            if (c < RR){
                sdt[c*17 + gid]     = v0;
                sdt[c*17 + gid + 8] = v1;
            } else if (c < RR + NN){
                g_bs[(base + t0 + gid)*NN + (c - RR)]     = v0;
                g_bs[(base + t0 + gid + 8)*NN + (c - RR)] = v1;
            } else if (c < RR + 2*NN){
                g_cs[(base + t0 + gid)*NN + (c - RR - NN)]     = v0;
                g_cs[(base + t0 + gid + 8)*NN + (c - RR - NN)] = v1;
            }
        }
    }
    __syncthreads();
    {
        int tt = tid & 15, dq = tid >> 4;
        float a2[12];
        #pragma unroll
        for (int j = 0; j < 12; j++) a2[j] = dtb[k*DN + dq*12 + j];
        float dts[6];
        #pragma unroll
        for (int r = 0; r < RR; r++) dts[r] = sdt[r*17 + tt];
        #pragma unroll
        for (int j = 0; j < 12; j++){
            int d = dq*12 + j;
            float a = a2[j];
            #pragma unroll
            for (int r = 0; r < RR; r++)
                a = fmaf(dts[r], sdtw[d*6 + r], a);
            float dl = (a > 20.f) ? a : log1pf(__expf(a));
            sdl[tt*DN + dq*12 + j] = dl;
        }
    }
    __syncthreads();
    for (int j = tid; j < 16*48; j += 256){
        int tt = j / 48, dq = j % 48;
        *(float4*)&g_delta[(base + t0 + tt)*DN + dq*4] = *(float4*)&sdl[tt*DN + dq*4];
    }
}

// ---------------- kF1: per-segment P (one exp) and offset q; packed DU ----------------
__global__ void kF1(const float* __restrict__ A_log){
    __shared__ __align__(16) float sDU[16*8*2];
    __shared__ __align__(16) float sB[16*16];
    __shared__ float sSum[8];
    int bid = blockIdx.x;
    int dg = (bid % 24) * 8;
    int s  = (bid / 24) % (SEG-1);
    int k  = (bid / (24*(SEG-1))) % 4;
    int b  = bid / (24*(SEG-1)*4);
    int tid = threadIdx.x;
    int ch = tid >> 4, n = tid & 15;
    int d  = dg + ch;
    int base = (b*KK + k)*LL + s*SEGLEN;
    int xrow = (b*2 + (k & 1))*LL;
    bool rev = (k >= 2);

    float a = -__expf(A_log[(k*DN + d)*NN + n]) * LOG2E;
    float h = 0.f;

    int lt = tid >> 3, lc = tid & 7;
    float dsum = 0.f;
    float rD, rX, rB[2];
    {
        int t_abs = s*SEGLEN + lt;
        int xr = rev ? (LL-1 - t_abs) : t_abs;
        rD = g_delta[(base + lt)*DN + dg + lc];
        rX = g_xs   [(xrow + xr)*DN + dg + lc];
    }
    #pragma unroll
    for (int i = 0; i < 2; i++){
        int jj = tid + i*128;
        rB[i] = g_bs[base*NN + jj];
    }
    for (int chunk = 0; chunk < SEGLEN/16; chunk++){
        *(float2*)&sDU[tid*2] = make_float2(rD, rD * rX);
        sB[tid] = rB[0];  sB[tid+128] = rB[1];
        dsum += rD;
        __syncthreads();
        if (chunk < SEGLEN/16 - 1){
            int t0n = (chunk + 1) * 16;
            int t_abs = s*SEGLEN + t0n + lt;
            int xr = rev ? (LL-1 - t_abs) : t_abs;
            rD = g_delta[(base + t0n + lt)*DN + dg + lc];
            rX = g_xs   [(xrow + xr)*DN + dg + lc];
            #pragma unroll
            for (int i = 0; i < 2; i++){
                int jj = tid + i*128;
                rB[i] = g_bs[(base + t0n)*NN + jj];
            }
        }
        #pragma unroll
        for (int t = 0; t < 16; t++){
            float2 du = *(float2*)&sDU[(t*8 + ch)*2];
            float Bn = sB[t*16 + n];
            float e  = exp2f(du.x * a);
            h = fmaf(e, h, du.y * Bn);
        }
        __syncthreads();
    }
    sDU[lt*8 + lc] = dsum;
    __syncthreads();
    if (tid < 8){
        float S = 0.f;
        #pragma unroll
        for (int i = 0; i < 16; i++) S += sDU[i*8 + tid];
        sSum[tid] = S;
    }
    __syncthreads();
    float P = exp2f(a * sSum[ch]);
    int chain = (b*KK + k)*DN + d;
    g_P[(chain*(SEG-1) + s)*NN + n] = P;
    g_q[(chain*(SEG-1) + s)*NN + n] = h;
}

// ---------------- kF2: prefix over segments -> g_h0 ----------------
__global__ void kF2(){
    int gid = blockIdx.x*blockDim.x + threadIdx.x;
    int chain = gid >> 4, n = gid & 15;
    float h = 0.f;
    g_h0[(chain*SEG + 0)*NN + n] = 0.f;
    #pragma unroll
    for (int s = 0; s < SEG-1; s++){
        float P = g_P[(chain*(SEG-1) + s)*NN + n];
        float q = g_q[(chain*(SEG-1) + s)*NN + n];
        h = fmaf(P, h, q);
        g_h0[(chain*SEG + s + 1)*NN + n] = h;
    }
}

// ---------------- kF3: packed DU/BC, smem transpose-reduce ----------------
__global__ void kF3(const float* __restrict__ A_log, const float* __restrict__ Ds){
    __shared__ __align__(16) float sDU[16*8*2];
    __shared__ __align__(16) float sBC[16*16*2];
    __shared__ __align__(16) float sP[NN*129];
    int bid = blockIdx.x;
    int dg = (bid % 24) * 8;
    int s  = (bid / 24) % SEG;
    int k  = (bid / (24*SEG)) % 4;
    int b  = bid / (24*SEG*4);
    int tid = threadIdx.x;
    int ch = tid >> 4, n = tid & 15;
    int d  = dg + ch;
    int base = (b*KK + k)*LL + s*SEGLEN;
    int chain = (b*KK + k)*DN + d;
    int xrow = (b*2 + (k & 1))*LL;
    bool rev = (k >= 2);

    float a  = -__expf(A_log[(k*DN + d)*NN + n]) * LOG2E;
    float h  = g_h0[(chain*SEG + s)*NN + n];

    int lt = tid >> 3, lc = tid & 7;
    float Dv2 = Ds[k*DN + dg + lc];
    float rD, rX, rB[2], rC[2];
    {
        int t_abs = s*SEGLEN + lt;
        int xr = rev ? (LL-1 - t_abs) : t_abs;
        rD = g_delta[(base + lt)*DN + dg + lc];
        rX = g_xs   [(xrow + xr)*DN + dg + lc];
    }
    #pragma unroll
    for (int i = 0; i < 2; i++){
        int jj = tid + i*128;
        rB[i] = g_bs[base*NN + jj];
        rC[i] = g_cs[base*NN + jj];
    }
    for (int chunk = 0; chunk < SEGLEN/16; chunk++){
        *(float2*)&sDU[tid*2] = make_float2(rD, rD * rX);
        *(float2*)&sBC[tid*2]       = make_float2(rB[0], rC[0]);
        *(float2*)&sBC[(tid+128)*2] = make_float2(rB[1], rC[1]);
        float xCur = rX;
        __syncthreads();
        if (chunk < SEGLEN/16 - 1){
            int t0n = (chunk + 1) * 16;
            int t_abs = s*SEGLEN + t0n + lt;
            int xr = rev ? (LL-1 - t_abs) : t_abs;
            rD = g_delta[(base + t0n + lt)*DN + dg + lc];
            rX = g_xs   [(xrow + xr)*DN + dg + lc];
            #pragma unroll
            for (int i = 0; i < 2; i++){
                int jj = tid + i*128;
                rB[i] = g_bs[(base + t0n)*NN + jj];
                rC[i] = g_cs[(base + t0n)*NN + jj];
            }
        }
        #pragma unroll
        for (int t = 0; t < 16; t++){
            float2 du = *(float2*)&sDU[(t*8 + ch)*2];
            float2 bc = *(float2*)&sBC[(t*16 + n)*2];
            float e  = exp2f(du.x * a);
            h = fmaf(e, h, du.y * bc.x);
            sP[n*129 + t*8 + ch] = h * bc.y;
        }
        __syncthreads();
        {
            float y = Dv2 * xCur;
            #pragma unroll
            for (int nn = 0; nn < NN; nn++)
                y += sP[nn*129 + tid];
            g_ys[(base + chunk*16 + lt)*DN + dg + lc] = y;
        }
    }
}

// ---------------- kGH: combine + LN + gate, then tf32 mma out_proj -> g_dd ----------
__global__ void kGH(const float* __restrict__ lng, const float* __restrict__ lnb,
                    const float* __restrict__ w, const float* __restrict__ bias){
    __shared__ __align__(16) float sA[32*196];
    __shared__ __align__(16) float sW[96*52];
    __shared__ __align__(16) float sS[256];
    __shared__ __align__(16) float sS2[256];
    __shared__ float sM[32], sR[32];
    uint32_t* sAu = (uint32_t*)sA;
    uint32_t* sWu = (uint32_t*)sW;
    int b = blockIdx.x >> 7;
    int pix0 = (blockIdx.x & 127) * 32;
    int tid = threadIdx.x;
    int tp = tid >> 3, tc = tid & 7;
    int l  = pix0 + tp;
    int hh = l >> 6, ww = l & 63;
    int t1 = ww*64 + hh;
    int b4 = b*KK*LL;
    const float* r0 = &g_ys[(b4 + l)*DN];
    const float* r1 = &g_ys[(b4 + 1*LL + t1)*DN];
    const float* r2 = &g_ys[(b4 + 2*LL + (LL-1-l))*DN];
    const float* r3 = &g_ys[(b4 + 3*LL + (LL-1-t1))*DN];
    float vloc[24];
    float s = 0.f, s2 = 0.f;
    #pragma unroll
    for (int jq = 0; jq < 6; jq++){
        int c = tc*24 + jq*4;
        float4 a0 = *(const float4*)&r0[c];
        float4 a1 = *(const float4*)&r1[c];
        float4 a2 = *(const float4*)&r2[c];
        float4 a3 = *(const float4*)&r3[c];
        float v0 = a0.x + a1.x + a2.x + a3.x;
        float v1 = a0.y + a1.y + a2.y + a3.y;
        float v2 = a0.z + a1.z + a2.z + a3.z;
        float v3 = a0.w + a1.w + a2.w + a3.w;
        vloc[jq*4+0] = v0; vloc[jq*4+1] = v1; vloc[jq*4+2] = v2; vloc[jq*4+3] = v3;
        s  += v0 + v1 + v2 + v3;
        s2 += v0*v0 + v1*v1 + v2*v2 + v3*v3;
    }
    sS[tid] = s;  sS2[tid] = s2;
    __syncthreads();
    if (tid < 32){
        float ss = 0.f, ss2 = 0.f;
        #pragma unroll
        for (int i = 0; i < 8; i++){ ss += sS[tid*8+i]; ss2 += sS2[tid*8+i]; }
        float m = ss * (1.f/192.f);
        float var = ss2 * (1.f/192.f) - m*m;
        sM[tid] = m;  sR[tid] = rsqrtf(var + 1e-5f);
    }
    __syncthreads();
    {
        float m = sM[tp], rs = sR[tp];
        const float* zrow = &g_z[(b*LL + l)*DN];
        #pragma unroll
        for (int jq = 0; jq < 6; jq++){
            int c = tc*24 + jq*4;
            float4 zv = *(const float4*)&zrow[c];
            float4 gv = *(const float4*)&lng[c];
            float4 bv = *(const float4*)&lnb[c];
            sAu[tp*196 + c + 0] = tf32(((vloc[jq*4+0]-m)*rs*gv.x + bv.x) * siluf(zv.x));
            sAu[tp*196 + c + 1] = tf32(((vloc[jq*4+1]-m)*rs*gv.y + bv.y) * siluf(zv.y));
            sAu[tp*196 + c + 2] = tf32(((vloc[jq*4+2]-m)*rs*gv.z + bv.z) * siluf(zv.z));
            sAu[tp*196 + c + 3] = tf32(((vloc[jq*4+3]-m)*rs*gv.w + bv.w) * siluf(zv.w));
        }
    }
    int wid = tid >> 5, lane = tid & 31;
    int gid = lane >> 2, tig = lane & 3;
    int pt = wid & 1;
    int ob = (wid >> 1) * 24;
    int prow = pt*16 + gid;
    float acc[3][4];
    #pragma unroll
    for (int j = 0; j < 3; j++){
        float b0v = bias[ob + j*8 + 2*tig];
        float b1v = bias[ob + j*8 + 2*tig + 1];
        acc[j][0] = b0v; acc[j][1] = b1v; acc[j][2] = b0v; acc[j][3] = b1v;
    }
    for (int kc = 0; kc < 4; kc++){
        __syncthreads();
        for (int j = tid; j < 96*12; j += 256){
            int o = j / 12, kq = j % 12;
            float4 v = *(const float4*)&w[o*DN + kc*48 + kq*4];
            uint32_t* dst = &sWu[o*52 + kq*4];
            dst[0] = tf32(v.x); dst[1] = tf32(v.y); dst[2] = tf32(v.z); dst[3] = tf32(v.w);
        }
        __syncthreads();
        #pragma unroll
        for (int sgl = 0; sgl < 6; sgl++){
            int kg = kc*48 + sgl*8;
            uint32_t a0 = sAu[prow*196     + kg + tig];
            uint32_t a1 = sAu[(prow+8)*196 + kg + tig];
            uint32_t a2 = sAu[prow*196     + kg + tig + 4];
            uint32_t a3 = sAu[(prow+8)*196 + kg + tig + 4];
            int kl = sgl*8;
            #pragma unroll
            for (int j = 0; j < 3; j++){
                uint32_t b0 = sWu[(ob + j*8 + gid)*52 + kl + tig];
                uint32_t b1 = sWu[(ob + j*8 + gid)*52 + kl + tig + 4];
                MMA_TF32(acc[j], a0,a1,a2,a3, b0,b1);
            }
        }
    }
    __syncthreads();
    float* st = sW;
    #pragma unroll
    for (int j = 0; j < 3; j++){
        int o0 = ob + j*8 + 2*tig;
        st[o0*33 + prow]         = acc[j][0];
        st[(o0+1)*33 + prow]     = acc[j][1];
        st[o0*33 + prow + 8]     = acc[j][2];
        st[(o0+1)*33 + prow + 8] = acc[j][3];
    }
    __syncthreads();
    for (int j = tid; j < 32*96; j += 256){
        int pp = j / 96, o = j % 96;
        g_dd[(b*LL + pix0 + pp)*CHID + o] = st[o*33 + pp];
    }
}

// ---------------- kI: up-proj via tf32 mma + bn + silu + residual + gate ------------
__global__ void kI(const float* __restrict__ w, const float* __restrict__ bias,
                   const float* __restrict__ bng, const float* __restrict__ bnb,
                   float* __restrict__ out){
    __shared__ __align__(16) float sA[32*100];
    __shared__ __align__(16) float sW[64*100];
    __shared__ __align__(16) float sO[64*33];
    uint32_t* sAu = (uint32_t*)sA;
    uint32_t* sWu = (uint32_t*)sW;
    int b = blockIdx.x >> 7;
    int pix0 = (blockIdx.x & 127) * 32;
    int tid = threadIdx.x;
    int wid = tid >> 5, lane = tid & 31;
    int gid = lane >> 2, tig = lane & 3;
    int pt = wid & 1;
    int ob = (wid >> 1) * 16;
    int prow = pt*16 + gid;

    for (int j = tid; j < 32*24; j += 256){
        int p = j / 24, cq = j % 24;
        float4 v = *(const float4*)&g_dd[(b*LL + pix0 + p)*CHID + cq*4];
        uint32_t* dst = &sAu[p*100 + cq*4];
        dst[0] = tf32(v.x); dst[1] = tf32(v.y); dst[2] = tf32(v.z); dst[3] = tf32(v.w);
    }
    for (int j = tid; j < 64*24; j += 256){
        int o = j / 24, kq = j % 24;
        float4 v = *(const float4*)&w[o*CHID + kq*4];
        uint32_t* dst = &sWu[o*100 + kq*4];
        dst[0] = tf32(v.x); dst[1] = tf32(v.y); dst[2] = tf32(v.z); dst[3] = tf32(v.w);
    }
    __syncthreads();
    float acc[2][4];
    #pragma unroll
    for (int j = 0; j < 2; j++){
        float b0v = bias[ob + j*8 + 2*tig];
        float b1v = bias[ob + j*8 + 2*tig + 1];
        acc[j][0] = b0v; acc[j][1] = b1v; acc[j][2] = b0v; acc[j][3] = b1v;
    }
    #pragma unroll 4
    for (int s = 0; s < 12; s++){
        int k0 = s*8;
        uint32_t a0 = sAu[prow*100     + k0 + tig];
        uint32_t a1 = sAu[(prow+8)*100 + k0 + tig];
        uint32_t a2 = sAu[prow*100     + k0 + tig + 4];
        uint32_t a3 = sAu[(prow+8)*100 + k0 + tig + 4];
        #pragma unroll
        for (int j = 0; j < 2; j++){
            uint32_t b0 = sWu[(ob + j*8 + gid)*100 + k0 + tig];
            uint32_t b1 = sWu[(ob + j*8 + gid)*100 + k0 + tig + 4];
            MMA_TF32(acc[j], a0,a1,a2,a3, b0,b1);
        }
    }
    #pragma unroll
    for (int j = 0; j < 2; j++){
        int o0 = ob + j*8 + 2*tig;
        float inv0 = bng[o0]   * rsqrtf(1.00001f);
        float inv1 = bng[o0+1] * rsqrtf(1.00001f);
        float bb0 = bnb[o0], bb1 = bnb[o0+1];
        sO[o0*33 + prow]         = siluf(acc[j][0]*inv0 + bb0);
        sO[(o0+1)*33 + prow]     = siluf(acc[j][1]*inv1 + bb1);
        sO[o0*33 + prow + 8]     = siluf(acc[j][2]*inv0 + bb0);
        sO[(o0+1)*33 + prow + 8] = siluf(acc[j][3]*inv1 + bb1);
    }
    __syncthreads();
    for (int j = tid; j < 64*32; j += 256){
        int o = j >> 5, pp = j & 31;
        int idx = (b*CIN + o)*LL + pix0 + pp;
        out[idx] = (sO[o*33 + pp] + g_diff[idx]) * g_gate[idx];
    }
}

// ---------------- launcher ----------------
extern "C" void kernel_launch(void* const* d_in, const int* in_sizes, int n_in,
                              void* d_out, int out_size){
    const float* pre        = (const float*)d_in[0];
    const float* post       = (const float*)d_in[1];
    const float* prepost_w  = (const float*)d_in[2];
    const float* prepost_b  = (const float*)d_in[3];
    const float* prepost_g  = (const float*)d_in[4];
    const float* prepost_bb = (const float*)d_in[5];
    const float* down_w     = (const float*)d_in[6];
    const float* down_b     = (const float*)d_in[7];
    const float* down_g     = (const float*)d_in[8];
    const float* down_bb    = (const float*)d_in[9];
    const float* up_w       = (const float*)d_in[10];
    const float* up_b       = (const float*)d_in[11];
    const float* up_g       = (const float*)d_in[12];
    const float* up_bb      = (const float*)d_in[13];
    const float* pe_w       = (const float*)d_in[14];
    const float* pe_b       = (const float*)d_in[15];
    const float* pe_ln_g    = (const float*)d_in[16];
    const float* pe_ln_b    = (const float*)d_in[17];
    const float* in_proj_w  = (const float*)d_in[18];
    const float* in_proj_b  = (const float*)d_in[19];
    const float* conv_w     = (const float*)d_in[20];
    const float* conv_b     = (const float*)d_in[21];
    const float* x_proj_w   = (const float*)d_in[22];
    const float* dt_w       = (const float*)d_in[23];
    const float* dt_b       = (const float*)d_in[24];
    const float* A_log      = (const float*)d_in[25];
    const float* Ds         = (const float*)d_in[26];
    const float* out_ln_g   = (const float*)d_in[27];
    const float* out_ln_b   = (const float*)d_in[28];
    const float* out_proj_w = (const float*)d_in[29];
    const float* out_proj_b = (const float*)d_in[30];
    float* out = (float*)d_out;

    kGB<<<BB*(LL/32), 256>>>(pre, post, prepost_w, prepost_b, prepost_g, prepost_bb,
                             down_w, down_b, down_g, down_bb);
    kCD<<<BB*(LL/32), 256>>>(pe_w, pe_b, pe_ln_g, pe_ln_b, in_proj_w, in_proj_b);
    kE<<<BB*DN, 256>>>(conv_w, conv_b);
    kX<<<BB*KK*(LL/16), 256>>>(x_proj_w, dt_w, dt_b);
    kF1<<<BB*KK*(SEG-1)*(DN/8), 128>>>(A_log);
    kF2<<<(BB*KK*DN*NN)/256, 256>>>();
    kF3<<<BB*KK*SEG*(DN/8), 128>>>(A_log, Ds);
    kGH<<<BB*(LL/32), 256>>>(out_ln_g, out_ln_b, out_proj_w, out_proj_b);
    kI<<<BB*(LL/32), 256>>>(up_w, up_b, up_g, up_bb, out);
}

// round 17
// speedup vs baseline: 1.7833x; 1.0269x over previous
#include <cuda_runtime.h>
#include <math.h>
#include <stdint.h>

#define BB 4
#define CIN 64
#define CHID 96
#define LL 4096
#define NN 16
#define RR 6
#define KK 4
#define DN 192
#define SEG 4
#define SEGLEN 1024

// ---------------- static scratch (no allocation anywhere) ----------------
__device__ float g_diff [BB*CIN*LL];
__device__ float g_gate [BB*CIN*LL];
__device__ float g_d1   [BB*LL*CHID];
__device__ float g_xc   [BB*DN*LL];
__device__ float g_xcv  [BB*DN*LL];
__device__ float g_xcvT [BB*DN*LL];
__device__ float g_z    [BB*LL*DN];
__device__ float g_xs   [BB*2*LL*DN];     // only k=0,1 stored; k=2,3 are flips
__device__ float g_delta[BB*KK*LL*DN];
__device__ float g_bs   [BB*KK*LL*NN];
__device__ float g_cs   [BB*KK*LL*NN];
__device__ float g_ys   [BB*KK*LL*DN];
__device__ float g_dd   [BB*LL*CHID];
__device__ float g_P [BB*KK*DN*(SEG-1)*NN];
__device__ float g_q [BB*KK*DN*(SEG-1)*NN];
__device__ float g_h0[BB*KK*DN*SEG*NN];

#define LOG2E 1.44269504f

__device__ __forceinline__ float sigm(float x){ return 1.f/(1.f+__expf(-x)); }
__device__ __forceinline__ float siluf(float x){ return x*sigm(x); }
__device__ __forceinline__ float dot4(float4 a, float4 w, float acc){
    acc = fmaf(a.x, w.x, acc);
    acc = fmaf(a.y, w.y, acc);
    acc = fmaf(a.z, w.z, acc);
    acc = fmaf(a.w, w.w, acc);
    return acc;
}
__device__ __forceinline__ uint32_t tf32(float x){
    uint32_t r; asm("cvt.rna.tf32.f32 %0, %1;" : "=r"(r) : "f"(x)); return r;
}
#define MMA_TF32(acc, a0,a1,a2,a3, b0,b1) \
    asm volatile( \
        "mma.sync.aligned.m16n8k8.row.col.f32.tf32.tf32.f32 " \
        "{%0,%1,%2,%3},{%4,%5,%6,%7},{%8,%9},{%0,%1,%2,%3};" \
        : "+f"(acc[0]), "+f"(acc[1]), "+f"(acc[2]), "+f"(acc[3]) \
        : "r"(a0), "r"(a1), "r"(a2), "r"(a3), "r"(b0), "r"(b1))

// ---------------- kGB: fused gate (prepost x2) + diff + down-proj ----------------
__global__ void kGB(const float* __restrict__ pre, const float* __restrict__ post,
                    const float* __restrict__ w, const float* __restrict__ bias,
                    const float* __restrict__ bng, const float* __restrict__ bnb,
                    const float* __restrict__ dw, const float* __restrict__ dbias,
                    const float* __restrict__ dbng, const float* __restrict__ dbnb){
    __shared__ __align__(16) float sP[CIN*32];
    __shared__ __align__(16) float sQ[CIN*32];
    __shared__ __align__(16) float sW[CHID*CIN];
    __shared__ __align__(16) float sO[CIN*32];
    int b = blockIdx.x >> 7;
    int pix0 = (blockIdx.x & 127) * 32;
    int tid = threadIdx.x;
    for (int j = tid; j < CIN*CIN/4; j += 256)
        ((float4*)sW)[j] = ((const float4*)w)[j];
    for (int j = tid; j < CIN*32; j += 256){
        int c = j >> 5, p = j & 31;
        int idx = (b*CIN + c)*LL + pix0 + p;
        float pv = pre[idx], qv = post[idx];
        sP[j] = pv;
        sQ[j] = qv;
        g_diff[idx] = fabsf(qv - pv);
    }
    __syncthreads();
    int p = tid & 31, og = tid >> 5;
    {
        float a1[8], a2[8];
        #pragma unroll
        for (int j = 0; j < 8; j++){ a1[j] = 0.f; a2[j] = 0.f; }
        for (int kq = 0; kq < 16; kq++){
            float x1[4], x2[4];
            #pragma unroll
            for (int i = 0; i < 4; i++){
                x1[i] = sP[(kq*4+i)*32 + p];
                x2[i] = sQ[(kq*4+i)*32 + p];
            }
            #pragma unroll
            for (int j = 0; j < 8; j++){
                float4 wv = *(float4*)&sW[(og*8+j)*CIN + kq*4];
                a1[j] = fmaf(x1[0],wv.x, fmaf(x1[1],wv.y, fmaf(x1[2],wv.z, fmaf(x1[3],wv.w, a1[j]))));
                a2[j] = fmaf(x2[0],wv.x, fmaf(x2[1],wv.y, fmaf(x2[2],wv.z, fmaf(x2[3],wv.w, a2[j]))));
            }
        }
        #pragma unroll
        for (int j = 0; j < 8; j++){
            int o = og*8 + j;
            float inv = bng[o] * rsqrtf(1.00001f);
            float bz  = bias[o];
            float bb  = bnb[o];
            float t1 = (a1[j] + bz) * inv + bb;
            float t2 = (a2[j] + bz) * inv + bb;
            sO[o*32 + p] = sigm(siluf(t1)) * sigm(siluf(t2));
        }
    }
    __syncthreads();
    for (int j = tid; j < CIN*32; j += 256){
        int o = j >> 5, pp = j & 31;
        g_gate[(b*CIN + o)*LL + pix0 + pp] = sO[j];
        sP[j] = fabsf(sQ[j] - sP[j]);
    }
    for (int j = tid; j < CHID*CIN/4; j += 256)
        ((float4*)sW)[j] = ((const float4*)dw)[j];
    __syncthreads();
    {
        float acc[12];
        #pragma unroll
        for (int j = 0; j < 12; j++) acc[j] = 0.f;
        for (int kq = 0; kq < 16; kq++){
            float x[4];
            #pragma unroll
            for (int i = 0; i < 4; i++) x[i] = sP[(kq*4+i)*32 + p];
            #pragma unroll
            for (int j = 0; j < 12; j++){
                float4 wv = *(float4*)&sW[(og*12+j)*CIN + kq*4];
                acc[j] = fmaf(x[0],wv.x, fmaf(x[1],wv.y, fmaf(x[2],wv.z, fmaf(x[3],wv.w, acc[j]))));
            }
        }
        float res[12];
        #pragma unroll
        for (int j = 0; j < 12; j++){
            int o = og*12 + j;
            float inv = dbng[o] * rsqrtf(1.00001f);
            float t = (acc[j] + dbias[o]) * inv + dbnb[o];
            res[j] = siluf(t);
        }
        float4* dst = (float4*)&g_d1[(b*LL + pix0 + p)*CHID + og*12];
        #pragma unroll
        for (int v = 0; v < 3; v++)
            dst[v] = make_float4(res[v*4], res[v*4+1], res[v*4+2], res[v*4+3]);
    }
}

// ---------------- kCD: fused LN(pe(d1)) + in_proj tf32 mma ----------------
__global__ void kCD(const float* __restrict__ w, const float* __restrict__ bias,
                    const float* __restrict__ lng, const float* __restrict__ lnb,
                    const float* __restrict__ iw, const float* __restrict__ ibias){
    __shared__ __align__(16) float sMem[3200 + 6400 + 2112];
    float* sA = sMem;
    float* sW = sMem + 3200;
    float* sO = sMem + 9600;
    float* sS  = sO;
    float* sS2 = sO + 512;
    float* sM  = sO + 1024;
    float* sR  = sO + 1056;
    uint32_t* sAu = (uint32_t*)sA;
    uint32_t* sWu = (uint32_t*)sW;
    int b = blockIdx.x >> 7;
    int pix0 = (blockIdx.x & 127) * 32;
    int tid = threadIdx.x;
    for (int j = tid; j < 32*24; j += 256){
        int p = j / 24, cq = j % 24;
        *(float4*)&sA[p*100 + cq*4] = *(const float4*)&g_d1[(b*LL + pix0 + p)*CHID + cq*4];
    }
    int p = tid & 15, og = tid >> 4;
    float accC[2][6];
    #pragma unroll
    for (int j = 0; j < 6; j++){ accC[0][j] = bias[og*6+j]; accC[1][j] = accC[0][j]; }
    for (int kc = 0; kc < 2; kc++){
        __syncthreads();
        for (int j = tid; j < 96*12; j += 256){
            int o = j / 12, kq = j % 12;
            *(float4*)&sW[o*48 + kq*4] = *(const float4*)&w[o*CHID + kc*48 + kq*4];
        }
        __syncthreads();
        #pragma unroll 4
        for (int kq = 0; kq < 12; kq++){
            float4 a0 = *(float4*)&sA[p*100 + kc*48 + kq*4];
            float4 a1 = *(float4*)&sA[(p+16)*100 + kc*48 + kq*4];
            #pragma unroll
            for (int j = 0; j < 6; j++){
                float4 wv = *(float4*)&sW[(og*6+j)*48 + kq*4];
                accC[0][j] = dot4(a0, wv, accC[0][j]);
                accC[1][j] = dot4(a1, wv, accC[1][j]);
            }
        }
    }
    #pragma unroll
    for (int pi = 0; pi < 2; pi++){
        float s = 0.f, s2 = 0.f;
        #pragma unroll
        for (int j = 0; j < 6; j++){ s += accC[pi][j]; s2 += accC[pi][j]*accC[pi][j]; }
        sS [(p + pi*16)*16 + og] = s;
        sS2[(p + pi*16)*16 + og] = s2;
    }
    __syncthreads();
    if (tid < 32){
        float ss = 0.f, ss2 = 0.f;
        #pragma unroll
        for (int i = 0; i < 16; i++){ ss += sS[tid*16+i]; ss2 += sS2[tid*16+i]; }
        float m = ss * (1.f/96.f);
        float var = ss2 * (1.f/96.f) - m*m;
        sM[tid] = m;  sR[tid] = rsqrtf(var + 1e-5f);
    }
    __syncthreads();
    #pragma unroll
    for (int pi = 0; pi < 2; pi++){
        int pp = p + pi*16;
        float m = sM[pp], rs = sR[pp];
        #pragma unroll
        for (int j = 0; j < 6; j++){
            int o = og*6 + j;
            sAu[pp*100 + o] = tf32((accC[pi][j] - m) * rs * lng[o] + lnb[o]);
        }
    }
    int wid = tid >> 5, lane = tid & 31;
    int gid = lane >> 2, tig = lane & 3;
    int pt = wid & 1;
    int ob = (wid >> 1) * 16;
    int prow = pt*16 + gid;
    for (int ch = 0; ch < 6; ch++){
        __syncthreads();
        for (int j = tid; j < 64*24; j += 256){
            int o = j / 24, kq = j % 24;
            float4 v = *(const float4*)&iw[(ch*64 + o)*CHID + kq*4];
            uint32_t* dst = &sWu[o*100 + kq*4];
            dst[0] = tf32(v.x); dst[1] = tf32(v.y); dst[2] = tf32(v.z); dst[3] = tf32(v.w);
        }
        __syncthreads();
        float acc[2][4];
        #pragma unroll
        for (int j = 0; j < 2; j++){
            float b0v = ibias[ch*64 + ob + j*8 + 2*tig];
            float b1v = ibias[ch*64 + ob + j*8 + 2*tig + 1];
            acc[j][0] = b0v; acc[j][1] = b1v; acc[j][2] = b0v; acc[j][3] = b1v;
        }
        #pragma unroll 4
        for (int s = 0; s < 12; s++){
            int k0 = s*8;
            uint32_t a0 = sAu[prow*100     + k0 + tig];
            uint32_t a1 = sAu[(prow+8)*100 + k0 + tig];
            uint32_t a2 = sAu[prow*100     + k0 + tig + 4];
            uint32_t a3 = sAu[(prow+8)*100 + k0 + tig + 4];
            #pragma unroll
            for (int j = 0; j < 2; j++){
                uint32_t b0 = sWu[(ob + j*8 + gid)*100 + k0 + tig];
                uint32_t b1 = sWu[(ob + j*8 + gid)*100 + k0 + tig + 4];
                MMA_TF32(acc[j], a0,a1,a2,a3, b0,b1);
            }
        }
        #pragma unroll
        for (int j = 0; j < 2; j++){
            int o0 = ob + j*8 + 2*tig;
            sO[o0*33 + prow]         = acc[j][0];
            sO[(o0+1)*33 + prow]     = acc[j][1];
            sO[o0*33 + prow + 8]     = acc[j][2];
            sO[(o0+1)*33 + prow + 8] = acc[j][3];
        }
        __syncthreads();
        if (ch < 3){
            for (int j = tid; j < 64*32; j += 256){
                int o = j >> 5, pp = j & 31;
                g_xc[(b*DN + ch*64 + o)*LL + pix0 + pp] = sO[o*33 + pp];
            }
        } else {
            for (int j = tid; j < 32*64; j += 256){
                int pp = j >> 6, oz = j & 63;
                g_z[(b*LL + pix0 + pp)*DN + (ch-3)*64 + oz] = sO[oz*33 + pp];
            }
        }
    }
}

// ---------------- kE: depthwise 3x3 conv + silu; writes g_xcv and g_xcvT ---------
__global__ void kE(const float* __restrict__ cw, const float* __restrict__ cb){
    __shared__ float sT[66*66];
    __shared__ float sO[64*65];
    int bd = blockIdx.x;
    int d  = bd % DN;
    int tid = threadIdx.x;
    const float* src = g_xc + bd*LL;
    for (int j = tid; j < 66*66; j += 256){
        int rr = j / 66, cc = j % 66;
        int r = rr - 1, c = cc - 1;
        float v = 0.f;
        if (r >= 0 && r < 64 && c >= 0 && c < 64) v = src[r*64 + c];
        sT[j] = v;
    }
    float w9[9];
    #pragma unroll
    for (int i = 0; i < 9; i++) w9[i] = cw[d*9 + i];
    float bz = cb[d];
    __syncthreads();
    for (int j = tid; j < 64*64; j += 256){
        int r = j >> 6, c = j & 63;
        float s = bz;
        #pragma unroll
        for (int ky = 0; ky < 3; ky++)
            #pragma unroll
            for (int kx = 0; kx < 3; kx++)
                s = fmaf(w9[ky*3+kx], sT[(r+ky)*66 + c + kx], s);
        sO[r*65 + c] = siluf(s);
    }
    __syncthreads();
    float* dst  = g_xcv  + bd*LL;
    float* dstT = g_xcvT + bd*LL;
    for (int j = tid; j < 64*64; j += 256){
        int r = j >> 6, c = j & 63;
        dst[j]  = sO[r*65 + c];
        dstT[j] = sO[c*65 + r];
    }
}

// ---------------- kX v6: direction-paired; one gather serves k and k+2 -------------
// grid = BB*2*(LL/16); bid -> (tile 256, kp 2, b)
__global__ void kX(const float* __restrict__ xpw, const float* __restrict__ dtw,
                   const float* __restrict__ dtb){
    __shared__ __align__(16) float sxs[16*196];
    __shared__ __align__(16) float sWk[40*100];
    __shared__ __align__(16) float sdtw[2*DN*6];
    __shared__ __align__(16) float sdt[6*17];
    uint32_t* sxu = (uint32_t*)sxs;
    uint32_t* sWu = (uint32_t*)sWk;
    int tile = blockIdx.x & 255;
    int kp   = (blockIdx.x >> 8) & 1;
    int b    = blockIdx.x >> 9;
    int t0   = tile * 16;
    int tid  = threadIdx.x;
    int wid = tid >> 5, lane = tid & 31;
    int gid = lane >> 2, tig = lane & 3;

    // both dt weight sets (kp and kp+2)
    for (int j = tid; j < DN*3; j += 256){
        ((float2*)sdtw)[j]        = ((const float2*)(dtw + kp*DN*6))[j];
        ((float2*)sdtw)[j + DN*3] = ((const float2*)(dtw + (kp+2)*DN*6))[j];
    }
    // coalesced forward gather from the kp plane
    {
        const float* src = kp ? g_xcvT : g_xcv;
        for (int j = tid; j < DN*4; j += 256){
            int d = j >> 2, q = j & 3;
            float4 v = *(const float4*)&src[(b*DN + d)*LL + t0 + q*4];
            int j0 = q*4;
            sxs[(j0+0)*196 + d] = v.x;
            sxs[(j0+1)*196 + d] = v.y;
            sxs[(j0+2)*196 + d] = v.z;
            sxs[(j0+3)*196 + d] = v.w;
        }
    }
    __syncthreads();
    {
        int xbase = (b*2 + kp)*LL;
        for (int j = tid; j < 16*48; j += 256){
            int tt = j / 48, dq = j % 48;
            *(float4*)&g_xs[(xbase + t0 + tt)*DN + dq*4] = *(float4*)&sxs[tt*196 + dq*4];
        }
    }
    __syncthreads();
    for (int j = tid; j < 16*DN; j += 256){
        int tt = j / 192, d = j - tt*192;
        sxu[tt*196 + d] = tf32(sxs[tt*196 + d]);
    }
    for (int half = 0; half < 2; half++){
        int kdir = kp + half*2;
        int base = (b*KK + kdir)*LL;
        float acc[4] = {0.f, 0.f, 0.f, 0.f};
        for (int kc = 0; kc < 2; kc++){
            __syncthreads();   // guards sWk reuse + (first entry) sxu convert + sdt reuse
            for (int j = tid; j < 40*24; j += 256){
                int c = j / 24, kq = j % 24;
                uint32_t* dst = &sWu[c*100 + kq*4];
                if (c < 38){
                    float4 v = *(const float4*)&xpw[(kdir*38 + c)*DN + kc*96 + kq*4];
                    dst[0] = tf32(v.x); dst[1] = tf32(v.y); dst[2] = tf32(v.z); dst[3] = tf32(v.w);
                } else {
                    dst[0] = 0u; dst[1] = 0u; dst[2] = 0u; dst[3] = 0u;
                }
            }
            __syncthreads();
            if (wid < 5){
                #pragma unroll 4
                for (int s = 0; s < 12; s++){
                    int kg = kc*96 + s*8;
                    uint32_t a0 = sxu[gid*196     + kg + tig];
                    uint32_t a1 = sxu[(gid+8)*196 + kg + tig];
                    uint32_t a2 = sxu[gid*196     + kg + tig + 4];
                    uint32_t a3 = sxu[(gid+8)*196 + kg + tig + 4];
                    uint32_t b0 = sWu[(wid*8 + gid)*100 + s*8 + tig];
                    uint32_t b1 = sWu[(wid*8 + gid)*100 + s*8 + tig + 4];
                    MMA_TF32(acc, a0,a1,a2,a3, b0,b1);
                }
            }
        }
        __syncthreads();
        // scatter: rows gid, gid+8 -> scan times (fwd) or mirrored (half=1)
        if (wid < 5){
            int st0 = half ? (LL-1 - (t0 + gid))     : (t0 + gid);
            int st1 = half ? (LL-1 - (t0 + gid + 8)) : (t0 + gid + 8);
            #pragma unroll
            for (int jj = 0; jj < 2; jj++){
                int c = wid*8 + 2*tig + jj;
                float v0 = acc[jj];
                float v1 = acc[2 + jj];
                if (c < RR){
                    sdt[c*17 + gid]     = v0;
                    sdt[c*17 + gid + 8] = v1;
                } else if (c < RR + NN){
                    g_bs[(base + st0)*NN + (c - RR)] = v0;
                    g_bs[(base + st1)*NN + (c - RR)] = v1;
                } else if (c < RR + 2*NN){
                    g_cs[(base + st0)*NN + (c - RR - NN)] = v0;
                    g_cs[(base + st1)*NN + (c - RR - NN)] = v1;
                }
            }
        }
        __syncthreads();
        // dt GEMM + softplus, direct g_delta store
        {
            int tt = tid & 15, dq = tid >> 4;
            const float* dtwl = &sdtw[half*DN*6];
            float a2[12];
            #pragma unroll
            for (int j = 0; j < 12; j++) a2[j] = dtb[kdir*DN + dq*12 + j];
            float dts[6];
            #pragma unroll
            for (int r = 0; r < RR; r++) dts[r] = sdt[r*17 + tt];
            float res[12];
            #pragma unroll
            for (int j = 0; j < 12; j++){
                int d = dq*12 + j;
                float a = a2[j];
                #pragma unroll
                for (int r = 0; r < RR; r++)
                    a = fmaf(dts[r], dtwl[d*6 + r], a);
                res[j] = (a > 20.f) ? a : log1pf(__expf(a));
            }
            int strow = half ? (LL-1 - (t0 + tt)) : (t0 + tt);
            float4* dst = (float4*)&g_delta[(base + strow)*DN + dq*12];
            dst[0] = make_float4(res[0], res[1], res[2],  res[3]);
            dst[1] = make_float4(res[4], res[5], res[6],  res[7]);
            dst[2] = make_float4(res[8], res[9], res[10], res[11]);
        }
    }
}

// ---------------- kF1: per-segment P (one exp) and offset q; packed DU ----------------
__global__ void kF1(const float* __restrict__ A_log){
    __shared__ __align__(16) float sDU[16*8*2];
    __shared__ __align__(16) float sB[16*16];
    __shared__ float sSum[8];
    int bid = blockIdx.x;
    int dg = (bid % 24) * 8;
    int s  = (bid / 24) % (SEG-1);
    int k  = (bid / (24*(SEG-1))) % 4;
    int b  = bid / (24*(SEG-1)*4);
    int tid = threadIdx.x;
    int ch = tid >> 4, n = tid & 15;
    int d  = dg + ch;
    int base = (b*KK + k)*LL + s*SEGLEN;
    int xrow = (b*2 + (k & 1))*LL;
    bool rev = (k >= 2);

    float a = -__expf(A_log[(k*DN + d)*NN + n]) * LOG2E;
    float h = 0.f;

    int lt = tid >> 3, lc = tid & 7;
    float dsum = 0.f;
    float rD, rX, rB[2];
    {
        int t_abs = s*SEGLEN + lt;
        int xr = rev ? (LL-1 - t_abs) : t_abs;
        rD = g_delta[(base + lt)*DN + dg + lc];
        rX = g_xs   [(xrow + xr)*DN + dg + lc];
    }
    #pragma unroll
    for (int i = 0; i < 2; i++){
        int jj = tid + i*128;
        rB[i] = g_bs[base*NN + jj];
    }
    for (int chunk = 0; chunk < SEGLEN/16; chunk++){
        *(float2*)&sDU[tid*2] = make_float2(rD, rD * rX);
        sB[tid] = rB[0];  sB[tid+128] = rB[1];
        dsum += rD;
        __syncthreads();
        if (chunk < SEGLEN/16 - 1){
            int t0n = (chunk + 1) * 16;
            int t_abs = s*SEGLEN + t0n + lt;
            int xr = rev ? (LL-1 - t_abs) : t_abs;
            rD = g_delta[(base + t0n + lt)*DN + dg + lc];
            rX = g_xs   [(xrow + xr)*DN + dg + lc];
            #pragma unroll
            for (int i = 0; i < 2; i++){
                int jj = tid + i*128;
                rB[i] = g_bs[(base + t0n)*NN + jj];
            }
        }
        #pragma unroll
        for (int t = 0; t < 16; t++){
            float2 du = *(float2*)&sDU[(t*8 + ch)*2];
            float Bn = sB[t*16 + n];
            float e  = exp2f(du.x * a);
            h = fmaf(e, h, du.y * Bn);
        }
        __syncthreads();
    }
    sDU[lt*8 + lc] = dsum;
    __syncthreads();
    if (tid < 8){
        float S = 0.f;
        #pragma unroll
        for (int i = 0; i < 16; i++) S += sDU[i*8 + tid];
        sSum[tid] = S;
    }
    __syncthreads();
    float P = exp2f(a * sSum[ch]);
    int chain = (b*KK + k)*DN + d;
    g_P[(chain*(SEG-1) + s)*NN + n] = P;
    g_q[(chain*(SEG-1) + s)*NN + n] = h;
}

// ---------------- kF2: prefix over segments -> g_h0 ----------------
__global__ void kF2(){
    int gid = blockIdx.x*blockDim.x + threadIdx.x;
    int chain = gid >> 4, n = gid & 15;
    float h = 0.f;
    g_h0[(chain*SEG + 0)*NN + n] = 0.f;
    #pragma unroll
    for (int s = 0; s < SEG-1; s++){
        float P = g_P[(chain*(SEG-1) + s)*NN + n];
        float q = g_q[(chain*(SEG-1) + s)*NN + n];
        h = fmaf(P, h, q);
        g_h0[(chain*SEG + s + 1)*NN + n] = h;
    }
}

// ---------------- kF3: packed DU/BC, smem transpose-reduce ----------------
__global__ void kF3(const float* __restrict__ A_log, const float* __restrict__ Ds){
    __shared__ __align__(16) float sDU[16*8*2];
    __shared__ __align__(16) float sBC[16*16*2];
    __shared__ __align__(16) float sP[NN*129];
    int bid = blockIdx.x;
    int dg = (bid % 24) * 8;
    int s  = (bid / 24) % SEG;
    int k  = (bid / (24*SEG)) % 4;
    int b  = bid / (24*SEG*4);
    int tid = threadIdx.x;
    int ch = tid >> 4, n = tid & 15;
    int d  = dg + ch;
    int base = (b*KK + k)*LL + s*SEGLEN;
    int chain = (b*KK + k)*DN + d;
    int xrow = (b*2 + (k & 1))*LL;
    bool rev = (k >= 2);

    float a  = -__expf(A_log[(k*DN + d)*NN + n]) * LOG2E;
    float h  = g_h0[(chain*SEG + s)*NN + n];

    int lt = tid >> 3, lc = tid & 7;
    float Dv2 = Ds[k*DN + dg + lc];
    float rD, rX, rB[2], rC[2];
    {
        int t_abs = s*SEGLEN + lt;
        int xr = rev ? (LL-1 - t_abs) : t_abs;
        rD = g_delta[(base + lt)*DN + dg + lc];
        rX = g_xs   [(xrow + xr)*DN + dg + lc];
    }
    #pragma unroll
    for (int i = 0; i < 2; i++){
        int jj = tid + i*128;
        rB[i] = g_bs[base*NN + jj];
        rC[i] = g_cs[base*NN + jj];
    }
    for (int chunk = 0; chunk < SEGLEN/16; chunk++){
        *(float2*)&sDU[tid*2] = make_float2(rD, rD * rX);
        *(float2*)&sBC[tid*2]       = make_float2(rB[0], rC[0]);
        *(float2*)&sBC[(tid+128)*2] = make_float2(rB[1], rC[1]);
        float xCur = rX;
        __syncthreads();
        if (chunk < SEGLEN/16 - 1){
            int t0n = (chunk + 1) * 16;
            int t_abs = s*SEGLEN + t0n + lt;
            int xr = rev ? (LL-1 - t_abs) : t_abs;
            rD = g_delta[(base + t0n + lt)*DN + dg + lc];
            rX = g_xs   [(xrow + xr)*DN + dg + lc];
            #pragma unroll
            for (int i = 0; i < 2; i++){
                int jj = tid + i*128;
                rB[i] = g_bs[(base + t0n)*NN + jj];
                rC[i] = g_cs[(base + t0n)*NN + jj];
            }
        }
        #pragma unroll
        for (int t = 0; t < 16; t++){
            float2 du = *(float2*)&sDU[(t*8 + ch)*2];
            float2 bc = *(float2*)&sBC[(t*16 + n)*2];
            float e  = exp2f(du.x * a);
            h = fmaf(e, h, du.y * bc.x);
            sP[n*129 + t*8 + ch] = h * bc.y;
        }
        __syncthreads();
        {
            float y = Dv2 * xCur;
            #pragma unroll
            for (int nn = 0; nn < NN; nn++)
                y += sP[nn*129 + tid];
            g_ys[(base + chunk*16 + lt)*DN + dg + lc] = y;
        }
    }
}

// ---------------- kGH: combine + LN + gate, then tf32 mma out_proj -> g_dd ----------
__global__ void kGH(const float* __restrict__ lng, const float* __restrict__ lnb,
                    const float* __restrict__ w, const float* __restrict__ bias){
    __shared__ __align__(16) float sA[32*196];
    __shared__ __align__(16) float sW[96*52];
    __shared__ __align__(16) float sS[256];
    __shared__ __align__(16) float sS2[256];
    __shared__ float sM[32], sR[32];
    uint32_t* sAu = (uint32_t*)sA;
    uint32_t* sWu = (uint32_t*)sW;
    int b = blockIdx.x >> 7;
    int pix0 = (blockIdx.x & 127) * 32;
    int tid = threadIdx.x;
    int tp = tid >> 3, tc = tid & 7;
    int l  = pix0 + tp;
    int hh = l >> 6, ww = l & 63;
    int t1 = ww*64 + hh;
    int b4 = b*KK*LL;
    const float* r0 = &g_ys[(b4 + l)*DN];
    const float* r1 = &g_ys[(b4 + 1*LL + t1)*DN];
    const float* r2 = &g_ys[(b4 + 2*LL + (LL-1-l))*DN];
    const float* r3 = &g_ys[(b4 + 3*LL + (LL-1-t1))*DN];
    float vloc[24];
    float s = 0.f, s2 = 0.f;
    #pragma unroll
    for (int jq = 0; jq < 6; jq++){
        int c = tc*24 + jq*4;
        float4 a0 = *(const float4*)&r0[c];
        float4 a1 = *(const float4*)&r1[c];
        float4 a2 = *(const float4*)&r2[c];
        float4 a3 = *(const float4*)&r3[c];
        float v0 = a0.x + a1.x + a2.x + a3.x;
        float v1 = a0.y + a1.y + a2.y + a3.y;
        float v2 = a0.z + a1.z + a2.z + a3.z;
        float v3 = a0.w + a1.w + a2.w + a3.w;
        vloc[jq*4+0] = v0; vloc[jq*4+1] = v1; vloc[jq*4+2] = v2; vloc[jq*4+3] = v3;
        s  += v0 + v1 + v2 + v3;
        s2 += v0*v0 + v1*v1 + v2*v2 + v3*v3;
    }
    sS[tid] = s;  sS2[tid] = s2;
    __syncthreads();
    if (tid < 32){
        float ss = 0.f, ss2 = 0.f;
        #pragma unroll
        for (int i = 0; i < 8; i++){ ss += sS[tid*8+i]; ss2 += sS2[tid*8+i]; }
        float m = ss * (1.f/192.f);
        float var = ss2 * (1.f/192.f) - m*m;
        sM[tid] = m;  sR[tid] = rsqrtf(var + 1e-5f);
    }
    __syncthreads();
    {
        float m = sM[tp], rs = sR[tp];
        const float* zrow = &g_z[(b*LL + l)*DN];
        #pragma unroll
        for (int jq = 0; jq < 6; jq++){
            int c = tc*24 + jq*4;
            float4 zv = *(const float4*)&zrow[c];
            float4 gv = *(const float4*)&lng[c];
            float4 bv = *(const float4*)&lnb[c];
            sAu[tp*196 + c + 0] = tf32(((vloc[jq*4+0]-m)*rs*gv.x + bv.x) * siluf(zv.x));
            sAu[tp*196 + c + 1] = tf32(((vloc[jq*4+1]-m)*rs*gv.y + bv.y) * siluf(zv.y));
            sAu[tp*196 + c + 2] = tf32(((vloc[jq*4+2]-m)*rs*gv.z + bv.z) * siluf(zv.z));
            sAu[tp*196 + c + 3] = tf32(((vloc[jq*4+3]-m)*rs*gv.w + bv.w) * siluf(zv.w));
        }
    }
    int wid = tid >> 5, lane = tid & 31;
    int gid = lane >> 2, tig = lane & 3;
    int pt = wid & 1;
    int ob = (wid >> 1) * 24;
    int prow = pt*16 + gid;
    float acc[3][4];
    #pragma unroll
    for (int j = 0; j < 3; j++){
        float b0v = bias[ob + j*8 + 2*tig];
        float b1v = bias[ob + j*8 + 2*tig + 1];
        acc[j][0] = b0v; acc[j][1] = b1v; acc[j][2] = b0v; acc[j][3] = b1v;
    }
    for (int kc = 0; kc < 4; kc++){
        __syncthreads();
        for (int j = tid; j < 96*12; j += 256){
            int o = j / 12, kq = j % 12;
            float4 v = *(const float4*)&w[o*DN + kc*48 + kq*4];
            uint32_t* dst = &sWu[o*52 + kq*4];
            dst[0] = tf32(v.x); dst[1] = tf32(v.y); dst[2] = tf32(v.z); dst[3] = tf32(v.w);
        }
        __syncthreads();
        #pragma unroll
        for (int sgl = 0; sgl < 6; sgl++){
            int kg = kc*48 + sgl*8;
            uint32_t a0 = sAu[prow*196     + kg + tig];
            uint32_t a1 = sAu[(prow+8)*196 + kg + tig];
            uint32_t a2 = sAu[prow*196     + kg + tig + 4];
            uint32_t a3 = sAu[(prow+8)*196 + kg + tig + 4];
            int kl = sgl*8;
            #pragma unroll
            for (int j = 0; j < 3; j++){
                uint32_t b0 = sWu[(ob + j*8 + gid)*52 + kl + tig];
                uint32_t b1 = sWu[(ob + j*8 + gid)*52 + kl + tig + 4];
                MMA_TF32(acc[j], a0,a1,a2,a3, b0,b1);
            }
        }
    }
    __syncthreads();
    float* st = sW;
    #pragma unroll
    for (int j = 0; j < 3; j++){
        int o0 = ob + j*8 + 2*tig;
        st[o0*33 + prow]         = acc[j][0];
        st[(o0+1)*33 + prow]     = acc[j][1];
        st[o0*33 + prow + 8]     = acc[j][2];
        st[(o0+1)*33 + prow + 8] = acc[j][3];
    }
    __syncthreads();
    for (int j = tid; j < 32*96; j += 256){
        int pp = j / 96, o = j % 96;
        g_dd[(b*LL + pix0 + pp)*CHID + o] = st[o*33 + pp];
    }
}

// ---------------- kI: up-proj via tf32 mma + bn + silu + residual + gate ------------
__global__ void kI(const float* __restrict__ w, const float* __restrict__ bias,
                   const float* __restrict__ bng, const float* __restrict__ bnb,
                   float* __restrict__ out){
    __shared__ __align__(16) float sA[32*100];
    __shared__ __align__(16) float sW[64*100];
    __shared__ __align__(16) float sO[64*33];
    uint32_t* sAu = (uint32_t*)sA;
    uint32_t* sWu = (uint32_t*)sW;
    int b = blockIdx.x >> 7;
    int pix0 = (blockIdx.x & 127) * 32;
    int tid = threadIdx.x;
    int wid = tid >> 5, lane = tid & 31;
    int gid = lane >> 2, tig = lane & 3;
    int pt = wid & 1;
    int ob = (wid >> 1) * 16;
    int prow = pt*16 + gid;

    for (int j = tid; j < 32*24; j += 256){
        int p = j / 24, cq = j % 24;
        float4 v = *(const float4*)&g_dd[(b*LL + pix0 + p)*CHID + cq*4];
        uint32_t* dst = &sAu[p*100 + cq*4];
        dst[0] = tf32(v.x); dst[1] = tf32(v.y); dst[2] = tf32(v.z); dst[3] = tf32(v.w);
    }
    for (int j = tid; j < 64*24; j += 256){
        int o = j / 24, kq = j % 24;
        float4 v = *(const float4*)&w[o*CHID + kq*4];
        uint32_t* dst = &sWu[o*100 + kq*4];
        dst[0] = tf32(v.x); dst[1] = tf32(v.y); dst[2] = tf32(v.z); dst[3] = tf32(v.w);
    }
    __syncthreads();
    float acc[2][4];
    #pragma unroll
    for (int j = 0; j < 2; j++){
        float b0v = bias[ob + j*8 + 2*tig];
        float b1v = bias[ob + j*8 + 2*tig + 1];
        acc[j][0] = b0v; acc[j][1] = b1v; acc[j][2] = b0v; acc[j][3] = b1v;
    }
    #pragma unroll 4
    for (int s = 0; s < 12; s++){
        int k0 = s*8;
        uint32_t a0 = sAu[prow*100     + k0 + tig];
        uint32_t a1 = sAu[(prow+8)*100 + k0 + tig];
        uint32_t a2 = sAu[prow*100     + k0 + tig + 4];
        uint32_t a3 = sAu[(prow+8)*100 + k0 + tig + 4];
        #pragma unroll
        for (int j = 0; j < 2; j++){
            uint32_t b0 = sWu[(ob + j*8 + gid)*100 + k0 + tig];
            uint32_t b1 = sWu[(ob + j*8 + gid)*100 + k0 + tig + 4];
            MMA_TF32(acc[j], a0,a1,a2,a3, b0,b1);
        }
    }
    #pragma unroll
    for (int j = 0; j < 2; j++){
        int o0 = ob + j*8 + 2*tig;
        float inv0 = bng[o0]   * rsqrtf(1.00001f);
        float inv1 = bng[o0+1] * rsqrtf(1.00001f);
        float bb0 = bnb[o0], bb1 = bnb[o0+1];
        sO[o0*33 + prow]         = siluf(acc[j][0]*inv0 + bb0);
        sO[(o0+1)*33 + prow]     = siluf(acc[j][1]*inv1 + bb1);
        sO[o0*33 + prow + 8]     = siluf(acc[j][2]*inv0 + bb0);
        sO[(o0+1)*33 + prow + 8] = siluf(acc[j][3]*inv1 + bb1);
    }
    __syncthreads();
    for (int j = tid; j < 64*32; j += 256){
        int o = j >> 5, pp = j & 31;
        int idx = (b*CIN + o)*LL + pix0 + pp;
        out[idx] = (sO[o*33 + pp] + g_diff[idx]) * g_gate[idx];
    }
}

// ---------------- launcher ----------------
extern "C" void kernel_launch(void* const* d_in, const int* in_sizes, int n_in,
                              void* d_out, int out_size){
    const float* pre        = (const float*)d_in[0];
    const float* post       = (const float*)d_in[1];
    const float* prepost_w  = (const float*)d_in[2];
    const float* prepost_b  = (const float*)d_in[3];
    const float* prepost_g  = (const float*)d_in[4];
    const float* prepost_bb = (const float*)d_in[5];
    const float* down_w     = (const float*)d_in[6];
    const float* down_b     = (const float*)d_in[7];
    const float* down_g     = (const float*)d_in[8];
    const float* down_bb    = (const float*)d_in[9];
    const float* up_w       = (const float*)d_in[10];
    const float* up_b       = (const float*)d_in[11];
    const float* up_g       = (const float*)d_in[12];
    const float* up_bb      = (const float*)d_in[13];
    const float* pe_w       = (const float*)d_in[14];
    const float* pe_b       = (const float*)d_in[15];
    const float* pe_ln_g    = (const float*)d_in[16];
    const float* pe_ln_b    = (const float*)d_in[17];
    const float* in_proj_w  = (const float*)d_in[18];
    const float* in_proj_b  = (const float*)d_in[19];
    const float* conv_w     = (const float*)d_in[20];
    const float* conv_b     = (const float*)d_in[21];
    const float* x_proj_w   = (const float*)d_in[22];
    const float* dt_w       = (const float*)d_in[23];
    const float* dt_b       = (const float*)d_in[24];
    const float* A_log      = (const float*)d_in[25];
    const float* Ds         = (const float*)d_in[26];
    const float* out_ln_g   = (const float*)d_in[27];
    const float* out_ln_b   = (const float*)d_in[28];
    const float* out_proj_w = (const float*)d_in[29];
    const float* out_proj_b = (const float*)d_in[30];
    float* out = (float*)d_out;

    kGB<<<BB*(LL/32), 256>>>(pre, post, prepost_w, prepost_b, prepost_g, prepost_bb,
                             down_w, down_b, down_g, down_bb);
    kCD<<<BB*(LL/32), 256>>>(pe_w, pe_b, pe_ln_g, pe_ln_b, in_proj_w, in_proj_b);
    kE<<<BB*DN, 256>>>(conv_w, conv_b);
    kX<<<BB*2*(LL/16), 256>>>(x_proj_w, dt_w, dt_b);
    kF1<<<BB*KK*(SEG-1)*(DN/8), 128>>>(A_log);
    kF2<<<(BB*KK*DN*NN)/256, 256>>>();
    kF3<<<BB*KK*SEG*(DN/8), 128>>>(A_log, Ds);
    kGH<<<BB*(LL/32), 256>>>(out_ln_g, out_ln_b, out_proj_w, out_proj_b);
    kI<<<BB*(LL/32), 256>>>(up_w, up_b, up_g, up_bb, out);
}